// round 5
// baseline (speedup 1.0000x reference)
#include <cuda_runtime.h>
#include <math.h>
#include <stdint.h>

#define BB 4
#define LL 2048
#define DD 1024
#define HH 16
#define HDIM 64
#define KK 24
#define MLPD 4096
#define BL (BB*LL)
#define NF 4096

// ---------------- scratch (device globals; allocation-free) ----------------
__device__ float  g_xi[BL*DD];
__device__ float  g_xt[BL*DD];
__device__ float2 g_Ffilt[(size_t)DD*NF];
__device__ float  g_projt[BL*DD];
__device__ float  g_stu[BL*DD];
__device__ float  g_x1[BL*DD];
__device__ float  g_q[BL*DD];
__device__ float  g_k[BL*DD];
__device__ float  g_v[BL*DD];
__device__ float  g_scores[(size_t)BB*HH*LL*LL];   // 1 GB
__device__ float  g_att[BL*DD];
__device__ float  g_xres[BL*DD];
__device__ float  g_y1[BL*DD];
__device__ float  g_h[(size_t)BL*MLPD];

// ---------------- helpers ----------------
__device__ __forceinline__ float gelu_f(float x) {
    float x3 = x*x*x;
    return 0.5f*x*(1.0f + tanhf(0.7978845608028654f*(x + 0.044715f*x3)));
}

// packed fp32x2 FMA (Blackwell 2xFP32 pipe; only reachable via PTX)
__device__ __forceinline__ void ffma2(unsigned long long &d,
                                      unsigned long long a,
                                      unsigned long long b) {
    asm("fma.rn.f32x2 %0, %1, %2, %0;" : "+l"(d) : "l"(a), "l"(b));
}
__device__ __forceinline__ float ull_lo(unsigned long long u) {
    return __uint_as_float((unsigned int)(u & 0xffffffffULL));
}
__device__ __forceinline__ float ull_hi(unsigned long long u) {
    return __uint_as_float((unsigned int)(u >> 32));
}

__device__ __forceinline__ float block_sum256(float v) {
    __shared__ float red[8];
    int lane = threadIdx.x & 31, w = threadIdx.x >> 5;
    #pragma unroll
    for (int o = 16; o; o >>= 1) v += __shfl_xor_sync(0xffffffffu, v, o);
    __syncthreads();
    if (lane == 0) red[w] = v;
    __syncthreads();
    if (threadIdx.x == 0) {
        float s = 0.f;
        #pragma unroll
        for (int i = 0; i < 8; i++) s += red[i];
        red[0] = s;
    }
    __syncthreads();
    return red[0];
}

__device__ __forceinline__ float block_max256(float v) {
    __shared__ float red[8];
    int lane = threadIdx.x & 31, w = threadIdx.x >> 5;
    #pragma unroll
    for (int o = 16; o; o >>= 1) v = fmaxf(v, __shfl_xor_sync(0xffffffffu, v, o));
    __syncthreads();
    if (lane == 0) red[w] = v;
    __syncthreads();
    if (threadIdx.x == 0) {
        float s = red[0];
        #pragma unroll
        for (int i = 1; i < 8; i++) s = fmaxf(s, red[i]);
        red[0] = s;
    }
    __syncthreads();
    return red[0];
}

// ---------------- tiled SGEMM with packed f32x2 microkernel ----------------
// C = alpha*(A @ B[ᵀ]) (+bias[n]) (gelu) (+resid); 2-component batch strides.
// mode bits: 1=bias, 2=gelu, 4=resid
// Tile: 128 x (32*JW). JW=4 -> N-tile 128 ; JW=2 -> N-tile 64.
// A is stored DUPLICATED in shared so (a,a) broadcast pairs load via LDS.128.
template<int TB, int JW>
__global__ void __launch_bounds__(256) sgemm(
    const float* __restrict__ A, const float* __restrict__ Bm, float* __restrict__ C,
    int M, int N, int Kd, int lda, int ldb, int ldc,
    long long sA1, long long sA2, long long sB1, long long sB2,
    long long sC1, long long sC2, int bdiv,
    float alpha, const float* __restrict__ bias,
    const float* __restrict__ resid, int mode)
{
    __shared__ __align__(16) float As[8][264];   // duplicated A: [kk][2*row{+0,1}]
    __shared__ __align__(16) float Bs[8][132];

    const int NT = 32 * JW;     // N tile width

    int z  = blockIdx.z;
    int z1 = z / bdiv, z2 = z - z1*bdiv;
    A  += (long long)z1*sA1 + (long long)z2*sA2;
    Bm += (long long)z1*sB1 + (long long)z2*sB2;
    long long offC = (long long)z1*sC1 + (long long)z2*sC2;
    C  += offC;
    const float* R = (mode & 4) ? (resid + offC) : nullptr;

    int tid   = threadIdx.x;
    int mBase = blockIdx.y * 128, nBase = blockIdx.x * NT;
    int arow  = tid >> 1;
    int ac4   = (tid & 1) << 2;
    int brow  = tid >> 5;
    int bc4   = (tid & 31) << 2;
    int rb    = (tid >> 4) << 3;            // 8 rows per thread
    int cb    = (tid & 15) * (2 * JW);      // 2*JW cols per thread

    unsigned long long acc[8][JW];
    #pragma unroll
    for (int i = 0; i < 8; i++)
        #pragma unroll
        for (int j = 0; j < JW; j++) acc[i][j] = 0ULL;

    for (int k0 = 0; k0 < Kd; k0 += 8) {
        // load A column-slab, store duplicated
        float4 av = make_float4(0.f,0.f,0.f,0.f);
        if (mBase + arow < M)
            av = *(const float4*)(A + (long long)(mBase+arow)*lda + (k0 + ac4));
        As[ac4+0][2*arow] = av.x; As[ac4+0][2*arow+1] = av.x;
        As[ac4+1][2*arow] = av.y; As[ac4+1][2*arow+1] = av.y;
        As[ac4+2][2*arow] = av.z; As[ac4+2][2*arow+1] = av.z;
        As[ac4+3][2*arow] = av.w; As[ac4+3][2*arow+1] = av.w;

        if (TB == 0) {
            if (bc4 < NT) {
                float4 bv = make_float4(0.f,0.f,0.f,0.f);
                if (nBase + bc4 < N)
                    bv = *(const float4*)(Bm + (long long)(k0+brow)*ldb + (nBase + bc4));
                *(float4*)&Bs[brow][bc4] = bv;
            }
        } else {
            if (arow < NT) {
                float4 bv = make_float4(0.f,0.f,0.f,0.f);
                if (nBase + arow < N)
                    bv = *(const float4*)(Bm + (long long)(nBase+arow)*ldb + (k0 + ac4));
                Bs[ac4+0][arow] = bv.x; Bs[ac4+1][arow] = bv.y;
                Bs[ac4+2][arow] = bv.z; Bs[ac4+3][arow] = bv.w;
            }
        }
        __syncthreads();

        #pragma unroll
        for (int kk = 0; kk < 8; kk++) {
            // (a,a) pairs: 16 duplicated floats = 4x LDS.128 (warp-broadcast)
            ulonglong2 aA = *(const ulonglong2*)&As[kk][2*rb + 0];
            ulonglong2 aB = *(const ulonglong2*)&As[kk][2*rb + 4];
            ulonglong2 aC = *(const ulonglong2*)&As[kk][2*rb + 8];
            ulonglong2 aD = *(const ulonglong2*)&As[kk][2*rb + 12];
            unsigned long long ap[8] = {aA.x, aA.y, aB.x, aB.y,
                                        aC.x, aC.y, aD.x, aD.y};
            unsigned long long bp[JW];
            {
                ulonglong2 b01 = *(const ulonglong2*)&Bs[kk][cb];
                bp[0] = b01.x; bp[1] = b01.y;
                if (JW == 4) {
                    ulonglong2 b23 = *(const ulonglong2*)&Bs[kk][cb + 4];
                    bp[2] = b23.x; bp[3] = b23.y;
                }
            }
            #pragma unroll
            for (int i = 0; i < 8; i++)
                #pragma unroll
                for (int j = 0; j < JW; j++)
                    ffma2(acc[i][j], ap[i], bp[j]);
        }
        __syncthreads();
    }

    bool hb = mode & 1, hg = mode & 2, hr = mode & 4;
    #pragma unroll
    for (int i = 0; i < 8; i++) {
        int m = mBase + rb + i;
        if (m >= M) continue;
        long long ro = (long long)m * ldc;
        #pragma unroll
        for (int j = 0; j < JW; j++) {
            float pv[2] = { ull_lo(acc[i][j]), ull_hi(acc[i][j]) };
            #pragma unroll
            for (int h = 0; h < 2; h++) {
                int n = nBase + cb + 2*j + h;
                if (n >= N) continue;
                float vv = pv[h] * alpha;
                if (hb) vv += bias[n];
                if (hg) vv = gelu_f(vv);
                if (hr) vv += R[ro + n];
                C[ro + n] = vv;
            }
        }
    }
}

// ---------------- transpose [rows,cols] -> [cols,rows] per batch ----------------
__global__ void transpose_kernel(const float* __restrict__ in, float* __restrict__ out,
                                 int rows, int cols)
{
    __shared__ float t[32][33];
    long long bo = (long long)blockIdx.z * rows * cols;
    int c0 = blockIdx.x * 32, r0 = blockIdx.y * 32;
    int tx = threadIdx.x, ty = threadIdx.y;
    #pragma unroll
    for (int i = 0; i < 32; i += 8)
        t[ty+i][tx] = in[bo + (long long)(r0+ty+i)*cols + (c0+tx)];
    __syncthreads();
    #pragma unroll
    for (int i = 0; i < 32; i += 8)
        out[bo + (long long)(c0+ty+i)*rows + (r0+tx)] = t[tx][ty+i];
}

// ---------------- FFT (radix-2 DIT, n=4096, 512 threads) ----------------
__device__ __forceinline__ int rev12(int i) { return __brev(i) >> 20; }

__device__ __forceinline__ void tw_init(float2* tw, int tid) {
    for (int m = tid; m < 1024; m += 512) {
        float sv, cv;
        sincosf(-6.283185307179586f * (float)m / 4096.0f, &sv, &cv);
        tw[m] = make_float2(cv, sv);
    }
}

__device__ void do_fft(float2* s, const float2* tw, int tid) {
    #pragma unroll 1
    for (int lh = 0; lh < 12; lh++) {
        int half = 1 << lh;
        #pragma unroll 1
        for (int idx = tid; idx < NF/2; idx += 512) {
            int j   = idx & (half - 1);
            int pos = 2*idx - j;
            int m   = j << (11 - lh);
            float2 w;
            if (m & 1024) { float2 t = tw[m & 1023]; w = make_float2(t.y, -t.x); }
            else          { w = tw[m]; }
            float2 u = s[pos];
            float2 q = s[pos + half];
            float2 v = make_float2(w.x*q.x - w.y*q.y, w.x*q.y + w.y*q.x);
            s[pos]        = make_float2(u.x + v.x, u.y + v.y);
            s[pos + half] = make_float2(u.x - v.x, u.y - v.y);
        }
        __syncthreads();
    }
}

// filters[t,d] = sum_k eig_vecs[t,k]*eig_vals[k]^0.25*w_filters[k,d]; store FFT per d
__global__ void __launch_bounds__(512) filters_kernel(
    const float* __restrict__ eig_vals, const float* __restrict__ eig_vecs,
    const float* __restrict__ w_filters, float2* __restrict__ Ffilt)
{
    __shared__ float2 s[NF];
    __shared__ float2 tw[1024];
    __shared__ float  wk[KK];
    int d = blockIdx.x, tid = threadIdx.x;
    if (tid < KK) wk[tid] = powf(eig_vals[tid], 0.25f) * w_filters[tid*DD + d];
    tw_init(tw, tid);
    for (int i = tid; i < NF; i += 512) s[i] = make_float2(0.f, 0.f);
    __syncthreads();
    for (int t = tid; t < LL; t += 512) {
        float f = 0.f;
        #pragma unroll
        for (int k = 0; k < KK; k++) f += eig_vecs[t*KK + k] * wk[k];
        s[rev12(t)] = make_float2(f, 0.f);
    }
    __syncthreads();
    do_fft(s, tw, tid);
    for (int i = tid; i < NF; i += 512)
        Ffilt[(long long)d*NF + i] = s[i];
}

// per-(b,d) channel: FFT(xi) * Ffilt, IFFT, keep first L real samples
__global__ void __launch_bounds__(512) conv_kernel(
    const float* __restrict__ xt, const float2* __restrict__ Ffilt,
    float* __restrict__ projt)
{
    __shared__ float2 s[NF];
    __shared__ float2 tw[1024];
    int z = blockIdx.x, tid = threadIdx.x;
    int d = z & (DD - 1);
    long long base = (long long)z * LL;
    tw_init(tw, tid);
    for (int i = tid; i < NF; i += 512) s[i] = make_float2(0.f, 0.f);
    __syncthreads();
    for (int t = tid; t < LL; t += 512)
        s[rev12(t)] = make_float2(xt[base + t], 0.f);
    __syncthreads();
    do_fft(s, tw, tid);
    for (int i = tid; i < NF; i += 512) {
        float2 a = s[i];
        float2 f = Ffilt[(long long)d*NF + i];
        s[i] = make_float2(a.x*f.x - a.y*f.y, -(a.x*f.y + a.y*f.x));
    }
    __syncthreads();
    float2 r[8];
    #pragma unroll
    for (int k = 0; k < 8; k++) r[k] = s[rev12(tid + k*512)];
    __syncthreads();
    #pragma unroll
    for (int k = 0; k < 8; k++) s[tid + k*512] = r[k];
    __syncthreads();
    do_fft(s, tw, tid);
    const float inv = 1.0f / 4096.0f;
    for (int l = tid; l < LL; l += 512)
        projt[base + l] = s[l].x * inv;
}

// ---------------- LayerNorm (one block per row of D=1024) ----------------
__global__ void __launch_bounds__(256) ln_kernel(
    const float* __restrict__ x, float* __restrict__ y,
    const float* __restrict__ sc, const float* __restrict__ bi)
{
    long long base = (long long)blockIdx.x * DD;
    int tid = threadIdx.x;
    float4 v = *(const float4*)(x + base + tid*4);
    float mean = block_sum256(v.x + v.y + v.z + v.w) * (1.0f/DD);
    float dx = v.x - mean, dy = v.y - mean, dz = v.z - mean, dw = v.w - mean;
    float var = block_sum256(dx*dx + dy*dy + dz*dz + dw*dw) * (1.0f/DD);
    float rstd = rsqrtf(var + 1e-6f);
    float4 s4 = *(const float4*)(sc + tid*4);
    float4 b4 = *(const float4*)(bi + tid*4);
    float4 o;
    o.x = dx*rstd*s4.x + b4.x;
    o.y = dy*rstd*s4.y + b4.y;
    o.z = dz*rstd*s4.z + b4.z;
    o.w = dw*rstd*s4.w + b4.w;
    *(float4*)(y + base + tid*4) = o;
}

// ---------------- softmax over rows of 2048 (in place) ----------------
__global__ void __launch_bounds__(256) softmax_kernel(float* __restrict__ S)
{
    long long base = (long long)blockIdx.x * LL;
    int tid = threadIdx.x;
    float v[8];
    float mx = -1e30f;
    #pragma unroll
    for (int k = 0; k < 8; k++) {
        v[k] = S[base + tid + k*256];
        mx = fmaxf(mx, v[k]);
    }
    mx = block_max256(mx);
    float lsum = 0.f;
    #pragma unroll
    for (int k = 0; k < 8; k++) { v[k] = expf(v[k] - mx); lsum += v[k]; }
    float inv = 1.0f / block_sum256(lsum);
    #pragma unroll
    for (int k = 0; k < 8; k++)
        S[base + tid + k*256] = v[k] * inv;
}

// ---------------- launch ----------------
static float* sym(const void* s) { void* p = nullptr; cudaGetSymbolAddress(&p, s); return (float*)p; }

extern "C" void kernel_launch(void* const* d_in, const int* in_sizes, int n_in,
                              void* d_out, int out_size)
{
    const float* inputs    = (const float*)d_in[0];
    const float* eig_vals  = (const float*)d_in[1];
    const float* eig_vecs  = (const float*)d_in[2];
    const float* w_filters = (const float*)d_in[3];
    const float* w_inputs  = (const float*)d_in[4];
    const float* ln1_s     = (const float*)d_in[5];
    const float* ln1_b     = (const float*)d_in[6];
    const float* wq        = (const float*)d_in[7];
    const float* wk        = (const float*)d_in[8];
    const float* wv        = (const float*)d_in[9];
    const float* wo        = (const float*)d_in[10];
    const float* ln2_s     = (const float*)d_in[11];
    const float* ln2_b     = (const float*)d_in[12];
    const float* mlp_w1    = (const float*)d_in[13];
    const float* mlp_b1    = (const float*)d_in[14];
    const float* mlp_w2    = (const float*)d_in[15];
    const float* mlp_b2    = (const float*)d_in[16];
    float* out = (float*)d_out;

    float*  xi     = sym(g_xi);
    float*  xt     = sym(g_xt);
    float2* Ffilt  = (float2*)sym(g_Ffilt);
    float*  projt  = sym(g_projt);
    float*  stu    = sym(g_stu);
    float*  x1     = sym(g_x1);
    float*  q      = sym(g_q);
    float*  kb     = sym(g_k);
    float*  vb     = sym(g_v);
    float*  sc     = sym(g_scores);
    float*  att    = sym(g_att);
    float*  xres   = sym(g_xres);
    float*  y1     = sym(g_y1);
    float*  hbuf   = sym(g_h);

    const long long LLD = (long long)LL * DD;
    const long long LL2 = (long long)LL * LL;

    // 1. filter spectrum per channel d
    filters_kernel<<<DD, 512>>>(eig_vals, eig_vecs, w_filters, Ffilt);

    // 2. xi = inputs @ w_inputs   [BL,D]
    sgemm<0,4><<<dim3(DD/128, BL/128, 1), 256>>>(inputs, w_inputs, xi,
        BL, DD, DD, DD, DD, DD, 0,0,0,0,0,0, 1, 1.0f, nullptr, nullptr, 0);

    // 3. transpose to [B,D,L] for coalesced FFT
    transpose_kernel<<<dim3(DD/32, LL/32, BB), dim3(32,8)>>>(xi, xt, LL, DD);

    // 4. spectral causal conv (FFT * filter * IFFT) per (b,d)
    conv_kernel<<<BB*DD, 512>>>(xt, Ffilt, projt);

    // 5. transpose back: stu_outs [B,L,D]
    transpose_kernel<<<dim3(LL/32, DD/32, BB), dim3(32,8)>>>(projt, stu, DD, LL);

    // 6. LN1
    ln_kernel<<<BL, 256>>>(stu, x1, ln1_s, ln1_b);

    // 7. Q (scaled 1/sqrt(hd)), K, V
    sgemm<0,4><<<dim3(8, 64, 1), 256>>>(x1, wq, q,
        BL, DD, DD, DD, DD, DD, 0,0,0,0,0,0, 1, 0.125f, nullptr, nullptr, 0);
    sgemm<0,4><<<dim3(8, 64, 1), 256>>>(x1, wk, kb,
        BL, DD, DD, DD, DD, DD, 0,0,0,0,0,0, 1, 1.0f, nullptr, nullptr, 0);
    sgemm<0,4><<<dim3(8, 64, 1), 256>>>(x1, wv, vb,
        BL, DD, DD, DD, DD, DD, 0,0,0,0,0,0, 1, 1.0f, nullptr, nullptr, 0);

    // 8. scores[b,h] = Q_bh @ K_bhᵀ   (batched NT, K=64)
    sgemm<1,4><<<dim3(16, 16, BB*HH), 256>>>(q, kb, sc,
        LL, LL, HDIM, DD, DD, LL,
        LLD, 64, LLD, 64, (long long)HH*LL2, LL2, HH,
        1.0f, nullptr, nullptr, 0);

    // 9. softmax rows
    softmax_kernel<<<BB*HH*LL, 256>>>(sc);

    // 10. att[b,q,h,:] = P_bh @ V_bh   (batched NN, N=64, 64-wide tile)
    sgemm<0,2><<<dim3(1, 16, BB*HH), 256>>>(sc, vb, att,
        LL, HDIM, LL, LL, DD, DD,
        (long long)HH*LL2, LL2, LLD, 64, LLD, 64, HH,
        1.0f, nullptr, nullptr, 0);

    // 11. x = att @ wo + stu
    sgemm<0,4><<<dim3(8, 64, 1), 256>>>(att, wo, xres,
        BL, DD, DD, DD, DD, DD, 0,0,0,0,0,0, 1, 1.0f, nullptr, stu, 4);

    // 12. LN2
    ln_kernel<<<BL, 256>>>(xres, y1, ln2_s, ln2_b);

    // 13. h = gelu(y1 @ mlp_w1 + b1)
    sgemm<0,4><<<dim3(MLPD/128, 64, 1), 256>>>(y1, mlp_w1, hbuf,
        BL, MLPD, DD, DD, MLPD, MLPD, 0,0,0,0,0,0, 1, 1.0f, mlp_b1, nullptr, 3);

    // 14. out = h @ mlp_w2 + b2 + x
    sgemm<0,4><<<dim3(8, 64, 1), 256>>>(hbuf, mlp_w2, out,
        BL, DD, MLPD, MLPD, DD, DD, 0,0,0,0,0,0, 1, 1.0f, mlp_b2, xres, 5);
}

// round 6
// speedup vs baseline: 2.3460x; 2.3460x over previous
#include <cuda_runtime.h>
#include <cuda_bf16.h>
#include <math.h>
#include <stdint.h>

#define BB 4
#define LL 2048
#define DD 1024
#define HH 16
#define HDIM 64
#define KK 24
#define MLPD 4096
#define BL (BB*LL)
#define NF4096 4096

typedef __nv_bfloat16 bf16;

// ---------------- scratch (device globals; allocation-free) ----------------
__device__ float  g_xi[BL*DD];
__device__ float  g_xt[BL*DD];
__device__ float2 g_Ffilt[(size_t)DD*NF4096];
__device__ float  g_projt[BL*DD];
__device__ float  g_stu[BL*DD];
__device__ float  g_v[BL*DD];
__device__ float  g_scores[(size_t)BB*HH*LL*LL];   // 1 GB
__device__ float  g_xres[BL*DD];

// bf16 split pairs
__device__ bf16 g_inh[BL*DD],  g_inl[BL*DD];
__device__ bf16 g_x1h[BL*DD],  g_x1l[BL*DD];
__device__ bf16 g_qh [BL*DD],  g_ql [BL*DD];
__device__ bf16 g_kh [BL*DD],  g_kl [BL*DD];
__device__ bf16 g_vTh[BL*DD],  g_vTl[BL*DD];       // [B,H,HD,L]
__device__ bf16 g_ath[BL*DD],  g_atl[BL*DD];
__device__ bf16 g_y1h[BL*DD],  g_y1l[BL*DD];
__device__ bf16 g_hh[(size_t)BL*MLPD], g_hl[(size_t)BL*MLPD];
__device__ bf16 g_Ph[(size_t)BB*HH*LL*LL], g_Pl[(size_t)BB*HH*LL*LL];  // 1 GB
// transposed-split weights [N][K]
__device__ bf16 g_wiTh[DD*DD],  g_wiTl[DD*DD];
__device__ bf16 g_wqTh[DD*DD],  g_wqTl[DD*DD];
__device__ bf16 g_wkTh[DD*DD],  g_wkTl[DD*DD];
__device__ bf16 g_wvTh[DD*DD],  g_wvTl[DD*DD];
__device__ bf16 g_woTh[DD*DD],  g_woTl[DD*DD];
__device__ bf16 g_w1Th[(size_t)DD*MLPD], g_w1Tl[(size_t)DD*MLPD];
__device__ bf16 g_w2Th[(size_t)DD*MLPD], g_w2Tl[(size_t)DD*MLPD];

// ---------------- helpers ----------------
__device__ __forceinline__ float gelu_f(float x) {
    float x3 = x*x*x;
    return 0.5f*x*(1.0f + tanhf(0.7978845608028654f*(x + 0.044715f*x3)));
}
__device__ __forceinline__ void split2(float v, bf16 &h, bf16 &l) {
    h = __float2bfloat16_rn(v);
    l = __float2bfloat16_rn(v - __bfloat162float(h));
}

__device__ __forceinline__ void cpa16(uint32_t s, const void* g) {
    asm volatile("cp.async.cg.shared.global [%0], [%1], 16;" :: "r"(s), "l"(g));
}
__device__ __forceinline__ void mma16816(float* c, const uint32_t* a, const uint32_t* b) {
    asm volatile("mma.sync.aligned.m16n8k16.row.col.f32.bf16.bf16.f32 "
                 "{%0,%1,%2,%3},{%4,%5,%6,%7},{%8,%9},{%0,%1,%2,%3};"
                 : "+f"(c[0]), "+f"(c[1]), "+f"(c[2]), "+f"(c[3])
                 : "r"(a[0]), "r"(a[1]), "r"(a[2]), "r"(a[3]),
                   "r"(b[0]), "r"(b[1]));
}

__device__ __forceinline__ float block_sum256(float v) {
    __shared__ float red[8];
    int lane = threadIdx.x & 31, w = threadIdx.x >> 5;
    #pragma unroll
    for (int o = 16; o; o >>= 1) v += __shfl_xor_sync(0xffffffffu, v, o);
    __syncthreads();
    if (lane == 0) red[w] = v;
    __syncthreads();
    if (threadIdx.x == 0) {
        float s = 0.f;
        #pragma unroll
        for (int i = 0; i < 8; i++) s += red[i];
        red[0] = s;
    }
    __syncthreads();
    return red[0];
}
__device__ __forceinline__ float block_max256(float v) {
    __shared__ float red[8];
    int lane = threadIdx.x & 31, w = threadIdx.x >> 5;
    #pragma unroll
    for (int o = 16; o; o >>= 1) v = fmaxf(v, __shfl_xor_sync(0xffffffffu, v, o));
    __syncthreads();
    if (lane == 0) red[w] = v;
    __syncthreads();
    if (threadIdx.x == 0) {
        float s = red[0];
        #pragma unroll
        for (int i = 1; i < 8; i++) s = fmaxf(s, red[i]);
        red[0] = s;
    }
    __syncthreads();
    return red[0];
}

// ---------------- split-bf16 tensor-core GEMM ----------------
// C[M,N] = alpha * A[M,K] @ B^T, A given as (Ahi+Alo) row-major [M,K] (lda),
// B given as (Bhi+Blo) stored [N,K] row-major (ldb). fp32 accumulate via
// 3 mma products (hh + lh + hl). Epilogue: +bias, gelu, +resid(f32),
// output f32 C or split bf16 (Chi,Clo). All of M,N,K multiples of tile dims.
// mode: 1=bias, 2=gelu, 4=resid, 8=split-out
template<int BNt>
__global__ void __launch_bounds__(256) gemm_bf16(
    const bf16* __restrict__ Ahi, const bf16* __restrict__ Alo,
    const bf16* __restrict__ Bhi, const bf16* __restrict__ Blo,
    float* __restrict__ C, bf16* __restrict__ Chi, bf16* __restrict__ Clo,
    int M, int N, int Kd, int lda, int ldb, int ldc,
    long long sA1, long long sA2, long long sB1, long long sB2,
    long long sC1, long long sC2, int bdiv,
    float alpha, const float* __restrict__ bias,
    const float* __restrict__ resid, int mode)
{
    constexpr int SP    = 40;            // padded K stride in halves (80 B)
    constexpr int AH    = 128 * SP;      // one A buffer (halves)
    constexpr int BHalf = BNt * SP;      // one B buffer (halves)
    constexpr int STAGE = 2*AH + 2*BHalf;
    constexpr int NFr   = BNt / 16;      // n-frags per warp
    constexpr int BITER = (BNt * 4) / 256;

    extern __shared__ __align__(16) char dsm[];
    uint32_t smem0 = (uint32_t)__cvta_generic_to_shared(dsm);

    int z  = blockIdx.z;
    int z1 = z / bdiv, z2 = z - z1*bdiv;
    long long offA = z1*sA1 + z2*sA2;
    long long offB = z1*sB1 + z2*sB2;
    long long offC = z1*sC1 + z2*sC2;

    int tid   = threadIdx.x;
    int mBase = blockIdx.y * 128, nBase = blockIdx.x * BNt;

    const bf16* pAh = Ahi + offA + (long long)mBase * lda;
    const bf16* pAl = Alo + offA + (long long)mBase * lda;
    const bf16* pBh = Bhi + offB + (long long)nBase * ldb;
    const bf16* pBl = Blo + offB + (long long)nBase * ldb;

    int warp = tid >> 5, lane = tid & 31;
    int wm = warp & 3, wn = warp >> 2;
    int g  = lane >> 2, tig = lane & 3;

    float acc[2][NFr][4];
    #pragma unroll
    for (int i = 0; i < 2; i++)
        #pragma unroll
        for (int j = 0; j < NFr; j++)
            #pragma unroll
            for (int c = 0; c < 4; c++) acc[i][j][c] = 0.f;

    auto load_stage = [&](int buf, int k0) {
        int so = buf * STAGE;
        #pragma unroll
        for (int i = 0; i < 2; i++) {               // A: 512 16B chunks
            int ci = tid + i*256;
            int row = ci >> 2, seg = ci & 3;
            long long go = (long long)row*lda + k0 + seg*8;
            uint32_t sa = smem0 + 2*(so + row*SP + seg*8);
            cpa16(sa,          pAh + go);
            cpa16(sa + 2*AH,   pAl + go);
        }
        #pragma unroll
        for (int i = 0; i < BITER; i++) {           // B: BNt*4 chunks
            int ci = tid + i*256;
            int row = ci >> 2, seg = ci & 3;
            long long go = (long long)row*ldb + k0 + seg*8;
            uint32_t sa = smem0 + 2*(so + 2*AH + row*SP + seg*8);
            cpa16(sa,            pBh + go);
            cpa16(sa + 2*BHalf,  pBl + go);
        }
        asm volatile("cp.async.commit_group;");
    };

    int nk = Kd >> 5;
    load_stage(0, 0);

    for (int ks = 0; ks < nk; ks++) {
        if (ks + 1 < nk) {
            load_stage((ks+1)&1, (ks+1) << 5);
            asm volatile("cp.async.wait_group 1;");
        } else {
            asm volatile("cp.async.wait_group 0;");
        }
        __syncthreads();
        int so = (ks & 1) * STAGE;

        #pragma unroll
        for (int kh = 0; kh < 2; kh++) {
            int ko = kh*16 + 2*tig;
            uint32_t ah[2][4], al[2][4];
            #pragma unroll
            for (int mi = 0; mi < 2; mi++) {
                int r = so + (wm*32 + mi*16 + g)*SP + ko;
                ah[mi][0] = *(const uint32_t*)(dsm + 2*(r));
                ah[mi][1] = *(const uint32_t*)(dsm + 2*(r + 8*SP));
                ah[mi][2] = *(const uint32_t*)(dsm + 2*(r + 8));
                ah[mi][3] = *(const uint32_t*)(dsm + 2*(r + 8*SP + 8));
                al[mi][0] = *(const uint32_t*)(dsm + 2*(r + AH));
                al[mi][1] = *(const uint32_t*)(dsm + 2*(r + AH + 8*SP));
                al[mi][2] = *(const uint32_t*)(dsm + 2*(r + AH + 8));
                al[mi][3] = *(const uint32_t*)(dsm + 2*(r + AH + 8*SP + 8));
            }
            uint32_t bh[NFr][2], bl[NFr][2];
            #pragma unroll
            for (int ni = 0; ni < NFr; ni++) {
                int r = so + 2*AH + (wn*(BNt/2) + ni*8 + g)*SP + ko;
                bh[ni][0] = *(const uint32_t*)(dsm + 2*(r));
                bh[ni][1] = *(const uint32_t*)(dsm + 2*(r + 8));
                bl[ni][0] = *(const uint32_t*)(dsm + 2*(r + BHalf));
                bl[ni][1] = *(const uint32_t*)(dsm + 2*(r + BHalf + 8));
            }
            #pragma unroll
            for (int mi = 0; mi < 2; mi++)
                #pragma unroll
                for (int ni = 0; ni < NFr; ni++) {
                    mma16816(acc[mi][ni], ah[mi], bh[ni]);
                    mma16816(acc[mi][ni], al[mi], bh[ni]);
                    mma16816(acc[mi][ni], ah[mi], bl[ni]);
                }
        }
        __syncthreads();
    }

    // epilogue
    bool hb = mode & 1, hg = mode & 2, hr = mode & 4, hs = mode & 8;
    float* Cp = C + offC;
    bf16*  Hh = Chi + offC;
    bf16*  Hl = Clo + offC;
    const float* Rp = resid + offC;
    #pragma unroll
    for (int mi = 0; mi < 2; mi++) {
        int m0 = mBase + wm*32 + mi*16 + g;
        #pragma unroll
        for (int ni = 0; ni < NFr; ni++) {
            int n = nBase + wn*(BNt/2) + ni*8 + 2*tig;
            #pragma unroll
            for (int hrow = 0; hrow < 2; hrow++) {
                int m = m0 + hrow*8;
                float v0 = acc[mi][ni][hrow*2+0] * alpha;
                float v1 = acc[mi][ni][hrow*2+1] * alpha;
                if (hb) { v0 += bias[n]; v1 += bias[n+1]; }
                if (hg) { v0 = gelu_f(v0); v1 = gelu_f(v1); }
                long long o = (long long)m*ldc + n;
                if (hr) { v0 += Rp[o]; v1 += Rp[o+1]; }
                if (hs) {
                    bf16 h0, l0, h1, l1;
                    split2(v0, h0, l0); split2(v1, h1, l1);
                    Hh[o] = h0; Hh[o+1] = h1;
                    Hl[o] = l0; Hl[o+1] = l1;
                } else {
                    Cp[o] = v0; Cp[o+1] = v1;
                }
            }
        }
    }
}

// ---------------- transpose [rows,cols] -> [cols,rows] per batch (f32) ----------------
__global__ void transpose_kernel(const float* __restrict__ in, float* __restrict__ out,
                                 int rows, int cols)
{
    __shared__ float t[32][33];
    long long bo = (long long)blockIdx.z * rows * cols;
    int c0 = blockIdx.x * 32, r0 = blockIdx.y * 32;
    int tx = threadIdx.x, ty = threadIdx.y;
    #pragma unroll
    for (int i = 0; i < 32; i += 8)
        t[ty+i][tx] = in[bo + (long long)(r0+ty+i)*cols + (c0+tx)];
    __syncthreads();
    #pragma unroll
    for (int i = 0; i < 32; i += 8)
        out[bo + (long long)(c0+ty+i)*rows + (r0+tx)] = t[tx][ty+i];
}

// ---------------- transpose + split: f32 [rows,cols] -> bf16 hi/lo [cols,rows] ----------------
__global__ void transpose_split_kernel(const float* __restrict__ in,
                                       bf16* __restrict__ oh, bf16* __restrict__ ol,
                                       int rows, int cols)
{
    __shared__ float t[32][33];
    long long bo = (long long)blockIdx.z * rows * cols;
    int c0 = blockIdx.x * 32, r0 = blockIdx.y * 32;
    int tx = threadIdx.x, ty = threadIdx.y;
    #pragma unroll
    for (int i = 0; i < 32; i += 8)
        t[ty+i][tx] = in[bo + (long long)(r0+ty+i)*cols + (c0+tx)];
    __syncthreads();
    #pragma unroll
    for (int i = 0; i < 32; i += 8) {
        float v = t[tx][ty+i];
        bf16 h, l; split2(v, h, l);
        long long o = bo + (long long)(c0+ty+i)*rows + (r0+tx);
        oh[o] = h; ol[o] = l;
    }
}

// ---------------- elementwise split (no transpose) ----------------
__global__ void split_kernel(const float* __restrict__ x,
                             bf16* __restrict__ oh, bf16* __restrict__ ol)
{
    long long i = ((long long)blockIdx.x * 256 + threadIdx.x) * 4;
    float4 v = *(const float4*)(x + i);
    bf16 h, l;
    split2(v.x, h, l); oh[i+0] = h; ol[i+0] = l;
    split2(v.y, h, l); oh[i+1] = h; ol[i+1] = l;
    split2(v.z, h, l); oh[i+2] = h; ol[i+2] = l;
    split2(v.w, h, l); oh[i+3] = h; ol[i+3] = l;
}

// ---------------- FFT (radix-2 DIT, n=4096, 512 threads) ----------------
__device__ __forceinline__ int rev12(int i) { return __brev(i) >> 20; }

__device__ __forceinline__ void tw_init(float2* tw, int tid) {
    for (int m = tid; m < 1024; m += 512) {
        float sv, cv;
        sincosf(-6.283185307179586f * (float)m / 4096.0f, &sv, &cv);
        tw[m] = make_float2(cv, sv);
    }
}

__device__ void do_fft(float2* s, const float2* tw, int tid) {
    #pragma unroll 1
    for (int lh = 0; lh < 12; lh++) {
        int half = 1 << lh;
        #pragma unroll 1
        for (int idx = tid; idx < NF4096/2; idx += 512) {
            int j   = idx & (half - 1);
            int pos = 2*idx - j;
            int m   = j << (11 - lh);
            float2 w;
            if (m & 1024) { float2 t = tw[m & 1023]; w = make_float2(t.y, -t.x); }
            else          { w = tw[m]; }
            float2 u = s[pos];
            float2 q = s[pos + half];
            float2 v = make_float2(w.x*q.x - w.y*q.y, w.x*q.y + w.y*q.x);
            s[pos]        = make_float2(u.x + v.x, u.y + v.y);
            s[pos + half] = make_float2(u.x - v.x, u.y - v.y);
        }
        __syncthreads();
    }
}

__global__ void __launch_bounds__(512) filters_kernel(
    const float* __restrict__ eig_vals, const float* __restrict__ eig_vecs,
    const float* __restrict__ w_filters, float2* __restrict__ Ffilt)
{
    __shared__ float2 s[NF4096];
    __shared__ float2 tw[1024];
    __shared__ float  wk[KK];
    int d = blockIdx.x, tid = threadIdx.x;
    if (tid < KK) wk[tid] = powf(eig_vals[tid], 0.25f) * w_filters[tid*DD + d];
    tw_init(tw, tid);
    for (int i = tid; i < NF4096; i += 512) s[i] = make_float2(0.f, 0.f);
    __syncthreads();
    for (int t = tid; t < LL; t += 512) {
        float f = 0.f;
        #pragma unroll
        for (int k = 0; k < KK; k++) f += eig_vecs[t*KK + k] * wk[k];
        s[rev12(t)] = make_float2(f, 0.f);
    }
    __syncthreads();
    do_fft(s, tw, tid);
    for (int i = tid; i < NF4096; i += 512)
        Ffilt[(long long)d*NF4096 + i] = s[i];
}

__global__ void __launch_bounds__(512) conv_kernel(
    const float* __restrict__ xt, const float2* __restrict__ Ffilt,
    float* __restrict__ projt)
{
    __shared__ float2 s[NF4096];
    __shared__ float2 tw[1024];
    int z = blockIdx.x, tid = threadIdx.x;
    int d = z & (DD - 1);
    long long base = (long long)z * LL;
    tw_init(tw, tid);
    for (int i = tid; i < NF4096; i += 512) s[i] = make_float2(0.f, 0.f);
    __syncthreads();
    for (int t = tid; t < LL; t += 512)
        s[rev12(t)] = make_float2(xt[base + t], 0.f);
    __syncthreads();
    do_fft(s, tw, tid);
    for (int i = tid; i < NF4096; i += 512) {
        float2 a = s[i];
        float2 f = Ffilt[(long long)d*NF4096 + i];
        s[i] = make_float2(a.x*f.x - a.y*f.y, -(a.x*f.y + a.y*f.x));
    }
    __syncthreads();
    float2 r[8];
    #pragma unroll
    for (int k = 0; k < 8; k++) r[k] = s[rev12(tid + k*512)];
    __syncthreads();
    #pragma unroll
    for (int k = 0; k < 8; k++) s[tid + k*512] = r[k];
    __syncthreads();
    do_fft(s, tw, tid);
    const float inv = 1.0f / 4096.0f;
    for (int l = tid; l < LL; l += 512)
        projt[base + l] = s[l].x * inv;
}

// ---------------- LayerNorm with split-bf16 output ----------------
__global__ void __launch_bounds__(256) ln_split_kernel(
    const float* __restrict__ x, bf16* __restrict__ yh, bf16* __restrict__ yl,
    const float* __restrict__ sc, const float* __restrict__ bi)
{
    long long base = (long long)blockIdx.x * DD;
    int tid = threadIdx.x;
    float4 v = *(const float4*)(x + base + tid*4);
    float mean = block_sum256(v.x + v.y + v.z + v.w) * (1.0f/DD);
    float dx = v.x - mean, dy = v.y - mean, dz = v.z - mean, dw = v.w - mean;
    float var = block_sum256(dx*dx + dy*dy + dz*dz + dw*dw) * (1.0f/DD);
    float rstd = rsqrtf(var + 1e-6f);
    float4 s4 = *(const float4*)(sc + tid*4);
    float4 b4 = *(const float4*)(bi + tid*4);
    float o0 = dx*rstd*s4.x + b4.x;
    float o1 = dy*rstd*s4.y + b4.y;
    float o2 = dz*rstd*s4.z + b4.z;
    float o3 = dw*rstd*s4.w + b4.w;
    long long i = base + tid*4;
    bf16 h, l;
    split2(o0, h, l); yh[i+0] = h; yl[i+0] = l;
    split2(o1, h, l); yh[i+1] = h; yl[i+1] = l;
    split2(o2, h, l); yh[i+2] = h; yl[i+2] = l;
    split2(o3, h, l); yh[i+3] = h; yl[i+3] = l;
}

// ---------------- softmax over rows of 2048, split-bf16 output ----------------
__global__ void __launch_bounds__(256) softmax_split_kernel(
    const float* __restrict__ S, bf16* __restrict__ Ph, bf16* __restrict__ Pl)
{
    long long base = (long long)blockIdx.x * LL;
    int tid = threadIdx.x;
    float v[8];
    float mx = -1e30f;
    #pragma unroll
    for (int k = 0; k < 8; k++) {
        v[k] = S[base + tid + k*256];
        mx = fmaxf(mx, v[k]);
    }
    mx = block_max256(mx);
    float lsum = 0.f;
    #pragma unroll
    for (int k = 0; k < 8; k++) { v[k] = expf(v[k] - mx); lsum += v[k]; }
    float inv = 1.0f / block_sum256(lsum);
    #pragma unroll
    for (int k = 0; k < 8; k++) {
        float p = v[k] * inv;
        bf16 h, l; split2(p, h, l);
        Ph[base + tid + k*256] = h;
        Pl[base + tid + k*256] = l;
    }
}

// ---------------- launch ----------------
static void* symv(const void* s) { void* p = nullptr; cudaGetSymbolAddress(&p, s); return p; }

extern "C" void kernel_launch(void* const* d_in, const int* in_sizes, int n_in,
                              void* d_out, int out_size)
{
    const float* inputs    = (const float*)d_in[0];
    const float* eig_vals  = (const float*)d_in[1];
    const float* eig_vecs  = (const float*)d_in[2];
    const float* w_filters = (const float*)d_in[3];
    const float* w_inputs  = (const float*)d_in[4];
    const float* ln1_s     = (const float*)d_in[5];
    const float* ln1_b     = (const float*)d_in[6];
    const float* wq        = (const float*)d_in[7];
    const float* wk        = (const float*)d_in[8];
    const float* wv        = (const float*)d_in[9];
    const float* wo        = (const float*)d_in[10];
    const float* ln2_s     = (const float*)d_in[11];
    const float* ln2_b     = (const float*)d_in[12];
    const float* mlp_w1    = (const float*)d_in[13];
    const float* mlp_b1    = (const float*)d_in[14];
    const float* mlp_w2    = (const float*)d_in[15];
    const float* mlp_b2    = (const float*)d_in[16];
    float* out = (float*)d_out;

    float*  xi    = (float*)symv(g_xi);
    float*  xt    = (float*)symv(g_xt);
    float2* Ffilt = (float2*)symv(g_Ffilt);
    float*  projt = (float*)symv(g_projt);
    float*  stu   = (float*)symv(g_stu);
    float*  vbuf  = (float*)symv(g_v);
    float*  sc    = (float*)symv(g_scores);
    float*  xres  = (float*)symv(g_xres);

    bf16 *inh=(bf16*)symv(g_inh),  *inl=(bf16*)symv(g_inl);
    bf16 *x1h=(bf16*)symv(g_x1h),  *x1l=(bf16*)symv(g_x1l);
    bf16 *qh =(bf16*)symv(g_qh),   *ql =(bf16*)symv(g_ql);
    bf16 *kh =(bf16*)symv(g_kh),   *kl =(bf16*)symv(g_kl);
    bf16 *vTh=(bf16*)symv(g_vTh),  *vTl=(bf16*)symv(g_vTl);
    bf16 *ath=(bf16*)symv(g_ath),  *atl=(bf16*)symv(g_atl);
    bf16 *y1h=(bf16*)symv(g_y1h),  *y1l=(bf16*)symv(g_y1l);
    bf16 *hh =(bf16*)symv(g_hh),   *hl =(bf16*)symv(g_hl);
    bf16 *Ph =(bf16*)symv(g_Ph),   *Pl =(bf16*)symv(g_Pl);
    bf16 *wiTh=(bf16*)symv(g_wiTh),*wiTl=(bf16*)symv(g_wiTl);
    bf16 *wqTh=(bf16*)symv(g_wqTh),*wqTl=(bf16*)symv(g_wqTl);
    bf16 *wkTh=(bf16*)symv(g_wkTh),*wkTl=(bf16*)symv(g_wkTl);
    bf16 *wvTh=(bf16*)symv(g_wvTh),*wvTl=(bf16*)symv(g_wvTl);
    bf16 *woTh=(bf16*)symv(g_woTh),*woTl=(bf16*)symv(g_woTl);
    bf16 *w1Th=(bf16*)symv(g_w1Th),*w1Tl=(bf16*)symv(g_w1Tl);
    bf16 *w2Th=(bf16*)symv(g_w2Th),*w2Tl=(bf16*)symv(g_w2Tl);

    const long long LLD = (long long)LL * DD;
    const long long LL2 = (long long)LL * LL;
    const int SM128 = 81920, SM64 = 61440;
    cudaFuncSetAttribute(gemm_bf16<128>, cudaFuncAttributeMaxDynamicSharedMemorySize, SM128);
    cudaFuncSetAttribute(gemm_bf16<64>,  cudaFuncAttributeMaxDynamicSharedMemorySize, SM64);

    dim3 t328(32, 8);

    // 1. filter spectrum per channel d
    filters_kernel<<<DD, 512>>>(eig_vals, eig_vecs, w_filters, Ffilt);

    // 2. split inputs; transpose-split all weights to [N][K]
    split_kernel<<<(BL*DD)/1024, 256>>>(inputs, inh, inl);
    transpose_split_kernel<<<dim3(32, 32, 1), t328>>>(w_inputs, wiTh, wiTl, DD, DD);
    transpose_split_kernel<<<dim3(32, 32, 1), t328>>>(wq, wqTh, wqTl, DD, DD);
    transpose_split_kernel<<<dim3(32, 32, 1), t328>>>(wk, wkTh, wkTl, DD, DD);
    transpose_split_kernel<<<dim3(32, 32, 1), t328>>>(wv, wvTh, wvTl, DD, DD);
    transpose_split_kernel<<<dim3(32, 32, 1), t328>>>(wo, woTh, woTl, DD, DD);
    transpose_split_kernel<<<dim3(MLPD/32, DD/32, 1), t328>>>(mlp_w1, w1Th, w1Tl, DD, MLPD);
    transpose_split_kernel<<<dim3(DD/32, MLPD/32, 1), t328>>>(mlp_w2, w2Th, w2Tl, MLPD, DD);

    // 3. xi = inputs @ w_inputs (f32 out for FFT)
    gemm_bf16<128><<<dim3(DD/128, BL/128, 1), 256, SM128>>>(
        inh, inl, wiTh, wiTl, xi, nullptr, nullptr,
        BL, DD, DD, DD, DD, DD, 0,0,0,0,0,0, 1, 1.0f, nullptr, nullptr, 0);

    // 4. spectral causal conv
    transpose_kernel<<<dim3(DD/32, LL/32, BB), t328>>>(xi, xt, LL, DD);
    conv_kernel<<<BB*DD, 512>>>(xt, Ffilt, projt);
    transpose_kernel<<<dim3(LL/32, DD/32, BB), t328>>>(projt, stu, DD, LL);

    // 5. LN1 -> split x1
    ln_split_kernel<<<BL, 256>>>(stu, x1h, x1l, ln1_s, ln1_b);

    // 6. Q (scaled, split), K (split), V (f32 then transpose-split)
    gemm_bf16<128><<<dim3(8, 64, 1), 256, SM128>>>(
        x1h, x1l, wqTh, wqTl, nullptr, qh, ql,
        BL, DD, DD, DD, DD, DD, 0,0,0,0,0,0, 1, 0.125f, nullptr, nullptr, 8);
    gemm_bf16<128><<<dim3(8, 64, 1), 256, SM128>>>(
        x1h, x1l, wkTh, wkTl, nullptr, kh, kl,
        BL, DD, DD, DD, DD, DD, 0,0,0,0,0,0, 1, 1.0f, nullptr, nullptr, 8);
    gemm_bf16<128><<<dim3(8, 64, 1), 256, SM128>>>(
        x1h, x1l, wvTh, wvTl, vbuf, nullptr, nullptr,
        BL, DD, DD, DD, DD, DD, 0,0,0,0,0,0, 1, 1.0f, nullptr, nullptr, 0);
    // V^T split: per b [L,D] -> [D,L]  == [B,H,HD,L]
    transpose_split_kernel<<<dim3(DD/32, LL/32, BB), t328>>>(vbuf, vTh, vTl, LL, DD);

    // 7. scores = Q @ K^T (per b,h), f32
    gemm_bf16<128><<<dim3(16, 16, BB*HH), 256, SM128>>>(
        qh, ql, kh, kl, sc, nullptr, nullptr,
        LL, LL, HDIM, DD, DD, LL,
        LLD, 64, LLD, 64, (long long)HH*LL2, LL2, HH,
        1.0f, nullptr, nullptr, 0);

    // 8. softmax -> split P
    softmax_split_kernel<<<BB*HH*LL, 256>>>(sc, Ph, Pl);

    // 9. att = P @ V (per b,h), split out
    gemm_bf16<64><<<dim3(1, 16, BB*HH), 256, SM64>>>(
        Ph, Pl, vTh, vTl, nullptr, ath, atl,
        LL, HDIM, LL, LL, LL, DD,
        (long long)HH*LL2, LL2, (long long)DD*LL, (long long)HDIM*LL, LLD, 64, HH,
        1.0f, nullptr, nullptr, 8);

    // 10. x = att @ wo + stu (f32)
    gemm_bf16<128><<<dim3(8, 64, 1), 256, SM128>>>(
        ath, atl, woTh, woTl, xres, nullptr, nullptr,
        BL, DD, DD, DD, DD, DD, 0,0,0,0,0,0, 1, 1.0f, nullptr, stu, 4);

    // 11. LN2 -> split y1
    ln_split_kernel<<<BL, 256>>>(xres, y1h, y1l, ln2_s, ln2_b);

    // 12. h = gelu(y1 @ w1 + b1), split out
    gemm_bf16<128><<<dim3(MLPD/128, 64, 1), 256, SM128>>>(
        y1h, y1l, w1Th, w1Tl, nullptr, hh, hl,
        BL, MLPD, DD, DD, DD, MLPD, 0,0,0,0,0,0, 1, 1.0f, mlp_b1, nullptr, 11);

    // 13. out = h @ w2 + b2 + x (f32)
    gemm_bf16<128><<<dim3(8, 64, 1), 256, SM128>>>(
        hh, hl, w2Th, w2Tl, out, nullptr, nullptr,
        BL, DD, MLPD, MLPD, MLPD, DD, 0,0,0,0,0,0, 1, 1.0f, mlp_b2, xres, 5);
}

// round 7
// speedup vs baseline: 2.9186x; 1.2441x over previous
#include <cuda_runtime.h>
#include <cuda_bf16.h>
#include <math.h>
#include <stdint.h>

#define BB 4
#define LL 2048
#define DD 1024
#define HH 16
#define HDIM 64
#define KK 24
#define MLPD 4096
#define BL (BB*LL)
#define NF4096 4096

typedef __nv_bfloat16 bf16;

// ---------------- scratch (device globals; allocation-free) ----------------
__device__ float  g_xi[BL*DD];
__device__ float  g_xt[BL*DD];
__device__ float2 g_Ffilt[(size_t)DD*NF4096];
__device__ float  g_projt[BL*DD];
__device__ float  g_stu[BL*DD];
__device__ float  g_v[BL*DD];
__device__ float  g_xres[BL*DD];

// bf16 split pairs
__device__ bf16 g_inh[BL*DD],  g_inl[BL*DD];
__device__ bf16 g_x1h[BL*DD],  g_x1l[BL*DD];
__device__ bf16 g_qh [BL*DD],  g_ql [BL*DD];
__device__ bf16 g_kh [BL*DD],  g_kl [BL*DD];
__device__ bf16 g_vTh[BL*DD],  g_vTl[BL*DD];       // [B,H*HD,L]
__device__ bf16 g_ath[BL*DD],  g_atl[BL*DD];
__device__ bf16 g_y1h[BL*DD],  g_y1l[BL*DD];
__device__ bf16 g_hh[(size_t)BL*MLPD], g_hl[(size_t)BL*MLPD];
// transposed-split weights [N][K]
__device__ bf16 g_wiTh[DD*DD],  g_wiTl[DD*DD];
__device__ bf16 g_wqTh[DD*DD],  g_wqTl[DD*DD];
__device__ bf16 g_wkTh[DD*DD],  g_wkTl[DD*DD];
__device__ bf16 g_wvTh[DD*DD],  g_wvTl[DD*DD];
__device__ bf16 g_woTh[DD*DD],  g_woTl[DD*DD];
__device__ bf16 g_w1Th[(size_t)DD*MLPD], g_w1Tl[(size_t)DD*MLPD];
__device__ bf16 g_w2Th[(size_t)DD*MLPD], g_w2Tl[(size_t)DD*MLPD];

// ---------------- helpers ----------------
__device__ __forceinline__ float gelu_f(float x) {
    float x3 = x*x*x;
    return 0.5f*x*(1.0f + tanhf(0.7978845608028654f*(x + 0.044715f*x3)));
}
__device__ __forceinline__ void split2(float v, bf16 &h, bf16 &l) {
    h = __float2bfloat16_rn(v);
    l = __float2bfloat16_rn(v - __bfloat162float(h));
}
__device__ __forceinline__ uint32_t packbf(float a, float b) {
    uint32_t lo = (uint32_t)__bfloat16_as_ushort(__float2bfloat16_rn(a));
    uint32_t hi = (uint32_t)__bfloat16_as_ushort(__float2bfloat16_rn(b));
    return lo | (hi << 16);
}

__device__ __forceinline__ void cpa16(uint32_t s, const void* g) {
    asm volatile("cp.async.cg.shared.global [%0], [%1], 16;" :: "r"(s), "l"(g));
}
__device__ __forceinline__ void mma16816(float* c, const uint32_t* a, const uint32_t* b) {
    asm volatile("mma.sync.aligned.m16n8k16.row.col.f32.bf16.bf16.f32 "
                 "{%0,%1,%2,%3},{%4,%5,%6,%7},{%8,%9},{%0,%1,%2,%3};"
                 : "+f"(c[0]), "+f"(c[1]), "+f"(c[2]), "+f"(c[3])
                 : "r"(a[0]), "r"(a[1]), "r"(a[2]), "r"(a[3]),
                   "r"(b[0]), "r"(b[1]));
}

__device__ __forceinline__ float block_sum256(float v) {
    __shared__ float red[8];
    int lane = threadIdx.x & 31, w = threadIdx.x >> 5;
    #pragma unroll
    for (int o = 16; o; o >>= 1) v += __shfl_xor_sync(0xffffffffu, v, o);
    __syncthreads();
    if (lane == 0) red[w] = v;
    __syncthreads();
    if (threadIdx.x == 0) {
        float s = 0.f;
        #pragma unroll
        for (int i = 0; i < 8; i++) s += red[i];
        red[0] = s;
    }
    __syncthreads();
    return red[0];
}

// ---------------- split-bf16 tensor-core GEMM (dense layers) ----------------
// mode: 1=bias, 2=gelu, 4=resid, 8=split-out
template<int BNt>
__global__ void __launch_bounds__(256) gemm_bf16(
    const bf16* __restrict__ Ahi, const bf16* __restrict__ Alo,
    const bf16* __restrict__ Bhi, const bf16* __restrict__ Blo,
    float* __restrict__ C, bf16* __restrict__ Chi, bf16* __restrict__ Clo,
    int M, int N, int Kd, int lda, int ldb, int ldc,
    long long sA1, long long sA2, long long sB1, long long sB2,
    long long sC1, long long sC2, int bdiv,
    float alpha, const float* __restrict__ bias,
    const float* __restrict__ resid, int mode)
{
    constexpr int SP    = 40;
    constexpr int AH    = 128 * SP;
    constexpr int BHalf = BNt * SP;
    constexpr int STAGE = 2*AH + 2*BHalf;
    constexpr int NFr   = BNt / 16;
    constexpr int BITER = (BNt * 4) / 256;

    extern __shared__ __align__(16) char dsm[];
    uint32_t smem0 = (uint32_t)__cvta_generic_to_shared(dsm);

    int z  = blockIdx.z;
    int z1 = z / bdiv, z2 = z - z1*bdiv;
    long long offA = z1*sA1 + z2*sA2;
    long long offB = z1*sB1 + z2*sB2;
    long long offC = z1*sC1 + z2*sC2;

    int tid   = threadIdx.x;
    int mBase = blockIdx.y * 128, nBase = blockIdx.x * BNt;

    const bf16* pAh = Ahi + offA + (long long)mBase * lda;
    const bf16* pAl = Alo + offA + (long long)mBase * lda;
    const bf16* pBh = Bhi + offB + (long long)nBase * ldb;
    const bf16* pBl = Blo + offB + (long long)nBase * ldb;

    int warp = tid >> 5, lane = tid & 31;
    int wm = warp & 3, wn = warp >> 2;
    int g  = lane >> 2, tig = lane & 3;

    float acc[2][NFr][4];
    #pragma unroll
    for (int i = 0; i < 2; i++)
        #pragma unroll
        for (int j = 0; j < NFr; j++)
            #pragma unroll
            for (int c = 0; c < 4; c++) acc[i][j][c] = 0.f;

    auto load_stage = [&](int buf, int k0) {
        int so = buf * STAGE;
        #pragma unroll
        for (int i = 0; i < 2; i++) {
            int ci = tid + i*256;
            int row = ci >> 2, seg = ci & 3;
            long long go = (long long)row*lda + k0 + seg*8;
            uint32_t sa = smem0 + 2*(so + row*SP + seg*8);
            cpa16(sa,          pAh + go);
            cpa16(sa + 2*AH,   pAl + go);
        }
        #pragma unroll
        for (int i = 0; i < BITER; i++) {
            int ci = tid + i*256;
            int row = ci >> 2, seg = ci & 3;
            long long go = (long long)row*ldb + k0 + seg*8;
            uint32_t sa = smem0 + 2*(so + 2*AH + row*SP + seg*8);
            cpa16(sa,            pBh + go);
            cpa16(sa + 2*BHalf,  pBl + go);
        }
        asm volatile("cp.async.commit_group;");
    };

    int nk = Kd >> 5;
    load_stage(0, 0);

    for (int ks = 0; ks < nk; ks++) {
        if (ks + 1 < nk) {
            load_stage((ks+1)&1, (ks+1) << 5);
            asm volatile("cp.async.wait_group 1;");
        } else {
            asm volatile("cp.async.wait_group 0;");
        }
        __syncthreads();
        int so = (ks & 1) * STAGE;

        #pragma unroll
        for (int kh = 0; kh < 2; kh++) {
            int ko = kh*16 + 2*tig;
            uint32_t ah[2][4], al[2][4];
            #pragma unroll
            for (int mi = 0; mi < 2; mi++) {
                int r = so + (wm*32 + mi*16 + g)*SP + ko;
                ah[mi][0] = *(const uint32_t*)(dsm + 2*(r));
                ah[mi][1] = *(const uint32_t*)(dsm + 2*(r + 8*SP));
                ah[mi][2] = *(const uint32_t*)(dsm + 2*(r + 8));
                ah[mi][3] = *(const uint32_t*)(dsm + 2*(r + 8*SP + 8));
                al[mi][0] = *(const uint32_t*)(dsm + 2*(r + AH));
                al[mi][1] = *(const uint32_t*)(dsm + 2*(r + AH + 8*SP));
                al[mi][2] = *(const uint32_t*)(dsm + 2*(r + AH + 8));
                al[mi][3] = *(const uint32_t*)(dsm + 2*(r + AH + 8*SP + 8));
            }
            uint32_t bh[NFr][2], bl[NFr][2];
            #pragma unroll
            for (int ni = 0; ni < NFr; ni++) {
                int r = so + 2*AH + (wn*(BNt/2) + ni*8 + g)*SP + ko;
                bh[ni][0] = *(const uint32_t*)(dsm + 2*(r));
                bh[ni][1] = *(const uint32_t*)(dsm + 2*(r + 8));
                bl[ni][0] = *(const uint32_t*)(dsm + 2*(r + BHalf));
                bl[ni][1] = *(const uint32_t*)(dsm + 2*(r + BHalf + 8));
            }
            #pragma unroll
            for (int mi = 0; mi < 2; mi++)
                #pragma unroll
                for (int ni = 0; ni < NFr; ni++) {
                    mma16816(acc[mi][ni], ah[mi], bh[ni]);
                    mma16816(acc[mi][ni], al[mi], bh[ni]);
                    mma16816(acc[mi][ni], ah[mi], bl[ni]);
                }
        }
        __syncthreads();
    }

    bool hb = mode & 1, hg = mode & 2, hr = mode & 4, hs = mode & 8;
    float* Cp = C + offC;
    bf16*  Hh = Chi + offC;
    bf16*  Hl = Clo + offC;
    const float* Rp = resid + offC;
    #pragma unroll
    for (int mi = 0; mi < 2; mi++) {
        int m0 = mBase + wm*32 + mi*16 + g;
        #pragma unroll
        for (int ni = 0; ni < NFr; ni++) {
            int n = nBase + wn*(BNt/2) + ni*8 + 2*tig;
            #pragma unroll
            for (int hrow = 0; hrow < 2; hrow++) {
                int m = m0 + hrow*8;
                float v0 = acc[mi][ni][hrow*2+0] * alpha;
                float v1 = acc[mi][ni][hrow*2+1] * alpha;
                if (hb) { v0 += bias[n]; v1 += bias[n+1]; }
                if (hg) { v0 = gelu_f(v0); v1 = gelu_f(v1); }
                long long o = (long long)m*ldc + n;
                if (hr) { v0 += Rp[o]; v1 += Rp[o+1]; }
                if (hs) {
                    bf16 h0, l0, h1, l1;
                    split2(v0, h0, l0); split2(v1, h1, l1);
                    Hh[o] = h0; Hh[o+1] = h1;
                    Hl[o] = l0; Hl[o+1] = l1;
                } else {
                    Cp[o] = v0; Cp[o+1] = v1;
                }
            }
        }
    }
}

// ---------------- flash attention (fused QK^T / softmax / PV) ----------------
// grid (L/128, B*H), 256 threads. Q,K: [B,L,H*HD] split; V^T: [B,H*HD,L] split.
// Output att split bf16 at [B,L,H*HD]. Q pre-scaled by 1/8.
__global__ void __launch_bounds__(256) flash_kernel(
    const bf16* __restrict__ Qh, const bf16* __restrict__ Ql,
    const bf16* __restrict__ Kh, const bf16* __restrict__ Kl,
    const bf16* __restrict__ Vth, const bf16* __restrict__ Vtl,
    bf16* __restrict__ Oh, bf16* __restrict__ Ol)
{
    constexpr int KSP = 72, VSP = 136;
    constexpr int KTH = 128*KSP;            // halves
    constexpr int VTH = 64*VSP;
    constexpr int STG = 2*KTH + 2*VTH;      // 35840 halves / stage

    extern __shared__ __align__(16) bf16 sm[];
    uint32_t smem0 = (uint32_t)__cvta_generic_to_shared(sm);

    int tid = threadIdx.x, warp = tid >> 5, lane = tid & 31;
    int g = lane >> 2, tig = lane & 3;
    int qt = blockIdx.x, bh = blockIdx.y;
    int b = bh >> 4, h = bh & 15;
    const long long LLD = (long long)LL * DD;
    long long baseQ = (long long)b*LLD + (long long)(qt*128)*DD + h*64;
    long long baseK = (long long)b*LLD + h*64;
    long long baseV = (long long)b*LLD + (long long)(h*64)*LL;

    // ---- Q fragments (held in registers for all 16 K-tiles) ----
    uint32_t qa_h[4][4], qa_l[4][4];
    {
        long long r0 = baseQ + (long long)(warp*16 + g)*DD;
        long long r8 = r0 + 8*DD;
        #pragma unroll
        for (int kf = 0; kf < 4; kf++) {
            int c = kf*16 + 2*tig;
            qa_h[kf][0] = *(const uint32_t*)(Qh + r0 + c);
            qa_h[kf][1] = *(const uint32_t*)(Qh + r8 + c);
            qa_h[kf][2] = *(const uint32_t*)(Qh + r0 + c + 8);
            qa_h[kf][3] = *(const uint32_t*)(Qh + r8 + c + 8);
            qa_l[kf][0] = *(const uint32_t*)(Ql + r0 + c);
            qa_l[kf][1] = *(const uint32_t*)(Ql + r8 + c);
            qa_l[kf][2] = *(const uint32_t*)(Ql + r0 + c + 8);
            qa_l[kf][3] = *(const uint32_t*)(Ql + r8 + c + 8);
        }
    }

    auto load_tiles = [&](int buf, int kt) {
        int so = buf * STG;
        #pragma unroll
        for (int i = 0; i < 4; i++) {           // K tile: 128 x 64 halves, hi+lo
            int ci = tid + i*256;
            int row = ci >> 3, ch = ci & 7;
            long long go = baseK + (long long)(kt*128 + row)*DD + ch*8;
            uint32_t sa = smem0 + 2*(so + row*KSP + ch*8);
            cpa16(sa,           Kh + go);
            cpa16(sa + 2*KTH,   Kl + go);
        }
        #pragma unroll
        for (int i = 0; i < 4; i++) {           // V^T tile: 64 x 128 halves, hi+lo
            int ci = tid + i*256;
            int row = ci >> 4, ch = ci & 15;
            long long go = baseV + (long long)row*LL + kt*128 + ch*8;
            uint32_t sa = smem0 + 2*(so + 2*KTH + row*VSP + ch*8);
            cpa16(sa,           Vth + go);
            cpa16(sa + 2*VTH,   Vtl + go);
        }
        asm volatile("cp.async.commit_group;");
    };

    float m_r[2] = {-1e30f, -1e30f};
    float l_r[2] = {0.f, 0.f};
    float o[8][4];
    #pragma unroll
    for (int n = 0; n < 8; n++)
        #pragma unroll
        for (int c = 0; c < 4; c++) o[n][c] = 0.f;

    load_tiles(0, 0);

    for (int kt = 0; kt < 16; kt++) {
        if (kt + 1 < 16) {
            load_tiles((kt+1)&1, kt+1);
            asm volatile("cp.async.wait_group 1;");
        } else {
            asm volatile("cp.async.wait_group 0;");
        }
        __syncthreads();
        int so = (kt & 1) * STG;

        // ---- S = Q K^T  (16x128 per warp) ----
        float s[16][4];
        #pragma unroll
        for (int n = 0; n < 16; n++)
            #pragma unroll
            for (int c = 0; c < 4; c++) s[n][c] = 0.f;

        #pragma unroll
        for (int kf = 0; kf < 4; kf++) {
            #pragma unroll
            for (int n = 0; n < 16; n++) {
                int r = so + (n*8 + g)*KSP + kf*16 + 2*tig;
                uint32_t bhf[2], blf[2];
                bhf[0] = *(const uint32_t*)(sm + r);
                bhf[1] = *(const uint32_t*)(sm + r + 8);
                blf[0] = *(const uint32_t*)(sm + r + KTH);
                blf[1] = *(const uint32_t*)(sm + r + KTH + 8);
                mma16816(s[n], qa_h[kf], bhf);
                mma16816(s[n], qa_l[kf], bhf);
                mma16816(s[n], qa_h[kf], blf);
            }
        }

        // ---- online softmax (rows g and g+8 of warp slab) ----
        float mx0 = -1e30f, mx1 = -1e30f;
        #pragma unroll
        for (int n = 0; n < 16; n++) {
            mx0 = fmaxf(mx0, fmaxf(s[n][0], s[n][1]));
            mx1 = fmaxf(mx1, fmaxf(s[n][2], s[n][3]));
        }
        #pragma unroll
        for (int off = 1; off < 4; off <<= 1) {
            mx0 = fmaxf(mx0, __shfl_xor_sync(0xffffffffu, mx0, off));
            mx1 = fmaxf(mx1, __shfl_xor_sync(0xffffffffu, mx1, off));
        }
        float mn0 = fmaxf(m_r[0], mx0), mn1 = fmaxf(m_r[1], mx1);
        float sf0 = __expf(m_r[0] - mn0), sf1 = __expf(m_r[1] - mn1);
        m_r[0] = mn0; m_r[1] = mn1;
        float sum0 = 0.f, sum1 = 0.f;
        #pragma unroll
        for (int n = 0; n < 16; n++) {
            s[n][0] = __expf(s[n][0] - mn0); sum0 += s[n][0];
            s[n][1] = __expf(s[n][1] - mn0); sum0 += s[n][1];
            s[n][2] = __expf(s[n][2] - mn1); sum1 += s[n][2];
            s[n][3] = __expf(s[n][3] - mn1); sum1 += s[n][3];
        }
        #pragma unroll
        for (int off = 1; off < 4; off <<= 1) {
            sum0 += __shfl_xor_sync(0xffffffffu, sum0, off);
            sum1 += __shfl_xor_sync(0xffffffffu, sum1, off);
        }
        l_r[0] = l_r[0]*sf0 + sum0;
        l_r[1] = l_r[1]*sf1 + sum1;
        #pragma unroll
        for (int n = 0; n < 8; n++) {
            o[n][0] *= sf0; o[n][1] *= sf0;
            o[n][2] *= sf1; o[n][3] *= sf1;
        }

        // ---- O += P V  (split P in registers) ----
        #pragma unroll
        for (int kf2 = 0; kf2 < 8; kf2++) {
            uint32_t pa_h[4], pa_l[4];
            #pragma unroll
            for (int q4 = 0; q4 < 2; q4++) {       // tiles 2kf2, 2kf2+1
                int t = 2*kf2 + q4;
                #pragma unroll
                for (int rr = 0; rr < 2; rr++) {   // row g / g+8
                    float p0 = s[t][rr*2+0], p1 = s[t][rr*2+1];
                    bf16 h0, l0, h1, l1;
                    split2(p0, h0, l0); split2(p1, h1, l1);
                    pa_h[q4*2+rr] = (uint32_t)__bfloat16_as_ushort(h0) |
                                    ((uint32_t)__bfloat16_as_ushort(h1) << 16);
                    pa_l[q4*2+rr] = (uint32_t)__bfloat16_as_ushort(l0) |
                                    ((uint32_t)__bfloat16_as_ushort(l1) << 16);
                }
            }
            #pragma unroll
            for (int n = 0; n < 8; n++) {
                int r = so + 2*KTH + (n*8 + g)*VSP + kf2*16 + 2*tig;
                uint32_t bhf[2], blf[2];
                bhf[0] = *(const uint32_t*)(sm + r);
                bhf[1] = *(const uint32_t*)(sm + r + 8);
                blf[0] = *(const uint32_t*)(sm + r + VTH);
                blf[1] = *(const uint32_t*)(sm + r + VTH + 8);
                mma16816(o[n], pa_h, bhf);
                mma16816(o[n], pa_l, bhf);
                mma16816(o[n], pa_h, blf);
            }
        }
        __syncthreads();
    }

    // ---- epilogue: O / l, split-bf16 store ----
    float il0 = 1.f / l_r[0], il1 = 1.f / l_r[1];
    long long r0 = baseQ + (long long)(warp*16 + g)*DD;
    long long r8 = r0 + 8*DD;
    #pragma unroll
    for (int n = 0; n < 8; n++) {
        int c = n*8 + 2*tig;
        float v0 = o[n][0]*il0, v1 = o[n][1]*il0;
        float v2 = o[n][2]*il1, v3 = o[n][3]*il1;
        bf16 h0,l0,h1,l1;
        split2(v0,h0,l0); split2(v1,h1,l1);
        *(uint32_t*)(Oh + r0 + c) = (uint32_t)__bfloat16_as_ushort(h0) |
                                    ((uint32_t)__bfloat16_as_ushort(h1) << 16);
        *(uint32_t*)(Ol + r0 + c) = (uint32_t)__bfloat16_as_ushort(l0) |
                                    ((uint32_t)__bfloat16_as_ushort(l1) << 16);
        split2(v2,h0,l0); split2(v3,h1,l1);
        *(uint32_t*)(Oh + r8 + c) = (uint32_t)__bfloat16_as_ushort(h0) |
                                    ((uint32_t)__bfloat16_as_ushort(h1) << 16);
        *(uint32_t*)(Ol + r8 + c) = (uint32_t)__bfloat16_as_ushort(l0) |
                                    ((uint32_t)__bfloat16_as_ushort(l1) << 16);
    }
}

// ---------------- transpose [rows,cols] -> [cols,rows] per batch (f32) ----------------
__global__ void transpose_kernel(const float* __restrict__ in, float* __restrict__ out,
                                 int rows, int cols)
{
    __shared__ float t[32][33];
    long long bo = (long long)blockIdx.z * rows * cols;
    int c0 = blockIdx.x * 32, r0 = blockIdx.y * 32;
    int tx = threadIdx.x, ty = threadIdx.y;
    #pragma unroll
    for (int i = 0; i < 32; i += 8)
        t[ty+i][tx] = in[bo + (long long)(r0+ty+i)*cols + (c0+tx)];
    __syncthreads();
    #pragma unroll
    for (int i = 0; i < 32; i += 8)
        out[bo + (long long)(c0+ty+i)*rows + (r0+tx)] = t[tx][ty+i];
}

// ---------------- transpose + split: f32 [rows,cols] -> bf16 hi/lo [cols,rows] ----------------
__global__ void transpose_split_kernel(const float* __restrict__ in,
                                       bf16* __restrict__ oh, bf16* __restrict__ ol,
                                       int rows, int cols)
{
    __shared__ float t[32][33];
    long long bo = (long long)blockIdx.z * rows * cols;
    int c0 = blockIdx.x * 32, r0 = blockIdx.y * 32;
    int tx = threadIdx.x, ty = threadIdx.y;
    #pragma unroll
    for (int i = 0; i < 32; i += 8)
        t[ty+i][tx] = in[bo + (long long)(r0+ty+i)*cols + (c0+tx)];
    __syncthreads();
    #pragma unroll
    for (int i = 0; i < 32; i += 8) {
        float v = t[tx][ty+i];
        bf16 h, l; split2(v, h, l);
        long long o = bo + (long long)(c0+ty+i)*rows + (r0+tx);
        oh[o] = h; ol[o] = l;
    }
}

// ---------------- elementwise split ----------------
__global__ void split_kernel(const float* __restrict__ x,
                             bf16* __restrict__ oh, bf16* __restrict__ ol)
{
    long long i = ((long long)blockIdx.x * 256 + threadIdx.x) * 4;
    float4 v = *(const float4*)(x + i);
    bf16 h, l;
    split2(v.x, h, l); oh[i+0] = h; ol[i+0] = l;
    split2(v.y, h, l); oh[i+1] = h; ol[i+1] = l;
    split2(v.z, h, l); oh[i+2] = h; ol[i+2] = l;
    split2(v.w, h, l); oh[i+3] = h; ol[i+3] = l;
}

// ---------------- FFT (radix-2 DIT, n=4096, 512 threads) ----------------
__device__ __forceinline__ int rev12(int i) { return __brev(i) >> 20; }

__device__ __forceinline__ void tw_init(float2* tw, int tid) {
    for (int m = tid; m < 1024; m += 512) {
        float sv, cv;
        sincosf(-6.283185307179586f * (float)m / 4096.0f, &sv, &cv);
        tw[m] = make_float2(cv, sv);
    }
}

__device__ void do_fft(float2* s, const float2* tw, int tid) {
    #pragma unroll 1
    for (int lh = 0; lh < 12; lh++) {
        int half = 1 << lh;
        #pragma unroll 1
        for (int idx = tid; idx < NF4096/2; idx += 512) {
            int j   = idx & (half - 1);
            int pos = 2*idx - j;
            int m   = j << (11 - lh);
            float2 w;
            if (m & 1024) { float2 t = tw[m & 1023]; w = make_float2(t.y, -t.x); }
            else          { w = tw[m]; }
            float2 u = s[pos];
            float2 q = s[pos + half];
            float2 v = make_float2(w.x*q.x - w.y*q.y, w.x*q.y + w.y*q.x);
            s[pos]        = make_float2(u.x + v.x, u.y + v.y);
            s[pos + half] = make_float2(u.x - v.x, u.y - v.y);
        }
        __syncthreads();
    }
}

__global__ void __launch_bounds__(512) filters_kernel(
    const float* __restrict__ eig_vals, const float* __restrict__ eig_vecs,
    const float* __restrict__ w_filters, float2* __restrict__ Ffilt)
{
    __shared__ float2 s[NF4096];
    __shared__ float2 tw[1024];
    __shared__ float  wk[KK];
    int d = blockIdx.x, tid = threadIdx.x;
    if (tid < KK) wk[tid] = powf(eig_vals[tid], 0.25f) * w_filters[tid*DD + d];
    tw_init(tw, tid);
    for (int i = tid; i < NF4096; i += 512) s[i] = make_float2(0.f, 0.f);
    __syncthreads();
    for (int t = tid; t < LL; t += 512) {
        float f = 0.f;
        #pragma unroll
        for (int k = 0; k < KK; k++) f += eig_vecs[t*KK + k] * wk[k];
        s[rev12(t)] = make_float2(f, 0.f);
    }
    __syncthreads();
    do_fft(s, tw, tid);
    for (int i = tid; i < NF4096; i += 512)
        Ffilt[(long long)d*NF4096 + i] = s[i];
}

// 2-for-1 packed conv: channels (2dp, 2dp+1) as re+im of one complex FFT
__global__ void __launch_bounds__(512) conv2_kernel(
    const float* __restrict__ xt, const float2* __restrict__ Ffilt,
    float* __restrict__ projt)
{
    __shared__ float2 s[NF4096];
    __shared__ float2 tw[1024];
    int z = blockIdx.x, tid = threadIdx.x;
    int b = z >> 9, dp = z & 511;
    int d0 = 2*dp;
    long long base0 = ((long long)b*DD + d0) * LL;
    long long base1 = base0 + LL;
    tw_init(tw, tid);
    for (int i = tid; i < NF4096; i += 512) s[i] = make_float2(0.f, 0.f);
    __syncthreads();
    for (int t = tid; t < LL; t += 512)
        s[rev12(t)] = make_float2(xt[base0 + t], xt[base1 + t]);
    __syncthreads();
    do_fft(s, tw, tid);

    const float2* F0 = Ffilt + (long long)d0 * NF4096;
    const float2* F1 = F0 + NF4096;
    for (int i = tid; i < 2048; i += 512) {
        if (i == 0) {
            #pragma unroll
            for (int q = 0; q < 2; q++) {
                int idx = q * 2048;
                float2 Z = s[idx];
                float X1 = Z.x, X2 = Z.y;           // both spectra real here
                float2 f0 = F0[idx], f1 = F1[idx];
                float2 Y1 = make_float2(X1*f0.x, X1*f0.y);
                float2 Y2 = make_float2(X2*f1.x, X2*f1.y);
                // W = Y1 + i*Y2 ; store conj(W)
                s[idx] = make_float2(Y1.x - Y2.y, -(Y1.y + Y2.x));
            }
        } else {
            float2 Za = s[i], Zb = s[NF4096 - i];
            float2 X1 = make_float2(0.5f*(Za.x + Zb.x), 0.5f*(Za.y - Zb.y));
            float2 Dd = make_float2(Za.x - Zb.x, Za.y + Zb.y);   // Za - conj(Zb)
            float2 X2 = make_float2(0.5f*Dd.y, -0.5f*Dd.x);      // -i*D/2
            float2 f0 = F0[i], f1 = F1[i];
            float2 Y1 = make_float2(X1.x*f0.x - X1.y*f0.y, X1.x*f0.y + X1.y*f0.x);
            float2 Y2 = make_float2(X2.x*f1.x - X2.y*f1.y, X2.x*f1.y + X2.y*f1.x);
            // s[i]   = conj(W_i)      = conj(Y1 + iY2)
            s[i]          = make_float2(Y1.x - Y2.y, -(Y1.y + Y2.x));
            // s[N-i] = conj(W_{N-i})  = Y1 - iY2
            s[NF4096 - i] = make_float2(Y1.x + Y2.y, Y1.y - Y2.x);
        }
    }
    __syncthreads();
    float2 r[8];
    #pragma unroll
    for (int k = 0; k < 8; k++) r[k] = s[rev12(tid + k*512)];
    __syncthreads();
    #pragma unroll
    for (int k = 0; k < 8; k++) s[tid + k*512] = r[k];
    __syncthreads();
    do_fft(s, tw, tid);
    const float inv = 1.0f / 4096.0f;
    for (int l = tid; l < LL; l += 512) {
        projt[base0 + l] =  s[l].x * inv;
        projt[base1 + l] = -s[l].y * inv;
    }
}

// ---------------- LayerNorm with split-bf16 output ----------------
__global__ void __launch_bounds__(256) ln_split_kernel(
    const float* __restrict__ x, bf16* __restrict__ yh, bf16* __restrict__ yl,
    const float* __restrict__ sc, const float* __restrict__ bi)
{
    long long base = (long long)blockIdx.x * DD;
    int tid = threadIdx.x;
    float4 v = *(const float4*)(x + base + tid*4);
    float mean = block_sum256(v.x + v.y + v.z + v.w) * (1.0f/DD);
    float dx = v.x - mean, dy = v.y - mean, dz = v.z - mean, dw = v.w - mean;
    float var = block_sum256(dx*dx + dy*dy + dz*dz + dw*dw) * (1.0f/DD);
    float rstd = rsqrtf(var + 1e-6f);
    float4 s4 = *(const float4*)(sc + tid*4);
    float4 b4 = *(const float4*)(bi + tid*4);
    float o0 = dx*rstd*s4.x + b4.x;
    float o1 = dy*rstd*s4.y + b4.y;
    float o2 = dz*rstd*s4.z + b4.z;
    float o3 = dw*rstd*s4.w + b4.w;
    long long i = base + tid*4;
    bf16 h, l;
    split2(o0, h, l); yh[i+0] = h; yl[i+0] = l;
    split2(o1, h, l); yh[i+1] = h; yl[i+1] = l;
    split2(o2, h, l); yh[i+2] = h; yl[i+2] = l;
    split2(o3, h, l); yh[i+3] = h; yl[i+3] = l;
}

// ---------------- launch ----------------
static void* symv(const void* s) { void* p = nullptr; cudaGetSymbolAddress(&p, s); return p; }

extern "C" void kernel_launch(void* const* d_in, const int* in_sizes, int n_in,
                              void* d_out, int out_size)
{
    const float* inputs    = (const float*)d_in[0];
    const float* eig_vals  = (const float*)d_in[1];
    const float* eig_vecs  = (const float*)d_in[2];
    const float* w_filters = (const float*)d_in[3];
    const float* w_inputs  = (const float*)d_in[4];
    const float* ln1_s     = (const float*)d_in[5];
    const float* ln1_b     = (const float*)d_in[6];
    const float* wq        = (const float*)d_in[7];
    const float* wk        = (const float*)d_in[8];
    const float* wv        = (const float*)d_in[9];
    const float* wo        = (const float*)d_in[10];
    const float* ln2_s     = (const float*)d_in[11];
    const float* ln2_b     = (const float*)d_in[12];
    const float* mlp_w1    = (const float*)d_in[13];
    const float* mlp_b1    = (const float*)d_in[14];
    const float* mlp_w2    = (const float*)d_in[15];
    const float* mlp_b2    = (const float*)d_in[16];
    float* out = (float*)d_out;

    float*  xi    = (float*)symv(g_xi);
    float*  xt    = (float*)symv(g_xt);
    float2* Ffilt = (float2*)symv(g_Ffilt);
    float*  projt = (float*)symv(g_projt);
    float*  stu   = (float*)symv(g_stu);
    float*  vbuf  = (float*)symv(g_v);
    float*  xres  = (float*)symv(g_xres);

    bf16 *inh=(bf16*)symv(g_inh),  *inl=(bf16*)symv(g_inl);
    bf16 *x1h=(bf16*)symv(g_x1h),  *x1l=(bf16*)symv(g_x1l);
    bf16 *qh =(bf16*)symv(g_qh),   *ql =(bf16*)symv(g_ql);
    bf16 *kh =(bf16*)symv(g_kh),   *kl =(bf16*)symv(g_kl);
    bf16 *vTh=(bf16*)symv(g_vTh),  *vTl=(bf16*)symv(g_vTl);
    bf16 *ath=(bf16*)symv(g_ath),  *atl=(bf16*)symv(g_atl);
    bf16 *y1h=(bf16*)symv(g_y1h),  *y1l=(bf16*)symv(g_y1l);
    bf16 *hh =(bf16*)symv(g_hh),   *hl =(bf16*)symv(g_hl);
    bf16 *wiTh=(bf16*)symv(g_wiTh),*wiTl=(bf16*)symv(g_wiTl);
    bf16 *wqTh=(bf16*)symv(g_wqTh),*wqTl=(bf16*)symv(g_wqTl);
    bf16 *wkTh=(bf16*)symv(g_wkTh),*wkTl=(bf16*)symv(g_wkTl);
    bf16 *wvTh=(bf16*)symv(g_wvTh),*wvTl=(bf16*)symv(g_wvTl);
    bf16 *woTh=(bf16*)symv(g_woTh),*woTl=(bf16*)symv(g_woTl);
    bf16 *w1Th=(bf16*)symv(g_w1Th),*w1Tl=(bf16*)symv(g_w1Tl);
    bf16 *w2Th=(bf16*)symv(g_w2Th),*w2Tl=(bf16*)symv(g_w2Tl);

    const int SM128 = 81920;
    const int SMFL  = 143360;
    cudaFuncSetAttribute(gemm_bf16<128>, cudaFuncAttributeMaxDynamicSharedMemorySize, SM128);
    cudaFuncSetAttribute(flash_kernel,   cudaFuncAttributeMaxDynamicSharedMemorySize, SMFL);

    dim3 t328(32, 8);

    // 1. filter spectrum per channel d
    filters_kernel<<<DD, 512>>>(eig_vals, eig_vecs, w_filters, Ffilt);

    // 2. split inputs; transpose-split all weights to [N][K]
    split_kernel<<<(BL*DD)/1024, 256>>>(inputs, inh, inl);
    transpose_split_kernel<<<dim3(32, 32, 1), t328>>>(w_inputs, wiTh, wiTl, DD, DD);
    transpose_split_kernel<<<dim3(32, 32, 1), t328>>>(wq, wqTh, wqTl, DD, DD);
    transpose_split_kernel<<<dim3(32, 32, 1), t328>>>(wk, wkTh, wkTl, DD, DD);
    transpose_split_kernel<<<dim3(32, 32, 1), t328>>>(wv, wvTh, wvTl, DD, DD);
    transpose_split_kernel<<<dim3(32, 32, 1), t328>>>(wo, woTh, woTl, DD, DD);
    transpose_split_kernel<<<dim3(MLPD/32, DD/32, 1), t328>>>(mlp_w1, w1Th, w1Tl, DD, MLPD);
    transpose_split_kernel<<<dim3(DD/32, MLPD/32, 1), t328>>>(mlp_w2, w2Th, w2Tl, MLPD, DD);

    // 3. xi = inputs @ w_inputs (f32 out for FFT)
    gemm_bf16<128><<<dim3(DD/128, BL/128, 1), 256, SM128>>>(
        inh, inl, wiTh, wiTl, xi, nullptr, nullptr,
        BL, DD, DD, DD, DD, DD, 0,0,0,0,0,0, 1, 1.0f, nullptr, nullptr, 0);

    // 4. spectral causal conv (2-for-1 packed FFT)
    transpose_kernel<<<dim3(DD/32, LL/32, BB), t328>>>(xi, xt, LL, DD);
    conv2_kernel<<<BB*DD/2, 512>>>(xt, Ffilt, projt);
    transpose_kernel<<<dim3(LL/32, DD/32, BB), t328>>>(projt, stu, DD, LL);

    // 5. LN1 -> split x1
    ln_split_kernel<<<BL, 256>>>(stu, x1h, x1l, ln1_s, ln1_b);

    // 6. Q (scaled, split), K (split), V (f32 then transpose-split)
    gemm_bf16<128><<<dim3(8, 64, 1), 256, SM128>>>(
        x1h, x1l, wqTh, wqTl, nullptr, qh, ql,
        BL, DD, DD, DD, DD, DD, 0,0,0,0,0,0, 1, 0.125f, nullptr, nullptr, 8);
    gemm_bf16<128><<<dim3(8, 64, 1), 256, SM128>>>(
        x1h, x1l, wkTh, wkTl, nullptr, kh, kl,
        BL, DD, DD, DD, DD, DD, 0,0,0,0,0,0, 1, 1.0f, nullptr, nullptr, 8);
    gemm_bf16<128><<<dim3(8, 64, 1), 256, SM128>>>(
        x1h, x1l, wvTh, wvTl, vbuf, nullptr, nullptr,
        BL, DD, DD, DD, DD, DD, 0,0,0,0,0,0, 1, 1.0f, nullptr, nullptr, 0);
    transpose_split_kernel<<<dim3(DD/32, LL/32, BB), t328>>>(vbuf, vTh, vTl, LL, DD);

    // 7. fused flash attention -> split att
    flash_kernel<<<dim3(LL/128, BB*HH), 256, SMFL>>>(
        qh, ql, kh, kl, vTh, vTl, ath, atl);

    // 8. x = att @ wo + stu (f32)
    gemm_bf16<128><<<dim3(8, 64, 1), 256, SM128>>>(
        ath, atl, woTh, woTl, xres, nullptr, nullptr,
        BL, DD, DD, DD, DD, DD, 0,0,0,0,0,0, 1, 1.0f, nullptr, stu, 4);

    // 9. LN2 -> split y1
    ln_split_kernel<<<BL, 256>>>(xres, y1h, y1l, ln2_s, ln2_b);

    // 10. h = gelu(y1 @ w1 + b1), split out
    gemm_bf16<128><<<dim3(MLPD/128, 64, 1), 256, SM128>>>(
        y1h, y1l, w1Th, w1Tl, nullptr, hh, hl,
        BL, MLPD, DD, DD, DD, MLPD, 0,0,0,0,0,0, 1, 1.0f, mlp_b1, nullptr, 11);

    // 11. out = h @ w2 + b2 + x (f32)
    gemm_bf16<128><<<dim3(8, 64, 1), 256, SM128>>>(
        hh, hl, w2Th, w2Tl, out, nullptr, nullptr,
        BL, DD, MLPD, MLPD, MLPD, DD, 0,0,0,0,0,0, 1, 1.0f, mlp_b2, xres, 5);
}

// round 9
// speedup vs baseline: 3.2974x; 1.1298x over previous
#include <cuda_runtime.h>
#include <cuda_bf16.h>
#include <math.h>
#include <stdint.h>

#define BB 4
#define LL 2048
#define DD 1024
#define HH 16
#define HDIM 64
#define KK 24
#define MLPD 4096
#define BL (BB*LL)
#define NF4096 4096

typedef __nv_bfloat16 bf16;

// ---------------- scratch (device globals; allocation-free) ----------------
__device__ float  g_xi[BL*DD];
__device__ float  g_xt[BL*DD];
__device__ float2 g_Ffilt[(size_t)DD*NF4096];
__device__ float  g_projt[BL*DD];
__device__ float  g_stu[BL*DD];
__device__ float  g_v[BL*DD];
__device__ float  g_xres[BL*DD];

__device__ bf16 g_inh[BL*DD],  g_inl[BL*DD];
__device__ bf16 g_x1h[BL*DD],  g_x1l[BL*DD];
__device__ bf16 g_qh [BL*DD],  g_ql [BL*DD];
__device__ bf16 g_kh [BL*DD],  g_kl [BL*DD];
__device__ bf16 g_vTh[BL*DD],  g_vTl[BL*DD];       // [B,H*HD,L]
__device__ bf16 g_ath[BL*DD],  g_atl[BL*DD];
__device__ bf16 g_y1h[BL*DD],  g_y1l[BL*DD];
__device__ bf16 g_hh[(size_t)BL*MLPD], g_hl[(size_t)BL*MLPD];
// transposed-split weights [N][K]
__device__ bf16 g_wiTh[DD*DD],  g_wiTl[DD*DD];
__device__ bf16 g_wqTh[DD*DD],  g_wqTl[DD*DD];
__device__ bf16 g_wkTh[DD*DD],  g_wkTl[DD*DD];
__device__ bf16 g_wvTh[DD*DD],  g_wvTl[DD*DD];
__device__ bf16 g_woTh[DD*DD],  g_woTl[DD*DD];
__device__ bf16 g_w1Th[(size_t)DD*MLPD], g_w1Tl[(size_t)DD*MLPD];
__device__ bf16 g_w2Th[(size_t)DD*MLPD], g_w2Tl[(size_t)DD*MLPD];

// ---------------- helpers ----------------
__device__ __forceinline__ float gelu_f(float x) {
    float x3 = x*x*x;
    return 0.5f*x*(1.0f + tanhf(0.7978845608028654f*(x + 0.044715f*x3)));
}
__device__ __forceinline__ void split2(float v, bf16 &h, bf16 &l) {
    h = __float2bfloat16_rn(v);
    l = __float2bfloat16_rn(v - __bfloat162float(h));
}
__device__ __forceinline__ uint32_t pack2(bf16 a, bf16 b) {
    return (uint32_t)__bfloat16_as_ushort(a) | ((uint32_t)__bfloat16_as_ushort(b) << 16);
}
__device__ __forceinline__ void cpa16(uint32_t s, const void* g) {
    asm volatile("cp.async.cg.shared.global [%0], [%1], 16;" :: "r"(s), "l"(g));
}
__device__ __forceinline__ void mma16816(float* c, const uint32_t* a, const uint32_t* b) {
    asm volatile("mma.sync.aligned.m16n8k16.row.col.f32.bf16.bf16.f32 "
                 "{%0,%1,%2,%3},{%4,%5,%6,%7},{%8,%9},{%0,%1,%2,%3};"
                 : "+f"(c[0]), "+f"(c[1]), "+f"(c[2]), "+f"(c[3])
                 : "r"(a[0]), "r"(a[1]), "r"(a[2]), "r"(a[3]),
                   "r"(b[0]), "r"(b[1]));
}
__device__ __forceinline__ float block_sum256(float v) {
    __shared__ float red[8];
    int lane = threadIdx.x & 31, w = threadIdx.x >> 5;
    #pragma unroll
    for (int o = 16; o; o >>= 1) v += __shfl_xor_sync(0xffffffffu, v, o);
    __syncthreads();
    if (lane == 0) red[w] = v;
    __syncthreads();
    if (threadIdx.x == 0) {
        float s = 0.f;
        #pragma unroll
        for (int i = 0; i < 8; i++) s += red[i];
        red[0] = s;
    }
    __syncthreads();
    return red[0];
}

// ---------------- split-bf16 tensor-core GEMM (dense layers) ----------------
// C[M,N] = alpha*(A@B^T) (+bias/gelu/resid/split). A split [M,K] row-major,
// B split [N,K] row-major. Tile 128x128, 2 CTAs/SM (128-reg cap), 2-stage.
// mode: 1=bias, 2=gelu, 4=resid, 8=split-out
__global__ void __launch_bounds__(256, 2) gemm_bf16(
    const bf16* __restrict__ Ahi, const bf16* __restrict__ Alo,
    const bf16* __restrict__ Bhi, const bf16* __restrict__ Blo,
    float* __restrict__ C, bf16* __restrict__ Chi, bf16* __restrict__ Clo,
    int M, int N, int Kd, int lda, int ldb, int ldc,
    float alpha, const float* __restrict__ bias,
    const float* __restrict__ resid, int mode)
{
    constexpr int SP    = 40;
    constexpr int AH    = 128 * SP;
    constexpr int BHalf = 128 * SP;
    constexpr int STAGE = 2*AH + 2*BHalf;   // 20480 halves = 40960 B

    extern __shared__ __align__(16) char dsm[];
    uint32_t smem0 = (uint32_t)__cvta_generic_to_shared(dsm);

    int tid   = threadIdx.x;
    int mBase = blockIdx.y * 128, nBase = blockIdx.x * 128;

    const bf16* pAh = Ahi + (long long)mBase * lda;
    const bf16* pAl = Alo + (long long)mBase * lda;
    const bf16* pBh = Bhi + (long long)nBase * ldb;
    const bf16* pBl = Blo + (long long)nBase * ldb;

    int warp = tid >> 5, lane = tid & 31;
    int wm = warp & 3, wn = warp >> 2;
    int g  = lane >> 2, tig = lane & 3;

    float acc[2][8][4];
    #pragma unroll
    for (int i = 0; i < 2; i++)
        #pragma unroll
        for (int j = 0; j < 8; j++)
            #pragma unroll
            for (int c = 0; c < 4; c++) acc[i][j][c] = 0.f;

    auto load_stage = [&](int buf, int k0) {
        int so = buf * STAGE;
        #pragma unroll
        for (int i = 0; i < 2; i++) {
            int ci = tid + i*256;
            int row = ci >> 2, seg = ci & 3;
            long long go = (long long)row*lda + k0 + seg*8;
            uint32_t sa = smem0 + 2*(so + row*SP + seg*8);
            cpa16(sa,          pAh + go);
            cpa16(sa + 2*AH,   pAl + go);
        }
        #pragma unroll
        for (int i = 0; i < 2; i++) {
            int ci = tid + i*256;
            int row = ci >> 2, seg = ci & 3;
            long long go = (long long)row*ldb + k0 + seg*8;
            uint32_t sa = smem0 + 2*(so + 2*AH + row*SP + seg*8);
            cpa16(sa,              pBh + go);
            cpa16(sa + 2*BHalf,    pBl + go);
        }
        asm volatile("cp.async.commit_group;");
    };

    int nk = Kd >> 5;
    load_stage(0, 0);

    for (int ks = 0; ks < nk; ks++) {
        if (ks + 1 < nk) {
            load_stage((ks+1)&1, (ks+1) << 5);
            asm volatile("cp.async.wait_group 1;");
        } else {
            asm volatile("cp.async.wait_group 0;");
        }
        __syncthreads();
        int so = (ks & 1) * STAGE;

        #pragma unroll
        for (int kh = 0; kh < 2; kh++) {
            int ko = kh*16 + 2*tig;
            uint32_t ah[2][4], al[2][4];
            #pragma unroll
            for (int mi = 0; mi < 2; mi++) {
                int r = so + (wm*32 + mi*16 + g)*SP + ko;
                ah[mi][0] = *(const uint32_t*)(dsm + 2*(r));
                ah[mi][1] = *(const uint32_t*)(dsm + 2*(r + 8*SP));
                ah[mi][2] = *(const uint32_t*)(dsm + 2*(r + 8));
                ah[mi][3] = *(const uint32_t*)(dsm + 2*(r + 8*SP + 8));
                al[mi][0] = *(const uint32_t*)(dsm + 2*(r + AH));
                al[mi][1] = *(const uint32_t*)(dsm + 2*(r + AH + 8*SP));
                al[mi][2] = *(const uint32_t*)(dsm + 2*(r + AH + 8));
                al[mi][3] = *(const uint32_t*)(dsm + 2*(r + AH + 8*SP + 8));
            }
            // consume B fragments immediately per ni to keep live regs low
            #pragma unroll
            for (int ni = 0; ni < 8; ni++) {
                int r = so + 2*AH + (wn*64 + ni*8 + g)*SP + ko;
                uint32_t bhf[2], blf[2];
                bhf[0] = *(const uint32_t*)(dsm + 2*(r));
                bhf[1] = *(const uint32_t*)(dsm + 2*(r + 8));
                blf[0] = *(const uint32_t*)(dsm + 2*(r + BHalf));
                blf[1] = *(const uint32_t*)(dsm + 2*(r + BHalf + 8));
                #pragma unroll
                for (int mi = 0; mi < 2; mi++) {
                    mma16816(acc[mi][ni], ah[mi], bhf);
                    mma16816(acc[mi][ni], al[mi], bhf);
                    mma16816(acc[mi][ni], ah[mi], blf);
                }
            }
        }
        __syncthreads();
    }

    bool hb = mode & 1, hg = mode & 2, hr = mode & 4, hs = mode & 8;
    #pragma unroll
    for (int mi = 0; mi < 2; mi++) {
        int m0 = mBase + wm*32 + mi*16 + g;
        #pragma unroll
        for (int ni = 0; ni < 8; ni++) {
            int n = nBase + wn*64 + ni*8 + 2*tig;
            #pragma unroll
            for (int hrow = 0; hrow < 2; hrow++) {
                int m = m0 + hrow*8;
                float v0 = acc[mi][ni][hrow*2+0] * alpha;
                float v1 = acc[mi][ni][hrow*2+1] * alpha;
                if (hb) { v0 += bias[n]; v1 += bias[n+1]; }
                if (hg) { v0 = gelu_f(v0); v1 = gelu_f(v1); }
                long long o = (long long)m*ldc + n;
                if (hr) { v0 += resid[o]; v1 += resid[o+1]; }
                if (hs) {
                    bf16 h0, l0, h1, l1;
                    split2(v0, h0, l0); split2(v1, h1, l1);
                    *(uint32_t*)(Chi + o) = pack2(h0, h1);
                    *(uint32_t*)(Clo + o) = pack2(l0, l1);
                } else {
                    C[o] = v0; C[o+1] = v1;
                }
            }
        }
    }
}

// ---------------- flash attention (fused QK^T / softmax / PV, mma.sync) ----------------
__global__ void __launch_bounds__(256) flash_kernel(
    const bf16* __restrict__ Qh, const bf16* __restrict__ Ql,
    const bf16* __restrict__ Kh, const bf16* __restrict__ Kl,
    const bf16* __restrict__ Vth, const bf16* __restrict__ Vtl,
    bf16* __restrict__ Oh, bf16* __restrict__ Ol)
{
    constexpr int KSP = 72, VSP = 136;
    constexpr int KTH = 128*KSP;
    constexpr int VTH = 64*VSP;
    constexpr int STG = 2*KTH + 2*VTH;

    extern __shared__ __align__(16) bf16 sm[];
    uint32_t smem0 = (uint32_t)__cvta_generic_to_shared(sm);

    int tid = threadIdx.x, warp = tid >> 5, lane = tid & 31;
    int g = lane >> 2, tig = lane & 3;
    int qt = blockIdx.x, bh = blockIdx.y;
    int b = bh >> 4, h = bh & 15;
    const long long LLD = (long long)LL * DD;
    long long baseQ = (long long)b*LLD + (long long)(qt*128)*DD + h*64;
    long long baseK = (long long)b*LLD + h*64;
    long long baseV = (long long)b*LLD + (long long)(h*64)*LL;

    uint32_t qa_h[4][4], qa_l[4][4];
    {
        long long r0 = baseQ + (long long)(warp*16 + g)*DD;
        long long r8 = r0 + 8*DD;
        #pragma unroll
        for (int kf = 0; kf < 4; kf++) {
            int c = kf*16 + 2*tig;
            qa_h[kf][0] = *(const uint32_t*)(Qh + r0 + c);
            qa_h[kf][1] = *(const uint32_t*)(Qh + r8 + c);
            qa_h[kf][2] = *(const uint32_t*)(Qh + r0 + c + 8);
            qa_h[kf][3] = *(const uint32_t*)(Qh + r8 + c + 8);
            qa_l[kf][0] = *(const uint32_t*)(Ql + r0 + c);
            qa_l[kf][1] = *(const uint32_t*)(Ql + r8 + c);
            qa_l[kf][2] = *(const uint32_t*)(Ql + r0 + c + 8);
            qa_l[kf][3] = *(const uint32_t*)(Ql + r8 + c + 8);
        }
    }

    auto load_tiles = [&](int buf, int kt) {
        int so = buf * STG;
        #pragma unroll
        for (int i = 0; i < 4; i++) {
            int ci = tid + i*256;
            int row = ci >> 3, ch = ci & 7;
            long long go = baseK + (long long)(kt*128 + row)*DD + ch*8;
            uint32_t sa = smem0 + 2*(so + row*KSP + ch*8);
            cpa16(sa,           Kh + go);
            cpa16(sa + 2*KTH,   Kl + go);
        }
        #pragma unroll
        for (int i = 0; i < 4; i++) {
            int ci = tid + i*256;
            int row = ci >> 4, ch = ci & 15;
            long long go = baseV + (long long)row*LL + kt*128 + ch*8;
            uint32_t sa = smem0 + 2*(so + 2*KTH + row*VSP + ch*8);
            cpa16(sa,           Vth + go);
            cpa16(sa + 2*VTH,   Vtl + go);
        }
        asm volatile("cp.async.commit_group;");
    };

    float m_r[2] = {-1e30f, -1e30f};
    float l_r[2] = {0.f, 0.f};
    float o[8][4];
    #pragma unroll
    for (int n = 0; n < 8; n++)
        #pragma unroll
        for (int c = 0; c < 4; c++) o[n][c] = 0.f;

    load_tiles(0, 0);

    for (int kt = 0; kt < 16; kt++) {
        if (kt + 1 < 16) {
            load_tiles((kt+1)&1, kt+1);
            asm volatile("cp.async.wait_group 1;");
        } else {
            asm volatile("cp.async.wait_group 0;");
        }
        __syncthreads();
        int so = (kt & 1) * STG;

        float s[16][4];
        #pragma unroll
        for (int n = 0; n < 16; n++)
            #pragma unroll
            for (int c = 0; c < 4; c++) s[n][c] = 0.f;

        #pragma unroll
        for (int kf = 0; kf < 4; kf++) {
            #pragma unroll
            for (int n = 0; n < 16; n++) {
                int r = so + (n*8 + g)*KSP + kf*16 + 2*tig;
                uint32_t bhf[2], blf[2];
                bhf[0] = *(const uint32_t*)(sm + r);
                bhf[1] = *(const uint32_t*)(sm + r + 8);
                blf[0] = *(const uint32_t*)(sm + r + KTH);
                blf[1] = *(const uint32_t*)(sm + r + KTH + 8);
                mma16816(s[n], qa_h[kf], bhf);
                mma16816(s[n], qa_l[kf], bhf);
                mma16816(s[n], qa_h[kf], blf);
            }
        }

        float mx0 = -1e30f, mx1 = -1e30f;
        #pragma unroll
        for (int n = 0; n < 16; n++) {
            mx0 = fmaxf(mx0, fmaxf(s[n][0], s[n][1]));
            mx1 = fmaxf(mx1, fmaxf(s[n][2], s[n][3]));
        }
        #pragma unroll
        for (int off = 1; off < 4; off <<= 1) {
            mx0 = fmaxf(mx0, __shfl_xor_sync(0xffffffffu, mx0, off));
            mx1 = fmaxf(mx1, __shfl_xor_sync(0xffffffffu, mx1, off));
        }
        float mn0 = fmaxf(m_r[0], mx0), mn1 = fmaxf(m_r[1], mx1);
        float sf0 = __expf(m_r[0] - mn0), sf1 = __expf(m_r[1] - mn1);
        m_r[0] = mn0; m_r[1] = mn1;
        float sum0 = 0.f, sum1 = 0.f;
        #pragma unroll
        for (int n = 0; n < 16; n++) {
            s[n][0] = __expf(s[n][0] - mn0); sum0 += s[n][0];
            s[n][1] = __expf(s[n][1] - mn0); sum0 += s[n][1];
            s[n][2] = __expf(s[n][2] - mn1); sum1 += s[n][2];
            s[n][3] = __expf(s[n][3] - mn1); sum1 += s[n][3];
        }
        #pragma unroll
        for (int off = 1; off < 4; off <<= 1) {
            sum0 += __shfl_xor_sync(0xffffffffu, sum0, off);
            sum1 += __shfl_xor_sync(0xffffffffu, sum1, off);
        }
        l_r[0] = l_r[0]*sf0 + sum0;
        l_r[1] = l_r[1]*sf1 + sum1;
        #pragma unroll
        for (int n = 0; n < 8; n++) {
            o[n][0] *= sf0; o[n][1] *= sf0;
            o[n][2] *= sf1; o[n][3] *= sf1;
        }

        #pragma unroll
        for (int kf2 = 0; kf2 < 8; kf2++) {
            uint32_t pa_h[4], pa_l[4];
            #pragma unroll
            for (int q4 = 0; q4 < 2; q4++) {
                int t = 2*kf2 + q4;
                #pragma unroll
                for (int rr = 0; rr < 2; rr++) {
                    float p0 = s[t][rr*2+0], p1 = s[t][rr*2+1];
                    bf16 h0, l0, h1, l1;
                    split2(p0, h0, l0); split2(p1, h1, l1);
                    pa_h[q4*2+rr] = pack2(h0, h1);
                    pa_l[q4*2+rr] = pack2(l0, l1);
                }
            }
            #pragma unroll
            for (int n = 0; n < 8; n++) {
                int r = so + 2*KTH + (n*8 + g)*VSP + kf2*16 + 2*tig;
                uint32_t bhf[2], blf[2];
                bhf[0] = *(const uint32_t*)(sm + r);
                bhf[1] = *(const uint32_t*)(sm + r + 8);
                blf[0] = *(const uint32_t*)(sm + r + VTH);
                blf[1] = *(const uint32_t*)(sm + r + VTH + 8);
                mma16816(o[n], pa_h, bhf);
                mma16816(o[n], pa_l, bhf);
                mma16816(o[n], pa_h, blf);
            }
        }
        __syncthreads();
    }

    float il0 = 1.f / l_r[0], il1 = 1.f / l_r[1];
    long long r0 = baseQ + (long long)(warp*16 + g)*DD;
    long long r8 = r0 + 8*DD;
    #pragma unroll
    for (int n = 0; n < 8; n++) {
        int c = n*8 + 2*tig;
        float v0 = o[n][0]*il0, v1 = o[n][1]*il0;
        float v2 = o[n][2]*il1, v3 = o[n][3]*il1;
        bf16 h0,l0,h1,l1;
        split2(v0,h0,l0); split2(v1,h1,l1);
        *(uint32_t*)(Oh + r0 + c) = pack2(h0,h1);
        *(uint32_t*)(Ol + r0 + c) = pack2(l0,l1);
        split2(v2,h0,l0); split2(v3,h1,l1);
        *(uint32_t*)(Oh + r8 + c) = pack2(h0,h1);
        *(uint32_t*)(Ol + r8 + c) = pack2(l0,l1);
    }
}

// ---------------- transpose [rows,cols] -> [cols,rows] per batch (f32) ----------------
__global__ void transpose_kernel(const float* __restrict__ in, float* __restrict__ out,
                                 int rows, int cols)
{
    __shared__ float t[32][33];
    long long bo = (long long)blockIdx.z * rows * cols;
    int c0 = blockIdx.x * 32, r0 = blockIdx.y * 32;
    int tx = threadIdx.x, ty = threadIdx.y;
    #pragma unroll
    for (int i = 0; i < 32; i += 8)
        t[ty+i][tx] = in[bo + (long long)(r0+ty+i)*cols + (c0+tx)];
    __syncthreads();
    #pragma unroll
    for (int i = 0; i < 32; i += 8)
        out[bo + (long long)(c0+ty+i)*rows + (r0+tx)] = t[tx][ty+i];
}

// ---------------- transpose + split ----------------
__global__ void transpose_split_kernel(const float* __restrict__ in,
                                       bf16* __restrict__ oh, bf16* __restrict__ ol,
                                       int rows, int cols)
{
    __shared__ float t[32][33];
    long long bo = (long long)blockIdx.z * rows * cols;
    int c0 = blockIdx.x * 32, r0 = blockIdx.y * 32;
    int tx = threadIdx.x, ty = threadIdx.y;
    #pragma unroll
    for (int i = 0; i < 32; i += 8)
        t[ty+i][tx] = in[bo + (long long)(r0+ty+i)*cols + (c0+tx)];
    __syncthreads();
    #pragma unroll
    for (int i = 0; i < 32; i += 8) {
        float v = t[tx][ty+i];
        bf16 h, l; split2(v, h, l);
        long long o = bo + (long long)(c0+ty+i)*rows + (r0+tx);
        oh[o] = h; ol[o] = l;
    }
}

// ---------------- elementwise split ----------------
__global__ void split_kernel(const float* __restrict__ x,
                             bf16* __restrict__ oh, bf16* __restrict__ ol)
{
    long long i = ((long long)blockIdx.x * 256 + threadIdx.x) * 4;
    float4 v = *(const float4*)(x + i);
    bf16 h, l;
    split2(v.x, h, l); oh[i+0] = h; ol[i+0] = l;
    split2(v.y, h, l); oh[i+1] = h; ol[i+1] = l;
    split2(v.z, h, l); oh[i+2] = h; ol[i+2] = l;
    split2(v.w, h, l); oh[i+3] = h; ol[i+3] = l;
}

// ---------------- FFT (radix-2 DIT, n=4096, 512 threads) ----------------
__device__ __forceinline__ int rev12(int i) { return __brev(i) >> 20; }

__device__ __forceinline__ void tw_init(float2* tw, int tid) {
    for (int m = tid; m < 1024; m += 512) {
        float sv, cv;
        sincosf(-6.283185307179586f * (float)m / 4096.0f, &sv, &cv);
        tw[m] = make_float2(cv, sv);
    }
}

__device__ void do_fft(float2* s, const float2* tw, int tid) {
    #pragma unroll 1
    for (int lh = 0; lh < 12; lh++) {
        int half = 1 << lh;
        #pragma unroll 1
        for (int idx = tid; idx < NF4096/2; idx += 512) {
            int j   = idx & (half - 1);
            int pos = 2*idx - j;
            int m   = j << (11 - lh);
            float2 w;
            if (m & 1024) { float2 t = tw[m & 1023]; w = make_float2(t.y, -t.x); }
            else          { w = tw[m]; }
            float2 u = s[pos];
            float2 q = s[pos + half];
            float2 v = make_float2(w.x*q.x - w.y*q.y, w.x*q.y + w.y*q.x);
            s[pos]        = make_float2(u.x + v.x, u.y + v.y);
            s[pos + half] = make_float2(u.x - v.x, u.y - v.y);
        }
        __syncthreads();
    }
}

__global__ void __launch_bounds__(512) filters_kernel(
    const float* __restrict__ eig_vals, const float* __restrict__ eig_vecs,
    const float* __restrict__ w_filters, float2* __restrict__ Ffilt)
{
    __shared__ float2 s[NF4096];
    __shared__ float2 tw[1024];
    __shared__ float  wk[KK];
    int d = blockIdx.x, tid = threadIdx.x;
    if (tid < KK) wk[tid] = powf(eig_vals[tid], 0.25f) * w_filters[tid*DD + d];
    tw_init(tw, tid);
    for (int i = tid; i < NF4096; i += 512) s[i] = make_float2(0.f, 0.f);
    __syncthreads();
    for (int t = tid; t < LL; t += 512) {
        float f = 0.f;
        #pragma unroll
        for (int k = 0; k < KK; k++) f += eig_vecs[t*KK + k] * wk[k];
        s[rev12(t)] = make_float2(f, 0.f);
    }
    __syncthreads();
    do_fft(s, tw, tid);
    for (int i = tid; i < NF4096; i += 512)
        Ffilt[(long long)d*NF4096 + i] = s[i];
}

// 2-for-1 packed conv
__global__ void __launch_bounds__(512) conv2_kernel(
    const float* __restrict__ xt, const float2* __restrict__ Ffilt,
    float* __restrict__ projt)
{
    __shared__ float2 s[NF4096];
    __shared__ float2 tw[1024];
    int z = blockIdx.x, tid = threadIdx.x;
    int b = z >> 9, dp = z & 511;
    int d0 = 2*dp;
    long long base0 = ((long long)b*DD + d0) * LL;
    long long base1 = base0 + LL;
    tw_init(tw, tid);
    for (int i = tid; i < NF4096; i += 512) s[i] = make_float2(0.f, 0.f);
    __syncthreads();
    for (int t = tid; t < LL; t += 512)
        s[rev12(t)] = make_float2(xt[base0 + t], xt[base1 + t]);
    __syncthreads();
    do_fft(s, tw, tid);

    const float2* F0 = Ffilt + (long long)d0 * NF4096;
    const float2* F1 = F0 + NF4096;
    for (int i = tid; i < 2048; i += 512) {
        if (i == 0) {
            #pragma unroll
            for (int q = 0; q < 2; q++) {
                int idx = q * 2048;
                float2 Z = s[idx];
                float X1 = Z.x, X2 = Z.y;
                float2 f0 = F0[idx], f1 = F1[idx];
                float2 Y1 = make_float2(X1*f0.x, X1*f0.y);
                float2 Y2 = make_float2(X2*f1.x, X2*f1.y);
                s[idx] = make_float2(Y1.x - Y2.y, -(Y1.y + Y2.x));
            }
        } else {
            float2 Za = s[i], Zb = s[NF4096 - i];
            float2 X1 = make_float2(0.5f*(Za.x + Zb.x), 0.5f*(Za.y - Zb.y));
            float2 Dd = make_float2(Za.x - Zb.x, Za.y + Zb.y);
            float2 X2 = make_float2(0.5f*Dd.y, -0.5f*Dd.x);
            float2 f0 = F0[i], f1 = F1[i];
            float2 Y1 = make_float2(X1.x*f0.x - X1.y*f0.y, X1.x*f0.y + X1.y*f0.x);
            float2 Y2 = make_float2(X2.x*f1.x - X2.y*f1.y, X2.x*f1.y + X2.y*f1.x);
            s[i]          = make_float2(Y1.x - Y2.y, -(Y1.y + Y2.x));
            s[NF4096 - i] = make_float2(Y1.x + Y2.y, Y1.y - Y2.x);
        }
    }
    __syncthreads();
    float2 r[8];
    #pragma unroll
    for (int k = 0; k < 8; k++) r[k] = s[rev12(tid + k*512)];
    __syncthreads();
    #pragma unroll
    for (int k = 0; k < 8; k++) s[tid + k*512] = r[k];
    __syncthreads();
    do_fft(s, tw, tid);
    const float inv = 1.0f / 4096.0f;
    for (int l = tid; l < LL; l += 512) {
        projt[base0 + l] =  s[l].x * inv;
        projt[base1 + l] = -s[l].y * inv;
    }
}

// ---------------- LayerNorm with split-bf16 output ----------------
__global__ void __launch_bounds__(256) ln_split_kernel(
    const float* __restrict__ x, bf16* __restrict__ yh, bf16* __restrict__ yl,
    const float* __restrict__ sc, const float* __restrict__ bi)
{
    long long base = (long long)blockIdx.x * DD;
    int tid = threadIdx.x;
    float4 v = *(const float4*)(x + base + tid*4);
    float mean = block_sum256(v.x + v.y + v.z + v.w) * (1.0f/DD);
    float dx = v.x - mean, dy = v.y - mean, dz = v.z - mean, dw = v.w - mean;
    float var = block_sum256(dx*dx + dy*dy + dz*dz + dw*dw) * (1.0f/DD);
    float rstd = rsqrtf(var + 1e-6f);
    float4 s4 = *(const float4*)(sc + tid*4);
    float4 b4 = *(const float4*)(bi + tid*4);
    float o0 = dx*rstd*s4.x + b4.x;
    float o1 = dy*rstd*s4.y + b4.y;
    float o2 = dz*rstd*s4.z + b4.z;
    float o3 = dw*rstd*s4.w + b4.w;
    long long i = base + tid*4;
    bf16 h, l;
    split2(o0, h, l); yh[i+0] = h; yl[i+0] = l;
    split2(o1, h, l); yh[i+1] = h; yl[i+1] = l;
    split2(o2, h, l); yh[i+2] = h; yl[i+2] = l;
    split2(o3, h, l); yh[i+3] = h; yl[i+3] = l;
}

// ---------------- launch ----------------
static void* symv(const void* s) { void* p = nullptr; cudaGetSymbolAddress(&p, s); return p; }

extern "C" void kernel_launch(void* const* d_in, const int* in_sizes, int n_in,
                              void* d_out, int out_size)
{
    const float* inputs    = (const float*)d_in[0];
    const float* eig_vals  = (const float*)d_in[1];
    const float* eig_vecs  = (const float*)d_in[2];
    const float* w_filters = (const float*)d_in[3];
    const float* w_inputs  = (const float*)d_in[4];
    const float* ln1_s     = (const float*)d_in[5];
    const float* ln1_b     = (const float*)d_in[6];
    const float* wq        = (const float*)d_in[7];
    const float* wk        = (const float*)d_in[8];
    const float* wv        = (const float*)d_in[9];
    const float* wo        = (const float*)d_in[10];
    const float* ln2_s     = (const float*)d_in[11];
    const float* ln2_b     = (const float*)d_in[12];
    const float* mlp_w1    = (const float*)d_in[13];
    const float* mlp_b1    = (const float*)d_in[14];
    const float* mlp_w2    = (const float*)d_in[15];
    const float* mlp_b2    = (const float*)d_in[16];
    float* out = (float*)d_out;

    float*  xi    = (float*)symv(g_xi);
    float*  xt    = (float*)symv(g_xt);
    float2* Ffilt = (float2*)symv(g_Ffilt);
    float*  projt = (float*)symv(g_projt);
    float*  stu   = (float*)symv(g_stu);
    float*  vbuf  = (float*)symv(g_v);
    float*  xres  = (float*)symv(g_xres);

    bf16 *inh=(bf16*)symv(g_inh),  *inl=(bf16*)symv(g_inl);
    bf16 *x1h=(bf16*)symv(g_x1h),  *x1l=(bf16*)symv(g_x1l);
    bf16 *qh =(bf16*)symv(g_qh),   *ql =(bf16*)symv(g_ql);
    bf16 *kh =(bf16*)symv(g_kh),   *kl =(bf16*)symv(g_kl);
    bf16 *vTh=(bf16*)symv(g_vTh),  *vTl=(bf16*)symv(g_vTl);
    bf16 *ath=(bf16*)symv(g_ath),  *atl=(bf16*)symv(g_atl);
    bf16 *y1h=(bf16*)symv(g_y1h),  *y1l=(bf16*)symv(g_y1l);
    bf16 *hh =(bf16*)symv(g_hh),   *hl =(bf16*)symv(g_hl);
    bf16 *wiTh=(bf16*)symv(g_wiTh),*wiTl=(bf16*)symv(g_wiTl);
    bf16 *wqTh=(bf16*)symv(g_wqTh),*wqTl=(bf16*)symv(g_wqTl);
    bf16 *wkTh=(bf16*)symv(g_wkTh),*wkTl=(bf16*)symv(g_wkTl);
    bf16 *wvTh=(bf16*)symv(g_wvTh),*wvTl=(bf16*)symv(g_wvTl);
    bf16 *woTh=(bf16*)symv(g_woTh),*woTl=(bf16*)symv(g_woTl);
    bf16 *w1Th=(bf16*)symv(g_w1Th),*w1Tl=(bf16*)symv(g_w1Tl);
    bf16 *w2Th=(bf16*)symv(g_w2Th),*w2Tl=(bf16*)symv(g_w2Tl);

    const int SMGE = 81920;
    const int SMFL = 143360;
    cudaFuncSetAttribute(gemm_bf16,    cudaFuncAttributeMaxDynamicSharedMemorySize, SMGE);
    cudaFuncSetAttribute(flash_kernel, cudaFuncAttributeMaxDynamicSharedMemorySize, SMFL);

    dim3 t328(32, 8);

    // 1. filter spectrum per channel d
    filters_kernel<<<DD, 512>>>(eig_vals, eig_vecs, w_filters, Ffilt);

    // 2. split inputs; transpose-split all weights to [N][K]
    split_kernel<<<(BL*DD)/1024, 256>>>(inputs, inh, inl);
    transpose_split_kernel<<<dim3(32, 32, 1), t328>>>(w_inputs, wiTh, wiTl, DD, DD);
    transpose_split_kernel<<<dim3(32, 32, 1), t328>>>(wq, wqTh, wqTl, DD, DD);
    transpose_split_kernel<<<dim3(32, 32, 1), t328>>>(wk, wkTh, wkTl, DD, DD);
    transpose_split_kernel<<<dim3(32, 32, 1), t328>>>(wv, wvTh, wvTl, DD, DD);
    transpose_split_kernel<<<dim3(32, 32, 1), t328>>>(wo, woTh, woTl, DD, DD);
    transpose_split_kernel<<<dim3(MLPD/32, DD/32, 1), t328>>>(mlp_w1, w1Th, w1Tl, DD, MLPD);
    transpose_split_kernel<<<dim3(DD/32, MLPD/32, 1), t328>>>(mlp_w2, w2Th, w2Tl, MLPD, DD);

    // 3. xi = inputs @ w_inputs (f32 out for FFT)
    gemm_bf16<<<dim3(8, 64, 1), 256, SMGE>>>(
        inh, inl, wiTh, wiTl, xi, nullptr, nullptr,
        BL, DD, DD, DD, DD, DD, 1.0f, nullptr, nullptr, 0);

    // 4. spectral causal conv (packed FFT)
    transpose_kernel<<<dim3(DD/32, LL/32, BB), t328>>>(xi, xt, LL, DD);
    conv2_kernel<<<BB*DD/2, 512>>>(xt, Ffilt, projt);
    transpose_kernel<<<dim3(LL/32, DD/32, BB), t328>>>(projt, stu, DD, LL);

    // 5. LN1 -> split x1
    ln_split_kernel<<<BL, 256>>>(stu, x1h, x1l, ln1_s, ln1_b);

    // 6. Q (scaled, split), K (split), V (f32 then transpose-split)
    gemm_bf16<<<dim3(8, 64, 1), 256, SMGE>>>(
        x1h, x1l, wqTh, wqTl, nullptr, qh, ql,
        BL, DD, DD, DD, DD, DD, 0.125f, nullptr, nullptr, 8);
    gemm_bf16<<<dim3(8, 64, 1), 256, SMGE>>>(
        x1h, x1l, wkTh, wkTl, nullptr, kh, kl,
        BL, DD, DD, DD, DD, DD, 1.0f, nullptr, nullptr, 8);
    gemm_bf16<<<dim3(8, 64, 1), 256, SMGE>>>(
        x1h, x1l, wvTh, wvTl, vbuf, nullptr, nullptr,
        BL, DD, DD, DD, DD, DD, 1.0f, nullptr, nullptr, 0);
    transpose_split_kernel<<<dim3(DD/32, LL/32, BB), t328>>>(vbuf, vTh, vTl, LL, DD);

    // 7. fused flash attention -> split att
    flash_kernel<<<dim3(LL/128, BB*HH), 256, SMFL>>>(
        qh, ql, kh, kl, vTh, vTl, ath, atl);

    // 8. x = att @ wo + stu (f32)
    gemm_bf16<<<dim3(8, 64, 1), 256, SMGE>>>(
        ath, atl, woTh, woTl, xres, nullptr, nullptr,
        BL, DD, DD, DD, DD, DD, 1.0f, nullptr, stu, 4);

    // 9. LN2 -> split y1
    ln_split_kernel<<<BL, 256>>>(xres, y1h, y1l, ln2_s, ln2_b);

    // 10. h = gelu(y1 @ w1 + b1), split out
    gemm_bf16<<<dim3(MLPD/128, 64, 1), 256, SMGE>>>(
        y1h, y1l, w1Th, w1Tl, nullptr, hh, hl,
        BL, MLPD, DD, DD, DD, MLPD, 1.0f, mlp_b1, nullptr, 11);

    // 11. out = h @ w2 + b2 + x (f32)
    gemm_bf16<<<dim3(8, 64, 1), 256, SMGE>>>(
        hh, hl, w2Th, w2Tl, out, nullptr, nullptr,
        BL, DD, MLPD, MLPD, MLPD, DD, 1.0f, mlp_b2, xres, 5);
}

// round 10
// speedup vs baseline: 3.4767x; 1.0544x over previous
#include <cuda_runtime.h>
#include <cuda_bf16.h>
#include <math.h>
#include <stdint.h>

#define BB 4
#define LL 2048
#define DD 1024
#define HH 16
#define HDIM 64
#define KK 24
#define MLPD 4096
#define BL (BB*LL)
#define NF4096 4096

typedef __nv_bfloat16 bf16;

// ---------------- scratch (device globals; allocation-free) ----------------
__device__ float  g_xi[BL*DD];
__device__ float2 g_Ffilt[(size_t)DD*NF4096];
__device__ float  g_stu[BL*DD];
__device__ float  g_v[BL*DD];
__device__ float  g_xres[BL*DD];

__device__ bf16 g_inh[BL*DD],  g_inl[BL*DD];
__device__ bf16 g_x1h[BL*DD],  g_x1l[BL*DD];
__device__ bf16 g_qh [BL*DD],  g_ql [BL*DD];
__device__ bf16 g_kh [BL*DD],  g_kl [BL*DD];
__device__ bf16 g_vTh[BL*DD],  g_vTl[BL*DD];       // [B,H*HD,L]
__device__ bf16 g_ath[BL*DD],  g_atl[BL*DD];
__device__ bf16 g_y1h[BL*DD],  g_y1l[BL*DD];
__device__ bf16 g_hh[(size_t)BL*MLPD], g_hl[(size_t)BL*MLPD];
// transposed-split weights [N][K]
__device__ bf16 g_wiTh[DD*DD],  g_wiTl[DD*DD];
__device__ bf16 g_wqTh[DD*DD],  g_wqTl[DD*DD];
__device__ bf16 g_wkTh[DD*DD],  g_wkTl[DD*DD];
__device__ bf16 g_wvTh[DD*DD],  g_wvTl[DD*DD];
__device__ bf16 g_woTh[DD*DD],  g_woTl[DD*DD];
__device__ bf16 g_w1Th[(size_t)DD*MLPD], g_w1Tl[(size_t)DD*MLPD];
__device__ bf16 g_w2Th[(size_t)DD*MLPD], g_w2Tl[(size_t)DD*MLPD];

// ---------------- helpers ----------------
__device__ __forceinline__ float gelu_f(float x) {
    float x3 = x*x*x;
    return 0.5f*x*(1.0f + tanhf(0.7978845608028654f*(x + 0.044715f*x3)));
}
__device__ __forceinline__ void split2(float v, bf16 &h, bf16 &l) {
    h = __float2bfloat16_rn(v);
    l = __float2bfloat16_rn(v - __bfloat162float(h));
}
__device__ __forceinline__ uint32_t pack2(bf16 a, bf16 b) {
    return (uint32_t)__bfloat16_as_ushort(a) | ((uint32_t)__bfloat16_as_ushort(b) << 16);
}
__device__ __forceinline__ void cpa16(uint32_t s, const void* g) {
    asm volatile("cp.async.cg.shared.global [%0], [%1], 16;" :: "r"(s), "l"(g));
}
__device__ __forceinline__ void mma16816(float* c, const uint32_t* a, const uint32_t* b) {
    asm volatile("mma.sync.aligned.m16n8k16.row.col.f32.bf16.bf16.f32 "
                 "{%0,%1,%2,%3},{%4,%5,%6,%7},{%8,%9},{%0,%1,%2,%3};"
                 : "+f"(c[0]), "+f"(c[1]), "+f"(c[2]), "+f"(c[3])
                 : "r"(a[0]), "r"(a[1]), "r"(a[2]), "r"(a[3]),
                   "r"(b[0]), "r"(b[1]));
}
__device__ __forceinline__ float block_sum256(float v) {
    __shared__ float red[8];
    int lane = threadIdx.x & 31, w = threadIdx.x >> 5;
    #pragma unroll
    for (int o = 16; o; o >>= 1) v += __shfl_xor_sync(0xffffffffu, v, o);
    __syncthreads();
    if (lane == 0) red[w] = v;
    __syncthreads();
    if (threadIdx.x == 0) {
        float s = 0.f;
        #pragma unroll
        for (int i = 0; i < 8; i++) s += red[i];
        red[0] = s;
    }
    __syncthreads();
    return red[0];
}

// ---------------- split-bf16 tensor-core GEMM (dense layers) ----------------
// C[M,N] = alpha*(A@B^T) (+bias/gelu/resid/split). A split [M,K] row-major,
// B split [N,K] row-major. Tile 128x128, 2 CTAs/SM (128-reg cap), 2-stage.
// mode: 1=bias, 2=gelu, 4=resid, 8=split-out
__global__ void __launch_bounds__(256, 2) gemm_bf16(
    const bf16* __restrict__ Ahi, const bf16* __restrict__ Alo,
    const bf16* __restrict__ Bhi, const bf16* __restrict__ Blo,
    float* __restrict__ C, bf16* __restrict__ Chi, bf16* __restrict__ Clo,
    int M, int N, int Kd, int lda, int ldb, int ldc,
    float alpha, const float* __restrict__ bias,
    const float* __restrict__ resid, int mode)
{
    constexpr int SP    = 40;
    constexpr int AH    = 128 * SP;
    constexpr int BHalf = 128 * SP;
    constexpr int STAGE = 2*AH + 2*BHalf;   // 20480 halves = 40960 B

    extern __shared__ __align__(16) char dsm[];
    uint32_t smem0 = (uint32_t)__cvta_generic_to_shared(dsm);

    int tid   = threadIdx.x;
    int mBase = blockIdx.y * 128, nBase = blockIdx.x * 128;

    const bf16* pAh = Ahi + (long long)mBase * lda;
    const bf16* pAl = Alo + (long long)mBase * lda;
    const bf16* pBh = Bhi + (long long)nBase * ldb;
    const bf16* pBl = Blo + (long long)nBase * ldb;

    int warp = tid >> 5, lane = tid & 31;
    int wm = warp & 3, wn = warp >> 2;
    int g  = lane >> 2, tig = lane & 3;

    float acc[2][8][4];
    #pragma unroll
    for (int i = 0; i < 2; i++)
        #pragma unroll
        for (int j = 0; j < 8; j++)
            #pragma unroll
            for (int c = 0; c < 4; c++) acc[i][j][c] = 0.f;

    auto load_stage = [&](int buf, int k0) {
        int so = buf * STAGE;
        #pragma unroll
        for (int i = 0; i < 2; i++) {
            int ci = tid + i*256;
            int row = ci >> 2, seg = ci & 3;
            long long go = (long long)row*lda + k0 + seg*8;
            uint32_t sa = smem0 + 2*(so + row*SP + seg*8);
            cpa16(sa,          pAh + go);
            cpa16(sa + 2*AH,   pAl + go);
        }
        #pragma unroll
        for (int i = 0; i < 2; i++) {
            int ci = tid + i*256;
            int row = ci >> 2, seg = ci & 3;
            long long go = (long long)row*ldb + k0 + seg*8;
            uint32_t sa = smem0 + 2*(so + 2*AH + row*SP + seg*8);
            cpa16(sa,              pBh + go);
            cpa16(sa + 2*BHalf,    pBl + go);
        }
        asm volatile("cp.async.commit_group;");
    };

    int nk = Kd >> 5;
    load_stage(0, 0);

    for (int ks = 0; ks < nk; ks++) {
        if (ks + 1 < nk) {
            load_stage((ks+1)&1, (ks+1) << 5);
            asm volatile("cp.async.wait_group 1;");
        } else {
            asm volatile("cp.async.wait_group 0;");
        }
        __syncthreads();
        int so = (ks & 1) * STAGE;

        #pragma unroll
        for (int kh = 0; kh < 2; kh++) {
            int ko = kh*16 + 2*tig;
            uint32_t ah[2][4], al[2][4];
            #pragma unroll
            for (int mi = 0; mi < 2; mi++) {
                int r = so + (wm*32 + mi*16 + g)*SP + ko;
                ah[mi][0] = *(const uint32_t*)(dsm + 2*(r));
                ah[mi][1] = *(const uint32_t*)(dsm + 2*(r + 8*SP));
                ah[mi][2] = *(const uint32_t*)(dsm + 2*(r + 8));
                ah[mi][3] = *(const uint32_t*)(dsm + 2*(r + 8*SP + 8));
                al[mi][0] = *(const uint32_t*)(dsm + 2*(r + AH));
                al[mi][1] = *(const uint32_t*)(dsm + 2*(r + AH + 8*SP));
                al[mi][2] = *(const uint32_t*)(dsm + 2*(r + AH + 8));
                al[mi][3] = *(const uint32_t*)(dsm + 2*(r + AH + 8*SP + 8));
            }
            #pragma unroll
            for (int ni = 0; ni < 8; ni++) {
                int r = so + 2*AH + (wn*64 + ni*8 + g)*SP + ko;
                uint32_t bhf[2], blf[2];
                bhf[0] = *(const uint32_t*)(dsm + 2*(r));
                bhf[1] = *(const uint32_t*)(dsm + 2*(r + 8));
                blf[0] = *(const uint32_t*)(dsm + 2*(r + BHalf));
                blf[1] = *(const uint32_t*)(dsm + 2*(r + BHalf + 8));
                #pragma unroll
                for (int mi = 0; mi < 2; mi++) {
                    mma16816(acc[mi][ni], ah[mi], bhf);
                    mma16816(acc[mi][ni], al[mi], bhf);
                    mma16816(acc[mi][ni], ah[mi], blf);
                }
            }
        }
        __syncthreads();
    }

    bool hb = mode & 1, hg = mode & 2, hr = mode & 4, hs = mode & 8;
    #pragma unroll
    for (int mi = 0; mi < 2; mi++) {
        int m0 = mBase + wm*32 + mi*16 + g;
        #pragma unroll
        for (int ni = 0; ni < 8; ni++) {
            int n = nBase + wn*64 + ni*8 + 2*tig;
            #pragma unroll
            for (int hrow = 0; hrow < 2; hrow++) {
                int m = m0 + hrow*8;
                float v0 = acc[mi][ni][hrow*2+0] * alpha;
                float v1 = acc[mi][ni][hrow*2+1] * alpha;
                if (hb) { v0 += bias[n]; v1 += bias[n+1]; }
                if (hg) { v0 = gelu_f(v0); v1 = gelu_f(v1); }
                long long o = (long long)m*ldc + n;
                if (hr) { v0 += resid[o]; v1 += resid[o+1]; }
                if (hs) {
                    bf16 h0, l0, h1, l1;
                    split2(v0, h0, l0); split2(v1, h1, l1);
                    *(uint32_t*)(Chi + o) = pack2(h0, h1);
                    *(uint32_t*)(Clo + o) = pack2(l0, l1);
                } else {
                    C[o] = v0; C[o+1] = v1;
                }
            }
        }
    }
}

// ---------------- flash attention (fused QK^T / softmax / PV, mma.sync) ----------------
__global__ void __launch_bounds__(256) flash_kernel(
    const bf16* __restrict__ Qh, const bf16* __restrict__ Ql,
    const bf16* __restrict__ Kh, const bf16* __restrict__ Kl,
    const bf16* __restrict__ Vth, const bf16* __restrict__ Vtl,
    bf16* __restrict__ Oh, bf16* __restrict__ Ol)
{
    constexpr int KSP = 72, VSP = 136;
    constexpr int KTH = 128*KSP;
    constexpr int VTH = 64*VSP;
    constexpr int STG = 2*KTH + 2*VTH;

    extern __shared__ __align__(16) bf16 sm[];
    uint32_t smem0 = (uint32_t)__cvta_generic_to_shared(sm);

    int tid = threadIdx.x, warp = tid >> 5, lane = tid & 31;
    int g = lane >> 2, tig = lane & 3;
    int qt = blockIdx.x, bh = blockIdx.y;
    int b = bh >> 4, h = bh & 15;
    const long long LLD = (long long)LL * DD;
    long long baseQ = (long long)b*LLD + (long long)(qt*128)*DD + h*64;
    long long baseK = (long long)b*LLD + h*64;
    long long baseV = (long long)b*LLD + (long long)(h*64)*LL;

    uint32_t qa_h[4][4], qa_l[4][4];
    {
        long long r0 = baseQ + (long long)(warp*16 + g)*DD;
        long long r8 = r0 + 8*DD;
        #pragma unroll
        for (int kf = 0; kf < 4; kf++) {
            int c = kf*16 + 2*tig;
            qa_h[kf][0] = *(const uint32_t*)(Qh + r0 + c);
            qa_h[kf][1] = *(const uint32_t*)(Qh + r8 + c);
            qa_h[kf][2] = *(const uint32_t*)(Qh + r0 + c + 8);
            qa_h[kf][3] = *(const uint32_t*)(Qh + r8 + c + 8);
            qa_l[kf][0] = *(const uint32_t*)(Ql + r0 + c);
            qa_l[kf][1] = *(const uint32_t*)(Ql + r8 + c);
            qa_l[kf][2] = *(const uint32_t*)(Ql + r0 + c + 8);
            qa_l[kf][3] = *(const uint32_t*)(Ql + r8 + c + 8);
        }
    }

    auto load_tiles = [&](int buf, int kt) {
        int so = buf * STG;
        #pragma unroll
        for (int i = 0; i < 4; i++) {
            int ci = tid + i*256;
            int row = ci >> 3, ch = ci & 7;
            long long go = baseK + (long long)(kt*128 + row)*DD + ch*8;
            uint32_t sa = smem0 + 2*(so + row*KSP + ch*8);
            cpa16(sa,           Kh + go);
            cpa16(sa + 2*KTH,   Kl + go);
        }
        #pragma unroll
        for (int i = 0; i < 4; i++) {
            int ci = tid + i*256;
            int row = ci >> 4, ch = ci & 15;
            long long go = baseV + (long long)row*LL + kt*128 + ch*8;
            uint32_t sa = smem0 + 2*(so + 2*KTH + row*VSP + ch*8);
            cpa16(sa,           Vth + go);
            cpa16(sa + 2*VTH,   Vtl + go);
        }
        asm volatile("cp.async.commit_group;");
    };

    float m_r[2] = {-1e30f, -1e30f};
    float l_r[2] = {0.f, 0.f};
    float o[8][4];
    #pragma unroll
    for (int n = 0; n < 8; n++)
        #pragma unroll
        for (int c = 0; c < 4; c++) o[n][c] = 0.f;

    load_tiles(0, 0);

    for (int kt = 0; kt < 16; kt++) {
        if (kt + 1 < 16) {
            load_tiles((kt+1)&1, kt+1);
            asm volatile("cp.async.wait_group 1;");
        } else {
            asm volatile("cp.async.wait_group 0;");
        }
        __syncthreads();
        int so = (kt & 1) * STG;

        float s[16][4];
        #pragma unroll
        for (int n = 0; n < 16; n++)
            #pragma unroll
            for (int c = 0; c < 4; c++) s[n][c] = 0.f;

        #pragma unroll
        for (int kf = 0; kf < 4; kf++) {
            #pragma unroll
            for (int n = 0; n < 16; n++) {
                int r = so + (n*8 + g)*KSP + kf*16 + 2*tig;
                uint32_t bhf[2], blf[2];
                bhf[0] = *(const uint32_t*)(sm + r);
                bhf[1] = *(const uint32_t*)(sm + r + 8);
                blf[0] = *(const uint32_t*)(sm + r + KTH);
                blf[1] = *(const uint32_t*)(sm + r + KTH + 8);
                mma16816(s[n], qa_h[kf], bhf);
                mma16816(s[n], qa_l[kf], bhf);
                mma16816(s[n], qa_h[kf], blf);
            }
        }

        float mx0 = -1e30f, mx1 = -1e30f;
        #pragma unroll
        for (int n = 0; n < 16; n++) {
            mx0 = fmaxf(mx0, fmaxf(s[n][0], s[n][1]));
            mx1 = fmaxf(mx1, fmaxf(s[n][2], s[n][3]));
        }
        #pragma unroll
        for (int off = 1; off < 4; off <<= 1) {
            mx0 = fmaxf(mx0, __shfl_xor_sync(0xffffffffu, mx0, off));
            mx1 = fmaxf(mx1, __shfl_xor_sync(0xffffffffu, mx1, off));
        }
        float mn0 = fmaxf(m_r[0], mx0), mn1 = fmaxf(m_r[1], mx1);
        float sf0 = __expf(m_r[0] - mn0), sf1 = __expf(m_r[1] - mn1);
        m_r[0] = mn0; m_r[1] = mn1;
        float sum0 = 0.f, sum1 = 0.f;
        #pragma unroll
        for (int n = 0; n < 16; n++) {
            s[n][0] = __expf(s[n][0] - mn0); sum0 += s[n][0];
            s[n][1] = __expf(s[n][1] - mn0); sum0 += s[n][1];
            s[n][2] = __expf(s[n][2] - mn1); sum1 += s[n][2];
            s[n][3] = __expf(s[n][3] - mn1); sum1 += s[n][3];
        }
        #pragma unroll
        for (int off = 1; off < 4; off <<= 1) {
            sum0 += __shfl_xor_sync(0xffffffffu, sum0, off);
            sum1 += __shfl_xor_sync(0xffffffffu, sum1, off);
        }
        l_r[0] = l_r[0]*sf0 + sum0;
        l_r[1] = l_r[1]*sf1 + sum1;
        #pragma unroll
        for (int n = 0; n < 8; n++) {
            o[n][0] *= sf0; o[n][1] *= sf0;
            o[n][2] *= sf1; o[n][3] *= sf1;
        }

        #pragma unroll
        for (int kf2 = 0; kf2 < 8; kf2++) {
            uint32_t pa_h[4], pa_l[4];
            #pragma unroll
            for (int q4 = 0; q4 < 2; q4++) {
                int t = 2*kf2 + q4;
                #pragma unroll
                for (int rr = 0; rr < 2; rr++) {
                    float p0 = s[t][rr*2+0], p1 = s[t][rr*2+1];
                    bf16 h0, l0, h1, l1;
                    split2(p0, h0, l0); split2(p1, h1, l1);
                    pa_h[q4*2+rr] = pack2(h0, h1);
                    pa_l[q4*2+rr] = pack2(l0, l1);
                }
            }
            #pragma unroll
            for (int n = 0; n < 8; n++) {
                int r = so + 2*KTH + (n*8 + g)*VSP + kf2*16 + 2*tig;
                uint32_t bhf[2], blf[2];
                bhf[0] = *(const uint32_t*)(sm + r);
                bhf[1] = *(const uint32_t*)(sm + r + 8);
                blf[0] = *(const uint32_t*)(sm + r + VTH);
                blf[1] = *(const uint32_t*)(sm + r + VTH + 8);
                mma16816(o[n], pa_h, bhf);
                mma16816(o[n], pa_l, bhf);
                mma16816(o[n], pa_h, blf);
            }
        }
        __syncthreads();
    }

    float il0 = 1.f / l_r[0], il1 = 1.f / l_r[1];
    long long r0 = baseQ + (long long)(warp*16 + g)*DD;
    long long r8 = r0 + 8*DD;
    #pragma unroll
    for (int n = 0; n < 8; n++) {
        int c = n*8 + 2*tig;
        float v0 = o[n][0]*il0, v1 = o[n][1]*il0;
        float v2 = o[n][2]*il1, v3 = o[n][3]*il1;
        bf16 h0,l0,h1,l1;
        split2(v0,h0,l0); split2(v1,h1,l1);
        *(uint32_t*)(Oh + r0 + c) = pack2(h0,h1);
        *(uint32_t*)(Ol + r0 + c) = pack2(l0,l1);
        split2(v2,h0,l0); split2(v3,h1,l1);
        *(uint32_t*)(Oh + r8 + c) = pack2(h0,h1);
        *(uint32_t*)(Ol + r8 + c) = pack2(l0,l1);
    }
}

// ---------------- transpose + split: f32 [rows,cols] -> bf16 hi/lo [cols,rows] ----------------
__global__ void transpose_split_kernel(const float* __restrict__ in,
                                       bf16* __restrict__ oh, bf16* __restrict__ ol,
                                       int rows, int cols)
{
    __shared__ float t[32][33];
    long long bo = (long long)blockIdx.z * rows * cols;
    int c0 = blockIdx.x * 32, r0 = blockIdx.y * 32;
    int tx = threadIdx.x, ty = threadIdx.y;
    #pragma unroll
    for (int i = 0; i < 32; i += 8)
        t[ty+i][tx] = in[bo + (long long)(r0+ty+i)*cols + (c0+tx)];
    __syncthreads();
    #pragma unroll
    for (int i = 0; i < 32; i += 8) {
        float v = t[tx][ty+i];
        bf16 h, l; split2(v, h, l);
        long long o = bo + (long long)(c0+ty+i)*rows + (r0+tx);
        oh[o] = h; ol[o] = l;
    }
}

// ---------------- elementwise split ----------------
__global__ void split_kernel(const float* __restrict__ x,
                             bf16* __restrict__ oh, bf16* __restrict__ ol)
{
    long long i = ((long long)blockIdx.x * 256 + threadIdx.x) * 4;
    float4 v = *(const float4*)(x + i);
    bf16 h, l;
    split2(v.x, h, l); oh[i+0] = h; ol[i+0] = l;
    split2(v.y, h, l); oh[i+1] = h; ol[i+1] = l;
    split2(v.z, h, l); oh[i+2] = h; ol[i+2] = l;
    split2(v.w, h, l); oh[i+3] = h; ol[i+3] = l;
}

// ---------------- FFT (radix-4 DIT, n=4096, 512 threads) ----------------
// base-4 digit reversal of 12-bit index = bit-reverse then swap adjacent bits
__device__ __forceinline__ int rev4(int i) {
    int r = __brev(i) >> 20;
    return ((r & 0x555) << 1) | ((r >> 1) & 0x555);
}
__device__ __forceinline__ float2 cmulf(float2 a, float2 b) {
    return make_float2(a.x*b.x - a.y*b.y, a.x*b.y + a.y*b.x);
}
__device__ __forceinline__ void tw_init(float2* tw, int tid) {
    for (int m = tid; m < 1024; m += 512) {
        float sv, cv;
        sincosf(-6.283185307179586f * (float)m / 4096.0f, &sv, &cv);
        tw[m] = make_float2(cv, sv);
    }
}

// in-place radix-4 DIT; input digit-reversed (rev4), output natural order
__device__ void do_fft4(float2* s, const float2* tw, int tid) {
    #pragma unroll 1
    for (int st = 0; st < 6; st++) {
        int Q  = 1 << (2*st);
        int sh = 10 - 2*st;
        #pragma unroll 1
        for (int idx = tid; idx < 1024; idx += 512) {
            int j    = idx & (Q - 1);
            int blk  = idx >> (2*st);
            int base = blk*(Q << 2) + j;
            float2 x0 = s[base];
            float2 x1 = s[base + Q];
            float2 x2 = s[base + 2*Q];
            float2 x3 = s[base + 3*Q];
            float2 w1 = tw[j << sh];
            float2 w2 = cmulf(w1, w1);
            float2 w3 = cmulf(w2, w1);
            float2 y1 = cmulf(w1, x1);
            float2 y2 = cmulf(w2, x2);
            float2 y3 = cmulf(w3, x3);
            float2 u0 = make_float2(x0.x + y2.x, x0.y + y2.y);
            float2 u1 = make_float2(x0.x - y2.x, x0.y - y2.y);
            float2 u2 = make_float2(y1.x + y3.x, y1.y + y3.y);
            float2 u3 = make_float2(y1.x - y3.x, y1.y - y3.y);
            s[base]       = make_float2(u0.x + u2.x, u0.y + u2.y);
            s[base + Q]   = make_float2(u1.x + u3.y, u1.y - u3.x);   // u1 - i*u3
            s[base + 2*Q] = make_float2(u0.x - u2.x, u0.y - u2.y);
            s[base + 3*Q] = make_float2(u1.x - u3.y, u1.y + u3.x);   // u1 + i*u3
        }
        __syncthreads();
    }
}

__global__ void __launch_bounds__(512) filters_kernel(
    const float* __restrict__ eig_vals, const float* __restrict__ eig_vecs,
    const float* __restrict__ w_filters, float2* __restrict__ Ffilt)
{
    __shared__ float2 s[NF4096];
    __shared__ float2 tw[1024];
    __shared__ float  wk[KK];
    int d = blockIdx.x, tid = threadIdx.x;
    if (tid < KK) wk[tid] = powf(eig_vals[tid], 0.25f) * w_filters[tid*DD + d];
    tw_init(tw, tid);
    for (int i = tid; i < NF4096; i += 512) s[i] = make_float2(0.f, 0.f);
    __syncthreads();
    for (int t = tid; t < LL; t += 512) {
        float f = 0.f;
        #pragma unroll
        for (int k = 0; k < KK; k++) f += eig_vecs[t*KK + k] * wk[k];
        s[rev4(t)] = make_float2(f, 0.f);
    }
    __syncthreads();
    do_fft4(s, tw, tid);
    for (int i = tid; i < NF4096; i += 512)
        Ffilt[(long long)d*NF4096 + i] = s[i];
}

// 2-for-1 packed conv with fused gather/scatter: reads xi [B,L,D] directly
// (adjacent channel pair = one float2), writes stu [B,L,D] directly.
__global__ void __launch_bounds__(512) conv3_kernel(
    const float* __restrict__ xi, const float2* __restrict__ Ffilt,
    float* __restrict__ stu)
{
    __shared__ float2 s[NF4096];
    __shared__ float2 tw[1024];
    int z = blockIdx.x, tid = threadIdx.x;
    int b = z >> 9, dp = z & 511;
    int d0 = 2*dp;
    const float* xib = xi + (long long)b*LL*DD + d0;
    float* stb = stu + (long long)b*LL*DD + d0;
    tw_init(tw, tid);
    for (int i = tid; i < NF4096; i += 512) s[i] = make_float2(0.f, 0.f);
    __syncthreads();
    for (int t = tid; t < LL; t += 512)
        s[rev4(t)] = *(const float2*)(xib + (long long)t*DD);
    __syncthreads();
    do_fft4(s, tw, tid);

    const float2* F0 = Ffilt + (long long)d0 * NF4096;
    const float2* F1 = F0 + NF4096;
    for (int i = tid; i < 2048; i += 512) {
        if (i == 0) {
            #pragma unroll
            for (int q = 0; q < 2; q++) {
                int idx = q * 2048;
                float2 Z = s[idx];
                float X1 = Z.x, X2 = Z.y;
                float2 f0 = F0[idx], f1 = F1[idx];
                float2 Y1 = make_float2(X1*f0.x, X1*f0.y);
                float2 Y2 = make_float2(X2*f1.x, X2*f1.y);
                s[idx] = make_float2(Y1.x - Y2.y, -(Y1.y + Y2.x));
            }
        } else {
            float2 Za = s[i], Zb = s[NF4096 - i];
            float2 X1 = make_float2(0.5f*(Za.x + Zb.x), 0.5f*(Za.y - Zb.y));
            float2 Dd = make_float2(Za.x - Zb.x, Za.y + Zb.y);
            float2 X2 = make_float2(0.5f*Dd.y, -0.5f*Dd.x);
            float2 f0 = F0[i], f1 = F1[i];
            float2 Y1 = make_float2(X1.x*f0.x - X1.y*f0.y, X1.x*f0.y + X1.y*f0.x);
            float2 Y2 = make_float2(X2.x*f1.x - X2.y*f1.y, X2.x*f1.y + X2.y*f1.x);
            s[i]          = make_float2(Y1.x - Y2.y, -(Y1.y + Y2.x));
            s[NF4096 - i] = make_float2(Y1.x + Y2.y, Y1.y - Y2.x);
        }
    }
    __syncthreads();
    float2 r[8];
    #pragma unroll
    for (int k = 0; k < 8; k++) r[k] = s[rev4(tid + k*512)];
    __syncthreads();
    #pragma unroll
    for (int k = 0; k < 8; k++) s[tid + k*512] = r[k];
    __syncthreads();
    do_fft4(s, tw, tid);
    const float inv = 1.0f / 4096.0f;
    for (int l = tid; l < LL; l += 512) {
        float2 w = make_float2(s[l].x * inv, -s[l].y * inv);
        *(float2*)(stb + (long long)l*DD) = w;
    }
}

// ---------------- LayerNorm with split-bf16 output ----------------
__global__ void __launch_bounds__(256) ln_split_kernel(
    const float* __restrict__ x, bf16* __restrict__ yh, bf16* __restrict__ yl,
    const float* __restrict__ sc, const float* __restrict__ bi)
{
    long long base = (long long)blockIdx.x * DD;
    int tid = threadIdx.x;
    float4 v = *(const float4*)(x + base + tid*4);
    float mean = block_sum256(v.x + v.y + v.z + v.w) * (1.0f/DD);
    float dx = v.x - mean, dy = v.y - mean, dz = v.z - mean, dw = v.w - mean;
    float var = block_sum256(dx*dx + dy*dy + dz*dz + dw*dw) * (1.0f/DD);
    float rstd = rsqrtf(var + 1e-6f);
    float4 s4 = *(const float4*)(sc + tid*4);
    float4 b4 = *(const float4*)(bi + tid*4);
    float o0 = dx*rstd*s4.x + b4.x;
    float o1 = dy*rstd*s4.y + b4.y;
    float o2 = dz*rstd*s4.z + b4.z;
    float o3 = dw*rstd*s4.w + b4.w;
    long long i = base + tid*4;
    bf16 h, l;
    split2(o0, h, l); yh[i+0] = h; yl[i+0] = l;
    split2(o1, h, l); yh[i+1] = h; yl[i+1] = l;
    split2(o2, h, l); yh[i+2] = h; yl[i+2] = l;
    split2(o3, h, l); yh[i+3] = h; yl[i+3] = l;
}

// ---------------- launch ----------------
static void* symv(const void* s) { void* p = nullptr; cudaGetSymbolAddress(&p, s); return p; }

extern "C" void kernel_launch(void* const* d_in, const int* in_sizes, int n_in,
                              void* d_out, int out_size)
{
    const float* inputs    = (const float*)d_in[0];
    const float* eig_vals  = (const float*)d_in[1];
    const float* eig_vecs  = (const float*)d_in[2];
    const float* w_filters = (const float*)d_in[3];
    const float* w_inputs  = (const float*)d_in[4];
    const float* ln1_s     = (const float*)d_in[5];
    const float* ln1_b     = (const float*)d_in[6];
    const float* wq        = (const float*)d_in[7];
    const float* wk        = (const float*)d_in[8];
    const float* wv        = (const float*)d_in[9];
    const float* wo        = (const float*)d_in[10];
    const float* ln2_s     = (const float*)d_in[11];
    const float* ln2_b     = (const float*)d_in[12];
    const float* mlp_w1    = (const float*)d_in[13];
    const float* mlp_b1    = (const float*)d_in[14];
    const float* mlp_w2    = (const float*)d_in[15];
    const float* mlp_b2    = (const float*)d_in[16];
    float* out = (float*)d_out;

    float*  xi    = (float*)symv(g_xi);
    float2* Ffilt = (float2*)symv(g_Ffilt);
    float*  stu   = (float*)symv(g_stu);
    float*  vbuf  = (float*)symv(g_v);
    float*  xres  = (float*)symv(g_xres);

    bf16 *inh=(bf16*)symv(g_inh),  *inl=(bf16*)symv(g_inl);
    bf16 *x1h=(bf16*)symv(g_x1h),  *x1l=(bf16*)symv(g_x1l);
    bf16 *qh =(bf16*)symv(g_qh),   *ql =(bf16*)symv(g_ql);
    bf16 *kh =(bf16*)symv(g_kh),   *kl =(bf16*)symv(g_kl);
    bf16 *vTh=(bf16*)symv(g_vTh),  *vTl=(bf16*)symv(g_vTl);
    bf16 *ath=(bf16*)symv(g_ath),  *atl=(bf16*)symv(g_atl);
    bf16 *y1h=(bf16*)symv(g_y1h),  *y1l=(bf16*)symv(g_y1l);
    bf16 *hh =(bf16*)symv(g_hh),   *hl =(bf16*)symv(g_hl);
    bf16 *wiTh=(bf16*)symv(g_wiTh),*wiTl=(bf16*)symv(g_wiTl);
    bf16 *wqTh=(bf16*)symv(g_wqTh),*wqTl=(bf16*)symv(g_wqTl);
    bf16 *wkTh=(bf16*)symv(g_wkTh),*wkTl=(bf16*)symv(g_wkTl);
    bf16 *wvTh=(bf16*)symv(g_wvTh),*wvTl=(bf16*)symv(g_wvTl);
    bf16 *woTh=(bf16*)symv(g_woTh),*woTl=(bf16*)symv(g_woTl);
    bf16 *w1Th=(bf16*)symv(g_w1Th),*w1Tl=(bf16*)symv(g_w1Tl);
    bf16 *w2Th=(bf16*)symv(g_w2Th),*w2Tl=(bf16*)symv(g_w2Tl);

    const int SMGE = 81920;
    const int SMFL = 143360;
    cudaFuncSetAttribute(gemm_bf16,    cudaFuncAttributeMaxDynamicSharedMemorySize, SMGE);
    cudaFuncSetAttribute(flash_kernel, cudaFuncAttributeMaxDynamicSharedMemorySize, SMFL);

    dim3 t328(32, 8);

    // 1. filter spectrum per channel d
    filters_kernel<<<DD, 512>>>(eig_vals, eig_vecs, w_filters, Ffilt);

    // 2. split inputs; transpose-split all weights to [N][K]
    split_kernel<<<(BL*DD)/1024, 256>>>(inputs, inh, inl);
    transpose_split_kernel<<<dim3(32, 32, 1), t328>>>(w_inputs, wiTh, wiTl, DD, DD);
    transpose_split_kernel<<<dim3(32, 32, 1), t328>>>(wq, wqTh, wqTl, DD, DD);
    transpose_split_kernel<<<dim3(32, 32, 1), t328>>>(wk, wkTh, wkTl, DD, DD);
    transpose_split_kernel<<<dim3(32, 32, 1), t328>>>(wv, wvTh, wvTl, DD, DD);
    transpose_split_kernel<<<dim3(32, 32, 1), t328>>>(wo, woTh, woTl, DD, DD);
    transpose_split_kernel<<<dim3(MLPD/32, DD/32, 1), t328>>>(mlp_w1, w1Th, w1Tl, DD, MLPD);
    transpose_split_kernel<<<dim3(DD/32, MLPD/32, 1), t328>>>(mlp_w2, w2Th, w2Tl, MLPD, DD);

    // 3. xi = inputs @ w_inputs (f32 out for FFT)
    gemm_bf16<<<dim3(8, 64, 1), 256, SMGE>>>(
        inh, inl, wiTh, wiTl, xi, nullptr, nullptr,
        BL, DD, DD, DD, DD, DD, 1.0f, nullptr, nullptr, 0);

    // 4. spectral causal conv (radix-4 packed FFT, fused gather/scatter)
    conv3_kernel<<<BB*DD/2, 512>>>(xi, Ffilt, stu);

    // 5. LN1 -> split x1
    ln_split_kernel<<<BL, 256>>>(stu, x1h, x1l, ln1_s, ln1_b);

    // 6. Q (scaled, split), K (split), V (f32 then transpose-split)
    gemm_bf16<<<dim3(8, 64, 1), 256, SMGE>>>(
        x1h, x1l, wqTh, wqTl, nullptr, qh, ql,
        BL, DD, DD, DD, DD, DD, 0.125f, nullptr, nullptr, 8);
    gemm_bf16<<<dim3(8, 64, 1), 256, SMGE>>>(
        x1h, x1l, wkTh, wkTl, nullptr, kh, kl,
        BL, DD, DD, DD, DD, DD, 1.0f, nullptr, nullptr, 8);
    gemm_bf16<<<dim3(8, 64, 1), 256, SMGE>>>(
        x1h, x1l, wvTh, wvTl, vbuf, nullptr, nullptr,
        BL, DD, DD, DD, DD, DD, 1.0f, nullptr, nullptr, 0);
    transpose_split_kernel<<<dim3(DD/32, LL/32, BB), t328>>>(vbuf, vTh, vTl, LL, DD);

    // 7. fused flash attention -> split att
    flash_kernel<<<dim3(LL/128, BB*HH), 256, SMFL>>>(
        qh, ql, kh, kl, vTh, vTl, ath, atl);

    // 8. x = att @ wo + stu (f32)
    gemm_bf16<<<dim3(8, 64, 1), 256, SMGE>>>(
        ath, atl, woTh, woTl, xres, nullptr, nullptr,
        BL, DD, DD, DD, DD, DD, 1.0f, nullptr, stu, 4);

    // 9. LN2 -> split y1
    ln_split_kernel<<<BL, 256>>>(xres, y1h, y1l, ln2_s, ln2_b);

    // 10. h = gelu(y1 @ w1 + b1), split out
    gemm_bf16<<<dim3(MLPD/128, 64, 1), 256, SMGE>>>(
        y1h, y1l, w1Th, w1Tl, nullptr, hh, hl,
        BL, MLPD, DD, DD, DD, MLPD, 1.0f, mlp_b1, nullptr, 11);

    // 11. out = h @ w2 + b2 + x (f32)
    gemm_bf16<<<dim3(8, 64, 1), 256, SMGE>>>(
        hh, hl, w2Th, w2Tl, out, nullptr, nullptr,
        BL, DD, MLPD, MLPD, MLPD, DD, 1.0f, mlp_b2, xres, 5);
}

// round 11
// speedup vs baseline: 3.7633x; 1.0824x over previous
#include <cuda_runtime.h>
#include <cuda_bf16.h>
#include <math.h>
#include <stdint.h>

#define BB 4
#define LL 2048
#define DD 1024
#define HH 16
#define HDIM 64
#define KK 24
#define MLPD 4096
#define BL (BB*LL)
#define NF4096 4096

typedef __nv_bfloat16 bf16;

// ---------------- scratch (device globals; allocation-free) ----------------
__device__ float  g_xi[BL*DD];
__device__ float2 g_Ffilt[(size_t)DD*NF4096];
__device__ float  g_stu[BL*DD];
__device__ float  g_v[BL*DD];
__device__ float  g_xres[BL*DD];

__device__ bf16 g_inh[BL*DD],  g_inl[BL*DD];
__device__ bf16 g_x1h[BL*DD],  g_x1l[BL*DD];
__device__ bf16 g_qh [BL*DD],  g_ql [BL*DD];
__device__ bf16 g_kh [BL*DD],  g_kl [BL*DD];
__device__ bf16 g_vTh[BL*DD],  g_vTl[BL*DD];       // [B,H*HD,L]
__device__ bf16 g_ath[BL*DD],  g_atl[BL*DD];
__device__ bf16 g_y1h[BL*DD],  g_y1l[BL*DD];
__device__ bf16 g_hh[(size_t)BL*MLPD], g_hl[(size_t)BL*MLPD];
// transposed-split weights [N][K]
__device__ bf16 g_wiTh[DD*DD],  g_wiTl[DD*DD];
__device__ bf16 g_wqTh[DD*DD],  g_wqTl[DD*DD];
__device__ bf16 g_wkTh[DD*DD],  g_wkTl[DD*DD];
__device__ bf16 g_wvTh[DD*DD],  g_wvTl[DD*DD];
__device__ bf16 g_woTh[DD*DD],  g_woTl[DD*DD];
__device__ bf16 g_w1Th[(size_t)DD*MLPD], g_w1Tl[(size_t)DD*MLPD];
__device__ bf16 g_w2Th[(size_t)DD*MLPD], g_w2Tl[(size_t)DD*MLPD];

// ---------------- helpers ----------------
__device__ __forceinline__ float gelu_f(float x) {
    float x3 = x*x*x;
    return 0.5f*x*(1.0f + tanhf(0.7978845608028654f*(x + 0.044715f*x3)));
}
__device__ __forceinline__ void split2(float v, bf16 &h, bf16 &l) {
    h = __float2bfloat16_rn(v);
    l = __float2bfloat16_rn(v - __bfloat162float(h));
}
__device__ __forceinline__ uint32_t pack2(bf16 a, bf16 b) {
    return (uint32_t)__bfloat16_as_ushort(a) | ((uint32_t)__bfloat16_as_ushort(b) << 16);
}
__device__ __forceinline__ void cpa16(uint32_t s, const void* g) {
    asm volatile("cp.async.cg.shared.global [%0], [%1], 16;" :: "r"(s), "l"(g));
}
__device__ __forceinline__ void mma16816(float* c, const uint32_t* a, const uint32_t* b) {
    asm volatile("mma.sync.aligned.m16n8k16.row.col.f32.bf16.bf16.f32 "
                 "{%0,%1,%2,%3},{%4,%5,%6,%7},{%8,%9},{%0,%1,%2,%3};"
                 : "+f"(c[0]), "+f"(c[1]), "+f"(c[2]), "+f"(c[3])
                 : "r"(a[0]), "r"(a[1]), "r"(a[2]), "r"(a[3]),
                   "r"(b[0]), "r"(b[1]));
}
__device__ __forceinline__ void ldsm_x4(uint32_t* r, uint32_t saddr) {
    asm volatile("ldmatrix.sync.aligned.m8n8.x4.shared.b16 {%0,%1,%2,%3}, [%4];"
        : "=r"(r[0]), "=r"(r[1]), "=r"(r[2]), "=r"(r[3]) : "r"(saddr));
}
__device__ __forceinline__ float block_sum256(float v) {
    __shared__ float red[8];
    int lane = threadIdx.x & 31, w = threadIdx.x >> 5;
    #pragma unroll
    for (int o = 16; o; o >>= 1) v += __shfl_xor_sync(0xffffffffu, v, o);
    __syncthreads();
    if (lane == 0) red[w] = v;
    __syncthreads();
    if (threadIdx.x == 0) {
        float s = 0.f;
        #pragma unroll
        for (int i = 0; i < 8; i++) s += red[i];
        red[0] = s;
    }
    __syncthreads();
    return red[0];
}

// ---------------- split-bf16 tensor-core GEMM (dense layers) ----------------
// C[M,N] = alpha*(A@B^T) (+bias/gelu/resid/split). A split [M,K] row-major,
// B split [N,K] row-major. Tile 128x128, 2 CTAs/SM, 2-stage, ldmatrix frags.
// mode: 1=bias, 2=gelu, 4=resid, 8=split-out
__global__ void __launch_bounds__(256, 2) gemm_bf16(
    const bf16* __restrict__ Ahi, const bf16* __restrict__ Alo,
    const bf16* __restrict__ Bhi, const bf16* __restrict__ Blo,
    float* __restrict__ C, bf16* __restrict__ Chi, bf16* __restrict__ Clo,
    int M, int N, int Kd, int lda, int ldb, int ldc,
    float alpha, const float* __restrict__ bias,
    const float* __restrict__ resid, int mode)
{
    constexpr int SP    = 40;
    constexpr int AH    = 128 * SP;
    constexpr int BHalf = 128 * SP;
    constexpr int STAGE = 2*AH + 2*BHalf;   // 20480 halves = 40960 B

    extern __shared__ __align__(16) char dsm[];
    uint32_t smem0 = (uint32_t)__cvta_generic_to_shared(dsm);

    int tid   = threadIdx.x;
    int mBase = blockIdx.y * 128, nBase = blockIdx.x * 128;

    const bf16* pAh = Ahi + (long long)mBase * lda;
    const bf16* pAl = Alo + (long long)mBase * lda;
    const bf16* pBh = Bhi + (long long)nBase * ldb;
    const bf16* pBl = Blo + (long long)nBase * ldb;

    int warp = tid >> 5, lane = tid & 31;
    int wm = warp & 3, wn = warp >> 2;
    int g  = lane >> 2, tig = lane & 3;

    // ldmatrix per-lane address components
    int aRow = wm*32 + (lane & 15);          // + mi*16
    int aCol = (lane & 16) ? 8 : 0;          // + kh*16
    int bRow = wn*64 + ((lane >> 4) << 3) + (lane & 7);   // + nip*16
    int bCol = (lane & 8) ? 8 : 0;           // + kh*16

    float acc[2][8][4];
    #pragma unroll
    for (int i = 0; i < 2; i++)
        #pragma unroll
        for (int j = 0; j < 8; j++)
            #pragma unroll
            for (int c = 0; c < 4; c++) acc[i][j][c] = 0.f;

    auto load_stage = [&](int buf, int k0) {
        int so = buf * STAGE;
        #pragma unroll
        for (int i = 0; i < 2; i++) {
            int ci = tid + i*256;
            int row = ci >> 2, seg = ci & 3;
            long long go = (long long)row*lda + k0 + seg*8;
            uint32_t sa = smem0 + 2*(so + row*SP + seg*8);
            cpa16(sa,          pAh + go);
            cpa16(sa + 2*AH,   pAl + go);
        }
        #pragma unroll
        for (int i = 0; i < 2; i++) {
            int ci = tid + i*256;
            int row = ci >> 2, seg = ci & 3;
            long long go = (long long)row*ldb + k0 + seg*8;
            uint32_t sa = smem0 + 2*(so + 2*AH + row*SP + seg*8);
            cpa16(sa,              pBh + go);
            cpa16(sa + 2*BHalf,    pBl + go);
        }
        asm volatile("cp.async.commit_group;");
    };

    int nk = Kd >> 5;
    load_stage(0, 0);

    for (int ks = 0; ks < nk; ks++) {
        asm volatile("cp.async.wait_group 0;");
        __syncthreads();
        if (ks + 1 < nk) load_stage((ks+1)&1, (ks+1) << 5);
        int so = (ks & 1) * STAGE;

        #pragma unroll
        for (int kh = 0; kh < 2; kh++) {
            int kb = kh*16;
            uint32_t ah[2][4], al[2][4];
            #pragma unroll
            for (int mi = 0; mi < 2; mi++) {
                uint32_t ad = smem0 + 2*(so + (aRow + mi*16)*SP + kb + aCol);
                ldsm_x4(ah[mi], ad);
                ldsm_x4(al[mi], ad + 2*AH);
            }
            #pragma unroll
            for (int nip = 0; nip < 4; nip++) {
                uint32_t bd = smem0 + 2*(so + 2*AH + (bRow + nip*16)*SP + kb + bCol);
                uint32_t bh4[4], bl4[4];
                ldsm_x4(bh4, bd);
                ldsm_x4(bl4, bd + 2*BHalf);
                #pragma unroll
                for (int q = 0; q < 2; q++) {
                    int ni = nip*2 + q;
                    #pragma unroll
                    for (int mi = 0; mi < 2; mi++) {
                        mma16816(acc[mi][ni], ah[mi], bh4 + 2*q);
                        mma16816(acc[mi][ni], al[mi], bh4 + 2*q);
                        mma16816(acc[mi][ni], ah[mi], bl4 + 2*q);
                    }
                }
            }
        }
    }

    bool hb = mode & 1, hg = mode & 2, hr = mode & 4, hs = mode & 8;
    #pragma unroll
    for (int mi = 0; mi < 2; mi++) {
        int m0 = mBase + wm*32 + mi*16 + g;
        #pragma unroll
        for (int ni = 0; ni < 8; ni++) {
            int n = nBase + wn*64 + ni*8 + 2*tig;
            #pragma unroll
            for (int hrow = 0; hrow < 2; hrow++) {
                int m = m0 + hrow*8;
                float v0 = acc[mi][ni][hrow*2+0] * alpha;
                float v1 = acc[mi][ni][hrow*2+1] * alpha;
                if (hb) { v0 += bias[n]; v1 += bias[n+1]; }
                if (hg) { v0 = gelu_f(v0); v1 = gelu_f(v1); }
                long long o = (long long)m*ldc + n;
                if (hr) { v0 += resid[o]; v1 += resid[o+1]; }
                if (hs) {
                    bf16 h0, l0, h1, l1;
                    split2(v0, h0, l0); split2(v1, h1, l1);
                    *(uint32_t*)(Chi + o) = pack2(h0, h1);
                    *(uint32_t*)(Clo + o) = pack2(l0, l1);
                } else {
                    C[o] = v0; C[o+1] = v1;
                }
            }
        }
    }
}

// ---------------- flash attention (fused QK^T / softmax / PV, mma.sync) ----------------
__global__ void __launch_bounds__(256) flash_kernel(
    const bf16* __restrict__ Qh, const bf16* __restrict__ Ql,
    const bf16* __restrict__ Kh, const bf16* __restrict__ Kl,
    const bf16* __restrict__ Vth, const bf16* __restrict__ Vtl,
    bf16* __restrict__ Oh, bf16* __restrict__ Ol)
{
    constexpr int KSP = 72, VSP = 136;
    constexpr int KTH = 128*KSP;
    constexpr int VTH = 64*VSP;
    constexpr int STG = 2*KTH + 2*VTH;

    extern __shared__ __align__(16) bf16 sm[];
    uint32_t smem0 = (uint32_t)__cvta_generic_to_shared(sm);

    int tid = threadIdx.x, warp = tid >> 5, lane = tid & 31;
    int g = lane >> 2, tig = lane & 3;
    int qt = blockIdx.x, bh = blockIdx.y;
    int b = bh >> 4, h = bh & 15;
    const long long LLD = (long long)LL * DD;
    long long baseQ = (long long)b*LLD + (long long)(qt*128)*DD + h*64;
    long long baseK = (long long)b*LLD + h*64;
    long long baseV = (long long)b*LLD + (long long)(h*64)*LL;

    // ldmatrix per-lane address components (pairs of 8-row fragments)
    int fRow = ((lane >> 4) << 3) + (lane & 7);   // 0..15
    int fCol = (lane & 8) ? 8 : 0;

    uint32_t qa_h[4][4], qa_l[4][4];
    {
        long long r0 = baseQ + (long long)(warp*16 + g)*DD;
        long long r8 = r0 + 8*DD;
        #pragma unroll
        for (int kf = 0; kf < 4; kf++) {
            int c = kf*16 + 2*tig;
            qa_h[kf][0] = *(const uint32_t*)(Qh + r0 + c);
            qa_h[kf][1] = *(const uint32_t*)(Qh + r8 + c);
            qa_h[kf][2] = *(const uint32_t*)(Qh + r0 + c + 8);
            qa_h[kf][3] = *(const uint32_t*)(Qh + r8 + c + 8);
            qa_l[kf][0] = *(const uint32_t*)(Ql + r0 + c);
            qa_l[kf][1] = *(const uint32_t*)(Ql + r8 + c);
            qa_l[kf][2] = *(const uint32_t*)(Ql + r0 + c + 8);
            qa_l[kf][3] = *(const uint32_t*)(Ql + r8 + c + 8);
        }
    }

    auto load_tiles = [&](int buf, int kt) {
        int so = buf * STG;
        #pragma unroll
        for (int i = 0; i < 4; i++) {
            int ci = tid + i*256;
            int row = ci >> 3, ch = ci & 7;
            long long go = baseK + (long long)(kt*128 + row)*DD + ch*8;
            uint32_t sa = smem0 + 2*(so + row*KSP + ch*8);
            cpa16(sa,           Kh + go);
            cpa16(sa + 2*KTH,   Kl + go);
        }
        #pragma unroll
        for (int i = 0; i < 4; i++) {
            int ci = tid + i*256;
            int row = ci >> 4, ch = ci & 15;
            long long go = baseV + (long long)row*LL + kt*128 + ch*8;
            uint32_t sa = smem0 + 2*(so + 2*KTH + row*VSP + ch*8);
            cpa16(sa,           Vth + go);
            cpa16(sa + 2*VTH,   Vtl + go);
        }
        asm volatile("cp.async.commit_group;");
    };

    float m_r[2] = {-1e30f, -1e30f};
    float l_r[2] = {0.f, 0.f};
    float o[8][4];
    #pragma unroll
    for (int n = 0; n < 8; n++)
        #pragma unroll
        for (int c = 0; c < 4; c++) o[n][c] = 0.f;

    load_tiles(0, 0);

    for (int kt = 0; kt < 16; kt++) {
        asm volatile("cp.async.wait_group 0;");
        __syncthreads();
        if (kt + 1 < 16) load_tiles((kt+1)&1, kt+1);
        int so = (kt & 1) * STG;

        float s[16][4];
        #pragma unroll
        for (int n = 0; n < 16; n++)
            #pragma unroll
            for (int c = 0; c < 4; c++) s[n][c] = 0.f;

        #pragma unroll
        for (int kf = 0; kf < 4; kf++) {
            #pragma unroll
            for (int np = 0; np < 8; np++) {
                uint32_t kd = smem0 + 2*(so + (np*16 + fRow)*KSP + kf*16 + fCol);
                uint32_t kh4[4], kl4[4];
                ldsm_x4(kh4, kd);
                ldsm_x4(kl4, kd + 2*KTH);
                #pragma unroll
                for (int q = 0; q < 2; q++) {
                    int n = np*2 + q;
                    mma16816(s[n], qa_h[kf], kh4 + 2*q);
                    mma16816(s[n], qa_l[kf], kh4 + 2*q);
                    mma16816(s[n], qa_h[kf], kl4 + 2*q);
                }
            }
        }

        float mx0 = -1e30f, mx1 = -1e30f;
        #pragma unroll
        for (int n = 0; n < 16; n++) {
            mx0 = fmaxf(mx0, fmaxf(s[n][0], s[n][1]));
            mx1 = fmaxf(mx1, fmaxf(s[n][2], s[n][3]));
        }
        #pragma unroll
        for (int off = 1; off < 4; off <<= 1) {
            mx0 = fmaxf(mx0, __shfl_xor_sync(0xffffffffu, mx0, off));
            mx1 = fmaxf(mx1, __shfl_xor_sync(0xffffffffu, mx1, off));
        }
        float mn0 = fmaxf(m_r[0], mx0), mn1 = fmaxf(m_r[1], mx1);
        float sf0 = __expf(m_r[0] - mn0), sf1 = __expf(m_r[1] - mn1);
        m_r[0] = mn0; m_r[1] = mn1;
        float sum0 = 0.f, sum1 = 0.f;
        #pragma unroll
        for (int n = 0; n < 16; n++) {
            s[n][0] = __expf(s[n][0] - mn0); sum0 += s[n][0];
            s[n][1] = __expf(s[n][1] - mn0); sum0 += s[n][1];
            s[n][2] = __expf(s[n][2] - mn1); sum1 += s[n][2];
            s[n][3] = __expf(s[n][3] - mn1); sum1 += s[n][3];
        }
        #pragma unroll
        for (int off = 1; off < 4; off <<= 1) {
            sum0 += __shfl_xor_sync(0xffffffffu, sum0, off);
            sum1 += __shfl_xor_sync(0xffffffffu, sum1, off);
        }
        l_r[0] = l_r[0]*sf0 + sum0;
        l_r[1] = l_r[1]*sf1 + sum1;
        #pragma unroll
        for (int n = 0; n < 8; n++) {
            o[n][0] *= sf0; o[n][1] *= sf0;
            o[n][2] *= sf1; o[n][3] *= sf1;
        }

        #pragma unroll
        for (int kf2 = 0; kf2 < 8; kf2++) {
            uint32_t pa_h[4], pa_l[4];
            #pragma unroll
            for (int q4 = 0; q4 < 2; q4++) {
                int t = 2*kf2 + q4;
                #pragma unroll
                for (int rr = 0; rr < 2; rr++) {
                    float p0 = s[t][rr*2+0], p1 = s[t][rr*2+1];
                    bf16 h0, l0, h1, l1;
                    split2(p0, h0, l0); split2(p1, h1, l1);
                    pa_h[q4*2+rr] = pack2(h0, h1);
                    pa_l[q4*2+rr] = pack2(l0, l1);
                }
            }
            #pragma unroll
            for (int np2 = 0; np2 < 4; np2++) {
                uint32_t vd = smem0 + 2*(so + 2*KTH + (np2*16 + fRow)*VSP + kf2*16 + fCol);
                uint32_t vh4[4], vl4[4];
                ldsm_x4(vh4, vd);
                ldsm_x4(vl4, vd + 2*VTH);
                #pragma unroll
                for (int q = 0; q < 2; q++) {
                    int n = np2*2 + q;
                    mma16816(o[n], pa_h, vh4 + 2*q);
                    mma16816(o[n], pa_l, vh4 + 2*q);
                    mma16816(o[n], pa_h, vl4 + 2*q);
                }
            }
        }
    }

    float il0 = 1.f / l_r[0], il1 = 1.f / l_r[1];
    long long r0 = baseQ + (long long)(warp*16 + g)*DD;
    long long r8 = r0 + 8*DD;
    #pragma unroll
    for (int n = 0; n < 8; n++) {
        int c = n*8 + 2*tig;
        float v0 = o[n][0]*il0, v1 = o[n][1]*il0;
        float v2 = o[n][2]*il1, v3 = o[n][3]*il1;
        bf16 h0,l0,h1,l1;
        split2(v0,h0,l0); split2(v1,h1,l1);
        *(uint32_t*)(Oh + r0 + c) = pack2(h0,h1);
        *(uint32_t*)(Ol + r0 + c) = pack2(l0,l1);
        split2(v2,h0,l0); split2(v3,h1,l1);
        *(uint32_t*)(Oh + r8 + c) = pack2(h0,h1);
        *(uint32_t*)(Ol + r8 + c) = pack2(l0,l1);
    }
}

// ---------------- transpose + split: f32 [rows,cols] -> bf16 hi/lo [cols,rows] ----------------
__global__ void transpose_split_kernel(const float* __restrict__ in,
                                       bf16* __restrict__ oh, bf16* __restrict__ ol,
                                       int rows, int cols)
{
    __shared__ float t[32][33];
    long long bo = (long long)blockIdx.z * rows * cols;
    int c0 = blockIdx.x * 32, r0 = blockIdx.y * 32;
    int tx = threadIdx.x, ty = threadIdx.y;
    #pragma unroll
    for (int i = 0; i < 32; i += 8)
        t[ty+i][tx] = in[bo + (long long)(r0+ty+i)*cols + (c0+tx)];
    __syncthreads();
    #pragma unroll
    for (int i = 0; i < 32; i += 8) {
        float v = t[tx][ty+i];
        bf16 h, l; split2(v, h, l);
        long long o = bo + (long long)(c0+ty+i)*rows + (r0+tx);
        oh[o] = h; ol[o] = l;
    }
}

// ---------------- elementwise split ----------------
__global__ void split_kernel(const float* __restrict__ x,
                             bf16* __restrict__ oh, bf16* __restrict__ ol)
{
    long long i = ((long long)blockIdx.x * 256 + threadIdx.x) * 4;
    float4 v = *(const float4*)(x + i);
    bf16 h, l;
    split2(v.x, h, l); oh[i+0] = h; ol[i+0] = l;
    split2(v.y, h, l); oh[i+1] = h; ol[i+1] = l;
    split2(v.z, h, l); oh[i+2] = h; ol[i+2] = l;
    split2(v.w, h, l); oh[i+3] = h; ol[i+3] = l;
}

// ---------------- FFT (radix-4 DIT, n=4096, 512 threads) ----------------
__device__ __forceinline__ int rev4(int i) {
    int r = __brev(i) >> 20;
    return ((r & 0x555) << 1) | ((r >> 1) & 0x555);
}
__device__ __forceinline__ float2 cmulf(float2 a, float2 b) {
    return make_float2(a.x*b.x - a.y*b.y, a.x*b.y + a.y*b.x);
}
__device__ __forceinline__ void tw_init(float2* tw, int tid) {
    for (int m = tid; m < 1024; m += 512) {
        float sv, cv;
        sincosf(-6.283185307179586f * (float)m / 4096.0f, &sv, &cv);
        tw[m] = make_float2(cv, sv);
    }
}

__device__ void do_fft4(float2* s, const float2* tw, int tid) {
    #pragma unroll 1
    for (int st = 0; st < 6; st++) {
        int Q  = 1 << (2*st);
        int sh = 10 - 2*st;
        #pragma unroll 1
        for (int idx = tid; idx < 1024; idx += 512) {
            int j    = idx & (Q - 1);
            int blk  = idx >> (2*st);
            int base = blk*(Q << 2) + j;
            float2 x0 = s[base];
            float2 x1 = s[base + Q];
            float2 x2 = s[base + 2*Q];
            float2 x3 = s[base + 3*Q];
            float2 w1 = tw[j << sh];
            float2 w2 = cmulf(w1, w1);
            float2 w3 = cmulf(w2, w1);
            float2 y1 = cmulf(w1, x1);
            float2 y2 = cmulf(w2, x2);
            float2 y3 = cmulf(w3, x3);
            float2 u0 = make_float2(x0.x + y2.x, x0.y + y2.y);
            float2 u1 = make_float2(x0.x - y2.x, x0.y - y2.y);
            float2 u2 = make_float2(y1.x + y3.x, y1.y + y3.y);
            float2 u3 = make_float2(y1.x - y3.x, y1.y - y3.y);
            s[base]       = make_float2(u0.x + u2.x, u0.y + u2.y);
            s[base + Q]   = make_float2(u1.x + u3.y, u1.y - u3.x);
            s[base + 2*Q] = make_float2(u0.x - u2.x, u0.y - u2.y);
            s[base + 3*Q] = make_float2(u1.x - u3.y, u1.y + u3.x);
        }
        __syncthreads();
    }
}

__global__ void __launch_bounds__(512) filters_kernel(
    const float* __restrict__ eig_vals, const float* __restrict__ eig_vecs,
    const float* __restrict__ w_filters, float2* __restrict__ Ffilt)
{
    __shared__ float2 s[NF4096];
    __shared__ float2 tw[1024];
    __shared__ float  wk[KK];
    int d = blockIdx.x, tid = threadIdx.x;
    if (tid < KK) wk[tid] = powf(eig_vals[tid], 0.25f) * w_filters[tid*DD + d];
    tw_init(tw, tid);
    for (int i = tid; i < NF4096; i += 512) s[i] = make_float2(0.f, 0.f);
    __syncthreads();
    for (int t = tid; t < LL; t += 512) {
        float f = 0.f;
        #pragma unroll
        for (int k = 0; k < KK; k++) f += eig_vecs[t*KK + k] * wk[k];
        s[rev4(t)] = make_float2(f, 0.f);
    }
    __syncthreads();
    do_fft4(s, tw, tid);
    for (int i = tid; i < NF4096; i += 512)
        Ffilt[(long long)d*NF4096 + i] = s[i];
}

// 2-for-1 packed conv with fused gather/scatter
__global__ void __launch_bounds__(512) conv3_kernel(
    const float* __restrict__ xi, const float2* __restrict__ Ffilt,
    float* __restrict__ stu)
{
    __shared__ float2 s[NF4096];
    __shared__ float2 tw[1024];
    int z = blockIdx.x, tid = threadIdx.x;
    int b = z >> 9, dp = z & 511;
    int d0 = 2*dp;
    const float* xib = xi + (long long)b*LL*DD + d0;
    float* stb = stu + (long long)b*LL*DD + d0;
    tw_init(tw, tid);
    for (int i = tid; i < NF4096; i += 512) s[i] = make_float2(0.f, 0.f);
    __syncthreads();
    for (int t = tid; t < LL; t += 512)
        s[rev4(t)] = *(const float2*)(xib + (long long)t*DD);
    __syncthreads();
    do_fft4(s, tw, tid);

    const float2* F0 = Ffilt + (long long)d0 * NF4096;
    const float2* F1 = F0 + NF4096;
    for (int i = tid; i < 2048; i += 512) {
        if (i == 0) {
            #pragma unroll
            for (int q = 0; q < 2; q++) {
                int idx = q * 2048;
                float2 Z = s[idx];
                float X1 = Z.x, X2 = Z.y;
                float2 f0 = F0[idx], f1 = F1[idx];
                float2 Y1 = make_float2(X1*f0.x, X1*f0.y);
                float2 Y2 = make_float2(X2*f1.x, X2*f1.y);
                s[idx] = make_float2(Y1.x - Y2.y, -(Y1.y + Y2.x));
            }
        } else {
            float2 Za = s[i], Zb = s[NF4096 - i];
            float2 X1 = make_float2(0.5f*(Za.x + Zb.x), 0.5f*(Za.y - Zb.y));
            float2 Dd = make_float2(Za.x - Zb.x, Za.y + Zb.y);
            float2 X2 = make_float2(0.5f*Dd.y, -0.5f*Dd.x);
            float2 f0 = F0[i], f1 = F1[i];
            float2 Y1 = make_float2(X1.x*f0.x - X1.y*f0.y, X1.x*f0.y + X1.y*f0.x);
            float2 Y2 = make_float2(X2.x*f1.x - X2.y*f1.y, X2.x*f1.y + X2.y*f1.x);
            s[i]          = make_float2(Y1.x - Y2.y, -(Y1.y + Y2.x));
            s[NF4096 - i] = make_float2(Y1.x + Y2.y, Y1.y - Y2.x);
        }
    }
    __syncthreads();
    float2 r[8];
    #pragma unroll
    for (int k = 0; k < 8; k++) r[k] = s[rev4(tid + k*512)];
    __syncthreads();
    #pragma unroll
    for (int k = 0; k < 8; k++) s[tid + k*512] = r[k];
    __syncthreads();
    do_fft4(s, tw, tid);
    const float inv = 1.0f / 4096.0f;
    for (int l = tid; l < LL; l += 512) {
        float2 w = make_float2(s[l].x * inv, -s[l].y * inv);
        *(float2*)(stb + (long long)l*DD) = w;
    }
}

// ---------------- LayerNorm with split-bf16 output ----------------
__global__ void __launch_bounds__(256) ln_split_kernel(
    const float* __restrict__ x, bf16* __restrict__ yh, bf16* __restrict__ yl,
    const float* __restrict__ sc, const float* __restrict__ bi)
{
    long long base = (long long)blockIdx.x * DD;
    int tid = threadIdx.x;
    float4 v = *(const float4*)(x + base + tid*4);
    float mean = block_sum256(v.x + v.y + v.z + v.w) * (1.0f/DD);
    float dx = v.x - mean, dy = v.y - mean, dz = v.z - mean, dw = v.w - mean;
    float var = block_sum256(dx*dx + dy*dy + dz*dz + dw*dw) * (1.0f/DD);
    float rstd = rsqrtf(var + 1e-6f);
    float4 s4 = *(const float4*)(sc + tid*4);
    float4 b4 = *(const float4*)(bi + tid*4);
    float o0 = dx*rstd*s4.x + b4.x;
    float o1 = dy*rstd*s4.y + b4.y;
    float o2 = dz*rstd*s4.z + b4.z;
    float o3 = dw*rstd*s4.w + b4.w;
    long long i = base + tid*4;
    bf16 h, l;
    split2(o0, h, l); yh[i+0] = h; yl[i+0] = l;
    split2(o1, h, l); yh[i+1] = h; yl[i+1] = l;
    split2(o2, h, l); yh[i+2] = h; yl[i+2] = l;
    split2(o3, h, l); yh[i+3] = h; yl[i+3] = l;
}

// ---------------- launch ----------------
static void* symv(const void* s) { void* p = nullptr; cudaGetSymbolAddress(&p, s); return p; }

extern "C" void kernel_launch(void* const* d_in, const int* in_sizes, int n_in,
                              void* d_out, int out_size)
{
    const float* inputs    = (const float*)d_in[0];
    const float* eig_vals  = (const float*)d_in[1];
    const float* eig_vecs  = (const float*)d_in[2];
    const float* w_filters = (const float*)d_in[3];
    const float* w_inputs  = (const float*)d_in[4];
    const float* ln1_s     = (const float*)d_in[5];
    const float* ln1_b     = (const float*)d_in[6];
    const float* wq        = (const float*)d_in[7];
    const float* wk        = (const float*)d_in[8];
    const float* wv        = (const float*)d_in[9];
    const float* wo        = (const float*)d_in[10];
    const float* ln2_s     = (const float*)d_in[11];
    const float* ln2_b     = (const float*)d_in[12];
    const float* mlp_w1    = (const float*)d_in[13];
    const float* mlp_b1    = (const float*)d_in[14];
    const float* mlp_w2    = (const float*)d_in[15];
    const float* mlp_b2    = (const float*)d_in[16];
    float* out = (float*)d_out;

    float*  xi    = (float*)symv(g_xi);
    float2* Ffilt = (float2*)symv(g_Ffilt);
    float*  stu   = (float*)symv(g_stu);
    float*  vbuf  = (float*)symv(g_v);
    float*  xres  = (float*)symv(g_xres);

    bf16 *inh=(bf16*)symv(g_inh),  *inl=(bf16*)symv(g_inl);
    bf16 *x1h=(bf16*)symv(g_x1h),  *x1l=(bf16*)symv(g_x1l);
    bf16 *qh =(bf16*)symv(g_qh),   *ql =(bf16*)symv(g_ql);
    bf16 *kh =(bf16*)symv(g_kh),   *kl =(bf16*)symv(g_kl);
    bf16 *vTh=(bf16*)symv(g_vTh),  *vTl=(bf16*)symv(g_vTl);
    bf16 *ath=(bf16*)symv(g_ath),  *atl=(bf16*)symv(g_atl);
    bf16 *y1h=(bf16*)symv(g_y1h),  *y1l=(bf16*)symv(g_y1l);
    bf16 *hh =(bf16*)symv(g_hh),   *hl =(bf16*)symv(g_hl);
    bf16 *wiTh=(bf16*)symv(g_wiTh),*wiTl=(bf16*)symv(g_wiTl);
    bf16 *wqTh=(bf16*)symv(g_wqTh),*wqTl=(bf16*)symv(g_wqTl);
    bf16 *wkTh=(bf16*)symv(g_wkTh),*wkTl=(bf16*)symv(g_wkTl);
    bf16 *wvTh=(bf16*)symv(g_wvTh),*wvTl=(bf16*)symv(g_wvTl);
    bf16 *woTh=(bf16*)symv(g_woTh),*woTl=(bf16*)symv(g_woTl);
    bf16 *w1Th=(bf16*)symv(g_w1Th),*w1Tl=(bf16*)symv(g_w1Tl);
    bf16 *w2Th=(bf16*)symv(g_w2Th),*w2Tl=(bf16*)symv(g_w2Tl);

    const int SMGE = 81920;
    const int SMFL = 143360;
    cudaFuncSetAttribute(gemm_bf16,    cudaFuncAttributeMaxDynamicSharedMemorySize, SMGE);
    cudaFuncSetAttribute(flash_kernel, cudaFuncAttributeMaxDynamicSharedMemorySize, SMFL);

    dim3 t328(32, 8);

    // 1. filter spectrum per channel d
    filters_kernel<<<DD, 512>>>(eig_vals, eig_vecs, w_filters, Ffilt);

    // 2. split inputs; transpose-split all weights to [N][K]
    split_kernel<<<(BL*DD)/1024, 256>>>(inputs, inh, inl);
    transpose_split_kernel<<<dim3(32, 32, 1), t328>>>(w_inputs, wiTh, wiTl, DD, DD);
    transpose_split_kernel<<<dim3(32, 32, 1), t328>>>(wq, wqTh, wqTl, DD, DD);
    transpose_split_kernel<<<dim3(32, 32, 1), t328>>>(wk, wkTh, wkTl, DD, DD);
    transpose_split_kernel<<<dim3(32, 32, 1), t328>>>(wv, wvTh, wvTl, DD, DD);
    transpose_split_kernel<<<dim3(32, 32, 1), t328>>>(wo, woTh, woTl, DD, DD);
    transpose_split_kernel<<<dim3(MLPD/32, DD/32, 1), t328>>>(mlp_w1, w1Th, w1Tl, DD, MLPD);
    transpose_split_kernel<<<dim3(DD/32, MLPD/32, 1), t328>>>(mlp_w2, w2Th, w2Tl, MLPD, DD);

    // 3. xi = inputs @ w_inputs (f32 out for FFT)
    gemm_bf16<<<dim3(8, 64, 1), 256, SMGE>>>(
        inh, inl, wiTh, wiTl, xi, nullptr, nullptr,
        BL, DD, DD, DD, DD, DD, 1.0f, nullptr, nullptr, 0);

    // 4. spectral causal conv (radix-4 packed FFT, fused gather/scatter)
    conv3_kernel<<<BB*DD/2, 512>>>(xi, Ffilt, stu);

    // 5. LN1 -> split x1
    ln_split_kernel<<<BL, 256>>>(stu, x1h, x1l, ln1_s, ln1_b);

    // 6. Q (scaled, split), K (split), V (f32 then transpose-split)
    gemm_bf16<<<dim3(8, 64, 1), 256, SMGE>>>(
        x1h, x1l, wqTh, wqTl, nullptr, qh, ql,
        BL, DD, DD, DD, DD, DD, 0.125f, nullptr, nullptr, 8);
    gemm_bf16<<<dim3(8, 64, 1), 256, SMGE>>>(
        x1h, x1l, wkTh, wkTl, nullptr, kh, kl,
        BL, DD, DD, DD, DD, DD, 1.0f, nullptr, nullptr, 8);
    gemm_bf16<<<dim3(8, 64, 1), 256, SMGE>>>(
        x1h, x1l, wvTh, wvTl, vbuf, nullptr, nullptr,
        BL, DD, DD, DD, DD, DD, 1.0f, nullptr, nullptr, 0);
    transpose_split_kernel<<<dim3(DD/32, LL/32, BB), t328>>>(vbuf, vTh, vTl, LL, DD);

    // 7. fused flash attention -> split att
    flash_kernel<<<dim3(LL/128, BB*HH), 256, SMFL>>>(
        qh, ql, kh, kl, vTh, vTl, ath, atl);

    // 8. x = att @ wo + stu (f32)
    gemm_bf16<<<dim3(8, 64, 1), 256, SMGE>>>(
        ath, atl, woTh, woTl, xres, nullptr, nullptr,
        BL, DD, DD, DD, DD, DD, 1.0f, nullptr, stu, 4);

    // 9. LN2 -> split y1
    ln_split_kernel<<<BL, 256>>>(xres, y1h, y1l, ln2_s, ln2_b);

    // 10. h = gelu(y1 @ w1 + b1), split out
    gemm_bf16<<<dim3(MLPD/128, 64, 1), 256, SMGE>>>(
        y1h, y1l, w1Th, w1Tl, nullptr, hh, hl,
        BL, MLPD, DD, DD, DD, MLPD, 1.0f, mlp_b1, nullptr, 11);

    // 11. out = h @ w2 + b2 + x (f32)
    gemm_bf16<<<dim3(8, 64, 1), 256, SMGE>>>(
        hh, hl, w2Th, w2Tl, out, nullptr, nullptr,
        BL, DD, MLPD, MLPD, MLPD, DD, 1.0f, mlp_b2, xres, 5);
}

// round 12
// speedup vs baseline: 3.8763x; 1.0300x over previous
#include <cuda_runtime.h>
#include <cuda_bf16.h>
#include <math.h>
#include <stdint.h>

#define BB 4
#define LL 2048
#define DD 1024
#define HH 16
#define HDIM 64
#define KK 24
#define MLPD 4096
#define BL (BB*LL)
#define NF4096 4096
#define QKV (3*DD)

typedef __nv_bfloat16 bf16;

// ---------------- scratch (device globals; allocation-free) ----------------
__device__ float  g_xi[BL*DD];
__device__ float2 g_Ffilt[(size_t)DD*NF4096];
__device__ float  g_stu[BL*DD];
__device__ float  g_xres[BL*DD];

__device__ bf16 g_inh[BL*DD],  g_inl[BL*DD];
__device__ bf16 g_x1h[BL*DD],  g_x1l[BL*DD];
__device__ bf16 g_qkvh[(size_t)BL*QKV], g_qkvl[(size_t)BL*QKV];  // packed Q|K|V
__device__ bf16 g_vTh[BL*DD],  g_vTl[BL*DD];       // [B,H*HD,L]
__device__ bf16 g_ath[BL*DD],  g_atl[BL*DD];
__device__ bf16 g_y1h[BL*DD],  g_y1l[BL*DD];
__device__ bf16 g_hh[(size_t)BL*MLPD], g_hl[(size_t)BL*MLPD];
// transposed-split weights [N][K]
__device__ bf16 g_wiTh[DD*DD],   g_wiTl[DD*DD];
__device__ bf16 g_wqkvTh[(size_t)QKV*DD], g_wqkvTl[(size_t)QKV*DD];
__device__ bf16 g_woTh[DD*DD],   g_woTl[DD*DD];
__device__ bf16 g_w1Th[(size_t)DD*MLPD], g_w1Tl[(size_t)DD*MLPD];
__device__ bf16 g_w2Th[(size_t)DD*MLPD], g_w2Tl[(size_t)DD*MLPD];

// ---------------- helpers ----------------
__device__ __forceinline__ float gelu_f(float x) {
    float x3 = x*x*x;
    return 0.5f*x*(1.0f + tanhf(0.7978845608028654f*(x + 0.044715f*x3)));
}
__device__ __forceinline__ void split2(float v, bf16 &h, bf16 &l) {
    h = __float2bfloat16_rn(v);
    l = __float2bfloat16_rn(v - __bfloat162float(h));
}
__device__ __forceinline__ uint32_t pack2(bf16 a, bf16 b) {
    return (uint32_t)__bfloat16_as_ushort(a) | ((uint32_t)__bfloat16_as_ushort(b) << 16);
}
__device__ __forceinline__ void cpa16(uint32_t s, const void* g) {
    asm volatile("cp.async.cg.shared.global [%0], [%1], 16;" :: "r"(s), "l"(g));
}
__device__ __forceinline__ void mma16816(float* c, const uint32_t* a, const uint32_t* b) {
    asm volatile("mma.sync.aligned.m16n8k16.row.col.f32.bf16.bf16.f32 "
                 "{%0,%1,%2,%3},{%4,%5,%6,%7},{%8,%9},{%0,%1,%2,%3};"
                 : "+f"(c[0]), "+f"(c[1]), "+f"(c[2]), "+f"(c[3])
                 : "r"(a[0]), "r"(a[1]), "r"(a[2]), "r"(a[3]),
                   "r"(b[0]), "r"(b[1]));
}
__device__ __forceinline__ void ldsm_x4(uint32_t* r, uint32_t saddr) {
    asm volatile("ldmatrix.sync.aligned.m8n8.x4.shared.b16 {%0,%1,%2,%3}, [%4];"
        : "=r"(r[0]), "=r"(r[1]), "=r"(r[2]), "=r"(r[3]) : "r"(saddr));
}
__device__ __forceinline__ float block_sum256(float v) {
    __shared__ float red[8];
    int lane = threadIdx.x & 31, w = threadIdx.x >> 5;
    #pragma unroll
    for (int o = 16; o; o >>= 1) v += __shfl_xor_sync(0xffffffffu, v, o);
    __syncthreads();
    if (lane == 0) red[w] = v;
    __syncthreads();
    if (threadIdx.x == 0) {
        float s = 0.f;
        #pragma unroll
        for (int i = 0; i < 8; i++) s += red[i];
        red[0] = s;
    }
    __syncthreads();
    return red[0];
}

// ---------------- split-bf16 tensor-core GEMM (dense layers) ----------------
// C[M,N] = alpha*(A@B^T) (+bias/gelu/resid/split). Tile 128x128, 2 CTAs/SM,
// 2-stage cp.async, ldmatrix fragments. mode: 1=bias, 2=gelu, 4=resid, 8=split-out
__global__ void __launch_bounds__(256, 2) gemm_bf16(
    const bf16* __restrict__ Ahi, const bf16* __restrict__ Alo,
    const bf16* __restrict__ Bhi, const bf16* __restrict__ Blo,
    float* __restrict__ C, bf16* __restrict__ Chi, bf16* __restrict__ Clo,
    int M, int N, int Kd, int lda, int ldb, int ldc,
    float alpha, const float* __restrict__ bias,
    const float* __restrict__ resid, int mode)
{
    constexpr int SP    = 40;
    constexpr int AH    = 128 * SP;
    constexpr int BHalf = 128 * SP;
    constexpr int STAGE = 2*AH + 2*BHalf;

    extern __shared__ __align__(16) char dsm[];
    uint32_t smem0 = (uint32_t)__cvta_generic_to_shared(dsm);

    int tid   = threadIdx.x;
    int mBase = blockIdx.y * 128, nBase = blockIdx.x * 128;

    const bf16* pAh = Ahi + (long long)mBase * lda;
    const bf16* pAl = Alo + (long long)mBase * lda;
    const bf16* pBh = Bhi + (long long)nBase * ldb;
    const bf16* pBl = Blo + (long long)nBase * ldb;

    int warp = tid >> 5, lane = tid & 31;
    int wm = warp & 3, wn = warp >> 2;
    int g  = lane >> 2, tig = lane & 3;

    int aRow = wm*32 + (lane & 15);
    int aCol = (lane & 16) ? 8 : 0;
    int bRow = wn*64 + ((lane >> 4) << 3) + (lane & 7);
    int bCol = (lane & 8) ? 8 : 0;

    float acc[2][8][4];
    #pragma unroll
    for (int i = 0; i < 2; i++)
        #pragma unroll
        for (int j = 0; j < 8; j++)
            #pragma unroll
            for (int c = 0; c < 4; c++) acc[i][j][c] = 0.f;

    auto load_stage = [&](int buf, int k0) {
        int so = buf * STAGE;
        #pragma unroll
        for (int i = 0; i < 2; i++) {
            int ci = tid + i*256;
            int row = ci >> 2, seg = ci & 3;
            long long go = (long long)row*lda + k0 + seg*8;
            uint32_t sa = smem0 + 2*(so + row*SP + seg*8);
            cpa16(sa,          pAh + go);
            cpa16(sa + 2*AH,   pAl + go);
        }
        #pragma unroll
        for (int i = 0; i < 2; i++) {
            int ci = tid + i*256;
            int row = ci >> 2, seg = ci & 3;
            long long go = (long long)row*ldb + k0 + seg*8;
            uint32_t sa = smem0 + 2*(so + 2*AH + row*SP + seg*8);
            cpa16(sa,              pBh + go);
            cpa16(sa + 2*BHalf,    pBl + go);
        }
        asm volatile("cp.async.commit_group;");
    };

    int nk = Kd >> 5;
    load_stage(0, 0);

    for (int ks = 0; ks < nk; ks++) {
        asm volatile("cp.async.wait_group 0;");
        __syncthreads();
        if (ks + 1 < nk) load_stage((ks+1)&1, (ks+1) << 5);
        int so = (ks & 1) * STAGE;

        #pragma unroll
        for (int kh = 0; kh < 2; kh++) {
            int kb = kh*16;
            uint32_t ah[2][4], al[2][4];
            #pragma unroll
            for (int mi = 0; mi < 2; mi++) {
                uint32_t ad = smem0 + 2*(so + (aRow + mi*16)*SP + kb + aCol);
                ldsm_x4(ah[mi], ad);
                ldsm_x4(al[mi], ad + 2*AH);
            }
            #pragma unroll
            for (int nip = 0; nip < 4; nip++) {
                uint32_t bd = smem0 + 2*(so + 2*AH + (bRow + nip*16)*SP + kb + bCol);
                uint32_t bh4[4], bl4[4];
                ldsm_x4(bh4, bd);
                ldsm_x4(bl4, bd + 2*BHalf);
                #pragma unroll
                for (int q = 0; q < 2; q++) {
                    int ni = nip*2 + q;
                    #pragma unroll
                    for (int mi = 0; mi < 2; mi++) {
                        mma16816(acc[mi][ni], ah[mi], bh4 + 2*q);
                        mma16816(acc[mi][ni], al[mi], bh4 + 2*q);
                        mma16816(acc[mi][ni], ah[mi], bl4 + 2*q);
                    }
                }
            }
        }
    }

    bool hb = mode & 1, hg = mode & 2, hr = mode & 4, hs = mode & 8;
    #pragma unroll
    for (int mi = 0; mi < 2; mi++) {
        int m0 = mBase + wm*32 + mi*16 + g;
        #pragma unroll
        for (int ni = 0; ni < 8; ni++) {
            int n = nBase + wn*64 + ni*8 + 2*tig;
            #pragma unroll
            for (int hrow = 0; hrow < 2; hrow++) {
                int m = m0 + hrow*8;
                float v0 = acc[mi][ni][hrow*2+0] * alpha;
                float v1 = acc[mi][ni][hrow*2+1] * alpha;
                if (hb) { v0 += bias[n]; v1 += bias[n+1]; }
                if (hg) { v0 = gelu_f(v0); v1 = gelu_f(v1); }
                long long o = (long long)m*ldc + n;
                if (hr) { v0 += resid[o]; v1 += resid[o+1]; }
                if (hs) {
                    bf16 h0, l0, h1, l1;
                    split2(v0, h0, l0); split2(v1, h1, l1);
                    *(uint32_t*)(Chi + o) = pack2(h0, h1);
                    *(uint32_t*)(Clo + o) = pack2(l0, l1);
                } else {
                    C[o] = v0; C[o+1] = v1;
                }
            }
        }
    }
}

// ---------------- flash attention (64-row KV tiles, 2 CTAs/SM) ----------------
// Q,K from packed qkv [B,L,3072] split; V^T [B,H*HD,L] split; out att [B,L,D] split.
__global__ void __launch_bounds__(256, 2) flash_kernel(
    const bf16* __restrict__ QKVh, const bf16* __restrict__ QKVl,
    const bf16* __restrict__ Vth,  const bf16* __restrict__ Vtl,
    bf16* __restrict__ Oh, bf16* __restrict__ Ol)
{
    constexpr int KSP = 72, VSP = 72;
    constexpr int KTH = 64*KSP;
    constexpr int VTH = 64*VSP;
    constexpr int STG = 2*KTH + 2*VTH;   // 18432 halves / stage

    extern __shared__ __align__(16) bf16 sm[];
    uint32_t smem0 = (uint32_t)__cvta_generic_to_shared(sm);

    int tid = threadIdx.x, warp = tid >> 5, lane = tid & 31;
    int g = lane >> 2, tig = lane & 3;
    int qt = blockIdx.x, bh = blockIdx.y;
    int b = bh >> 4, h = bh & 15;
    long long baseQ = (long long)b*LL*QKV + (long long)(qt*128)*QKV + h*64;
    long long baseK = (long long)b*LL*QKV + DD + h*64;
    long long baseV = (long long)b*LL*DD + (long long)(h*64)*LL;
    long long baseO = (long long)b*LL*DD + (long long)(qt*128)*DD + h*64;

    int fRow = ((lane >> 4) << 3) + (lane & 7);
    int fCol = (lane & 8) ? 8 : 0;

    uint32_t qa_h[4][4], qa_l[4][4];
    {
        long long r0 = baseQ + (long long)(warp*16 + g)*QKV;
        long long r8 = r0 + 8*QKV;
        #pragma unroll
        for (int kf = 0; kf < 4; kf++) {
            int c = kf*16 + 2*tig;
            qa_h[kf][0] = *(const uint32_t*)(QKVh + r0 + c);
            qa_h[kf][1] = *(const uint32_t*)(QKVh + r8 + c);
            qa_h[kf][2] = *(const uint32_t*)(QKVh + r0 + c + 8);
            qa_h[kf][3] = *(const uint32_t*)(QKVh + r8 + c + 8);
            qa_l[kf][0] = *(const uint32_t*)(QKVl + r0 + c);
            qa_l[kf][1] = *(const uint32_t*)(QKVl + r8 + c);
            qa_l[kf][2] = *(const uint32_t*)(QKVl + r0 + c + 8);
            qa_l[kf][3] = *(const uint32_t*)(QKVl + r8 + c + 8);
        }
    }

    auto load_tiles = [&](int buf, int kt) {
        int so = buf * STG;
        #pragma unroll
        for (int i = 0; i < 2; i++) {            // K tile: 64 rows x 64 halves
            int ci = tid + i*256;
            int row = ci >> 3, ch = ci & 7;
            long long go = baseK + (long long)(kt*64 + row)*QKV + ch*8;
            uint32_t sa = smem0 + 2*(so + row*KSP + ch*8);
            cpa16(sa,           QKVh + go);
            cpa16(sa + 2*KTH,   QKVl + go);
        }
        #pragma unroll
        for (int i = 0; i < 2; i++) {            // V^T tile: 64 d x 64 L halves
            int ci = tid + i*256;
            int row = ci >> 3, ch = ci & 7;
            long long go = baseV + (long long)row*LL + kt*64 + ch*8;
            uint32_t sa = smem0 + 2*(so + 2*KTH + row*VSP + ch*8);
            cpa16(sa,           Vth + go);
            cpa16(sa + 2*VTH,   Vtl + go);
        }
        asm volatile("cp.async.commit_group;");
    };

    float m_r[2] = {-1e30f, -1e30f};
    float l_r[2] = {0.f, 0.f};
    float o[8][4];
    #pragma unroll
    for (int n = 0; n < 8; n++)
        #pragma unroll
        for (int c = 0; c < 4; c++) o[n][c] = 0.f;

    load_tiles(0, 0);

    for (int kt = 0; kt < 32; kt++) {
        asm volatile("cp.async.wait_group 0;");
        __syncthreads();
        if (kt + 1 < 32) load_tiles((kt+1)&1, kt+1);
        int so = (kt & 1) * STG;

        float s[8][4];
        #pragma unroll
        for (int n = 0; n < 8; n++)
            #pragma unroll
            for (int c = 0; c < 4; c++) s[n][c] = 0.f;

        #pragma unroll
        for (int kf = 0; kf < 4; kf++) {
            #pragma unroll
            for (int np = 0; np < 4; np++) {
                uint32_t kd = smem0 + 2*(so + (np*16 + fRow)*KSP + kf*16 + fCol);
                uint32_t kh4[4], kl4[4];
                ldsm_x4(kh4, kd);
                ldsm_x4(kl4, kd + 2*KTH);
                #pragma unroll
                for (int q = 0; q < 2; q++) {
                    int n = np*2 + q;
                    mma16816(s[n], qa_h[kf], kh4 + 2*q);
                    mma16816(s[n], qa_l[kf], kh4 + 2*q);
                    mma16816(s[n], qa_h[kf], kl4 + 2*q);
                }
            }
        }

        float mx0 = -1e30f, mx1 = -1e30f;
        #pragma unroll
        for (int n = 0; n < 8; n++) {
            mx0 = fmaxf(mx0, fmaxf(s[n][0], s[n][1]));
            mx1 = fmaxf(mx1, fmaxf(s[n][2], s[n][3]));
        }
        #pragma unroll
        for (int off = 1; off < 4; off <<= 1) {
            mx0 = fmaxf(mx0, __shfl_xor_sync(0xffffffffu, mx0, off));
            mx1 = fmaxf(mx1, __shfl_xor_sync(0xffffffffu, mx1, off));
        }
        float mn0 = fmaxf(m_r[0], mx0), mn1 = fmaxf(m_r[1], mx1);
        float sf0 = __expf(m_r[0] - mn0), sf1 = __expf(m_r[1] - mn1);
        m_r[0] = mn0; m_r[1] = mn1;
        float sum0 = 0.f, sum1 = 0.f;
        #pragma unroll
        for (int n = 0; n < 8; n++) {
            s[n][0] = __expf(s[n][0] - mn0); sum0 += s[n][0];
            s[n][1] = __expf(s[n][1] - mn0); sum0 += s[n][1];
            s[n][2] = __expf(s[n][2] - mn1); sum1 += s[n][2];
            s[n][3] = __expf(s[n][3] - mn1); sum1 += s[n][3];
        }
        #pragma unroll
        for (int off = 1; off < 4; off <<= 1) {
            sum0 += __shfl_xor_sync(0xffffffffu, sum0, off);
            sum1 += __shfl_xor_sync(0xffffffffu, sum1, off);
        }
        l_r[0] = l_r[0]*sf0 + sum0;
        l_r[1] = l_r[1]*sf1 + sum1;
        #pragma unroll
        for (int n = 0; n < 8; n++) {
            o[n][0] *= sf0; o[n][1] *= sf0;
            o[n][2] *= sf1; o[n][3] *= sf1;
        }

        #pragma unroll
        for (int kf2 = 0; kf2 < 4; kf2++) {
            uint32_t pa_h[4], pa_l[4];
            #pragma unroll
            for (int q4 = 0; q4 < 2; q4++) {
                int t = 2*kf2 + q4;
                #pragma unroll
                for (int rr = 0; rr < 2; rr++) {
                    float p0 = s[t][rr*2+0], p1 = s[t][rr*2+1];
                    bf16 h0, l0, h1, l1;
                    split2(p0, h0, l0); split2(p1, h1, l1);
                    pa_h[q4*2+rr] = pack2(h0, h1);
                    pa_l[q4*2+rr] = pack2(l0, l1);
                }
            }
            #pragma unroll
            for (int np2 = 0; np2 < 4; np2++) {
                uint32_t vd = smem0 + 2*(so + 2*KTH + (np2*16 + fRow)*VSP + kf2*16 + fCol);
                uint32_t vh4[4], vl4[4];
                ldsm_x4(vh4, vd);
                ldsm_x4(vl4, vd + 2*VTH);
                #pragma unroll
                for (int q = 0; q < 2; q++) {
                    int n = np2*2 + q;
                    mma16816(o[n], pa_h, vh4 + 2*q);
                    mma16816(o[n], pa_l, vh4 + 2*q);
                    mma16816(o[n], pa_h, vl4 + 2*q);
                }
            }
        }
    }

    float il0 = 1.f / l_r[0], il1 = 1.f / l_r[1];
    long long r0 = baseO + (long long)(warp*16 + g)*DD;
    long long r8 = r0 + 8*DD;
    #pragma unroll
    for (int n = 0; n < 8; n++) {
        int c = n*8 + 2*tig;
        float v0 = o[n][0]*il0, v1 = o[n][1]*il0;
        float v2 = o[n][2]*il1, v3 = o[n][3]*il1;
        bf16 h0,l0,h1,l1;
        split2(v0,h0,l0); split2(v1,h1,l1);
        *(uint32_t*)(Oh + r0 + c) = pack2(h0,h1);
        *(uint32_t*)(Ol + r0 + c) = pack2(l0,l1);
        split2(v2,h0,l0); split2(v3,h1,l1);
        *(uint32_t*)(Oh + r8 + c) = pack2(h0,h1);
        *(uint32_t*)(Ol + r8 + c) = pack2(l0,l1);
    }
}

// ---------------- transpose + split weights (optional scale) ----------------
__global__ void transpose_split_kernel(const float* __restrict__ in,
                                       bf16* __restrict__ oh, bf16* __restrict__ ol,
                                       int rows, int cols, float alpha)
{
    __shared__ float t[32][33];
    long long bo = (long long)blockIdx.z * rows * cols;
    int c0 = blockIdx.x * 32, r0 = blockIdx.y * 32;
    int tx = threadIdx.x, ty = threadIdx.y;
    #pragma unroll
    for (int i = 0; i < 32; i += 8)
        t[ty+i][tx] = in[bo + (long long)(r0+ty+i)*cols + (c0+tx)];
    __syncthreads();
    #pragma unroll
    for (int i = 0; i < 32; i += 8) {
        float v = t[tx][ty+i] * alpha;
        bf16 h, l; split2(v, h, l);
        long long o = bo + (long long)(c0+ty+i)*rows + (r0+tx);
        oh[o] = h; ol[o] = l;
    }
}

// ---------------- bf16 pair transpose: V slice of packed qkv -> V^T ----------------
// in: [L, D] at row stride QKV (hi/lo), per batch stride L*QKV; out [D, L] per batch.
__global__ void transpose_pair_kernel(const bf16* __restrict__ inh, const bf16* __restrict__ inl,
                                      bf16* __restrict__ oh, bf16* __restrict__ ol)
{
    __shared__ unsigned short th[32][33], tl[32][33];
    long long ibo = (long long)blockIdx.z * LL * QKV;
    long long obo = (long long)blockIdx.z * DD * LL;
    int c0 = blockIdx.x * 32, r0 = blockIdx.y * 32;
    int tx = threadIdx.x, ty = threadIdx.y;
    #pragma unroll
    for (int i = 0; i < 32; i += 8) {
        long long p = ibo + (long long)(r0+ty+i)*QKV + c0 + tx;
        th[ty+i][tx] = __bfloat16_as_ushort(inh[p]);
        tl[ty+i][tx] = __bfloat16_as_ushort(inl[p]);
    }
    __syncthreads();
    #pragma unroll
    for (int i = 0; i < 32; i += 8) {
        long long o = obo + (long long)(c0+ty+i)*LL + r0 + tx;
        oh[o] = __ushort_as_bfloat16(th[tx][ty+i]);
        ol[o] = __ushort_as_bfloat16(tl[tx][ty+i]);
    }
}

// ---------------- elementwise split ----------------
__global__ void split_kernel(const float* __restrict__ x,
                             bf16* __restrict__ oh, bf16* __restrict__ ol)
{
    long long i = ((long long)blockIdx.x * 256 + threadIdx.x) * 4;
    float4 v = *(const float4*)(x + i);
    bf16 h, l;
    split2(v.x, h, l); oh[i+0] = h; ol[i+0] = l;
    split2(v.y, h, l); oh[i+1] = h; ol[i+1] = l;
    split2(v.z, h, l); oh[i+2] = h; ol[i+2] = l;
    split2(v.w, h, l); oh[i+3] = h; ol[i+3] = l;
}

// ---------------- FFT (radix-4 DIT, n=4096, 512 threads) ----------------
__device__ __forceinline__ int rev4(int i) {
    int r = __brev(i) >> 20;
    return ((r & 0x555) << 1) | ((r >> 1) & 0x555);
}
__device__ __forceinline__ float2 cmulf(float2 a, float2 b) {
    return make_float2(a.x*b.x - a.y*b.y, a.x*b.y + a.y*b.x);
}
__device__ __forceinline__ void tw_init(float2* tw, int tid) {
    for (int m = tid; m < 1024; m += 512) {
        float sv, cv;
        sincosf(-6.283185307179586f * (float)m / 4096.0f, &sv, &cv);
        tw[m] = make_float2(cv, sv);
    }
}

__device__ void do_fft4(float2* s, const float2* tw, int tid) {
    #pragma unroll 1
    for (int st = 0; st < 6; st++) {
        int Q  = 1 << (2*st);
        int sh = 10 - 2*st;
        #pragma unroll 1
        for (int idx = tid; idx < 1024; idx += 512) {
            int j    = idx & (Q - 1);
            int blk  = idx >> (2*st);
            int base = blk*(Q << 2) + j;
            float2 x0 = s[base];
            float2 x1 = s[base + Q];
            float2 x2 = s[base + 2*Q];
            float2 x3 = s[base + 3*Q];
            float2 w1 = tw[j << sh];
            float2 w2 = cmulf(w1, w1);
            float2 w3 = cmulf(w2, w1);
            float2 y1 = cmulf(w1, x1);
            float2 y2 = cmulf(w2, x2);
            float2 y3 = cmulf(w3, x3);
            float2 u0 = make_float2(x0.x + y2.x, x0.y + y2.y);
            float2 u1 = make_float2(x0.x - y2.x, x0.y - y2.y);
            float2 u2 = make_float2(y1.x + y3.x, y1.y + y3.y);
            float2 u3 = make_float2(y1.x - y3.x, y1.y - y3.y);
            s[base]       = make_float2(u0.x + u2.x, u0.y + u2.y);
            s[base + Q]   = make_float2(u1.x + u3.y, u1.y - u3.x);
            s[base + 2*Q] = make_float2(u0.x - u2.x, u0.y - u2.y);
            s[base + 3*Q] = make_float2(u1.x - u3.y, u1.y + u3.x);
        }
        __syncthreads();
    }
}

__global__ void __launch_bounds__(512) filters_kernel(
    const float* __restrict__ eig_vals, const float* __restrict__ eig_vecs,
    const float* __restrict__ w_filters, float2* __restrict__ Ffilt)
{
    __shared__ float2 s[NF4096];
    __shared__ float2 tw[1024];
    __shared__ float  wk[KK];
    int d = blockIdx.x, tid = threadIdx.x;
    if (tid < KK) wk[tid] = powf(eig_vals[tid], 0.25f) * w_filters[tid*DD + d];
    tw_init(tw, tid);
    for (int i = tid; i < NF4096; i += 512) s[i] = make_float2(0.f, 0.f);
    __syncthreads();
    for (int t = tid; t < LL; t += 512) {
        float f = 0.f;
        #pragma unroll
        for (int k = 0; k < KK; k++) f += eig_vecs[t*KK + k] * wk[k];
        s[rev4(t)] = make_float2(f, 0.f);
    }
    __syncthreads();
    do_fft4(s, tw, tid);
    for (int i = tid; i < NF4096; i += 512)
        Ffilt[(long long)d*NF4096 + i] = s[i];
}

// 2-for-1 packed conv with fused gather/scatter
__global__ void __launch_bounds__(512) conv3_kernel(
    const float* __restrict__ xi, const float2* __restrict__ Ffilt,
    float* __restrict__ stu)
{
    __shared__ float2 s[NF4096];
    __shared__ float2 tw[1024];
    int z = blockIdx.x, tid = threadIdx.x;
    int b = z >> 9, dp = z & 511;
    int d0 = 2*dp;
    const float* xib = xi + (long long)b*LL*DD + d0;
    float* stb = stu + (long long)b*LL*DD + d0;
    tw_init(tw, tid);
    for (int i = tid; i < NF4096; i += 512) s[i] = make_float2(0.f, 0.f);
    __syncthreads();
    for (int t = tid; t < LL; t += 512)
        s[rev4(t)] = *(const float2*)(xib + (long long)t*DD);
    __syncthreads();
    do_fft4(s, tw, tid);

    const float2* F0 = Ffilt + (long long)d0 * NF4096;
    const float2* F1 = F0 + NF4096;
    for (int i = tid; i < 2048; i += 512) {
        if (i == 0) {
            #pragma unroll
            for (int q = 0; q < 2; q++) {
                int idx = q * 2048;
                float2 Z = s[idx];
                float X1 = Z.x, X2 = Z.y;
                float2 f0 = F0[idx], f1 = F1[idx];
                float2 Y1 = make_float2(X1*f0.x, X1*f0.y);
                float2 Y2 = make_float2(X2*f1.x, X2*f1.y);
                s[idx] = make_float2(Y1.x - Y2.y, -(Y1.y + Y2.x));
            }
        } else {
            float2 Za = s[i], Zb = s[NF4096 - i];
            float2 X1 = make_float2(0.5f*(Za.x + Zb.x), 0.5f*(Za.y - Zb.y));
            float2 Dd = make_float2(Za.x - Zb.x, Za.y + Zb.y);
            float2 X2 = make_float2(0.5f*Dd.y, -0.5f*Dd.x);
            float2 f0 = F0[i], f1 = F1[i];
            float2 Y1 = make_float2(X1.x*f0.x - X1.y*f0.y, X1.x*f0.y + X1.y*f0.x);
            float2 Y2 = make_float2(X2.x*f1.x - X2.y*f1.y, X2.x*f1.y + X2.y*f1.x);
            s[i]          = make_float2(Y1.x - Y2.y, -(Y1.y + Y2.x));
            s[NF4096 - i] = make_float2(Y1.x + Y2.y, Y1.y - Y2.x);
        }
    }
    __syncthreads();
    float2 r[8];
    #pragma unroll
    for (int k = 0; k < 8; k++) r[k] = s[rev4(tid + k*512)];
    __syncthreads();
    #pragma unroll
    for (int k = 0; k < 8; k++) s[tid + k*512] = r[k];
    __syncthreads();
    do_fft4(s, tw, tid);
    const float inv = 1.0f / 4096.0f;
    for (int l = tid; l < LL; l += 512) {
        float2 w = make_float2(s[l].x * inv, -s[l].y * inv);
        *(float2*)(stb + (long long)l*DD) = w;
    }
}

// ---------------- LayerNorm with split-bf16 output ----------------
__global__ void __launch_bounds__(256) ln_split_kernel(
    const float* __restrict__ x, bf16* __restrict__ yh, bf16* __restrict__ yl,
    const float* __restrict__ sc, const float* __restrict__ bi)
{
    long long base = (long long)blockIdx.x * DD;
    int tid = threadIdx.x;
    float4 v = *(const float4*)(x + base + tid*4);
    float mean = block_sum256(v.x + v.y + v.z + v.w) * (1.0f/DD);
    float dx = v.x - mean, dy = v.y - mean, dz = v.z - mean, dw = v.w - mean;
    float var = block_sum256(dx*dx + dy*dy + dz*dz + dw*dw) * (1.0f/DD);
    float rstd = rsqrtf(var + 1e-6f);
    float4 s4 = *(const float4*)(sc + tid*4);
    float4 b4 = *(const float4*)(bi + tid*4);
    float o0 = dx*rstd*s4.x + b4.x;
    float o1 = dy*rstd*s4.y + b4.y;
    float o2 = dz*rstd*s4.z + b4.z;
    float o3 = dw*rstd*s4.w + b4.w;
    long long i = base + tid*4;
    bf16 h, l;
    split2(o0, h, l); yh[i+0] = h; yl[i+0] = l;
    split2(o1, h, l); yh[i+1] = h; yl[i+1] = l;
    split2(o2, h, l); yh[i+2] = h; yl[i+2] = l;
    split2(o3, h, l); yh[i+3] = h; yl[i+3] = l;
}

// ---------------- launch ----------------
static void* symv(const void* s) { void* p = nullptr; cudaGetSymbolAddress(&p, s); return p; }

extern "C" void kernel_launch(void* const* d_in, const int* in_sizes, int n_in,
                              void* d_out, int out_size)
{
    const float* inputs    = (const float*)d_in[0];
    const float* eig_vals  = (const float*)d_in[1];
    const float* eig_vecs  = (const float*)d_in[2];
    const float* w_filters = (const float*)d_in[3];
    const float* w_inputs  = (const float*)d_in[4];
    const float* ln1_s     = (const float*)d_in[5];
    const float* ln1_b     = (const float*)d_in[6];
    const float* wq        = (const float*)d_in[7];
    const float* wk        = (const float*)d_in[8];
    const float* wv        = (const float*)d_in[9];
    const float* wo        = (const float*)d_in[10];
    const float* ln2_s     = (const float*)d_in[11];
    const float* ln2_b     = (const float*)d_in[12];
    const float* mlp_w1    = (const float*)d_in[13];
    const float* mlp_b1    = (const float*)d_in[14];
    const float* mlp_w2    = (const float*)d_in[15];
    const float* mlp_b2    = (const float*)d_in[16];
    float* out = (float*)d_out;

    float*  xi    = (float*)symv(g_xi);
    float2* Ffilt = (float2*)symv(g_Ffilt);
    float*  stu   = (float*)symv(g_stu);
    float*  xres  = (float*)symv(g_xres);

    bf16 *inh=(bf16*)symv(g_inh),    *inl=(bf16*)symv(g_inl);
    bf16 *x1h=(bf16*)symv(g_x1h),    *x1l=(bf16*)symv(g_x1l);
    bf16 *qkvh=(bf16*)symv(g_qkvh),  *qkvl=(bf16*)symv(g_qkvl);
    bf16 *vTh=(bf16*)symv(g_vTh),    *vTl=(bf16*)symv(g_vTl);
    bf16 *ath=(bf16*)symv(g_ath),    *atl=(bf16*)symv(g_atl);
    bf16 *y1h=(bf16*)symv(g_y1h),    *y1l=(bf16*)symv(g_y1l);
    bf16 *hh =(bf16*)symv(g_hh),     *hl =(bf16*)symv(g_hl);
    bf16 *wiTh=(bf16*)symv(g_wiTh),  *wiTl=(bf16*)symv(g_wiTl);
    bf16 *wqkvTh=(bf16*)symv(g_wqkvTh), *wqkvTl=(bf16*)symv(g_wqkvTl);
    bf16 *woTh=(bf16*)symv(g_woTh),  *woTl=(bf16*)symv(g_woTl);
    bf16 *w1Th=(bf16*)symv(g_w1Th),  *w1Tl=(bf16*)symv(g_w1Tl);
    bf16 *w2Th=(bf16*)symv(g_w2Th),  *w2Tl=(bf16*)symv(g_w2Tl);

    const int SMGE = 81920;
    const int SMFL = 73728;
    cudaFuncSetAttribute(gemm_bf16,    cudaFuncAttributeMaxDynamicSharedMemorySize, SMGE);
    cudaFuncSetAttribute(flash_kernel, cudaFuncAttributeMaxDynamicSharedMemorySize, SMFL);

    dim3 t328(32, 8);

    // 1. filter spectrum per channel d
    filters_kernel<<<DD, 512>>>(eig_vals, eig_vecs, w_filters, Ffilt);

    // 2. split inputs; transpose-split all weights to [N][K] (wq pre-scaled by 1/8)
    split_kernel<<<(BL*DD)/1024, 256>>>(inputs, inh, inl);
    transpose_split_kernel<<<dim3(32, 32, 1), t328>>>(w_inputs, wiTh, wiTl, DD, DD, 1.0f);
    transpose_split_kernel<<<dim3(32, 32, 1), t328>>>(wq, wqkvTh,          wqkvTl,          DD, DD, 0.125f);
    transpose_split_kernel<<<dim3(32, 32, 1), t328>>>(wk, wqkvTh + DD*DD,  wqkvTl + DD*DD,  DD, DD, 1.0f);
    transpose_split_kernel<<<dim3(32, 32, 1), t328>>>(wv, wqkvTh + 2*DD*DD,wqkvTl + 2*DD*DD,DD, DD, 1.0f);
    transpose_split_kernel<<<dim3(32, 32, 1), t328>>>(wo, woTh, woTl, DD, DD, 1.0f);
    transpose_split_kernel<<<dim3(MLPD/32, DD/32, 1), t328>>>(mlp_w1, w1Th, w1Tl, DD, MLPD, 1.0f);
    transpose_split_kernel<<<dim3(DD/32, MLPD/32, 1), t328>>>(mlp_w2, w2Th, w2Tl, MLPD, DD, 1.0f);

    // 3. xi = inputs @ w_inputs (f32 out for FFT)
    gemm_bf16<<<dim3(8, 64, 1), 256, SMGE>>>(
        inh, inl, wiTh, wiTl, xi, nullptr, nullptr,
        BL, DD, DD, DD, DD, DD, 1.0f, nullptr, nullptr, 0);

    // 4. spectral causal conv (radix-4 packed FFT, fused gather/scatter)
    conv3_kernel<<<BB*DD/2, 512>>>(xi, Ffilt, stu);

    // 5. LN1 -> split x1
    ln_split_kernel<<<BL, 256>>>(stu, x1h, x1l, ln1_s, ln1_b);

    // 6. fused QKV gemm (N=3072), split out to packed qkv
    gemm_bf16<<<dim3(QKV/128, BL/128, 1), 256, SMGE>>>(
        x1h, x1l, wqkvTh, wqkvTl, nullptr, qkvh, qkvl,
        BL, QKV, DD, DD, DD, QKV, 1.0f, nullptr, nullptr, 8);

    // 7. V^T pair transpose from packed qkv (columns 2048..3071)
    transpose_pair_kernel<<<dim3(DD/32, LL/32, BB), t328>>>(
        qkvh + 2*DD, qkvl + 2*DD, vTh, vTl);

    // 8. fused flash attention -> split att
    flash_kernel<<<dim3(LL/128, BB*HH), 256, SMFL>>>(
        qkvh, qkvl, vTh, vTl, ath, atl);

    // 9. x = att @ wo + stu (f32)
    gemm_bf16<<<dim3(8, 64, 1), 256, SMGE>>>(
        ath, atl, woTh, woTl, xres, nullptr, nullptr,
        BL, DD, DD, DD, DD, DD, 1.0f, nullptr, stu, 4);

    // 10. LN2 -> split y1
    ln_split_kernel<<<BL, 256>>>(xres, y1h, y1l, ln2_s, ln2_b);

    // 11. h = gelu(y1 @ w1 + b1), split out
    gemm_bf16<<<dim3(MLPD/128, 64, 1), 256, SMGE>>>(
        y1h, y1l, w1Th, w1Tl, nullptr, hh, hl,
        BL, MLPD, DD, DD, DD, MLPD, 1.0f, mlp_b1, nullptr, 11);

    // 12. out = h @ w2 + b2 + x (f32)
    gemm_bf16<<<dim3(8, 64, 1), 256, SMGE>>>(
        hh, hl, w2Th, w2Tl, out, nullptr, nullptr,
        BL, DD, MLPD, MLPD, MLPD, DD, 1.0f, mlp_b2, xres, 5);
}

// round 13
// speedup vs baseline: 5.0051x; 1.2912x over previous
#include <cuda_runtime.h>
#include <cuda_fp16.h>
#include <math.h>
#include <stdint.h>

#define BB 4
#define LL 2048
#define DD 1024
#define HH 16
#define HDIM 64
#define KK 24
#define MLPD 4096
#define BL (BB*LL)
#define NF4096 4096
#define QKV (3*DD)

typedef __half f16;

// ---------------- scratch (device globals; allocation-free) ----------------
__device__ float  g_xi[BL*DD];
__device__ float2 g_Ffilt[(size_t)DD*NF4096];
__device__ float  g_stu[BL*DD];
__device__ float  g_xres[BL*DD];

__device__ f16 g_inh[BL*DD],  g_inl[BL*DD];
__device__ f16 g_x1h[BL*DD],  g_x1l[BL*DD];
__device__ f16 g_qkvh[(size_t)BL*QKV], g_qkvl[(size_t)BL*QKV];  // packed Q|K|V
__device__ f16 g_vTh[BL*DD];                         // [B,H*HD,L] (hi only)
__device__ f16 g_ath[BL*DD],  g_atl[BL*DD];
__device__ f16 g_y1h[BL*DD],  g_y1l[BL*DD];
__device__ f16 g_hh[(size_t)BL*MLPD], g_hl[(size_t)BL*MLPD];
// transposed-cast weights [N][K] (hi only — B-side lo term dropped)
__device__ f16 g_wiT[DD*DD];
__device__ f16 g_wqkvT[(size_t)QKV*DD];
__device__ f16 g_woT[DD*DD];
__device__ f16 g_w1T[(size_t)DD*MLPD];
__device__ f16 g_w2T[(size_t)DD*MLPD];

// ---------------- helpers ----------------
__device__ __forceinline__ float gelu_f(float x) {
    float x3 = x*x*x;
    return 0.5f*x*(1.0f + tanhf(0.7978845608028654f*(x + 0.044715f*x3)));
}
__device__ __forceinline__ void split2(float v, f16 &h, f16 &l) {
    h = __float2half_rn(v);
    l = __float2half_rn(v - __half2float(h));
}
__device__ __forceinline__ uint32_t pack2(f16 a, f16 b) {
    return (uint32_t)__half_as_ushort(a) | ((uint32_t)__half_as_ushort(b) << 16);
}
__device__ __forceinline__ void cpa16(uint32_t s, const void* g) {
    asm volatile("cp.async.cg.shared.global [%0], [%1], 16;" :: "r"(s), "l"(g));
}
__device__ __forceinline__ void mma16816(float* c, const uint32_t* a, const uint32_t* b) {
    asm volatile("mma.sync.aligned.m16n8k16.row.col.f32.f16.f16.f32 "
                 "{%0,%1,%2,%3},{%4,%5,%6,%7},{%8,%9},{%0,%1,%2,%3};"
                 : "+f"(c[0]), "+f"(c[1]), "+f"(c[2]), "+f"(c[3])
                 : "r"(a[0]), "r"(a[1]), "r"(a[2]), "r"(a[3]),
                   "r"(b[0]), "r"(b[1]));
}
__device__ __forceinline__ void ldsm_x4(uint32_t* r, uint32_t saddr) {
    asm volatile("ldmatrix.sync.aligned.m8n8.x4.shared.b16 {%0,%1,%2,%3}, [%4];"
        : "=r"(r[0]), "=r"(r[1]), "=r"(r[2]), "=r"(r[3]) : "r"(saddr));
}
__device__ __forceinline__ float block_sum256(float v) {
    __shared__ float red[8];
    int lane = threadIdx.x & 31, w = threadIdx.x >> 5;
    #pragma unroll
    for (int o = 16; o; o >>= 1) v += __shfl_xor_sync(0xffffffffu, v, o);
    __syncthreads();
    if (lane == 0) red[w] = v;
    __syncthreads();
    if (threadIdx.x == 0) {
        float s = 0.f;
        #pragma unroll
        for (int i = 0; i < 8; i++) s += red[i];
        red[0] = s;
    }
    __syncthreads();
    return red[0];
}

// ---------------- split-fp16 tensor-core GEMM (2-product: Ah·Bh + Al·Bh) ----------------
// C[M,N] = alpha*(A@B^T) (+bias/gelu/resid/split). A split hi/lo [M,K]; B hi-only [N,K].
// Tile 128x128, 2 CTAs/SM, 2-stage cp.async, ldmatrix. mode: 1=bias,2=gelu,4=resid,8=split-out
__global__ void __launch_bounds__(256, 2) gemm_fp16(
    const f16* __restrict__ Ahi, const f16* __restrict__ Alo,
    const f16* __restrict__ Bh,
    float* __restrict__ C, f16* __restrict__ Chi, f16* __restrict__ Clo,
    int M, int N, int Kd, int lda, int ldb, int ldc,
    float alpha, const float* __restrict__ bias,
    const float* __restrict__ resid, int mode)
{
    constexpr int SP    = 40;
    constexpr int AH    = 128 * SP;
    constexpr int BH_   = 128 * SP;
    constexpr int STAGE = 2*AH + BH_;    // 15360 halves = 30720 B

    extern __shared__ __align__(16) char dsm[];
    uint32_t smem0 = (uint32_t)__cvta_generic_to_shared(dsm);

    int tid   = threadIdx.x;
    int mBase = blockIdx.y * 128, nBase = blockIdx.x * 128;

    const f16* pAh = Ahi + (long long)mBase * lda;
    const f16* pAl = Alo + (long long)mBase * lda;
    const f16* pB  = Bh  + (long long)nBase * ldb;

    int warp = tid >> 5, lane = tid & 31;
    int wm = warp & 3, wn = warp >> 2;
    int g  = lane >> 2, tig = lane & 3;

    int aRow = wm*32 + (lane & 15);
    int aCol = (lane & 16) ? 8 : 0;
    int bRow = wn*64 + ((lane >> 4) << 3) + (lane & 7);
    int bCol = (lane & 8) ? 8 : 0;

    float acc[2][8][4];
    #pragma unroll
    for (int i = 0; i < 2; i++)
        #pragma unroll
        for (int j = 0; j < 8; j++)
            #pragma unroll
            for (int c = 0; c < 4; c++) acc[i][j][c] = 0.f;

    auto load_stage = [&](int buf, int k0) {
        int so = buf * STAGE;
        #pragma unroll
        for (int i = 0; i < 2; i++) {
            int ci = tid + i*256;
            int row = ci >> 2, seg = ci & 3;
            long long go = (long long)row*lda + k0 + seg*8;
            uint32_t sa = smem0 + 2*(so + row*SP + seg*8);
            cpa16(sa,          pAh + go);
            cpa16(sa + 2*AH,   pAl + go);
        }
        #pragma unroll
        for (int i = 0; i < 2; i++) {
            int ci = tid + i*256;
            int row = ci >> 2, seg = ci & 3;
            long long go = (long long)row*ldb + k0 + seg*8;
            uint32_t sa = smem0 + 2*(so + 2*AH + row*SP + seg*8);
            cpa16(sa, pB + go);
        }
        asm volatile("cp.async.commit_group;");
    };

    int nk = Kd >> 5;
    load_stage(0, 0);

    for (int ks = 0; ks < nk; ks++) {
        asm volatile("cp.async.wait_group 0;");
        __syncthreads();
        if (ks + 1 < nk) load_stage((ks+1)&1, (ks+1) << 5);
        int so = (ks & 1) * STAGE;

        #pragma unroll
        for (int kh = 0; kh < 2; kh++) {
            int kb = kh*16;
            uint32_t ah[2][4], al[2][4];
            #pragma unroll
            for (int mi = 0; mi < 2; mi++) {
                uint32_t ad = smem0 + 2*(so + (aRow + mi*16)*SP + kb + aCol);
                ldsm_x4(ah[mi], ad);
                ldsm_x4(al[mi], ad + 2*AH);
            }
            #pragma unroll
            for (int nip = 0; nip < 4; nip++) {
                uint32_t bd = smem0 + 2*(so + 2*AH + (bRow + nip*16)*SP + kb + bCol);
                uint32_t bh4[4];
                ldsm_x4(bh4, bd);
                #pragma unroll
                for (int q = 0; q < 2; q++) {
                    int ni = nip*2 + q;
                    #pragma unroll
                    for (int mi = 0; mi < 2; mi++) {
                        mma16816(acc[mi][ni], ah[mi], bh4 + 2*q);
                        mma16816(acc[mi][ni], al[mi], bh4 + 2*q);
                    }
                }
            }
        }
    }

    bool hb = mode & 1, hg = mode & 2, hr = mode & 4, hs = mode & 8;
    #pragma unroll
    for (int mi = 0; mi < 2; mi++) {
        int m0 = mBase + wm*32 + mi*16 + g;
        #pragma unroll
        for (int ni = 0; ni < 8; ni++) {
            int n = nBase + wn*64 + ni*8 + 2*tig;
            #pragma unroll
            for (int hrow = 0; hrow < 2; hrow++) {
                int m = m0 + hrow*8;
                float v0 = acc[mi][ni][hrow*2+0] * alpha;
                float v1 = acc[mi][ni][hrow*2+1] * alpha;
                if (hb) { v0 += bias[n]; v1 += bias[n+1]; }
                if (hg) { v0 = gelu_f(v0); v1 = gelu_f(v1); }
                long long o = (long long)m*ldc + n;
                if (hr) { v0 += resid[o]; v1 += resid[o+1]; }
                if (hs) {
                    f16 h0, l0, h1, l1;
                    split2(v0, h0, l0); split2(v1, h1, l1);
                    *(uint32_t*)(Chi + o) = pack2(h0, h1);
                    *(uint32_t*)(Clo + o) = pack2(l0, l1);
                } else {
                    C[o] = v0; C[o+1] = v1;
                }
            }
        }
    }
}

// ---------------- flash attention (QK 3-product, PV 2-product, 2 CTAs/SM) ----------------
// Q,K from packed qkv [B,L,3072] split; V^T [B,H*HD,L] hi-only; out att [B,L,D] split.
__global__ void __launch_bounds__(256, 2) flash_kernel(
    const f16* __restrict__ QKVh, const f16* __restrict__ QKVl,
    const f16* __restrict__ Vt,
    f16* __restrict__ Oh, f16* __restrict__ Ol)
{
    constexpr int KSP = 72, VSP = 72;
    constexpr int KTH = 64*KSP;          // one K half-buffer (halves)
    constexpr int VTH = 64*VSP;
    constexpr int STG = 2*KTH + VTH;     // 13824 halves = 27648 B

    extern __shared__ __align__(16) f16 sm[];
    uint32_t smem0 = (uint32_t)__cvta_generic_to_shared(sm);

    int tid = threadIdx.x, warp = tid >> 5, lane = tid & 31;
    int g = lane >> 2, tig = lane & 3;
    int qt = blockIdx.x, bh = blockIdx.y;
    int b = bh >> 4, h = bh & 15;
    long long baseQ = (long long)b*LL*QKV + (long long)(qt*128)*QKV + h*64;
    long long baseK = (long long)b*LL*QKV + DD + h*64;
    long long baseV = (long long)b*LL*DD + (long long)(h*64)*LL;
    long long baseO = (long long)b*LL*DD + (long long)(qt*128)*DD + h*64;

    int fRow = ((lane >> 4) << 3) + (lane & 7);
    int fCol = (lane & 8) ? 8 : 0;

    uint32_t qa_h[4][4], qa_l[4][4];
    {
        long long r0 = baseQ + (long long)(warp*16 + g)*QKV;
        long long r8 = r0 + 8*QKV;
        #pragma unroll
        for (int kf = 0; kf < 4; kf++) {
            int c = kf*16 + 2*tig;
            qa_h[kf][0] = *(const uint32_t*)(QKVh + r0 + c);
            qa_h[kf][1] = *(const uint32_t*)(QKVh + r8 + c);
            qa_h[kf][2] = *(const uint32_t*)(QKVh + r0 + c + 8);
            qa_h[kf][3] = *(const uint32_t*)(QKVh + r8 + c + 8);
            qa_l[kf][0] = *(const uint32_t*)(QKVl + r0 + c);
            qa_l[kf][1] = *(const uint32_t*)(QKVl + r8 + c);
            qa_l[kf][2] = *(const uint32_t*)(QKVl + r0 + c + 8);
            qa_l[kf][3] = *(const uint32_t*)(QKVl + r8 + c + 8);
        }
    }

    auto load_tiles = [&](int buf, int kt) {
        int so = buf * STG;
        #pragma unroll
        for (int i = 0; i < 2; i++) {            // K tile: 64 rows x 64 halves, hi+lo
            int ci = tid + i*256;
            int row = ci >> 3, ch = ci & 7;
            long long go = baseK + (long long)(kt*64 + row)*QKV + ch*8;
            uint32_t sa = smem0 + 2*(so + row*KSP + ch*8);
            cpa16(sa,           QKVh + go);
            cpa16(sa + 2*KTH,   QKVl + go);
        }
        #pragma unroll
        for (int i = 0; i < 2; i++) {            // V^T tile: 64 d x 64 L halves, hi only
            int ci = tid + i*256;
            int row = ci >> 3, ch = ci & 7;
            long long go = baseV + (long long)row*LL + kt*64 + ch*8;
            uint32_t sa = smem0 + 2*(so + 2*KTH + row*VSP + ch*8);
            cpa16(sa, Vt + go);
        }
        asm volatile("cp.async.commit_group;");
    };

    float m_r[2] = {-1e30f, -1e30f};
    float l_r[2] = {0.f, 0.f};
    float o[8][4];
    #pragma unroll
    for (int n = 0; n < 8; n++)
        #pragma unroll
        for (int c = 0; c < 4; c++) o[n][c] = 0.f;

    load_tiles(0, 0);

    for (int kt = 0; kt < 32; kt++) {
        asm volatile("cp.async.wait_group 0;");
        __syncthreads();
        if (kt + 1 < 32) load_tiles((kt+1)&1, kt+1);
        int so = (kt & 1) * STG;

        float s[8][4];
        #pragma unroll
        for (int n = 0; n < 8; n++)
            #pragma unroll
            for (int c = 0; c < 4; c++) s[n][c] = 0.f;

        #pragma unroll
        for (int kf = 0; kf < 4; kf++) {
            #pragma unroll
            for (int np = 0; np < 4; np++) {
                uint32_t kd = smem0 + 2*(so + (np*16 + fRow)*KSP + kf*16 + fCol);
                uint32_t kh4[4], kl4[4];
                ldsm_x4(kh4, kd);
                ldsm_x4(kl4, kd + 2*KTH);
                #pragma unroll
                for (int q = 0; q < 2; q++) {
                    int n = np*2 + q;
                    mma16816(s[n], qa_h[kf], kh4 + 2*q);
                    mma16816(s[n], qa_l[kf], kh4 + 2*q);
                    mma16816(s[n], qa_h[kf], kl4 + 2*q);
                }
            }
        }

        float mx0 = -1e30f, mx1 = -1e30f;
        #pragma unroll
        for (int n = 0; n < 8; n++) {
            mx0 = fmaxf(mx0, fmaxf(s[n][0], s[n][1]));
            mx1 = fmaxf(mx1, fmaxf(s[n][2], s[n][3]));
        }
        #pragma unroll
        for (int off = 1; off < 4; off <<= 1) {
            mx0 = fmaxf(mx0, __shfl_xor_sync(0xffffffffu, mx0, off));
            mx1 = fmaxf(mx1, __shfl_xor_sync(0xffffffffu, mx1, off));
        }
        float mn0 = fmaxf(m_r[0], mx0), mn1 = fmaxf(m_r[1], mx1);
        float sf0 = __expf(m_r[0] - mn0), sf1 = __expf(m_r[1] - mn1);
        m_r[0] = mn0; m_r[1] = mn1;
        float sum0 = 0.f, sum1 = 0.f;
        #pragma unroll
        for (int n = 0; n < 8; n++) {
            s[n][0] = __expf(s[n][0] - mn0); sum0 += s[n][0];
            s[n][1] = __expf(s[n][1] - mn0); sum0 += s[n][1];
            s[n][2] = __expf(s[n][2] - mn1); sum1 += s[n][2];
            s[n][3] = __expf(s[n][3] - mn1); sum1 += s[n][3];
        }
        #pragma unroll
        for (int off = 1; off < 4; off <<= 1) {
            sum0 += __shfl_xor_sync(0xffffffffu, sum0, off);
            sum1 += __shfl_xor_sync(0xffffffffu, sum1, off);
        }
        l_r[0] = l_r[0]*sf0 + sum0;
        l_r[1] = l_r[1]*sf1 + sum1;
        #pragma unroll
        for (int n = 0; n < 8; n++) {
            o[n][0] *= sf0; o[n][1] *= sf0;
            o[n][2] *= sf1; o[n][3] *= sf1;
        }

        #pragma unroll
        for (int kf2 = 0; kf2 < 4; kf2++) {
            uint32_t pa_h[4], pa_l[4];
            #pragma unroll
            for (int q4 = 0; q4 < 2; q4++) {
                int t = 2*kf2 + q4;
                #pragma unroll
                for (int rr = 0; rr < 2; rr++) {
                    float p0 = s[t][rr*2+0], p1 = s[t][rr*2+1];
                    f16 h0, l0, h1, l1;
                    split2(p0, h0, l0); split2(p1, h1, l1);
                    pa_h[q4*2+rr] = pack2(h0, h1);
                    pa_l[q4*2+rr] = pack2(l0, l1);
                }
            }
            #pragma unroll
            for (int np2 = 0; np2 < 4; np2++) {
                uint32_t vd = smem0 + 2*(so + 2*KTH + (np2*16 + fRow)*VSP + kf2*16 + fCol);
                uint32_t vh4[4];
                ldsm_x4(vh4, vd);
                #pragma unroll
                for (int q = 0; q < 2; q++) {
                    int n = np2*2 + q;
                    mma16816(o[n], pa_h, vh4 + 2*q);
                    mma16816(o[n], pa_l, vh4 + 2*q);
                }
            }
        }
    }

    float il0 = 1.f / l_r[0], il1 = 1.f / l_r[1];
    long long r0 = baseO + (long long)(warp*16 + g)*DD;
    long long r8 = r0 + 8*DD;
    #pragma unroll
    for (int n = 0; n < 8; n++) {
        int c = n*8 + 2*tig;
        float v0 = o[n][0]*il0, v1 = o[n][1]*il0;
        float v2 = o[n][2]*il1, v3 = o[n][3]*il1;
        f16 h0,l0,h1,l1;
        split2(v0,h0,l0); split2(v1,h1,l1);
        *(uint32_t*)(Oh + r0 + c) = pack2(h0,h1);
        *(uint32_t*)(Ol + r0 + c) = pack2(l0,l1);
        split2(v2,h0,l0); split2(v3,h1,l1);
        *(uint32_t*)(Oh + r8 + c) = pack2(h0,h1);
        *(uint32_t*)(Ol + r8 + c) = pack2(l0,l1);
    }
}

// ---------------- transpose + cast weights (hi only, optional scale) ----------------
__global__ void transpose_cast_kernel(const float* __restrict__ in,
                                      f16* __restrict__ oh,
                                      int rows, int cols, float alpha)
{
    __shared__ float t[32][33];
    long long bo = (long long)blockIdx.z * rows * cols;
    int c0 = blockIdx.x * 32, r0 = blockIdx.y * 32;
    int tx = threadIdx.x, ty = threadIdx.y;
    #pragma unroll
    for (int i = 0; i < 32; i += 8)
        t[ty+i][tx] = in[bo + (long long)(r0+ty+i)*cols + (c0+tx)];
    __syncthreads();
    #pragma unroll
    for (int i = 0; i < 32; i += 8) {
        float v = t[tx][ty+i] * alpha;
        long long o = bo + (long long)(c0+ty+i)*rows + (r0+tx);
        oh[o] = __float2half_rn(v);
    }
}

// ---------------- f16 transpose: V slice of packed qkv -> V^T (hi only) ----------------
__global__ void transpose_half_kernel(const f16* __restrict__ inh,
                                      f16* __restrict__ oh)
{
    __shared__ unsigned short th[32][33];
    long long ibo = (long long)blockIdx.z * LL * QKV;
    long long obo = (long long)blockIdx.z * DD * LL;
    int c0 = blockIdx.x * 32, r0 = blockIdx.y * 32;
    int tx = threadIdx.x, ty = threadIdx.y;
    #pragma unroll
    for (int i = 0; i < 32; i += 8) {
        long long p = ibo + (long long)(r0+ty+i)*QKV + c0 + tx;
        th[ty+i][tx] = __half_as_ushort(inh[p]);
    }
    __syncthreads();
    #pragma unroll
    for (int i = 0; i < 32; i += 8) {
        long long o = obo + (long long)(c0+ty+i)*LL + r0 + tx;
        oh[o] = __ushort_as_half(th[tx][ty+i]);
    }
}

// ---------------- elementwise split ----------------
__global__ void split_kernel(const float* __restrict__ x,
                             f16* __restrict__ oh, f16* __restrict__ ol)
{
    long long i = ((long long)blockIdx.x * 256 + threadIdx.x) * 4;
    float4 v = *(const float4*)(x + i);
    f16 h, l;
    split2(v.x, h, l); oh[i+0] = h; ol[i+0] = l;
    split2(v.y, h, l); oh[i+1] = h; ol[i+1] = l;
    split2(v.z, h, l); oh[i+2] = h; ol[i+2] = l;
    split2(v.w, h, l); oh[i+3] = h; ol[i+3] = l;
}

// ---------------- FFT (radix-4 DIT, n=4096, 512 threads) ----------------
__device__ __forceinline__ int rev4(int i) {
    int r = __brev(i) >> 20;
    return ((r & 0x555) << 1) | ((r >> 1) & 0x555);
}
__device__ __forceinline__ float2 cmulf(float2 a, float2 b) {
    return make_float2(a.x*b.x - a.y*b.y, a.x*b.y + a.y*b.x);
}
__device__ __forceinline__ void tw_init(float2* tw, int tid) {
    for (int m = tid; m < 1024; m += 512) {
        float sv, cv;
        sincosf(-6.283185307179586f * (float)m / 4096.0f, &sv, &cv);
        tw[m] = make_float2(cv, sv);
    }
}

__device__ void do_fft4(float2* s, const float2* tw, int tid) {
    #pragma unroll 1
    for (int st = 0; st < 6; st++) {
        int Q  = 1 << (2*st);
        int sh = 10 - 2*st;
        #pragma unroll 1
        for (int idx = tid; idx < 1024; idx += 512) {
            int j    = idx & (Q - 1);
            int blk  = idx >> (2*st);
            int base = blk*(Q << 2) + j;
            float2 x0 = s[base];
            float2 x1 = s[base + Q];
            float2 x2 = s[base + 2*Q];
            float2 x3 = s[base + 3*Q];
            float2 w1 = tw[j << sh];
            float2 w2 = cmulf(w1, w1);
            float2 w3 = cmulf(w2, w1);
            float2 y1 = cmulf(w1, x1);
            float2 y2 = cmulf(w2, x2);
            float2 y3 = cmulf(w3, x3);
            float2 u0 = make_float2(x0.x + y2.x, x0.y + y2.y);
            float2 u1 = make_float2(x0.x - y2.x, x0.y - y2.y);
            float2 u2 = make_float2(y1.x + y3.x, y1.y + y3.y);
            float2 u3 = make_float2(y1.x - y3.x, y1.y - y3.y);
            s[base]       = make_float2(u0.x + u2.x, u0.y + u2.y);
            s[base + Q]   = make_float2(u1.x + u3.y, u1.y - u3.x);
            s[base + 2*Q] = make_float2(u0.x - u2.x, u0.y - u2.y);
            s[base + 3*Q] = make_float2(u1.x - u3.y, u1.y + u3.x);
        }
        __syncthreads();
    }
}

__global__ void __launch_bounds__(512) filters_kernel(
    const float* __restrict__ eig_vals, const float* __restrict__ eig_vecs,
    const float* __restrict__ w_filters, float2* __restrict__ Ffilt)
{
    __shared__ float2 s[NF4096];
    __shared__ float2 tw[1024];
    __shared__ float  wk[KK];
    int d = blockIdx.x, tid = threadIdx.x;
    if (tid < KK) wk[tid] = powf(eig_vals[tid], 0.25f) * w_filters[tid*DD + d];
    tw_init(tw, tid);
    for (int i = tid; i < NF4096; i += 512) s[i] = make_float2(0.f, 0.f);
    __syncthreads();
    for (int t = tid; t < LL; t += 512) {
        float f = 0.f;
        #pragma unroll
        for (int k = 0; k < KK; k++) f += eig_vecs[t*KK + k] * wk[k];
        s[rev4(t)] = make_float2(f, 0.f);
    }
    __syncthreads();
    do_fft4(s, tw, tid);
    for (int i = tid; i < NF4096; i += 512)
        Ffilt[(long long)d*NF4096 + i] = s[i];
}

// 2-for-1 packed conv with fused gather/scatter
__global__ void __launch_bounds__(512) conv3_kernel(
    const float* __restrict__ xi, const float2* __restrict__ Ffilt,
    float* __restrict__ stu)
{
    __shared__ float2 s[NF4096];
    __shared__ float2 tw[1024];
    int z = blockIdx.x, tid = threadIdx.x;
    int b = z >> 9, dp = z & 511;
    int d0 = 2*dp;
    const float* xib = xi + (long long)b*LL*DD + d0;
    float* stb = stu + (long long)b*LL*DD + d0;
    tw_init(tw, tid);
    for (int i = tid; i < NF4096; i += 512) s[i] = make_float2(0.f, 0.f);
    __syncthreads();
    for (int t = tid; t < LL; t += 512)
        s[rev4(t)] = *(const float2*)(xib + (long long)t*DD);
    __syncthreads();
    do_fft4(s, tw, tid);

    const float2* F0 = Ffilt + (long long)d0 * NF4096;
    const float2* F1 = F0 + NF4096;
    for (int i = tid; i < 2048; i += 512) {
        if (i == 0) {
            #pragma unroll
            for (int q = 0; q < 2; q++) {
                int idx = q * 2048;
                float2 Z = s[idx];
                float X1 = Z.x, X2 = Z.y;
                float2 f0 = F0[idx], f1 = F1[idx];
                float2 Y1 = make_float2(X1*f0.x, X1*f0.y);
                float2 Y2 = make_float2(X2*f1.x, X2*f1.y);
                s[idx] = make_float2(Y1.x - Y2.y, -(Y1.y + Y2.x));
            }
        } else {
            float2 Za = s[i], Zb = s[NF4096 - i];
            float2 X1 = make_float2(0.5f*(Za.x + Zb.x), 0.5f*(Za.y - Zb.y));
            float2 Dd = make_float2(Za.x - Zb.x, Za.y + Zb.y);
            float2 X2 = make_float2(0.5f*Dd.y, -0.5f*Dd.x);
            float2 f0 = F0[i], f1 = F1[i];
            float2 Y1 = make_float2(X1.x*f0.x - X1.y*f0.y, X1.x*f0.y + X1.y*f0.x);
            float2 Y2 = make_float2(X2.x*f1.x - X2.y*f1.y, X2.x*f1.y + X2.y*f1.x);
            s[i]          = make_float2(Y1.x - Y2.y, -(Y1.y + Y2.x));
            s[NF4096 - i] = make_float2(Y1.x + Y2.y, Y1.y - Y2.x);
        }
    }
    __syncthreads();
    float2 r[8];
    #pragma unroll
    for (int k = 0; k < 8; k++) r[k] = s[rev4(tid + k*512)];
    __syncthreads();
    #pragma unroll
    for (int k = 0; k < 8; k++) s[tid + k*512] = r[k];
    __syncthreads();
    do_fft4(s, tw, tid);
    const float inv = 1.0f / 4096.0f;
    for (int l = tid; l < LL; l += 512) {
        float2 w = make_float2(s[l].x * inv, -s[l].y * inv);
        *(float2*)(stb + (long long)l*DD) = w;
    }
}

// ---------------- LayerNorm with split-fp16 output ----------------
__global__ void __launch_bounds__(256) ln_split_kernel(
    const float* __restrict__ x, f16* __restrict__ yh, f16* __restrict__ yl,
    const float* __restrict__ sc, const float* __restrict__ bi)
{
    long long base = (long long)blockIdx.x * DD;
    int tid = threadIdx.x;
    float4 v = *(const float4*)(x + base + tid*4);
    float mean = block_sum256(v.x + v.y + v.z + v.w) * (1.0f/DD);
    float dx = v.x - mean, dy = v.y - mean, dz = v.z - mean, dw = v.w - mean;
    float var = block_sum256(dx*dx + dy*dy + dz*dz + dw*dw) * (1.0f/DD);
    float rstd = rsqrtf(var + 1e-6f);
    float4 s4 = *(const float4*)(sc + tid*4);
    float4 b4 = *(const float4*)(bi + tid*4);
    float o0 = dx*rstd*s4.x + b4.x;
    float o1 = dy*rstd*s4.y + b4.y;
    float o2 = dz*rstd*s4.z + b4.z;
    float o3 = dw*rstd*s4.w + b4.w;
    long long i = base + tid*4;
    f16 h, l;
    split2(o0, h, l); yh[i+0] = h; yl[i+0] = l;
    split2(o1, h, l); yh[i+1] = h; yl[i+1] = l;
    split2(o2, h, l); yh[i+2] = h; yl[i+2] = l;
    split2(o3, h, l); yh[i+3] = h; yl[i+3] = l;
}

// ---------------- launch ----------------
static void* symv(const void* s) { void* p = nullptr; cudaGetSymbolAddress(&p, s); return p; }

extern "C" void kernel_launch(void* const* d_in, const int* in_sizes, int n_in,
                              void* d_out, int out_size)
{
    const float* inputs    = (const float*)d_in[0];
    const float* eig_vals  = (const float*)d_in[1];
    const float* eig_vecs  = (const float*)d_in[2];
    const float* w_filters = (const float*)d_in[3];
    const float* w_inputs  = (const float*)d_in[4];
    const float* ln1_s     = (const float*)d_in[5];
    const float* ln1_b     = (const float*)d_in[6];
    const float* wq        = (const float*)d_in[7];
    const float* wk        = (const float*)d_in[8];
    const float* wv        = (const float*)d_in[9];
    const float* wo        = (const float*)d_in[10];
    const float* ln2_s     = (const float*)d_in[11];
    const float* ln2_b     = (const float*)d_in[12];
    const float* mlp_w1    = (const float*)d_in[13];
    const float* mlp_b1    = (const float*)d_in[14];
    const float* mlp_w2    = (const float*)d_in[15];
    const float* mlp_b2    = (const float*)d_in[16];
    float* out = (float*)d_out;

    float*  xi    = (float*)symv(g_xi);
    float2* Ffilt = (float2*)symv(g_Ffilt);
    float*  stu   = (float*)symv(g_stu);
    float*  xres  = (float*)symv(g_xres);

    f16 *inh=(f16*)symv(g_inh),    *inl=(f16*)symv(g_inl);
    f16 *x1h=(f16*)symv(g_x1h),    *x1l=(f16*)symv(g_x1l);
    f16 *qkvh=(f16*)symv(g_qkvh),  *qkvl=(f16*)symv(g_qkvl);
    f16 *vTh=(f16*)symv(g_vTh);
    f16 *ath=(f16*)symv(g_ath),    *atl=(f16*)symv(g_atl);
    f16 *y1h=(f16*)symv(g_y1h),    *y1l=(f16*)symv(g_y1l);
    f16 *hh =(f16*)symv(g_hh),     *hl =(f16*)symv(g_hl);
    f16 *wiT=(f16*)symv(g_wiT);
    f16 *wqkvT=(f16*)symv(g_wqkvT);
    f16 *woT=(f16*)symv(g_woT);
    f16 *w1T=(f16*)symv(g_w1T);
    f16 *w2T=(f16*)symv(g_w2T);

    const int SMGE = 61440;
    const int SMFL = 55296;
    cudaFuncSetAttribute(gemm_fp16,    cudaFuncAttributeMaxDynamicSharedMemorySize, SMGE);
    cudaFuncSetAttribute(flash_kernel, cudaFuncAttributeMaxDynamicSharedMemorySize, SMFL);

    dim3 t328(32, 8);

    // 1. filter spectrum per channel d
    filters_kernel<<<DD, 512>>>(eig_vals, eig_vecs, w_filters, Ffilt);

    // 2. split inputs; transpose-cast all weights to [N][K] hi (wq pre-scaled 1/8)
    split_kernel<<<(BL*DD)/1024, 256>>>(inputs, inh, inl);
    transpose_cast_kernel<<<dim3(32, 32, 1), t328>>>(w_inputs, wiT, DD, DD, 1.0f);
    transpose_cast_kernel<<<dim3(32, 32, 1), t328>>>(wq, wqkvT,           DD, DD, 0.125f);
    transpose_cast_kernel<<<dim3(32, 32, 1), t328>>>(wk, wqkvT + DD*DD,   DD, DD, 1.0f);
    transpose_cast_kernel<<<dim3(32, 32, 1), t328>>>(wv, wqkvT + 2*DD*DD, DD, DD, 1.0f);
    transpose_cast_kernel<<<dim3(32, 32, 1), t328>>>(wo, woT, DD, DD, 1.0f);
    transpose_cast_kernel<<<dim3(MLPD/32, DD/32, 1), t328>>>(mlp_w1, w1T, DD, MLPD, 1.0f);
    transpose_cast_kernel<<<dim3(DD/32, MLPD/32, 1), t328>>>(mlp_w2, w2T, MLPD, DD, 1.0f);

    // 3. xi = inputs @ w_inputs (f32 out for FFT)
    gemm_fp16<<<dim3(8, 64, 1), 256, SMGE>>>(
        inh, inl, wiT, xi, nullptr, nullptr,
        BL, DD, DD, DD, DD, DD, 1.0f, nullptr, nullptr, 0);

    // 4. spectral causal conv (radix-4 packed FFT, fused gather/scatter)
    conv3_kernel<<<BB*DD/2, 512>>>(xi, Ffilt, stu);

    // 5. LN1 -> split x1
    ln_split_kernel<<<BL, 256>>>(stu, x1h, x1l, ln1_s, ln1_b);

    // 6. fused QKV gemm (N=3072), split out
    gemm_fp16<<<dim3(QKV/128, BL/128, 1), 256, SMGE>>>(
        x1h, x1l, wqkvT, nullptr, qkvh, qkvl,
        BL, QKV, DD, DD, DD, QKV, 1.0f, nullptr, nullptr, 8);

    // 7. V^T transpose from packed qkv (hi only; columns 2048..3071)
    transpose_half_kernel<<<dim3(DD/32, LL/32, BB), t328>>>(qkvh + 2*DD, vTh);

    // 8. fused flash attention -> split att
    flash_kernel<<<dim3(LL/128, BB*HH), 256, SMFL>>>(
        qkvh, qkvl, vTh, ath, atl);

    // 9. x = att @ wo + stu (f32)
    gemm_fp16<<<dim3(8, 64, 1), 256, SMGE>>>(
        ath, atl, woT, xres, nullptr, nullptr,
        BL, DD, DD, DD, DD, DD, 1.0f, nullptr, stu, 4);

    // 10. LN2 -> split y1
    ln_split_kernel<<<BL, 256>>>(xres, y1h, y1l, ln2_s, ln2_b);

    // 11. h = gelu(y1 @ w1 + b1), split out
    gemm_fp16<<<dim3(MLPD/128, 64, 1), 256, SMGE>>>(
        y1h, y1l, w1T, nullptr, hh, hl,
        BL, MLPD, DD, DD, DD, MLPD, 1.0f, mlp_b1, nullptr, 11);

    // 12. out = h @ w2 + b2 + x (f32)
    gemm_fp16<<<dim3(8, 64, 1), 256, SMGE>>>(
        hh, hl, w2T, out, nullptr, nullptr,
        BL, DD, MLPD, MLPD, MLPD, DD, 1.0f, mlp_b2, xres, 5);
}

// round 14
// speedup vs baseline: 5.5817x; 1.1152x over previous
#include <cuda_runtime.h>
#include <cuda_fp16.h>
#include <math.h>
#include <stdint.h>

#define BB 4
#define LL 2048
#define DD 1024
#define HH 16
#define HDIM 64
#define KK 24
#define MLPD 4096
#define BL (BB*LL)
#define NF4096 4096
#define QKV (3*DD)

typedef __half f16;

// ---------------- scratch (device globals; allocation-free) ----------------
__device__ float  g_xi[BL*DD];
__device__ float2 g_Ffilt[(size_t)DD*NF4096];
__device__ float  g_stu[BL*DD];
__device__ float  g_xres[BL*DD];

__device__ f16 g_inh[BL*DD],  g_inl[BL*DD];
__device__ f16 g_x1h[BL*DD],  g_x1l[BL*DD];
__device__ f16 g_qkvh[(size_t)BL*QKV], g_qkvl[(size_t)BL*QKV];  // packed Q|K|V
__device__ f16 g_vTh[BL*DD];                         // [B,H*HD,L] (hi only)
__device__ f16 g_ath[BL*DD];                         // att (hi only)
__device__ f16 g_y1h[BL*DD],  g_y1l[BL*DD];
__device__ f16 g_hh[(size_t)BL*MLPD];                // h (hi only)
// transposed-cast weights [N][K] (hi only)
__device__ f16 g_wiT[DD*DD];
__device__ f16 g_wqkvT[(size_t)QKV*DD];
__device__ f16 g_woT[DD*DD];
__device__ f16 g_w1T[(size_t)DD*MLPD];
__device__ f16 g_w2T[(size_t)DD*MLPD];

// ---------------- helpers ----------------
__device__ __forceinline__ float gelu_f(float x) {
    float x3 = x*x*x;
    return 0.5f*x*(1.0f + tanhf(0.7978845608028654f*(x + 0.044715f*x3)));
}
__device__ __forceinline__ void split2(float v, f16 &h, f16 &l) {
    h = __float2half_rn(v);
    l = __float2half_rn(v - __half2float(h));
}
__device__ __forceinline__ uint32_t pack2(f16 a, f16 b) {
    return (uint32_t)__half_as_ushort(a) | ((uint32_t)__half_as_ushort(b) << 16);
}
__device__ __forceinline__ void cpa16(uint32_t s, const void* g) {
    asm volatile("cp.async.cg.shared.global [%0], [%1], 16;" :: "r"(s), "l"(g));
}
__device__ __forceinline__ void mma16816(float* c, const uint32_t* a, const uint32_t* b) {
    asm volatile("mma.sync.aligned.m16n8k16.row.col.f32.f16.f16.f32 "
                 "{%0,%1,%2,%3},{%4,%5,%6,%7},{%8,%9},{%0,%1,%2,%3};"
                 : "+f"(c[0]), "+f"(c[1]), "+f"(c[2]), "+f"(c[3])
                 : "r"(a[0]), "r"(a[1]), "r"(a[2]), "r"(a[3]),
                   "r"(b[0]), "r"(b[1]));
}
__device__ __forceinline__ void ldsm_x4(uint32_t* r, uint32_t saddr) {
    asm volatile("ldmatrix.sync.aligned.m8n8.x4.shared.b16 {%0,%1,%2,%3}, [%4];"
        : "=r"(r[0]), "=r"(r[1]), "=r"(r[2]), "=r"(r[3]) : "r"(saddr));
}
__device__ __forceinline__ float block_sum256(float v) {
    __shared__ float red[8];
    int lane = threadIdx.x & 31, w = threadIdx.x >> 5;
    #pragma unroll
    for (int o = 16; o; o >>= 1) v += __shfl_xor_sync(0xffffffffu, v, o);
    __syncthreads();
    if (lane == 0) red[w] = v;
    __syncthreads();
    if (threadIdx.x == 0) {
        float s = 0.f;
        #pragma unroll
        for (int i = 0; i < 8; i++) s += red[i];
        red[0] = s;
    }
    __syncthreads();
    return red[0];
}

// ---------------- split-fp16 tensor-core GEMM ----------------
// PROD=2: C = (Ah+Al)@Bh^T ; PROD=1: C = Ah@Bh^T. B always hi-only [N,K].
// Tile 128x128, 2 CTAs/SM, 2-stage cp.async, ldmatrix.
// mode: 1=bias, 2=gelu, 4=resid, 8=split-out (Clo may be null -> hi-only cast out)
template<int PROD>
__global__ void __launch_bounds__(256, 2) gemm_fp16(
    const f16* __restrict__ Ahi, const f16* __restrict__ Alo,
    const f16* __restrict__ Bh,
    float* __restrict__ C, f16* __restrict__ Chi, f16* __restrict__ Clo,
    int M, int N, int Kd, int lda, int ldb, int ldc,
    float alpha, const float* __restrict__ bias,
    const float* __restrict__ resid, int mode)
{
    constexpr int SP    = 40;
    constexpr int AH    = 128 * SP;
    constexpr int BOFF  = PROD * AH;        // B half-offset within stage
    constexpr int STAGE = BOFF + 128*SP;    // halves

    extern __shared__ __align__(16) char dsm[];
    uint32_t smem0 = (uint32_t)__cvta_generic_to_shared(dsm);

    int tid   = threadIdx.x;
    int mBase = blockIdx.y * 128, nBase = blockIdx.x * 128;

    const f16* pAh = Ahi + (long long)mBase * lda;
    const f16* pAl = (PROD == 2) ? (Alo + (long long)mBase * lda) : nullptr;
    const f16* pB  = Bh  + (long long)nBase * ldb;

    int warp = tid >> 5, lane = tid & 31;
    int wm = warp & 3, wn = warp >> 2;
    int g  = lane >> 2, tig = lane & 3;

    int aRow = wm*32 + (lane & 15);
    int aCol = (lane & 16) ? 8 : 0;
    int bRow = wn*64 + ((lane >> 4) << 3) + (lane & 7);
    int bCol = (lane & 8) ? 8 : 0;

    float acc[2][8][4];
    #pragma unroll
    for (int i = 0; i < 2; i++)
        #pragma unroll
        for (int j = 0; j < 8; j++)
            #pragma unroll
            for (int c = 0; c < 4; c++) acc[i][j][c] = 0.f;

    auto load_stage = [&](int buf, int k0) {
        int so = buf * STAGE;
        #pragma unroll
        for (int i = 0; i < 2; i++) {
            int ci = tid + i*256;
            int row = ci >> 2, seg = ci & 3;
            long long go = (long long)row*lda + k0 + seg*8;
            uint32_t sa = smem0 + 2*(so + row*SP + seg*8);
            cpa16(sa, pAh + go);
            if (PROD == 2) cpa16(sa + 2*AH, pAl + go);
        }
        #pragma unroll
        for (int i = 0; i < 2; i++) {
            int ci = tid + i*256;
            int row = ci >> 2, seg = ci & 3;
            long long go = (long long)row*ldb + k0 + seg*8;
            uint32_t sa = smem0 + 2*(so + BOFF + row*SP + seg*8);
            cpa16(sa, pB + go);
        }
        asm volatile("cp.async.commit_group;");
    };

    int nk = Kd >> 5;
    load_stage(0, 0);

    for (int ks = 0; ks < nk; ks++) {
        asm volatile("cp.async.wait_group 0;");
        __syncthreads();
        if (ks + 1 < nk) load_stage((ks+1)&1, (ks+1) << 5);
        int so = (ks & 1) * STAGE;

        #pragma unroll
        for (int kh = 0; kh < 2; kh++) {
            int kb = kh*16;
            uint32_t ah[2][4], al[2][4];
            #pragma unroll
            for (int mi = 0; mi < 2; mi++) {
                uint32_t ad = smem0 + 2*(so + (aRow + mi*16)*SP + kb + aCol);
                ldsm_x4(ah[mi], ad);
                if (PROD == 2) ldsm_x4(al[mi], ad + 2*AH);
            }
            #pragma unroll
            for (int nip = 0; nip < 4; nip++) {
                uint32_t bd = smem0 + 2*(so + BOFF + (bRow + nip*16)*SP + kb + bCol);
                uint32_t bh4[4];
                ldsm_x4(bh4, bd);
                #pragma unroll
                for (int q = 0; q < 2; q++) {
                    int ni = nip*2 + q;
                    #pragma unroll
                    for (int mi = 0; mi < 2; mi++) {
                        mma16816(acc[mi][ni], ah[mi], bh4 + 2*q);
                        if (PROD == 2) mma16816(acc[mi][ni], al[mi], bh4 + 2*q);
                    }
                }
            }
        }
    }

    bool hb = mode & 1, hg = mode & 2, hr = mode & 4, hs = mode & 8;
    bool hlo = hs && (Clo != nullptr);
    #pragma unroll
    for (int mi = 0; mi < 2; mi++) {
        int m0 = mBase + wm*32 + mi*16 + g;
        #pragma unroll
        for (int ni = 0; ni < 8; ni++) {
            int n = nBase + wn*64 + ni*8 + 2*tig;
            #pragma unroll
            for (int hrow = 0; hrow < 2; hrow++) {
                int m = m0 + hrow*8;
                float v0 = acc[mi][ni][hrow*2+0] * alpha;
                float v1 = acc[mi][ni][hrow*2+1] * alpha;
                if (hb) { v0 += bias[n]; v1 += bias[n+1]; }
                if (hg) { v0 = gelu_f(v0); v1 = gelu_f(v1); }
                long long o = (long long)m*ldc + n;
                if (hr) { v0 += resid[o]; v1 += resid[o+1]; }
                if (hs) {
                    f16 h0, l0, h1, l1;
                    split2(v0, h0, l0); split2(v1, h1, l1);
                    *(uint32_t*)(Chi + o) = pack2(h0, h1);
                    if (hlo) *(uint32_t*)(Clo + o) = pack2(l0, l1);
                } else {
                    C[o] = v0; C[o+1] = v1;
                }
            }
        }
    }
}

// ---------------- flash attention (QK 3-product, PV 2-product, 2 CTAs/SM) ----------------
// Q,K from packed qkv split; V^T hi-only; out att [B,L,D] fp16 hi only.
__global__ void __launch_bounds__(256, 2) flash_kernel(
    const f16* __restrict__ QKVh, const f16* __restrict__ QKVl,
    const f16* __restrict__ Vt,
    f16* __restrict__ Oh)
{
    constexpr int KSP = 72, VSP = 72;
    constexpr int KTH = 64*KSP;
    constexpr int VTH = 64*VSP;
    constexpr int STG = 2*KTH + VTH;

    extern __shared__ __align__(16) f16 sm[];
    uint32_t smem0 = (uint32_t)__cvta_generic_to_shared(sm);

    int tid = threadIdx.x, warp = tid >> 5, lane = tid & 31;
    int g = lane >> 2, tig = lane & 3;
    int qt = blockIdx.x, bh = blockIdx.y;
    int b = bh >> 4, h = bh & 15;
    long long baseQ = (long long)b*LL*QKV + (long long)(qt*128)*QKV + h*64;
    long long baseK = (long long)b*LL*QKV + DD + h*64;
    long long baseV = (long long)b*LL*DD + (long long)(h*64)*LL;
    long long baseO = (long long)b*LL*DD + (long long)(qt*128)*DD + h*64;

    int fRow = ((lane >> 4) << 3) + (lane & 7);
    int fCol = (lane & 8) ? 8 : 0;

    uint32_t qa_h[4][4], qa_l[4][4];
    {
        long long r0 = baseQ + (long long)(warp*16 + g)*QKV;
        long long r8 = r0 + 8*QKV;
        #pragma unroll
        for (int kf = 0; kf < 4; kf++) {
            int c = kf*16 + 2*tig;
            qa_h[kf][0] = *(const uint32_t*)(QKVh + r0 + c);
            qa_h[kf][1] = *(const uint32_t*)(QKVh + r8 + c);
            qa_h[kf][2] = *(const uint32_t*)(QKVh + r0 + c + 8);
            qa_h[kf][3] = *(const uint32_t*)(QKVh + r8 + c + 8);
            qa_l[kf][0] = *(const uint32_t*)(QKVl + r0 + c);
            qa_l[kf][1] = *(const uint32_t*)(QKVl + r8 + c);
            qa_l[kf][2] = *(const uint32_t*)(QKVl + r0 + c + 8);
            qa_l[kf][3] = *(const uint32_t*)(QKVl + r8 + c + 8);
        }
    }

    auto load_tiles = [&](int buf, int kt) {
        int so = buf * STG;
        #pragma unroll
        for (int i = 0; i < 2; i++) {
            int ci = tid + i*256;
            int row = ci >> 3, ch = ci & 7;
            long long go = baseK + (long long)(kt*64 + row)*QKV + ch*8;
            uint32_t sa = smem0 + 2*(so + row*KSP + ch*8);
            cpa16(sa,           QKVh + go);
            cpa16(sa + 2*KTH,   QKVl + go);
        }
        #pragma unroll
        for (int i = 0; i < 2; i++) {
            int ci = tid + i*256;
            int row = ci >> 3, ch = ci & 7;
            long long go = baseV + (long long)row*LL + kt*64 + ch*8;
            uint32_t sa = smem0 + 2*(so + 2*KTH + row*VSP + ch*8);
            cpa16(sa, Vt + go);
        }
        asm volatile("cp.async.commit_group;");
    };

    float m_r[2] = {-1e30f, -1e30f};
    float l_r[2] = {0.f, 0.f};
    float o[8][4];
    #pragma unroll
    for (int n = 0; n < 8; n++)
        #pragma unroll
        for (int c = 0; c < 4; c++) o[n][c] = 0.f;

    load_tiles(0, 0);

    for (int kt = 0; kt < 32; kt++) {
        asm volatile("cp.async.wait_group 0;");
        __syncthreads();
        if (kt + 1 < 32) load_tiles((kt+1)&1, kt+1);
        int so = (kt & 1) * STG;

        float s[8][4];
        #pragma unroll
        for (int n = 0; n < 8; n++)
            #pragma unroll
            for (int c = 0; c < 4; c++) s[n][c] = 0.f;

        #pragma unroll
        for (int kf = 0; kf < 4; kf++) {
            #pragma unroll
            for (int np = 0; np < 4; np++) {
                uint32_t kd = smem0 + 2*(so + (np*16 + fRow)*KSP + kf*16 + fCol);
                uint32_t kh4[4], kl4[4];
                ldsm_x4(kh4, kd);
                ldsm_x4(kl4, kd + 2*KTH);
                #pragma unroll
                for (int q = 0; q < 2; q++) {
                    int n = np*2 + q;
                    mma16816(s[n], qa_h[kf], kh4 + 2*q);
                    mma16816(s[n], qa_l[kf], kh4 + 2*q);
                    mma16816(s[n], qa_h[kf], kl4 + 2*q);
                }
            }
        }

        float mx0 = -1e30f, mx1 = -1e30f;
        #pragma unroll
        for (int n = 0; n < 8; n++) {
            mx0 = fmaxf(mx0, fmaxf(s[n][0], s[n][1]));
            mx1 = fmaxf(mx1, fmaxf(s[n][2], s[n][3]));
        }
        #pragma unroll
        for (int off = 1; off < 4; off <<= 1) {
            mx0 = fmaxf(mx0, __shfl_xor_sync(0xffffffffu, mx0, off));
            mx1 = fmaxf(mx1, __shfl_xor_sync(0xffffffffu, mx1, off));
        }
        float mn0 = fmaxf(m_r[0], mx0), mn1 = fmaxf(m_r[1], mx1);
        float sf0 = __expf(m_r[0] - mn0), sf1 = __expf(m_r[1] - mn1);
        m_r[0] = mn0; m_r[1] = mn1;
        float sum0 = 0.f, sum1 = 0.f;
        #pragma unroll
        for (int n = 0; n < 8; n++) {
            s[n][0] = __expf(s[n][0] - mn0); sum0 += s[n][0];
            s[n][1] = __expf(s[n][1] - mn0); sum0 += s[n][1];
            s[n][2] = __expf(s[n][2] - mn1); sum1 += s[n][2];
            s[n][3] = __expf(s[n][3] - mn1); sum1 += s[n][3];
        }
        #pragma unroll
        for (int off = 1; off < 4; off <<= 1) {
            sum0 += __shfl_xor_sync(0xffffffffu, sum0, off);
            sum1 += __shfl_xor_sync(0xffffffffu, sum1, off);
        }
        l_r[0] = l_r[0]*sf0 + sum0;
        l_r[1] = l_r[1]*sf1 + sum1;
        #pragma unroll
        for (int n = 0; n < 8; n++) {
            o[n][0] *= sf0; o[n][1] *= sf0;
            o[n][2] *= sf1; o[n][3] *= sf1;
        }

        #pragma unroll
        for (int kf2 = 0; kf2 < 4; kf2++) {
            uint32_t pa_h[4], pa_l[4];
            #pragma unroll
            for (int q4 = 0; q4 < 2; q4++) {
                int t = 2*kf2 + q4;
                #pragma unroll
                for (int rr = 0; rr < 2; rr++) {
                    float p0 = s[t][rr*2+0], p1 = s[t][rr*2+1];
                    f16 h0, l0, h1, l1;
                    split2(p0, h0, l0); split2(p1, h1, l1);
                    pa_h[q4*2+rr] = pack2(h0, h1);
                    pa_l[q4*2+rr] = pack2(l0, l1);
                }
            }
            #pragma unroll
            for (int np2 = 0; np2 < 4; np2++) {
                uint32_t vd = smem0 + 2*(so + 2*KTH + (np2*16 + fRow)*VSP + kf2*16 + fCol);
                uint32_t vh4[4];
                ldsm_x4(vh4, vd);
                #pragma unroll
                for (int q = 0; q < 2; q++) {
                    int n = np2*2 + q;
                    mma16816(o[n], pa_h, vh4 + 2*q);
                    mma16816(o[n], pa_l, vh4 + 2*q);
                }
            }
        }
    }

    float il0 = 1.f / l_r[0], il1 = 1.f / l_r[1];
    long long r0 = baseO + (long long)(warp*16 + g)*DD;
    long long r8 = r0 + 8*DD;
    #pragma unroll
    for (int n = 0; n < 8; n++) {
        int c = n*8 + 2*tig;
        *(uint32_t*)(Oh + r0 + c) = pack2(__float2half_rn(o[n][0]*il0),
                                          __float2half_rn(o[n][1]*il0));
        *(uint32_t*)(Oh + r8 + c) = pack2(__float2half_rn(o[n][2]*il1),
                                          __float2half_rn(o[n][3]*il1));
    }
}

// ---------------- transpose + cast weights (hi only, optional scale) ----------------
__global__ void transpose_cast_kernel(const float* __restrict__ in,
                                      f16* __restrict__ oh,
                                      int rows, int cols, float alpha)
{
    __shared__ float t[32][33];
    long long bo = (long long)blockIdx.z * rows * cols;
    int c0 = blockIdx.x * 32, r0 = blockIdx.y * 32;
    int tx = threadIdx.x, ty = threadIdx.y;
    #pragma unroll
    for (int i = 0; i < 32; i += 8)
        t[ty+i][tx] = in[bo + (long long)(r0+ty+i)*cols + (c0+tx)];
    __syncthreads();
    #pragma unroll
    for (int i = 0; i < 32; i += 8) {
        float v = t[tx][ty+i] * alpha;
        long long o = bo + (long long)(c0+ty+i)*rows + (r0+tx);
        oh[o] = __float2half_rn(v);
    }
}

// ---------------- f16 transpose: V slice of packed qkv -> V^T (hi only) ----------------
__global__ void transpose_half_kernel(const f16* __restrict__ inh,
                                      f16* __restrict__ oh)
{
    __shared__ unsigned short th[32][33];
    long long ibo = (long long)blockIdx.z * LL * QKV;
    long long obo = (long long)blockIdx.z * DD * LL;
    int c0 = blockIdx.x * 32, r0 = blockIdx.y * 32;
    int tx = threadIdx.x, ty = threadIdx.y;
    #pragma unroll
    for (int i = 0; i < 32; i += 8) {
        long long p = ibo + (long long)(r0+ty+i)*QKV + c0 + tx;
        th[ty+i][tx] = __half_as_ushort(inh[p]);
    }
    __syncthreads();
    #pragma unroll
    for (int i = 0; i < 32; i += 8) {
        long long o = obo + (long long)(c0+ty+i)*LL + r0 + tx;
        oh[o] = __ushort_as_half(th[tx][ty+i]);
    }
}

// ---------------- elementwise split ----------------
__global__ void split_kernel(const float* __restrict__ x,
                             f16* __restrict__ oh, f16* __restrict__ ol)
{
    long long i = ((long long)blockIdx.x * 256 + threadIdx.x) * 4;
    float4 v = *(const float4*)(x + i);
    f16 h, l;
    split2(v.x, h, l); oh[i+0] = h; ol[i+0] = l;
    split2(v.y, h, l); oh[i+1] = h; ol[i+1] = l;
    split2(v.z, h, l); oh[i+2] = h; ol[i+2] = l;
    split2(v.w, h, l); oh[i+3] = h; ol[i+3] = l;
}

// ---------------- FFT (radix-4 DIT, n=4096, 512 threads) ----------------
__device__ __forceinline__ int rev4(int i) {
    int r = __brev(i) >> 20;
    return ((r & 0x555) << 1) | ((r >> 1) & 0x555);
}
__device__ __forceinline__ float2 cmulf(float2 a, float2 b) {
    return make_float2(a.x*b.x - a.y*b.y, a.x*b.y + a.y*b.x);
}
__device__ __forceinline__ void tw_init(float2* tw, int tid) {
    for (int m = tid; m < 1024; m += 512) {
        float sv, cv;
        sincosf(-6.283185307179586f * (float)m / 4096.0f, &sv, &cv);
        tw[m] = make_float2(cv, sv);
    }
}

__device__ void do_fft4(float2* s, const float2* tw, int tid) {
    #pragma unroll 1
    for (int st = 0; st < 6; st++) {
        int Q  = 1 << (2*st);
        int sh = 10 - 2*st;
        #pragma unroll 1
        for (int idx = tid; idx < 1024; idx += 512) {
            int j    = idx & (Q - 1);
            int blk  = idx >> (2*st);
            int base = blk*(Q << 2) + j;
            float2 x0 = s[base];
            float2 x1 = s[base + Q];
            float2 x2 = s[base + 2*Q];
            float2 x3 = s[base + 3*Q];
            float2 w1 = tw[j << sh];
            float2 w2 = cmulf(w1, w1);
            float2 w3 = cmulf(w2, w1);
            float2 y1 = cmulf(w1, x1);
            float2 y2 = cmulf(w2, x2);
            float2 y3 = cmulf(w3, x3);
            float2 u0 = make_float2(x0.x + y2.x, x0.y + y2.y);
            float2 u1 = make_float2(x0.x - y2.x, x0.y - y2.y);
            float2 u2 = make_float2(y1.x + y3.x, y1.y + y3.y);
            float2 u3 = make_float2(y1.x - y3.x, y1.y - y3.y);
            s[base]       = make_float2(u0.x + u2.x, u0.y + u2.y);
            s[base + Q]   = make_float2(u1.x + u3.y, u1.y - u3.x);
            s[base + 2*Q] = make_float2(u0.x - u2.x, u0.y - u2.y);
            s[base + 3*Q] = make_float2(u1.x - u3.y, u1.y + u3.x);
        }
        __syncthreads();
    }
}

__global__ void __launch_bounds__(512) filters_kernel(
    const float* __restrict__ eig_vals, const float* __restrict__ eig_vecs,
    const float* __restrict__ w_filters, float2* __restrict__ Ffilt)
{
    __shared__ float2 s[NF4096];
    __shared__ float2 tw[1024];
    __shared__ float  wk[KK];
    int d = blockIdx.x, tid = threadIdx.x;
    if (tid < KK) wk[tid] = powf(eig_vals[tid], 0.25f) * w_filters[tid*DD + d];
    tw_init(tw, tid);
    for (int i = tid; i < NF4096; i += 512) s[i] = make_float2(0.f, 0.f);
    __syncthreads();
    for (int t = tid; t < LL; t += 512) {
        float f = 0.f;
        #pragma unroll
        for (int k = 0; k < KK; k++) f += eig_vecs[t*KK + k] * wk[k];
        s[rev4(t)] = make_float2(f, 0.f);
    }
    __syncthreads();
    do_fft4(s, tw, tid);
    for (int i = tid; i < NF4096; i += 512)
        Ffilt[(long long)d*NF4096 + i] = s[i];
}

// 2-for-1 packed conv with fused gather/scatter
__global__ void __launch_bounds__(512) conv3_kernel(
    const float* __restrict__ xi, const float2* __restrict__ Ffilt,
    float* __restrict__ stu)
{
    __shared__ float2 s[NF4096];
    __shared__ float2 tw[1024];
    int z = blockIdx.x, tid = threadIdx.x;
    int b = z >> 9, dp = z & 511;
    int d0 = 2*dp;
    const float* xib = xi + (long long)b*LL*DD + d0;
    float* stb = stu + (long long)b*LL*DD + d0;
    tw_init(tw, tid);
    for (int i = tid; i < NF4096; i += 512) s[i] = make_float2(0.f, 0.f);
    __syncthreads();
    for (int t = tid; t < LL; t += 512)
        s[rev4(t)] = *(const float2*)(xib + (long long)t*DD);
    __syncthreads();
    do_fft4(s, tw, tid);

    const float2* F0 = Ffilt + (long long)d0 * NF4096;
    const float2* F1 = F0 + NF4096;
    for (int i = tid; i < 2048; i += 512) {
        if (i == 0) {
            #pragma unroll
            for (int q = 0; q < 2; q++) {
                int idx = q * 2048;
                float2 Z = s[idx];
                float X1 = Z.x, X2 = Z.y;
                float2 f0 = F0[idx], f1 = F1[idx];
                float2 Y1 = make_float2(X1*f0.x, X1*f0.y);
                float2 Y2 = make_float2(X2*f1.x, X2*f1.y);
                s[idx] = make_float2(Y1.x - Y2.y, -(Y1.y + Y2.x));
            }
        } else {
            float2 Za = s[i], Zb = s[NF4096 - i];
            float2 X1 = make_float2(0.5f*(Za.x + Zb.x), 0.5f*(Za.y - Zb.y));
            float2 Dd = make_float2(Za.x - Zb.x, Za.y + Zb.y);
            float2 X2 = make_float2(0.5f*Dd.y, -0.5f*Dd.x);
            float2 f0 = F0[i], f1 = F1[i];
            float2 Y1 = make_float2(X1.x*f0.x - X1.y*f0.y, X1.x*f0.y + X1.y*f0.x);
            float2 Y2 = make_float2(X2.x*f1.x - X2.y*f1.y, X2.x*f1.y + X2.y*f1.x);
            s[i]          = make_float2(Y1.x - Y2.y, -(Y1.y + Y2.x));
            s[NF4096 - i] = make_float2(Y1.x + Y2.y, Y1.y - Y2.x);
        }
    }
    __syncthreads();
    float2 r[8];
    #pragma unroll
    for (int k = 0; k < 8; k++) r[k] = s[rev4(tid + k*512)];
    __syncthreads();
    #pragma unroll
    for (int k = 0; k < 8; k++) s[tid + k*512] = r[k];
    __syncthreads();
    do_fft4(s, tw, tid);
    const float inv = 1.0f / 4096.0f;
    for (int l = tid; l < LL; l += 512) {
        float2 w = make_float2(s[l].x * inv, -s[l].y * inv);
        *(float2*)(stb + (long long)l*DD) = w;
    }
}

// ---------------- LayerNorm with split-fp16 output ----------------
__global__ void __launch_bounds__(256) ln_split_kernel(
    const float* __restrict__ x, f16* __restrict__ yh, f16* __restrict__ yl,
    const float* __restrict__ sc, const float* __restrict__ bi)
{
    long long base = (long long)blockIdx.x * DD;
    int tid = threadIdx.x;
    float4 v = *(const float4*)(x + base + tid*4);
    float mean = block_sum256(v.x + v.y + v.z + v.w) * (1.0f/DD);
    float dx = v.x - mean, dy = v.y - mean, dz = v.z - mean, dw = v.w - mean;
    float var = block_sum256(dx*dx + dy*dy + dz*dz + dw*dw) * (1.0f/DD);
    float rstd = rsqrtf(var + 1e-6f);
    float4 s4 = *(const float4*)(sc + tid*4);
    float4 b4 = *(const float4*)(bi + tid*4);
    float o0 = dx*rstd*s4.x + b4.x;
    float o1 = dy*rstd*s4.y + b4.y;
    float o2 = dz*rstd*s4.z + b4.z;
    float o3 = dw*rstd*s4.w + b4.w;
    long long i = base + tid*4;
    f16 h, l;
    split2(o0, h, l); yh[i+0] = h; yl[i+0] = l;
    split2(o1, h, l); yh[i+1] = h; yl[i+1] = l;
    split2(o2, h, l); yh[i+2] = h; yl[i+2] = l;
    split2(o3, h, l); yh[i+3] = h; yl[i+3] = l;
}

// ---------------- launch ----------------
static void* symv(const void* s) { void* p = nullptr; cudaGetSymbolAddress(&p, s); return p; }

extern "C" void kernel_launch(void* const* d_in, const int* in_sizes, int n_in,
                              void* d_out, int out_size)
{
    const float* inputs    = (const float*)d_in[0];
    const float* eig_vals  = (const float*)d_in[1];
    const float* eig_vecs  = (const float*)d_in[2];
    const float* w_filters = (const float*)d_in[3];
    const float* w_inputs  = (const float*)d_in[4];
    const float* ln1_s     = (const float*)d_in[5];
    const float* ln1_b     = (const float*)d_in[6];
    const float* wq        = (const float*)d_in[7];
    const float* wk        = (const float*)d_in[8];
    const float* wv        = (const float*)d_in[9];
    const float* wo        = (const float*)d_in[10];
    const float* ln2_s     = (const float*)d_in[11];
    const float* ln2_b     = (const float*)d_in[12];
    const float* mlp_w1    = (const float*)d_in[13];
    const float* mlp_b1    = (const float*)d_in[14];
    const float* mlp_w2    = (const float*)d_in[15];
    const float* mlp_b2    = (const float*)d_in[16];
    float* out = (float*)d_out;

    float*  xi    = (float*)symv(g_xi);
    float2* Ffilt = (float2*)symv(g_Ffilt);
    float*  stu   = (float*)symv(g_stu);
    float*  xres  = (float*)symv(g_xres);

    f16 *inh=(f16*)symv(g_inh),    *inl=(f16*)symv(g_inl);
    f16 *x1h=(f16*)symv(g_x1h),    *x1l=(f16*)symv(g_x1l);
    f16 *qkvh=(f16*)symv(g_qkvh),  *qkvl=(f16*)symv(g_qkvl);
    f16 *vTh=(f16*)symv(g_vTh);
    f16 *ath=(f16*)symv(g_ath);
    f16 *y1h=(f16*)symv(g_y1h),    *y1l=(f16*)symv(g_y1l);
    f16 *hh =(f16*)symv(g_hh);
    f16 *wiT=(f16*)symv(g_wiT);
    f16 *wqkvT=(f16*)symv(g_wqkvT);
    f16 *woT=(f16*)symv(g_woT);
    f16 *w1T=(f16*)symv(g_w1T);
    f16 *w2T=(f16*)symv(g_w2T);

    const int SMG2 = 61440;   // PROD=2 stage x2
    const int SMG1 = 40960;   // PROD=1 stage x2
    const int SMFL = 55296;
    cudaFuncSetAttribute(gemm_fp16<2>, cudaFuncAttributeMaxDynamicSharedMemorySize, SMG2);
    cudaFuncSetAttribute(gemm_fp16<1>, cudaFuncAttributeMaxDynamicSharedMemorySize, SMG1);
    cudaFuncSetAttribute(flash_kernel, cudaFuncAttributeMaxDynamicSharedMemorySize, SMFL);

    dim3 t328(32, 8);

    // 1. filter spectrum per channel d
    filters_kernel<<<DD, 512>>>(eig_vals, eig_vecs, w_filters, Ffilt);

    // 2. split inputs; transpose-cast all weights to [N][K] hi (wq pre-scaled 1/8)
    split_kernel<<<(BL*DD)/1024, 256>>>(inputs, inh, inl);
    transpose_cast_kernel<<<dim3(32, 32, 1), t328>>>(w_inputs, wiT, DD, DD, 1.0f);
    transpose_cast_kernel<<<dim3(32, 32, 1), t328>>>(wq, wqkvT,           DD, DD, 0.125f);
    transpose_cast_kernel<<<dim3(32, 32, 1), t328>>>(wk, wqkvT + DD*DD,   DD, DD, 1.0f);
    transpose_cast_kernel<<<dim3(32, 32, 1), t328>>>(wv, wqkvT + 2*DD*DD, DD, DD, 1.0f);
    transpose_cast_kernel<<<dim3(32, 32, 1), t328>>>(wo, woT, DD, DD, 1.0f);
    transpose_cast_kernel<<<dim3(MLPD/32, DD/32, 1), t328>>>(mlp_w1, w1T, DD, MLPD, 1.0f);
    transpose_cast_kernel<<<dim3(DD/32, MLPD/32, 1), t328>>>(mlp_w2, w2T, MLPD, DD, 1.0f);

    // 3. xi = inputs @ w_inputs (2-product, f32 out for FFT)
    gemm_fp16<2><<<dim3(8, 64, 1), 256, SMG2>>>(
        inh, inl, wiT, xi, nullptr, nullptr,
        BL, DD, DD, DD, DD, DD, 1.0f, nullptr, nullptr, 0);

    // 4. spectral causal conv
    conv3_kernel<<<BB*DD/2, 512>>>(xi, Ffilt, stu);

    // 5. LN1 -> split x1
    ln_split_kernel<<<BL, 256>>>(stu, x1h, x1l, ln1_s, ln1_b);

    // 6. fused QKV gemm (2-product, N=3072), split out
    gemm_fp16<2><<<dim3(QKV/128, BL/128, 1), 256, SMG2>>>(
        x1h, x1l, wqkvT, nullptr, qkvh, qkvl,
        BL, QKV, DD, DD, DD, QKV, 1.0f, nullptr, nullptr, 8);

    // 7. V^T transpose from packed qkv (hi only)
    transpose_half_kernel<<<dim3(DD/32, LL/32, BB), t328>>>(qkvh + 2*DD, vTh);

    // 8. fused flash attention -> att (fp16 hi only)
    flash_kernel<<<dim3(LL/128, BB*HH), 256, SMFL>>>(
        qkvh, qkvl, vTh, ath);

    // 9. x = att @ wo + stu (1-product, f32)
    gemm_fp16<1><<<dim3(8, 64, 1), 256, SMG1>>>(
        ath, nullptr, woT, xres, nullptr, nullptr,
        BL, DD, DD, DD, DD, DD, 1.0f, nullptr, stu, 4);

    // 10. LN2 -> split y1
    ln_split_kernel<<<BL, 256>>>(xres, y1h, y1l, ln2_s, ln2_b);

    // 11. h = gelu(y1 @ w1 + b1) (2-product), cast out hi only
    gemm_fp16<2><<<dim3(MLPD/128, 64, 1), 256, SMG2>>>(
        y1h, y1l, w1T, nullptr, hh, nullptr,
        BL, MLPD, DD, DD, DD, MLPD, 1.0f, mlp_b1, nullptr, 11);

    // 12. out = h @ w2 + b2 + x (1-product, f32)
    gemm_fp16<1><<<dim3(8, 64, 1), 256, SMG1>>>(
        hh, nullptr, w2T, out, nullptr, nullptr,
        BL, DD, MLPD, MLPD, MLPD, DD, 1.0f, mlp_b2, xres, 5);
}

// round 15
// speedup vs baseline: 6.4849x; 1.1618x over previous
#include <cuda_runtime.h>
#include <cuda_fp16.h>
#include <math.h>
#include <stdint.h>

#define BB 4
#define LL 2048
#define DD 1024
#define HH 16
#define HDIM 64
#define KK 24
#define MLPD 4096
#define BL (BB*LL)
#define NF4096 4096
#define QKV (3*DD)

typedef __half f16;

// ---------------- scratch (device globals; allocation-free) ----------------
__device__ float  g_xi[BL*DD];
__device__ float2 g_Ffilt[(size_t)DD*NF4096];
__device__ float  g_stu[BL*DD];
__device__ float  g_xres[BL*DD];

__device__ f16 g_inh[BL*DD];
__device__ f16 g_x1h[BL*DD],  g_x1l[BL*DD];
__device__ f16 g_qkvh[(size_t)BL*QKV], g_qkvl[(size_t)BL*QKV];  // packed Q|K|V
__device__ f16 g_vTh[BL*DD];                         // [B,H*HD,L] (hi only)
__device__ f16 g_ath[BL*DD];                         // att (hi only)
__device__ f16 g_y1h[BL*DD];                         // y1 (hi only)
__device__ f16 g_hh[(size_t)BL*MLPD];                // h (hi only)
// transposed-cast weights [N][K] (hi only)
__device__ f16 g_wiT[DD*DD];
__device__ f16 g_wqkvT[(size_t)QKV*DD];
__device__ f16 g_woT[DD*DD];
__device__ f16 g_w1T[(size_t)DD*MLPD];
__device__ f16 g_w2T[(size_t)DD*MLPD];

// ---------------- helpers ----------------
__device__ __forceinline__ float gelu_f(float x) {
    float x3 = x*x*x;
    return 0.5f*x*(1.0f + tanhf(0.7978845608028654f*(x + 0.044715f*x3)));
}
__device__ __forceinline__ void split2(float v, f16 &h, f16 &l) {
    h = __float2half_rn(v);
    l = __float2half_rn(v - __half2float(h));
}
__device__ __forceinline__ uint32_t pack2(f16 a, f16 b) {
    return (uint32_t)__half_as_ushort(a) | ((uint32_t)__half_as_ushort(b) << 16);
}
__device__ __forceinline__ void cpa16(uint32_t s, const void* g) {
    asm volatile("cp.async.cg.shared.global [%0], [%1], 16;" :: "r"(s), "l"(g));
}
__device__ __forceinline__ void mma16816(float* c, const uint32_t* a, const uint32_t* b) {
    asm volatile("mma.sync.aligned.m16n8k16.row.col.f32.f16.f16.f32 "
                 "{%0,%1,%2,%3},{%4,%5,%6,%7},{%8,%9},{%0,%1,%2,%3};"
                 : "+f"(c[0]), "+f"(c[1]), "+f"(c[2]), "+f"(c[3])
                 : "r"(a[0]), "r"(a[1]), "r"(a[2]), "r"(a[3]),
                   "r"(b[0]), "r"(b[1]));
}
__device__ __forceinline__ void ldsm_x4(uint32_t* r, uint32_t saddr) {
    asm volatile("ldmatrix.sync.aligned.m8n8.x4.shared.b16 {%0,%1,%2,%3}, [%4];"
        : "=r"(r[0]), "=r"(r[1]), "=r"(r[2]), "=r"(r[3]) : "r"(saddr));
}
__device__ __forceinline__ float block_sum256(float v) {
    __shared__ float red[8];
    int lane = threadIdx.x & 31, w = threadIdx.x >> 5;
    #pragma unroll
    for (int o = 16; o; o >>= 1) v += __shfl_xor_sync(0xffffffffu, v, o);
    __syncthreads();
    if (lane == 0) red[w] = v;
    __syncthreads();
    if (threadIdx.x == 0) {
        float s = 0.f;
        #pragma unroll
        for (int i = 0; i < 8; i++) s += red[i];
        red[0] = s;
    }
    __syncthreads();
    return red[0];
}

// ---------------- split-fp16 tensor-core GEMM ----------------
// PROD=2: C = (Ah+Al)@Bh^T ; PROD=1: C = Ah@Bh^T. B always hi-only [N,K].
// Tile 128x128, 2 CTAs/SM, 2-stage cp.async, ldmatrix.
// mode: 1=bias, 2=gelu, 4=resid, 8=split-out (Clo null -> hi-only cast out)
template<int PROD>
__global__ void __launch_bounds__(256, 2) gemm_fp16(
    const f16* __restrict__ Ahi, const f16* __restrict__ Alo,
    const f16* __restrict__ Bh,
    float* __restrict__ C, f16* __restrict__ Chi, f16* __restrict__ Clo,
    int M, int N, int Kd, int lda, int ldb, int ldc,
    float alpha, const float* __restrict__ bias,
    const float* __restrict__ resid, int mode)
{
    constexpr int SP    = 40;
    constexpr int AH    = 128 * SP;
    constexpr int BOFF  = PROD * AH;
    constexpr int STAGE = BOFF + 128*SP;

    extern __shared__ __align__(16) char dsm[];
    uint32_t smem0 = (uint32_t)__cvta_generic_to_shared(dsm);

    int tid   = threadIdx.x;
    int mBase = blockIdx.y * 128, nBase = blockIdx.x * 128;

    const f16* pAh = Ahi + (long long)mBase * lda;
    const f16* pAl = (PROD == 2) ? (Alo + (long long)mBase * lda) : nullptr;
    const f16* pB  = Bh  + (long long)nBase * ldb;

    int warp = tid >> 5, lane = tid & 31;
    int wm = warp & 3, wn = warp >> 2;
    int g  = lane >> 2, tig = lane & 3;

    int aRow = wm*32 + (lane & 15);
    int aCol = (lane & 16) ? 8 : 0;
    int bRow = wn*64 + ((lane >> 4) << 3) + (lane & 7);
    int bCol = (lane & 8) ? 8 : 0;

    float acc[2][8][4];
    #pragma unroll
    for (int i = 0; i < 2; i++)
        #pragma unroll
        for (int j = 0; j < 8; j++)
            #pragma unroll
            for (int c = 0; c < 4; c++) acc[i][j][c] = 0.f;

    auto load_stage = [&](int buf, int k0) {
        int so = buf * STAGE;
        #pragma unroll
        for (int i = 0; i < 2; i++) {
            int ci = tid + i*256;
            int row = ci >> 2, seg = ci & 3;
            long long go = (long long)row*lda + k0 + seg*8;
            uint32_t sa = smem0 + 2*(so + row*SP + seg*8);
            cpa16(sa, pAh + go);
            if (PROD == 2) cpa16(sa + 2*AH, pAl + go);
        }
        #pragma unroll
        for (int i = 0; i < 2; i++) {
            int ci = tid + i*256;
            int row = ci >> 2, seg = ci & 3;
            long long go = (long long)row*ldb + k0 + seg*8;
            uint32_t sa = smem0 + 2*(so + BOFF + row*SP + seg*8);
            cpa16(sa, pB + go);
        }
        asm volatile("cp.async.commit_group;");
    };

    int nk = Kd >> 5;
    load_stage(0, 0);

    for (int ks = 0; ks < nk; ks++) {
        asm volatile("cp.async.wait_group 0;");
        __syncthreads();
        if (ks + 1 < nk) load_stage((ks+1)&1, (ks+1) << 5);
        int so = (ks & 1) * STAGE;

        #pragma unroll
        for (int kh = 0; kh < 2; kh++) {
            int kb = kh*16;
            uint32_t ah[2][4], al[2][4];
            #pragma unroll
            for (int mi = 0; mi < 2; mi++) {
                uint32_t ad = smem0 + 2*(so + (aRow + mi*16)*SP + kb + aCol);
                ldsm_x4(ah[mi], ad);
                if (PROD == 2) ldsm_x4(al[mi], ad + 2*AH);
            }
            #pragma unroll
            for (int nip = 0; nip < 4; nip++) {
                uint32_t bd = smem0 + 2*(so + BOFF + (bRow + nip*16)*SP + kb + bCol);
                uint32_t bh4[4];
                ldsm_x4(bh4, bd);
                #pragma unroll
                for (int q = 0; q < 2; q++) {
                    int ni = nip*2 + q;
                    #pragma unroll
                    for (int mi = 0; mi < 2; mi++) {
                        mma16816(acc[mi][ni], ah[mi], bh4 + 2*q);
                        if (PROD == 2) mma16816(acc[mi][ni], al[mi], bh4 + 2*q);
                    }
                }
            }
        }
    }

    bool hb = mode & 1, hg = mode & 2, hr = mode & 4, hs = mode & 8;
    bool hlo = hs && (Clo != nullptr);
    #pragma unroll
    for (int mi = 0; mi < 2; mi++) {
        int m0 = mBase + wm*32 + mi*16 + g;
        #pragma unroll
        for (int ni = 0; ni < 8; ni++) {
            int n = nBase + wn*64 + ni*8 + 2*tig;
            #pragma unroll
            for (int hrow = 0; hrow < 2; hrow++) {
                int m = m0 + hrow*8;
                float v0 = acc[mi][ni][hrow*2+0] * alpha;
                float v1 = acc[mi][ni][hrow*2+1] * alpha;
                if (hb) { v0 += bias[n]; v1 += bias[n+1]; }
                if (hg) { v0 = gelu_f(v0); v1 = gelu_f(v1); }
                long long o = (long long)m*ldc + n;
                if (hr) { v0 += resid[o]; v1 += resid[o+1]; }
                if (hs) {
                    f16 h0, l0, h1, l1;
                    split2(v0, h0, l0); split2(v1, h1, l1);
                    *(uint32_t*)(Chi + o) = pack2(h0, h1);
                    if (hlo) *(uint32_t*)(Clo + o) = pack2(l0, l1);
                } else {
                    C[o] = v0; C[o+1] = v1;
                }
            }
        }
    }
}

// ---------------- flash attention (QK 3-product, PV 1-product, 2 CTAs/SM) ----------------
// Q,K from packed qkv split; V^T hi-only; out att [B,L,D] fp16 hi only.
__global__ void __launch_bounds__(256, 2) flash_kernel(
    const f16* __restrict__ QKVh, const f16* __restrict__ QKVl,
    const f16* __restrict__ Vt,
    f16* __restrict__ Oh)
{
    constexpr int KSP = 72, VSP = 72;
    constexpr int KTH = 64*KSP;
    constexpr int VTH = 64*VSP;
    constexpr int STG = 2*KTH + VTH;

    extern __shared__ __align__(16) f16 sm[];
    uint32_t smem0 = (uint32_t)__cvta_generic_to_shared(sm);

    int tid = threadIdx.x, warp = tid >> 5, lane = tid & 31;
    int g = lane >> 2, tig = lane & 3;
    int qt = blockIdx.x, bh = blockIdx.y;
    int b = bh >> 4, h = bh & 15;
    long long baseQ = (long long)b*LL*QKV + (long long)(qt*128)*QKV + h*64;
    long long baseK = (long long)b*LL*QKV + DD + h*64;
    long long baseV = (long long)b*LL*DD + (long long)(h*64)*LL;
    long long baseO = (long long)b*LL*DD + (long long)(qt*128)*DD + h*64;

    int fRow = ((lane >> 4) << 3) + (lane & 7);
    int fCol = (lane & 8) ? 8 : 0;

    uint32_t qa_h[4][4], qa_l[4][4];
    {
        long long r0 = baseQ + (long long)(warp*16 + g)*QKV;
        long long r8 = r0 + 8*QKV;
        #pragma unroll
        for (int kf = 0; kf < 4; kf++) {
            int c = kf*16 + 2*tig;
            qa_h[kf][0] = *(const uint32_t*)(QKVh + r0 + c);
            qa_h[kf][1] = *(const uint32_t*)(QKVh + r8 + c);
            qa_h[kf][2] = *(const uint32_t*)(QKVh + r0 + c + 8);
            qa_h[kf][3] = *(const uint32_t*)(QKVh + r8 + c + 8);
            qa_l[kf][0] = *(const uint32_t*)(QKVl + r0 + c);
            qa_l[kf][1] = *(const uint32_t*)(QKVl + r8 + c);
            qa_l[kf][2] = *(const uint32_t*)(QKVl + r0 + c + 8);
            qa_l[kf][3] = *(const uint32_t*)(QKVl + r8 + c + 8);
        }
    }

    auto load_tiles = [&](int buf, int kt) {
        int so = buf * STG;
        #pragma unroll
        for (int i = 0; i < 2; i++) {
            int ci = tid + i*256;
            int row = ci >> 3, ch = ci & 7;
            long long go = baseK + (long long)(kt*64 + row)*QKV + ch*8;
            uint32_t sa = smem0 + 2*(so + row*KSP + ch*8);
            cpa16(sa,           QKVh + go);
            cpa16(sa + 2*KTH,   QKVl + go);
        }
        #pragma unroll
        for (int i = 0; i < 2; i++) {
            int ci = tid + i*256;
            int row = ci >> 3, ch = ci & 7;
            long long go = baseV + (long long)row*LL + kt*64 + ch*8;
            uint32_t sa = smem0 + 2*(so + 2*KTH + row*VSP + ch*8);
            cpa16(sa, Vt + go);
        }
        asm volatile("cp.async.commit_group;");
    };

    float m_r[2] = {-1e30f, -1e30f};
    float l_r[2] = {0.f, 0.f};
    float o[8][4];
    #pragma unroll
    for (int n = 0; n < 8; n++)
        #pragma unroll
        for (int c = 0; c < 4; c++) o[n][c] = 0.f;

    load_tiles(0, 0);

    for (int kt = 0; kt < 32; kt++) {
        asm volatile("cp.async.wait_group 0;");
        __syncthreads();
        if (kt + 1 < 32) load_tiles((kt+1)&1, kt+1);
        int so = (kt & 1) * STG;

        float s[8][4];
        #pragma unroll
        for (int n = 0; n < 8; n++)
            #pragma unroll
            for (int c = 0; c < 4; c++) s[n][c] = 0.f;

        #pragma unroll
        for (int kf = 0; kf < 4; kf++) {
            #pragma unroll
            for (int np = 0; np < 4; np++) {
                uint32_t kd = smem0 + 2*(so + (np*16 + fRow)*KSP + kf*16 + fCol);
                uint32_t kh4[4], kl4[4];
                ldsm_x4(kh4, kd);
                ldsm_x4(kl4, kd + 2*KTH);
                #pragma unroll
                for (int q = 0; q < 2; q++) {
                    int n = np*2 + q;
                    mma16816(s[n], qa_h[kf], kh4 + 2*q);
                    mma16816(s[n], qa_l[kf], kh4 + 2*q);
                    mma16816(s[n], qa_h[kf], kl4 + 2*q);
                }
            }
        }

        float mx0 = -1e30f, mx1 = -1e30f;
        #pragma unroll
        for (int n = 0; n < 8; n++) {
            mx0 = fmaxf(mx0, fmaxf(s[n][0], s[n][1]));
            mx1 = fmaxf(mx1, fmaxf(s[n][2], s[n][3]));
        }
        #pragma unroll
        for (int off = 1; off < 4; off <<= 1) {
            mx0 = fmaxf(mx0, __shfl_xor_sync(0xffffffffu, mx0, off));
            mx1 = fmaxf(mx1, __shfl_xor_sync(0xffffffffu, mx1, off));
        }
        float mn0 = fmaxf(m_r[0], mx0), mn1 = fmaxf(m_r[1], mx1);
        float sf0 = __expf(m_r[0] - mn0), sf1 = __expf(m_r[1] - mn1);
        m_r[0] = mn0; m_r[1] = mn1;
        float sum0 = 0.f, sum1 = 0.f;
        #pragma unroll
        for (int n = 0; n < 8; n++) {
            s[n][0] = __expf(s[n][0] - mn0); sum0 += s[n][0];
            s[n][1] = __expf(s[n][1] - mn0); sum0 += s[n][1];
            s[n][2] = __expf(s[n][2] - mn1); sum1 += s[n][2];
            s[n][3] = __expf(s[n][3] - mn1); sum1 += s[n][3];
        }
        #pragma unroll
        for (int off = 1; off < 4; off <<= 1) {
            sum0 += __shfl_xor_sync(0xffffffffu, sum0, off);
            sum1 += __shfl_xor_sync(0xffffffffu, sum1, off);
        }
        l_r[0] = l_r[0]*sf0 + sum0;
        l_r[1] = l_r[1]*sf1 + sum1;
        #pragma unroll
        for (int n = 0; n < 8; n++) {
            o[n][0] *= sf0; o[n][1] *= sf0;
            o[n][2] *= sf1; o[n][3] *= sf1;
        }

        #pragma unroll
        for (int kf2 = 0; kf2 < 4; kf2++) {
            uint32_t pa_h[4];
            #pragma unroll
            for (int q4 = 0; q4 < 2; q4++) {
                int t = 2*kf2 + q4;
                #pragma unroll
                for (int rr = 0; rr < 2; rr++) {
                    pa_h[q4*2+rr] = pack2(__float2half_rn(s[t][rr*2+0]),
                                          __float2half_rn(s[t][rr*2+1]));
                }
            }
            #pragma unroll
            for (int np2 = 0; np2 < 4; np2++) {
                uint32_t vd = smem0 + 2*(so + 2*KTH + (np2*16 + fRow)*VSP + kf2*16 + fCol);
                uint32_t vh4[4];
                ldsm_x4(vh4, vd);
                #pragma unroll
                for (int q = 0; q < 2; q++) {
                    int n = np2*2 + q;
                    mma16816(o[n], pa_h, vh4 + 2*q);
                }
            }
        }
    }

    float il0 = 1.f / l_r[0], il1 = 1.f / l_r[1];
    long long r0 = baseO + (long long)(warp*16 + g)*DD;
    long long r8 = r0 + 8*DD;
    #pragma unroll
    for (int n = 0; n < 8; n++) {
        int c = n*8 + 2*tig;
        *(uint32_t*)(Oh + r0 + c) = pack2(__float2half_rn(o[n][0]*il0),
                                          __float2half_rn(o[n][1]*il0));
        *(uint32_t*)(Oh + r8 + c) = pack2(__float2half_rn(o[n][2]*il1),
                                          __float2half_rn(o[n][3]*il1));
    }
}

// ---------------- transpose + cast weights (hi only, optional scale) ----------------
__global__ void transpose_cast_kernel(const float* __restrict__ in,
                                      f16* __restrict__ oh,
                                      int rows, int cols, float alpha)
{
    __shared__ float t[32][33];
    long long bo = (long long)blockIdx.z * rows * cols;
    int c0 = blockIdx.x * 32, r0 = blockIdx.y * 32;
    int tx = threadIdx.x, ty = threadIdx.y;
    #pragma unroll
    for (int i = 0; i < 32; i += 8)
        t[ty+i][tx] = in[bo + (long long)(r0+ty+i)*cols + (c0+tx)];
    __syncthreads();
    #pragma unroll
    for (int i = 0; i < 32; i += 8) {
        float v = t[tx][ty+i] * alpha;
        long long o = bo + (long long)(c0+ty+i)*rows + (r0+tx);
        oh[o] = __float2half_rn(v);
    }
}

// ---------------- f16 transpose: V slice of packed qkv -> V^T (hi only) ----------------
__global__ void transpose_half_kernel(const f16* __restrict__ inh,
                                      f16* __restrict__ oh)
{
    __shared__ unsigned short th[32][33];
    long long ibo = (long long)blockIdx.z * LL * QKV;
    long long obo = (long long)blockIdx.z * DD * LL;
    int c0 = blockIdx.x * 32, r0 = blockIdx.y * 32;
    int tx = threadIdx.x, ty = threadIdx.y;
    #pragma unroll
    for (int i = 0; i < 32; i += 8) {
        long long p = ibo + (long long)(r0+ty+i)*QKV + c0 + tx;
        th[ty+i][tx] = __half_as_ushort(inh[p]);
    }
    __syncthreads();
    #pragma unroll
    for (int i = 0; i < 32; i += 8) {
        long long o = obo + (long long)(c0+ty+i)*LL + r0 + tx;
        oh[o] = __ushort_as_half(th[tx][ty+i]);
    }
}

// ---------------- elementwise cast (hi only) ----------------
__global__ void cast_kernel(const float* __restrict__ x, f16* __restrict__ oh)
{
    long long i = ((long long)blockIdx.x * 256 + threadIdx.x) * 4;
    float4 v = *(const float4*)(x + i);
    *(uint32_t*)(oh + i)     = pack2(__float2half_rn(v.x), __float2half_rn(v.y));
    *(uint32_t*)(oh + i + 2) = pack2(__float2half_rn(v.z), __float2half_rn(v.w));
}

// ---------------- FFT (radix-4 DIT, n=4096, 512 threads) ----------------
__device__ __forceinline__ int rev4(int i) {
    int r = __brev(i) >> 20;
    return ((r & 0x555) << 1) | ((r >> 1) & 0x555);
}
__device__ __forceinline__ float2 cmulf(float2 a, float2 b) {
    return make_float2(a.x*b.x - a.y*b.y, a.x*b.y + a.y*b.x);
}
__device__ __forceinline__ void tw_init(float2* tw, int tid) {
    for (int m = tid; m < 1024; m += 512) {
        float sv, cv;
        sincosf(-6.283185307179586f * (float)m / 4096.0f, &sv, &cv);
        tw[m] = make_float2(cv, sv);
    }
}

__device__ void do_fft4(float2* s, const float2* tw, int tid) {
    #pragma unroll 1
    for (int st = 0; st < 6; st++) {
        int Q  = 1 << (2*st);
        int sh = 10 - 2*st;
        #pragma unroll 1
        for (int idx = tid; idx < 1024; idx += 512) {
            int j    = idx & (Q - 1);
            int blk  = idx >> (2*st);
            int base = blk*(Q << 2) + j;
            float2 x0 = s[base];
            float2 x1 = s[base + Q];
            float2 x2 = s[base + 2*Q];
            float2 x3 = s[base + 3*Q];
            float2 w1 = tw[j << sh];
            float2 w2 = cmulf(w1, w1);
            float2 w3 = cmulf(w2, w1);
            float2 y1 = cmulf(w1, x1);
            float2 y2 = cmulf(w2, x2);
            float2 y3 = cmulf(w3, x3);
            float2 u0 = make_float2(x0.x + y2.x, x0.y + y2.y);
            float2 u1 = make_float2(x0.x - y2.x, x0.y - y2.y);
            float2 u2 = make_float2(y1.x + y3.x, y1.y + y3.y);
            float2 u3 = make_float2(y1.x - y3.x, y1.y - y3.y);
            s[base]       = make_float2(u0.x + u2.x, u0.y + u2.y);
            s[base + Q]   = make_float2(u1.x + u3.y, u1.y - u3.x);
            s[base + 2*Q] = make_float2(u0.x - u2.x, u0.y - u2.y);
            s[base + 3*Q] = make_float2(u1.x - u3.y, u1.y + u3.x);
        }
        __syncthreads();
    }
}

__global__ void __launch_bounds__(512) filters_kernel(
    const float* __restrict__ eig_vals, const float* __restrict__ eig_vecs,
    const float* __restrict__ w_filters, float2* __restrict__ Ffilt)
{
    __shared__ float2 s[NF4096];
    __shared__ float2 tw[1024];
    __shared__ float  wk[KK];
    int d = blockIdx.x, tid = threadIdx.x;
    if (tid < KK) wk[tid] = powf(eig_vals[tid], 0.25f) * w_filters[tid*DD + d];
    tw_init(tw, tid);
    for (int i = tid; i < NF4096; i += 512) s[i] = make_float2(0.f, 0.f);
    __syncthreads();
    for (int t = tid; t < LL; t += 512) {
        float f = 0.f;
        #pragma unroll
        for (int k = 0; k < KK; k++) f += eig_vecs[t*KK + k] * wk[k];
        s[rev4(t)] = make_float2(f, 0.f);
    }
    __syncthreads();
    do_fft4(s, tw, tid);
    for (int i = tid; i < NF4096; i += 512)
        Ffilt[(long long)d*NF4096 + i] = s[i];
}

// 2-for-1 packed conv with fused gather/scatter
__global__ void __launch_bounds__(512) conv3_kernel(
    const float* __restrict__ xi, const float2* __restrict__ Ffilt,
    float* __restrict__ stu)
{
    __shared__ float2 s[NF4096];
    __shared__ float2 tw[1024];
    int z = blockIdx.x, tid = threadIdx.x;
    int b = z >> 9, dp = z & 511;
    int d0 = 2*dp;
    const float* xib = xi + (long long)b*LL*DD + d0;
    float* stb = stu + (long long)b*LL*DD + d0;
    tw_init(tw, tid);
    for (int i = tid; i < NF4096; i += 512) s[i] = make_float2(0.f, 0.f);
    __syncthreads();
    for (int t = tid; t < LL; t += 512)
        s[rev4(t)] = *(const float2*)(xib + (long long)t*DD);
    __syncthreads();
    do_fft4(s, tw, tid);

    const float2* F0 = Ffilt + (long long)d0 * NF4096;
    const float2* F1 = F0 + NF4096;
    for (int i = tid; i < 2048; i += 512) {
        if (i == 0) {
            #pragma unroll
            for (int q = 0; q < 2; q++) {
                int idx = q * 2048;
                float2 Z = s[idx];
                float X1 = Z.x, X2 = Z.y;
                float2 f0 = F0[idx], f1 = F1[idx];
                float2 Y1 = make_float2(X1*f0.x, X1*f0.y);
                float2 Y2 = make_float2(X2*f1.x, X2*f1.y);
                s[idx] = make_float2(Y1.x - Y2.y, -(Y1.y + Y2.x));
            }
        } else {
            float2 Za = s[i], Zb = s[NF4096 - i];
            float2 X1 = make_float2(0.5f*(Za.x + Zb.x), 0.5f*(Za.y - Zb.y));
            float2 Dd = make_float2(Za.x - Zb.x, Za.y + Zb.y);
            float2 X2 = make_float2(0.5f*Dd.y, -0.5f*Dd.x);
            float2 f0 = F0[i], f1 = F1[i];
            float2 Y1 = make_float2(X1.x*f0.x - X1.y*f0.y, X1.x*f0.y + X1.y*f0.x);
            float2 Y2 = make_float2(X2.x*f1.x - X2.y*f1.y, X2.x*f1.y + X2.y*f1.x);
            s[i]          = make_float2(Y1.x - Y2.y, -(Y1.y + Y2.x));
            s[NF4096 - i] = make_float2(Y1.x + Y2.y, Y1.y - Y2.x);
        }
    }
    __syncthreads();
    float2 r[8];
    #pragma unroll
    for (int k = 0; k < 8; k++) r[k] = s[rev4(tid + k*512)];
    __syncthreads();
    #pragma unroll
    for (int k = 0; k < 8; k++) s[tid + k*512] = r[k];
    __syncthreads();
    do_fft4(s, tw, tid);
    const float inv = 1.0f / 4096.0f;
    for (int l = tid; l < LL; l += 512) {
        float2 w = make_float2(s[l].x * inv, -s[l].y * inv);
        *(float2*)(stb + (long long)l*DD) = w;
    }
}

// ---------------- LayerNorm: split-fp16 output ----------------
__global__ void __launch_bounds__(256) ln_split_kernel(
    const float* __restrict__ x, f16* __restrict__ yh, f16* __restrict__ yl,
    const float* __restrict__ sc, const float* __restrict__ bi)
{
    long long base = (long long)blockIdx.x * DD;
    int tid = threadIdx.x;
    float4 v = *(const float4*)(x + base + tid*4);
    float mean = block_sum256(v.x + v.y + v.z + v.w) * (1.0f/DD);
    float dx = v.x - mean, dy = v.y - mean, dz = v.z - mean, dw = v.w - mean;
    float var = block_sum256(dx*dx + dy*dy + dz*dz + dw*dw) * (1.0f/DD);
    float rstd = rsqrtf(var + 1e-6f);
    float4 s4 = *(const float4*)(sc + tid*4);
    float4 b4 = *(const float4*)(bi + tid*4);
    float o0 = dx*rstd*s4.x + b4.x;
    float o1 = dy*rstd*s4.y + b4.y;
    float o2 = dz*rstd*s4.z + b4.z;
    float o3 = dw*rstd*s4.w + b4.w;
    long long i = base + tid*4;
    f16 h, l;
    split2(o0, h, l); yh[i+0] = h; yl[i+0] = l;
    split2(o1, h, l); yh[i+1] = h; yl[i+1] = l;
    split2(o2, h, l); yh[i+2] = h; yl[i+2] = l;
    split2(o3, h, l); yh[i+3] = h; yl[i+3] = l;
}

// ---------------- LayerNorm: cast-fp16 output (hi only) ----------------
__global__ void __launch_bounds__(256) ln_cast_kernel(
    const float* __restrict__ x, f16* __restrict__ yh,
    const float* __restrict__ sc, const float* __restrict__ bi)
{
    long long base = (long long)blockIdx.x * DD;
    int tid = threadIdx.x;
    float4 v = *(const float4*)(x + base + tid*4);
    float mean = block_sum256(v.x + v.y + v.z + v.w) * (1.0f/DD);
    float dx = v.x - mean, dy = v.y - mean, dz = v.z - mean, dw = v.w - mean;
    float var = block_sum256(dx*dx + dy*dy + dz*dz + dw*dw) * (1.0f/DD);
    float rstd = rsqrtf(var + 1e-6f);
    float4 s4 = *(const float4*)(sc + tid*4);
    float4 b4 = *(const float4*)(bi + tid*4);
    long long i = base + tid*4;
    *(uint32_t*)(yh + i)     = pack2(__float2half_rn(dx*rstd*s4.x + b4.x),
                                     __float2half_rn(dy*rstd*s4.y + b4.y));
    *(uint32_t*)(yh + i + 2) = pack2(__float2half_rn(dz*rstd*s4.z + b4.z),
                                     __float2half_rn(dw*rstd*s4.w + b4.w));
}

// ---------------- launch ----------------
static void* symv(const void* s) { void* p = nullptr; cudaGetSymbolAddress(&p, s); return p; }

extern "C" void kernel_launch(void* const* d_in, const int* in_sizes, int n_in,
                              void* d_out, int out_size)
{
    const float* inputs    = (const float*)d_in[0];
    const float* eig_vals  = (const float*)d_in[1];
    const float* eig_vecs  = (const float*)d_in[2];
    const float* w_filters = (const float*)d_in[3];
    const float* w_inputs  = (const float*)d_in[4];
    const float* ln1_s     = (const float*)d_in[5];
    const float* ln1_b     = (const float*)d_in[6];
    const float* wq        = (const float*)d_in[7];
    const float* wk        = (const float*)d_in[8];
    const float* wv        = (const float*)d_in[9];
    const float* wo        = (const float*)d_in[10];
    const float* ln2_s     = (const float*)d_in[11];
    const float* ln2_b     = (const float*)d_in[12];
    const float* mlp_w1    = (const float*)d_in[13];
    const float* mlp_b1    = (const float*)d_in[14];
    const float* mlp_w2    = (const float*)d_in[15];
    const float* mlp_b2    = (const float*)d_in[16];
    float* out = (float*)d_out;

    float*  xi    = (float*)symv(g_xi);
    float2* Ffilt = (float2*)symv(g_Ffilt);
    float*  stu   = (float*)symv(g_stu);
    float*  xres  = (float*)symv(g_xres);

    f16 *inh=(f16*)symv(g_inh);
    f16 *x1h=(f16*)symv(g_x1h),    *x1l=(f16*)symv(g_x1l);
    f16 *qkvh=(f16*)symv(g_qkvh),  *qkvl=(f16*)symv(g_qkvl);
    f16 *vTh=(f16*)symv(g_vTh);
    f16 *ath=(f16*)symv(g_ath);
    f16 *y1h=(f16*)symv(g_y1h);
    f16 *hh =(f16*)symv(g_hh);
    f16 *wiT=(f16*)symv(g_wiT);
    f16 *wqkvT=(f16*)symv(g_wqkvT);
    f16 *woT=(f16*)symv(g_woT);
    f16 *w1T=(f16*)symv(g_w1T);
    f16 *w2T=(f16*)symv(g_w2T);

    const int SMG2 = 61440;
    const int SMG1 = 40960;
    const int SMFL = 55296;
    cudaFuncSetAttribute(gemm_fp16<2>, cudaFuncAttributeMaxDynamicSharedMemorySize, SMG2);
    cudaFuncSetAttribute(gemm_fp16<1>, cudaFuncAttributeMaxDynamicSharedMemorySize, SMG1);
    cudaFuncSetAttribute(flash_kernel, cudaFuncAttributeMaxDynamicSharedMemorySize, SMFL);

    dim3 t328(32, 8);

    // 1. filter spectrum per channel d
    filters_kernel<<<DD, 512>>>(eig_vals, eig_vecs, w_filters, Ffilt);

    // 2. cast inputs (hi only); transpose-cast all weights (wq pre-scaled 1/8)
    cast_kernel<<<(BL*DD)/1024, 256>>>(inputs, inh);
    transpose_cast_kernel<<<dim3(32, 32, 1), t328>>>(w_inputs, wiT, DD, DD, 1.0f);
    transpose_cast_kernel<<<dim3(32, 32, 1), t328>>>(wq, wqkvT,           DD, DD, 0.125f);
    transpose_cast_kernel<<<dim3(32, 32, 1), t328>>>(wk, wqkvT + DD*DD,   DD, DD, 1.0f);
    transpose_cast_kernel<<<dim3(32, 32, 1), t328>>>(wv, wqkvT + 2*DD*DD, DD, DD, 1.0f);
    transpose_cast_kernel<<<dim3(32, 32, 1), t328>>>(wo, woT, DD, DD, 1.0f);
    transpose_cast_kernel<<<dim3(MLPD/32, DD/32, 1), t328>>>(mlp_w1, w1T, DD, MLPD, 1.0f);
    transpose_cast_kernel<<<dim3(DD/32, MLPD/32, 1), t328>>>(mlp_w2, w2T, MLPD, DD, 1.0f);

    // 3. xi = inputs @ w_inputs (1-product, f32 out for FFT)
    gemm_fp16<1><<<dim3(8, 64, 1), 256, SMG1>>>(
        inh, nullptr, wiT, xi, nullptr, nullptr,
        BL, DD, DD, DD, DD, DD, 1.0f, nullptr, nullptr, 0);

    // 4. spectral causal conv
    conv3_kernel<<<BB*DD/2, 512>>>(xi, Ffilt, stu);

    // 5. LN1 -> split x1 (feeds 2-product QKV)
    ln_split_kernel<<<BL, 256>>>(stu, x1h, x1l, ln1_s, ln1_b);

    // 6. fused QKV gemm (2-product, N=3072), split out
    gemm_fp16<2><<<dim3(QKV/128, BL/128, 1), 256, SMG2>>>(
        x1h, x1l, wqkvT, nullptr, qkvh, qkvl,
        BL, QKV, DD, DD, DD, QKV, 1.0f, nullptr, nullptr, 8);

    // 7. V^T transpose from packed qkv (hi only)
    transpose_half_kernel<<<dim3(DD/32, LL/32, BB), t328>>>(qkvh + 2*DD, vTh);

    // 8. fused flash attention -> att (fp16 hi only)
    flash_kernel<<<dim3(LL/128, BB*HH), 256, SMFL>>>(
        qkvh, qkvl, vTh, ath);

    // 9. x = att @ wo + stu (1-product, f32)
    gemm_fp16<1><<<dim3(8, 64, 1), 256, SMG1>>>(
        ath, nullptr, woT, xres, nullptr, nullptr,
        BL, DD, DD, DD, DD, DD, 1.0f, nullptr, stu, 4);

    // 10. LN2 -> cast y1 (hi only; feeds 1-product mlp1)
    ln_cast_kernel<<<BL, 256>>>(xres, y1h, ln2_s, ln2_b);

    // 11. h = gelu(y1 @ w1 + b1) (1-product), cast out hi only
    gemm_fp16<1><<<dim3(MLPD/128, 64, 1), 256, SMG1>>>(
        y1h, nullptr, w1T, nullptr, hh, nullptr,
        BL, MLPD, DD, DD, DD, MLPD, 1.0f, mlp_b1, nullptr, 11);

    // 12. out = h @ w2 + b2 + x (1-product, f32)
    gemm_fp16<1><<<dim3(8, 64, 1), 256, SMG1>>>(
        hh, nullptr, w2T, out, nullptr, nullptr,
        BL, DD, MLPD, MLPD, MLPD, DD, 1.0f, mlp_b2, xres, 5);
}

// round 16
// speedup vs baseline: 7.6927x; 1.1862x over previous
#include <cuda_runtime.h>
#include <cuda_fp16.h>
#include <math.h>
#include <stdint.h>

#define BB 4
#define LL 2048
#define DD 1024
#define HH 16
#define HDIM 64
#define KK 24
#define MLPD 4096
#define BL (BB*LL)
#define NF4096 4096
#define QKV (3*DD)

typedef __half f16;

// ---------------- scratch (device globals; allocation-free) ----------------
__device__ float  g_xi[BL*DD];
__device__ float2 g_Ffilt[(size_t)DD*NF4096];
__device__ float  g_stu[BL*DD];
__device__ float  g_xres[BL*DD];

__device__ f16 g_inh[BL*DD];
__device__ f16 g_x1h[BL*DD];
__device__ f16 g_qkvh[(size_t)BL*QKV];               // packed Q|K|V (hi only)
__device__ f16 g_vTh[BL*DD];                         // [B,H*HD,L]
__device__ f16 g_ath[BL*DD];
__device__ f16 g_y1h[BL*DD];
__device__ f16 g_hh[(size_t)BL*MLPD];
// transposed-cast weights [N][K]
__device__ f16 g_wiT[DD*DD];
__device__ f16 g_wqkvT[(size_t)QKV*DD];
__device__ f16 g_woT[DD*DD];
__device__ f16 g_w1T[(size_t)DD*MLPD];
__device__ f16 g_w2T[(size_t)DD*MLPD];

// ---------------- helpers ----------------
__device__ __forceinline__ float gelu_f(float x) {
    float x3 = x*x*x;
    return 0.5f*x*(1.0f + tanhf(0.7978845608028654f*(x + 0.044715f*x3)));
}
__device__ __forceinline__ uint32_t pack2(f16 a, f16 b) {
    return (uint32_t)__half_as_ushort(a) | ((uint32_t)__half_as_ushort(b) << 16);
}
__device__ __forceinline__ void cpa16(uint32_t s, const void* g) {
    asm volatile("cp.async.cg.shared.global [%0], [%1], 16;" :: "r"(s), "l"(g));
}
__device__ __forceinline__ void mma16816(float* c, const uint32_t* a, const uint32_t* b) {
    asm volatile("mma.sync.aligned.m16n8k16.row.col.f32.f16.f16.f32 "
                 "{%0,%1,%2,%3},{%4,%5,%6,%7},{%8,%9},{%0,%1,%2,%3};"
                 : "+f"(c[0]), "+f"(c[1]), "+f"(c[2]), "+f"(c[3])
                 : "r"(a[0]), "r"(a[1]), "r"(a[2]), "r"(a[3]),
                   "r"(b[0]), "r"(b[1]));
}
__device__ __forceinline__ void ldsm_x4(uint32_t* r, uint32_t saddr) {
    asm volatile("ldmatrix.sync.aligned.m8n8.x4.shared.b16 {%0,%1,%2,%3}, [%4];"
        : "=r"(r[0]), "=r"(r[1]), "=r"(r[2]), "=r"(r[3]) : "r"(saddr));
}
__device__ __forceinline__ float block_sum256(float v) {
    __shared__ float red[8];
    int lane = threadIdx.x & 31, w = threadIdx.x >> 5;
    #pragma unroll
    for (int o = 16; o; o >>= 1) v += __shfl_xor_sync(0xffffffffu, v, o);
    __syncthreads();
    if (lane == 0) red[w] = v;
    __syncthreads();
    if (threadIdx.x == 0) {
        float s = 0.f;
        #pragma unroll
        for (int i = 0; i < 8; i++) s += red[i];
        red[0] = s;
    }
    __syncthreads();
    return red[0];
}

// ---------------- fp16 tensor-core GEMM (1-product) ----------------
// C[M,N] = alpha*(Ah@Bh^T) (+bias/gelu/resid), out f32 or cast-fp16.
// Tile 128x128, 2 CTAs/SM, 2-stage cp.async, ldmatrix.
// mode: 1=bias, 2=gelu, 4=resid, 8=cast-fp16-out
__global__ void __launch_bounds__(256, 2) gemm_fp16(
    const f16* __restrict__ Ahi, const f16* __restrict__ Bh,
    float* __restrict__ C, f16* __restrict__ Chi,
    int M, int N, int Kd, int lda, int ldb, int ldc,
    float alpha, const float* __restrict__ bias,
    const float* __restrict__ resid, int mode)
{
    constexpr int SP    = 40;
    constexpr int AH    = 128 * SP;
    constexpr int STAGE = 2 * AH;        // A + B halves

    extern __shared__ __align__(16) char dsm[];
    uint32_t smem0 = (uint32_t)__cvta_generic_to_shared(dsm);

    int tid   = threadIdx.x;
    int mBase = blockIdx.y * 128, nBase = blockIdx.x * 128;

    const f16* pAh = Ahi + (long long)mBase * lda;
    const f16* pB  = Bh  + (long long)nBase * ldb;

    int warp = tid >> 5, lane = tid & 31;
    int wm = warp & 3, wn = warp >> 2;
    int g  = lane >> 2, tig = lane & 3;

    int aRow = wm*32 + (lane & 15);
    int aCol = (lane & 16) ? 8 : 0;
    int bRow = wn*64 + ((lane >> 4) << 3) + (lane & 7);
    int bCol = (lane & 8) ? 8 : 0;

    float acc[2][8][4];
    #pragma unroll
    for (int i = 0; i < 2; i++)
        #pragma unroll
        for (int j = 0; j < 8; j++)
            #pragma unroll
            for (int c = 0; c < 4; c++) acc[i][j][c] = 0.f;

    auto load_stage = [&](int buf, int k0) {
        int so = buf * STAGE;
        #pragma unroll
        for (int i = 0; i < 2; i++) {
            int ci = tid + i*256;
            int row = ci >> 2, seg = ci & 3;
            long long go = (long long)row*lda + k0 + seg*8;
            uint32_t sa = smem0 + 2*(so + row*SP + seg*8);
            cpa16(sa, pAh + go);
        }
        #pragma unroll
        for (int i = 0; i < 2; i++) {
            int ci = tid + i*256;
            int row = ci >> 2, seg = ci & 3;
            long long go = (long long)row*ldb + k0 + seg*8;
            uint32_t sa = smem0 + 2*(so + AH + row*SP + seg*8);
            cpa16(sa, pB + go);
        }
        asm volatile("cp.async.commit_group;");
    };

    int nk = Kd >> 5;
    load_stage(0, 0);

    for (int ks = 0; ks < nk; ks++) {
        asm volatile("cp.async.wait_group 0;");
        __syncthreads();
        if (ks + 1 < nk) load_stage((ks+1)&1, (ks+1) << 5);
        int so = (ks & 1) * STAGE;

        #pragma unroll
        for (int kh = 0; kh < 2; kh++) {
            int kb = kh*16;
            uint32_t ah[2][4];
            #pragma unroll
            for (int mi = 0; mi < 2; mi++) {
                uint32_t ad = smem0 + 2*(so + (aRow + mi*16)*SP + kb + aCol);
                ldsm_x4(ah[mi], ad);
            }
            #pragma unroll
            for (int nip = 0; nip < 4; nip++) {
                uint32_t bd = smem0 + 2*(so + AH + (bRow + nip*16)*SP + kb + bCol);
                uint32_t bh4[4];
                ldsm_x4(bh4, bd);
                #pragma unroll
                for (int q = 0; q < 2; q++) {
                    int ni = nip*2 + q;
                    #pragma unroll
                    for (int mi = 0; mi < 2; mi++)
                        mma16816(acc[mi][ni], ah[mi], bh4 + 2*q);
                }
            }
        }
    }

    bool hb = mode & 1, hg = mode & 2, hr = mode & 4, hs = mode & 8;
    #pragma unroll
    for (int mi = 0; mi < 2; mi++) {
        int m0 = mBase + wm*32 + mi*16 + g;
        #pragma unroll
        for (int ni = 0; ni < 8; ni++) {
            int n = nBase + wn*64 + ni*8 + 2*tig;
            #pragma unroll
            for (int hrow = 0; hrow < 2; hrow++) {
                int m = m0 + hrow*8;
                float v0 = acc[mi][ni][hrow*2+0] * alpha;
                float v1 = acc[mi][ni][hrow*2+1] * alpha;
                if (hb) { v0 += bias[n]; v1 += bias[n+1]; }
                if (hg) { v0 = gelu_f(v0); v1 = gelu_f(v1); }
                long long o = (long long)m*ldc + n;
                if (hr) { v0 += resid[o]; v1 += resid[o+1]; }
                if (hs) {
                    *(uint32_t*)(Chi + o) = pack2(__float2half_rn(v0),
                                                  __float2half_rn(v1));
                } else {
                    C[o] = v0; C[o+1] = v1;
                }
            }
        }
    }
}

// ---------------- flash attention (QK 1-product, PV 1-product, 2 CTAs/SM) ----------------
// Q,K from packed qkv [B,L,3072] hi-only; V^T hi-only; out att [B,L,D] fp16.
__global__ void __launch_bounds__(256, 2) flash_kernel(
    const f16* __restrict__ QKVh,
    const f16* __restrict__ Vt,
    f16* __restrict__ Oh)
{
    constexpr int KSP = 72, VSP = 72;
    constexpr int KTH = 64*KSP;
    constexpr int VTH = 64*VSP;
    constexpr int STG = KTH + VTH;       // 9216 halves = 18432 B / stage

    extern __shared__ __align__(16) f16 sm[];
    uint32_t smem0 = (uint32_t)__cvta_generic_to_shared(sm);

    int tid = threadIdx.x, warp = tid >> 5, lane = tid & 31;
    int g = lane >> 2, tig = lane & 3;
    int qt = blockIdx.x, bh = blockIdx.y;
    int b = bh >> 4, h = bh & 15;
    long long baseQ = (long long)b*LL*QKV + (long long)(qt*128)*QKV + h*64;
    long long baseK = (long long)b*LL*QKV + DD + h*64;
    long long baseV = (long long)b*LL*DD + (long long)(h*64)*LL;
    long long baseO = (long long)b*LL*DD + (long long)(qt*128)*DD + h*64;

    int fRow = ((lane >> 4) << 3) + (lane & 7);
    int fCol = (lane & 8) ? 8 : 0;

    uint32_t qa_h[4][4];
    {
        long long r0 = baseQ + (long long)(warp*16 + g)*QKV;
        long long r8 = r0 + 8*QKV;
        #pragma unroll
        for (int kf = 0; kf < 4; kf++) {
            int c = kf*16 + 2*tig;
            qa_h[kf][0] = *(const uint32_t*)(QKVh + r0 + c);
            qa_h[kf][1] = *(const uint32_t*)(QKVh + r8 + c);
            qa_h[kf][2] = *(const uint32_t*)(QKVh + r0 + c + 8);
            qa_h[kf][3] = *(const uint32_t*)(QKVh + r8 + c + 8);
        }
    }

    auto load_tiles = [&](int buf, int kt) {
        int so = buf * STG;
        #pragma unroll
        for (int i = 0; i < 2; i++) {            // K tile: 64 rows x 64 halves
            int ci = tid + i*256;
            int row = ci >> 3, ch = ci & 7;
            long long go = baseK + (long long)(kt*64 + row)*QKV + ch*8;
            uint32_t sa = smem0 + 2*(so + row*KSP + ch*8);
            cpa16(sa, QKVh + go);
        }
        #pragma unroll
        for (int i = 0; i < 2; i++) {            // V^T tile: 64 d x 64 L halves
            int ci = tid + i*256;
            int row = ci >> 3, ch = ci & 7;
            long long go = baseV + (long long)row*LL + kt*64 + ch*8;
            uint32_t sa = smem0 + 2*(so + KTH + row*VSP + ch*8);
            cpa16(sa, Vt + go);
        }
        asm volatile("cp.async.commit_group;");
    };

    float m_r[2] = {-1e30f, -1e30f};
    float l_r[2] = {0.f, 0.f};
    float o[8][4];
    #pragma unroll
    for (int n = 0; n < 8; n++)
        #pragma unroll
        for (int c = 0; c < 4; c++) o[n][c] = 0.f;

    load_tiles(0, 0);

    for (int kt = 0; kt < 32; kt++) {
        asm volatile("cp.async.wait_group 0;");
        __syncthreads();
        if (kt + 1 < 32) load_tiles((kt+1)&1, kt+1);
        int so = (kt & 1) * STG;

        float s[8][4];
        #pragma unroll
        for (int n = 0; n < 8; n++)
            #pragma unroll
            for (int c = 0; c < 4; c++) s[n][c] = 0.f;

        #pragma unroll
        for (int kf = 0; kf < 4; kf++) {
            #pragma unroll
            for (int np = 0; np < 4; np++) {
                uint32_t kd = smem0 + 2*(so + (np*16 + fRow)*KSP + kf*16 + fCol);
                uint32_t kh4[4];
                ldsm_x4(kh4, kd);
                #pragma unroll
                for (int q = 0; q < 2; q++)
                    mma16816(s[np*2+q], qa_h[kf], kh4 + 2*q);
            }
        }

        float mx0 = -1e30f, mx1 = -1e30f;
        #pragma unroll
        for (int n = 0; n < 8; n++) {
            mx0 = fmaxf(mx0, fmaxf(s[n][0], s[n][1]));
            mx1 = fmaxf(mx1, fmaxf(s[n][2], s[n][3]));
        }
        #pragma unroll
        for (int off = 1; off < 4; off <<= 1) {
            mx0 = fmaxf(mx0, __shfl_xor_sync(0xffffffffu, mx0, off));
            mx1 = fmaxf(mx1, __shfl_xor_sync(0xffffffffu, mx1, off));
        }
        float mn0 = fmaxf(m_r[0], mx0), mn1 = fmaxf(m_r[1], mx1);
        float sf0 = __expf(m_r[0] - mn0), sf1 = __expf(m_r[1] - mn1);
        m_r[0] = mn0; m_r[1] = mn1;
        float sum0 = 0.f, sum1 = 0.f;
        #pragma unroll
        for (int n = 0; n < 8; n++) {
            s[n][0] = __expf(s[n][0] - mn0); sum0 += s[n][0];
            s[n][1] = __expf(s[n][1] - mn0); sum0 += s[n][1];
            s[n][2] = __expf(s[n][2] - mn1); sum1 += s[n][2];
            s[n][3] = __expf(s[n][3] - mn1); sum1 += s[n][3];
        }
        #pragma unroll
        for (int off = 1; off < 4; off <<= 1) {
            sum0 += __shfl_xor_sync(0xffffffffu, sum0, off);
            sum1 += __shfl_xor_sync(0xffffffffu, sum1, off);
        }
        l_r[0] = l_r[0]*sf0 + sum0;
        l_r[1] = l_r[1]*sf1 + sum1;
        #pragma unroll
        for (int n = 0; n < 8; n++) {
            o[n][0] *= sf0; o[n][1] *= sf0;
            o[n][2] *= sf1; o[n][3] *= sf1;
        }

        #pragma unroll
        for (int kf2 = 0; kf2 < 4; kf2++) {
            uint32_t pa_h[4];
            #pragma unroll
            for (int q4 = 0; q4 < 2; q4++) {
                int t = 2*kf2 + q4;
                #pragma unroll
                for (int rr = 0; rr < 2; rr++) {
                    pa_h[q4*2+rr] = pack2(__float2half_rn(s[t][rr*2+0]),
                                          __float2half_rn(s[t][rr*2+1]));
                }
            }
            #pragma unroll
            for (int np2 = 0; np2 < 4; np2++) {
                uint32_t vd = smem0 + 2*(so + KTH + (np2*16 + fRow)*VSP + kf2*16 + fCol);
                uint32_t vh4[4];
                ldsm_x4(vh4, vd);
                #pragma unroll
                for (int q = 0; q < 2; q++)
                    mma16816(o[np2*2+q], pa_h, vh4 + 2*q);
            }
        }
    }

    float il0 = 1.f / l_r[0], il1 = 1.f / l_r[1];
    long long r0 = baseO + (long long)(warp*16 + g)*DD;
    long long r8 = r0 + 8*DD;
    #pragma unroll
    for (int n = 0; n < 8; n++) {
        int c = n*8 + 2*tig;
        *(uint32_t*)(Oh + r0 + c) = pack2(__float2half_rn(o[n][0]*il0),
                                          __float2half_rn(o[n][1]*il0));
        *(uint32_t*)(Oh + r8 + c) = pack2(__float2half_rn(o[n][2]*il1),
                                          __float2half_rn(o[n][3]*il1));
    }
}

// ---------------- transpose + cast weights ----------------
__global__ void transpose_cast_kernel(const float* __restrict__ in,
                                      f16* __restrict__ oh,
                                      int rows, int cols, float alpha)
{
    __shared__ float t[32][33];
    long long bo = (long long)blockIdx.z * rows * cols;
    int c0 = blockIdx.x * 32, r0 = blockIdx.y * 32;
    int tx = threadIdx.x, ty = threadIdx.y;
    #pragma unroll
    for (int i = 0; i < 32; i += 8)
        t[ty+i][tx] = in[bo + (long long)(r0+ty+i)*cols + (c0+tx)];
    __syncthreads();
    #pragma unroll
    for (int i = 0; i < 32; i += 8) {
        float v = t[tx][ty+i] * alpha;
        long long o = bo + (long long)(c0+ty+i)*rows + (r0+tx);
        oh[o] = __float2half_rn(v);
    }
}

// ---------------- f16 transpose: V slice of packed qkv -> V^T ----------------
__global__ void transpose_half_kernel(const f16* __restrict__ inh,
                                      f16* __restrict__ oh)
{
    __shared__ unsigned short th[32][33];
    long long ibo = (long long)blockIdx.z * LL * QKV;
    long long obo = (long long)blockIdx.z * DD * LL;
    int c0 = blockIdx.x * 32, r0 = blockIdx.y * 32;
    int tx = threadIdx.x, ty = threadIdx.y;
    #pragma unroll
    for (int i = 0; i < 32; i += 8) {
        long long p = ibo + (long long)(r0+ty+i)*QKV + c0 + tx;
        th[ty+i][tx] = __half_as_ushort(inh[p]);
    }
    __syncthreads();
    #pragma unroll
    for (int i = 0; i < 32; i += 8) {
        long long o = obo + (long long)(c0+ty+i)*LL + r0 + tx;
        oh[o] = __ushort_as_half(th[tx][ty+i]);
    }
}

// ---------------- elementwise cast ----------------
__global__ void cast_kernel(const float* __restrict__ x, f16* __restrict__ oh)
{
    long long i = ((long long)blockIdx.x * 256 + threadIdx.x) * 4;
    float4 v = *(const float4*)(x + i);
    *(uint32_t*)(oh + i)     = pack2(__float2half_rn(v.x), __float2half_rn(v.y));
    *(uint32_t*)(oh + i + 2) = pack2(__float2half_rn(v.z), __float2half_rn(v.w));
}

// ---------------- FFT (radix-4 DIT, n=4096, 512 threads) ----------------
__device__ __forceinline__ int rev4(int i) {
    int r = __brev(i) >> 20;
    return ((r & 0x555) << 1) | ((r >> 1) & 0x555);
}
__device__ __forceinline__ float2 cmulf(float2 a, float2 b) {
    return make_float2(a.x*b.x - a.y*b.y, a.x*b.y + a.y*b.x);
}
__device__ __forceinline__ void tw_init(float2* tw, int tid) {
    for (int m = tid; m < 1024; m += 512) {
        float sv, cv;
        sincosf(-6.283185307179586f * (float)m / 4096.0f, &sv, &cv);
        tw[m] = make_float2(cv, sv);
    }
}

__device__ void do_fft4(float2* s, const float2* tw, int tid) {
    #pragma unroll 1
    for (int st = 0; st < 6; st++) {
        int Q  = 1 << (2*st);
        int sh = 10 - 2*st;
        #pragma unroll 1
        for (int idx = tid; idx < 1024; idx += 512) {
            int j    = idx & (Q - 1);
            int blk  = idx >> (2*st);
            int base = blk*(Q << 2) + j;
            float2 x0 = s[base];
            float2 x1 = s[base + Q];
            float2 x2 = s[base + 2*Q];
            float2 x3 = s[base + 3*Q];
            float2 w1 = tw[j << sh];
            float2 w2 = cmulf(w1, w1);
            float2 w3 = cmulf(w2, w1);
            float2 y1 = cmulf(w1, x1);
            float2 y2 = cmulf(w2, x2);
            float2 y3 = cmulf(w3, x3);
            float2 u0 = make_float2(x0.x + y2.x, x0.y + y2.y);
            float2 u1 = make_float2(x0.x - y2.x, x0.y - y2.y);
            float2 u2 = make_float2(y1.x + y3.x, y1.y + y3.y);
            float2 u3 = make_float2(y1.x - y3.x, y1.y - y3.y);
            s[base]       = make_float2(u0.x + u2.x, u0.y + u2.y);
            s[base + Q]   = make_float2(u1.x + u3.y, u1.y - u3.x);
            s[base + 2*Q] = make_float2(u0.x - u2.x, u0.y - u2.y);
            s[base + 3*Q] = make_float2(u1.x - u3.y, u1.y + u3.x);
        }
        __syncthreads();
    }
}

__global__ void __launch_bounds__(512) filters_kernel(
    const float* __restrict__ eig_vals, const float* __restrict__ eig_vecs,
    const float* __restrict__ w_filters, float2* __restrict__ Ffilt)
{
    __shared__ float2 s[NF4096];
    __shared__ float2 tw[1024];
    __shared__ float  wk[KK];
    int d = blockIdx.x, tid = threadIdx.x;
    if (tid < KK) wk[tid] = powf(eig_vals[tid], 0.25f) * w_filters[tid*DD + d];
    tw_init(tw, tid);
    for (int i = tid; i < NF4096; i += 512) s[i] = make_float2(0.f, 0.f);
    __syncthreads();
    for (int t = tid; t < LL; t += 512) {
        float f = 0.f;
        #pragma unroll
        for (int k = 0; k < KK; k++) f += eig_vecs[t*KK + k] * wk[k];
        s[rev4(t)] = make_float2(f, 0.f);
    }
    __syncthreads();
    do_fft4(s, tw, tid);
    for (int i = tid; i < NF4096; i += 512)
        Ffilt[(long long)d*NF4096 + i] = s[i];
}

// 2-for-1 packed conv with fused gather/scatter
__global__ void __launch_bounds__(512) conv3_kernel(
    const float* __restrict__ xi, const float2* __restrict__ Ffilt,
    float* __restrict__ stu)
{
    __shared__ float2 s[NF4096];
    __shared__ float2 tw[1024];
    int z = blockIdx.x, tid = threadIdx.x;
    int b = z >> 9, dp = z & 511;
    int d0 = 2*dp;
    const float* xib = xi + (long long)b*LL*DD + d0;
    float* stb = stu + (long long)b*LL*DD + d0;
    tw_init(tw, tid);
    for (int i = tid; i < NF4096; i += 512) s[i] = make_float2(0.f, 0.f);
    __syncthreads();
    for (int t = tid; t < LL; t += 512)
        s[rev4(t)] = *(const float2*)(xib + (long long)t*DD);
    __syncthreads();
    do_fft4(s, tw, tid);

    const float2* F0 = Ffilt + (long long)d0 * NF4096;
    const float2* F1 = F0 + NF4096;
    for (int i = tid; i < 2048; i += 512) {
        if (i == 0) {
            #pragma unroll
            for (int q = 0; q < 2; q++) {
                int idx = q * 2048;
                float2 Z = s[idx];
                float X1 = Z.x, X2 = Z.y;
                float2 f0 = F0[idx], f1 = F1[idx];
                float2 Y1 = make_float2(X1*f0.x, X1*f0.y);
                float2 Y2 = make_float2(X2*f1.x, X2*f1.y);
                s[idx] = make_float2(Y1.x - Y2.y, -(Y1.y + Y2.x));
            }
        } else {
            float2 Za = s[i], Zb = s[NF4096 - i];
            float2 X1 = make_float2(0.5f*(Za.x + Zb.x), 0.5f*(Za.y - Zb.y));
            float2 Dd = make_float2(Za.x - Zb.x, Za.y + Zb.y);
            float2 X2 = make_float2(0.5f*Dd.y, -0.5f*Dd.x);
            float2 f0 = F0[i], f1 = F1[i];
            float2 Y1 = make_float2(X1.x*f0.x - X1.y*f0.y, X1.x*f0.y + X1.y*f0.x);
            float2 Y2 = make_float2(X2.x*f1.x - X2.y*f1.y, X2.x*f1.y + X2.y*f1.x);
            s[i]          = make_float2(Y1.x - Y2.y, -(Y1.y + Y2.x));
            s[NF4096 - i] = make_float2(Y1.x + Y2.y, Y1.y - Y2.x);
        }
    }
    __syncthreads();
    float2 r[8];
    #pragma unroll
    for (int k = 0; k < 8; k++) r[k] = s[rev4(tid + k*512)];
    __syncthreads();
    #pragma unroll
    for (int k = 0; k < 8; k++) s[tid + k*512] = r[k];
    __syncthreads();
    do_fft4(s, tw, tid);
    const float inv = 1.0f / 4096.0f;
    for (int l = tid; l < LL; l += 512) {
        float2 w = make_float2(s[l].x * inv, -s[l].y * inv);
        *(float2*)(stb + (long long)l*DD) = w;
    }
}

// ---------------- LayerNorm: cast-fp16 output ----------------
__global__ void __launch_bounds__(256) ln_cast_kernel(
    const float* __restrict__ x, f16* __restrict__ yh,
    const float* __restrict__ sc, const float* __restrict__ bi)
{
    long long base = (long long)blockIdx.x * DD;
    int tid = threadIdx.x;
    float4 v = *(const float4*)(x + base + tid*4);
    float mean = block_sum256(v.x + v.y + v.z + v.w) * (1.0f/DD);
    float dx = v.x - mean, dy = v.y - mean, dz = v.z - mean, dw = v.w - mean;
    float var = block_sum256(dx*dx + dy*dy + dz*dz + dw*dw) * (1.0f/DD);
    float rstd = rsqrtf(var + 1e-6f);
    float4 s4 = *(const float4*)(sc + tid*4);
    float4 b4 = *(const float4*)(bi + tid*4);
    long long i = base + tid*4;
    *(uint32_t*)(yh + i)     = pack2(__float2half_rn(dx*rstd*s4.x + b4.x),
                                     __float2half_rn(dy*rstd*s4.y + b4.y));
    *(uint32_t*)(yh + i + 2) = pack2(__float2half_rn(dz*rstd*s4.z + b4.z),
                                     __float2half_rn(dw*rstd*s4.w + b4.w));
}

// ---------------- launch ----------------
static void* symv(const void* s) { void* p = nullptr; cudaGetSymbolAddress(&p, s); return p; }

extern "C" void kernel_launch(void* const* d_in, const int* in_sizes, int n_in,
                              void* d_out, int out_size)
{
    const float* inputs    = (const float*)d_in[0];
    const float* eig_vals  = (const float*)d_in[1];
    const float* eig_vecs  = (const float*)d_in[2];
    const float* w_filters = (const float*)d_in[3];
    const float* w_inputs  = (const float*)d_in[4];
    const float* ln1_s     = (const float*)d_in[5];
    const float* ln1_b     = (const float*)d_in[6];
    const float* wq        = (const float*)d_in[7];
    const float* wk        = (const float*)d_in[8];
    const float* wv        = (const float*)d_in[9];
    const float* wo        = (const float*)d_in[10];
    const float* ln2_s     = (const float*)d_in[11];
    const float* ln2_b     = (const float*)d_in[12];
    const float* mlp_w1    = (const float*)d_in[13];
    const float* mlp_b1    = (const float*)d_in[14];
    const float* mlp_w2    = (const float*)d_in[15];
    const float* mlp_b2    = (const float*)d_in[16];
    float* out = (float*)d_out;

    float*  xi    = (float*)symv(g_xi);
    float2* Ffilt = (float2*)symv(g_Ffilt);
    float*  stu   = (float*)symv(g_stu);
    float*  xres  = (float*)symv(g_xres);

    f16 *inh=(f16*)symv(g_inh);
    f16 *x1h=(f16*)symv(g_x1h);
    f16 *qkvh=(f16*)symv(g_qkvh);
    f16 *vTh=(f16*)symv(g_vTh);
    f16 *ath=(f16*)symv(g_ath);
    f16 *y1h=(f16*)symv(g_y1h);
    f16 *hh =(f16*)symv(g_hh);
    f16 *wiT=(f16*)symv(g_wiT);
    f16 *wqkvT=(f16*)symv(g_wqkvT);
    f16 *woT=(f16*)symv(g_woT);
    f16 *w1T=(f16*)symv(g_w1T);
    f16 *w2T=(f16*)symv(g_w2T);

    const int SMG1 = 40960;
    const int SMFL = 36864;
    cudaFuncSetAttribute(gemm_fp16,    cudaFuncAttributeMaxDynamicSharedMemorySize, SMG1);
    cudaFuncSetAttribute(flash_kernel, cudaFuncAttributeMaxDynamicSharedMemorySize, SMFL);

    dim3 t328(32, 8);

    // 1. filter spectrum per channel d
    filters_kernel<<<DD, 512>>>(eig_vals, eig_vecs, w_filters, Ffilt);

    // 2. cast inputs; transpose-cast all weights (wq pre-scaled 1/8)
    cast_kernel<<<(BL*DD)/1024, 256>>>(inputs, inh);
    transpose_cast_kernel<<<dim3(32, 32, 1), t328>>>(w_inputs, wiT, DD, DD, 1.0f);
    transpose_cast_kernel<<<dim3(32, 32, 1), t328>>>(wq, wqkvT,           DD, DD, 0.125f);
    transpose_cast_kernel<<<dim3(32, 32, 1), t328>>>(wk, wqkvT + DD*DD,   DD, DD, 1.0f);
    transpose_cast_kernel<<<dim3(32, 32, 1), t328>>>(wv, wqkvT + 2*DD*DD, DD, DD, 1.0f);
    transpose_cast_kernel<<<dim3(32, 32, 1), t328>>>(wo, woT, DD, DD, 1.0f);
    transpose_cast_kernel<<<dim3(MLPD/32, DD/32, 1), t328>>>(mlp_w1, w1T, DD, MLPD, 1.0f);
    transpose_cast_kernel<<<dim3(DD/32, MLPD/32, 1), t328>>>(mlp_w2, w2T, MLPD, DD, 1.0f);

    // 3. xi = inputs @ w_inputs (f32 out for FFT)
    gemm_fp16<<<dim3(8, 64, 1), 256, SMG1>>>(
        inh, wiT, xi, nullptr,
        BL, DD, DD, DD, DD, DD, 1.0f, nullptr, nullptr, 0);

    // 4. spectral causal conv
    conv3_kernel<<<BB*DD/2, 512>>>(xi, Ffilt, stu);

    // 5. LN1 -> cast x1
    ln_cast_kernel<<<BL, 256>>>(stu, x1h, ln1_s, ln1_b);

    // 6. fused QKV gemm (N=3072), cast out
    gemm_fp16<<<dim3(QKV/128, BL/128, 1), 256, SMG1>>>(
        x1h, wqkvT, nullptr, qkvh,
        BL, QKV, DD, DD, DD, QKV, 1.0f, nullptr, nullptr, 8);

    // 7. V^T transpose from packed qkv
    transpose_half_kernel<<<dim3(DD/32, LL/32, BB), t328>>>(qkvh + 2*DD, vTh);

    // 8. fused flash attention -> att (fp16)
    flash_kernel<<<dim3(LL/128, BB*HH), 256, SMFL>>>(qkvh, vTh, ath);

    // 9. x = att @ wo + stu (f32)
    gemm_fp16<<<dim3(8, 64, 1), 256, SMG1>>>(
        ath, woT, xres, nullptr,
        BL, DD, DD, DD, DD, DD, 1.0f, nullptr, stu, 4);

    // 10. LN2 -> cast y1
    ln_cast_kernel<<<BL, 256>>>(xres, y1h, ln2_s, ln2_b);

    // 11. h = gelu(y1 @ w1 + b1), cast out
    gemm_fp16<<<dim3(MLPD/128, 64, 1), 256, SMG1>>>(
        y1h, w1T, nullptr, hh,
        BL, MLPD, DD, DD, DD, MLPD, 1.0f, mlp_b1, nullptr, 11);

    // 12. out = h @ w2 + b2 + x (f32)
    gemm_fp16<<<dim3(8, 64, 1), 256, SMG1>>>(
        hh, w2T, out, nullptr,
        BL, DD, MLPD, MLPD, MLPD, DD, 1.0f, mlp_b2, xres, 5);
}

// round 17
// speedup vs baseline: 7.9614x; 1.0349x over previous
#include <cuda_runtime.h>
#include <cuda_fp16.h>
#include <math.h>
#include <stdint.h>

#define BB 4
#define LL 2048
#define DD 1024
#define HH 16
#define HDIM 64
#define KK 24
#define MLPD 4096
#define BL (BB*LL)
#define NF4096 4096
#define QKV (3*DD)

typedef __half f16;

// ---------------- scratch (device globals; allocation-free) ----------------
__device__ float  g_xi[BL*DD];
__device__ float2 g_Ffilt[(size_t)DD*NF4096];
__device__ float  g_stu[BL*DD];
__device__ float  g_xres[BL*DD];

__device__ f16 g_inh[BL*DD];
__device__ f16 g_x1h[BL*DD];
__device__ f16 g_qkvh[(size_t)BL*QKV];               // packed Q|K|V
__device__ f16 g_vTh[BL*DD];                         // [B,H*HD,L]
__device__ f16 g_ath[BL*DD];
__device__ f16 g_y1h[BL*DD];
__device__ f16 g_hh[(size_t)BL*MLPD];
// transposed-cast weights [N][K]
__device__ f16 g_wiT[DD*DD];
__device__ f16 g_wqkvT[(size_t)QKV*DD];
__device__ f16 g_woT[DD*DD];
__device__ f16 g_w1T[(size_t)DD*MLPD];
__device__ f16 g_w2T[(size_t)DD*MLPD];

// ---------------- helpers ----------------
__device__ __forceinline__ float gelu_f(float x) {
    float x3 = x*x*x;
    return 0.5f*x*(1.0f + tanhf(0.7978845608028654f*(x + 0.044715f*x3)));
}
__device__ __forceinline__ uint32_t pack2(f16 a, f16 b) {
    return (uint32_t)__half_as_ushort(a) | ((uint32_t)__half_as_ushort(b) << 16);
}
__device__ __forceinline__ void cpa16(uint32_t s, const void* g) {
    asm volatile("cp.async.cg.shared.global [%0], [%1], 16;" :: "r"(s), "l"(g));
}
__device__ __forceinline__ void mma16816(float* c, const uint32_t* a, const uint32_t* b) {
    asm volatile("mma.sync.aligned.m16n8k16.row.col.f32.f16.f16.f32 "
                 "{%0,%1,%2,%3},{%4,%5,%6,%7},{%8,%9},{%0,%1,%2,%3};"
                 : "+f"(c[0]), "+f"(c[1]), "+f"(c[2]), "+f"(c[3])
                 : "r"(a[0]), "r"(a[1]), "r"(a[2]), "r"(a[3]),
                   "r"(b[0]), "r"(b[1]));
}
__device__ __forceinline__ void ldsm_x4(uint32_t* r, uint32_t saddr) {
    asm volatile("ldmatrix.sync.aligned.m8n8.x4.shared.b16 {%0,%1,%2,%3}, [%4];"
        : "=r"(r[0]), "=r"(r[1]), "=r"(r[2]), "=r"(r[3]) : "r"(saddr));
}
__device__ __forceinline__ float block_sum256(float v) {
    __shared__ float red[8];
    int lane = threadIdx.x & 31, w = threadIdx.x >> 5;
    #pragma unroll
    for (int o = 16; o; o >>= 1) v += __shfl_xor_sync(0xffffffffu, v, o);
    __syncthreads();
    if (lane == 0) red[w] = v;
    __syncthreads();
    if (threadIdx.x == 0) {
        float s = 0.f;
        #pragma unroll
        for (int i = 0; i < 8; i++) s += red[i];
        red[0] = s;
    }
    __syncthreads();
    return red[0];
}

// ---------------- fp16 tensor-core GEMM (1-product, 3-stage pipeline) ----------------
// C[M,N] = alpha*(Ah@Bh^T) (+bias/gelu/resid), out f32 or cast-fp16.
// Tile 128x128, 2 CTAs/SM, 3-stage cp.async ring, ldmatrix.
// mode: 1=bias, 2=gelu, 4=resid, 8=cast-fp16-out
__global__ void __launch_bounds__(256, 2) gemm_fp16(
    const f16* __restrict__ Ahi, const f16* __restrict__ Bh,
    float* __restrict__ C, f16* __restrict__ Chi,
    int M, int N, int Kd, int lda, int ldb, int ldc,
    float alpha, const float* __restrict__ bias,
    const float* __restrict__ resid, int mode)
{
    constexpr int SP    = 40;
    constexpr int AH    = 128 * SP;
    constexpr int STAGE = 2 * AH;        // A + B halves (20480 B)

    extern __shared__ __align__(16) char dsm[];
    uint32_t smem0 = (uint32_t)__cvta_generic_to_shared(dsm);

    int tid   = threadIdx.x;
    int mBase = blockIdx.y * 128, nBase = blockIdx.x * 128;

    const f16* pAh = Ahi + (long long)mBase * lda;
    const f16* pB  = Bh  + (long long)nBase * ldb;

    int warp = tid >> 5, lane = tid & 31;
    int wm = warp & 3, wn = warp >> 2;
    int g  = lane >> 2, tig = lane & 3;

    int aRow = wm*32 + (lane & 15);
    int aCol = (lane & 16) ? 8 : 0;
    int bRow = wn*64 + ((lane >> 4) << 3) + (lane & 7);
    int bCol = (lane & 8) ? 8 : 0;

    float acc[2][8][4];
    #pragma unroll
    for (int i = 0; i < 2; i++)
        #pragma unroll
        for (int j = 0; j < 8; j++)
            #pragma unroll
            for (int c = 0; c < 4; c++) acc[i][j][c] = 0.f;

    auto load_stage = [&](int buf, int k0) {
        int so = buf * STAGE;
        #pragma unroll
        for (int i = 0; i < 2; i++) {
            int ci = tid + i*256;
            int row = ci >> 2, seg = ci & 3;
            long long go = (long long)row*lda + k0 + seg*8;
            uint32_t sa = smem0 + 2*(so + row*SP + seg*8);
            cpa16(sa, pAh + go);
        }
        #pragma unroll
        for (int i = 0; i < 2; i++) {
            int ci = tid + i*256;
            int row = ci >> 2, seg = ci & 3;
            long long go = (long long)row*ldb + k0 + seg*8;
            uint32_t sa = smem0 + 2*(so + AH + row*SP + seg*8);
            cpa16(sa, pB + go);
        }
        asm volatile("cp.async.commit_group;");
    };

    int nk = Kd >> 5;
    load_stage(0, 0);
    load_stage(1, 32);

    int buf = 0;
    for (int ks = 0; ks < nk; ks++) {
        if (ks + 1 < nk) asm volatile("cp.async.wait_group 1;");
        else             asm volatile("cp.async.wait_group 0;");
        __syncthreads();
        if (ks + 2 < nk) {
            int nb = buf + 2; if (nb >= 3) nb -= 3;
            load_stage(nb, (ks+2) << 5);
        }
        int so = buf * STAGE;

        #pragma unroll
        for (int kh = 0; kh < 2; kh++) {
            int kb = kh*16;
            uint32_t ah[2][4];
            #pragma unroll
            for (int mi = 0; mi < 2; mi++) {
                uint32_t ad = smem0 + 2*(so + (aRow + mi*16)*SP + kb + aCol);
                ldsm_x4(ah[mi], ad);
            }
            #pragma unroll
            for (int nip = 0; nip < 4; nip++) {
                uint32_t bd = smem0 + 2*(so + AH + (bRow + nip*16)*SP + kb + bCol);
                uint32_t bh4[4];
                ldsm_x4(bh4, bd);
                #pragma unroll
                for (int q = 0; q < 2; q++) {
                    int ni = nip*2 + q;
                    #pragma unroll
                    for (int mi = 0; mi < 2; mi++)
                        mma16816(acc[mi][ni], ah[mi], bh4 + 2*q);
                }
            }
        }
        buf++; if (buf >= 3) buf = 0;
    }

    bool hb = mode & 1, hg = mode & 2, hr = mode & 4, hs = mode & 8;
    #pragma unroll
    for (int mi = 0; mi < 2; mi++) {
        int m0 = mBase + wm*32 + mi*16 + g;
        #pragma unroll
        for (int ni = 0; ni < 8; ni++) {
            int n = nBase + wn*64 + ni*8 + 2*tig;
            #pragma unroll
            for (int hrow = 0; hrow < 2; hrow++) {
                int m = m0 + hrow*8;
                float v0 = acc[mi][ni][hrow*2+0] * alpha;
                float v1 = acc[mi][ni][hrow*2+1] * alpha;
                if (hb) { v0 += bias[n]; v1 += bias[n+1]; }
                if (hg) { v0 = gelu_f(v0); v1 = gelu_f(v1); }
                long long o = (long long)m*ldc + n;
                if (hr) {
                    float2 rr = *(const float2*)(resid + o);
                    v0 += rr.x; v1 += rr.y;
                }
                if (hs) {
                    *(uint32_t*)(Chi + o) = pack2(__float2half_rn(v0),
                                                  __float2half_rn(v1));
                } else {
                    *(float2*)(C + o) = make_float2(v0, v1);
                }
            }
        }
    }
}

// ---------------- flash attention (1-product, 3-stage pipeline, 2 CTAs/SM) ----------------
__global__ void __launch_bounds__(256, 2) flash_kernel(
    const f16* __restrict__ QKVh,
    const f16* __restrict__ Vt,
    f16* __restrict__ Oh)
{
    constexpr int KSP = 72, VSP = 72;
    constexpr int KTH = 64*KSP;
    constexpr int VTH = 64*VSP;
    constexpr int STG = KTH + VTH;       // 9216 halves = 18432 B / stage

    extern __shared__ __align__(16) f16 sm[];
    uint32_t smem0 = (uint32_t)__cvta_generic_to_shared(sm);

    int tid = threadIdx.x, warp = tid >> 5, lane = tid & 31;
    int g = lane >> 2, tig = lane & 3;
    int qt = blockIdx.x, bh = blockIdx.y;
    int b = bh >> 4, h = bh & 15;
    long long baseQ = (long long)b*LL*QKV + (long long)(qt*128)*QKV + h*64;
    long long baseK = (long long)b*LL*QKV + DD + h*64;
    long long baseV = (long long)b*LL*DD + (long long)(h*64)*LL;
    long long baseO = (long long)b*LL*DD + (long long)(qt*128)*DD + h*64;

    int fRow = ((lane >> 4) << 3) + (lane & 7);
    int fCol = (lane & 8) ? 8 : 0;

    uint32_t qa_h[4][4];
    {
        long long r0 = baseQ + (long long)(warp*16 + g)*QKV;
        long long r8 = r0 + 8*QKV;
        #pragma unroll
        for (int kf = 0; kf < 4; kf++) {
            int c = kf*16 + 2*tig;
            qa_h[kf][0] = *(const uint32_t*)(QKVh + r0 + c);
            qa_h[kf][1] = *(const uint32_t*)(QKVh + r8 + c);
            qa_h[kf][2] = *(const uint32_t*)(QKVh + r0 + c + 8);
            qa_h[kf][3] = *(const uint32_t*)(QKVh + r8 + c + 8);
        }
    }

    auto load_tiles = [&](int buf, int kt) {
        int so = buf * STG;
        #pragma unroll
        for (int i = 0; i < 2; i++) {
            int ci = tid + i*256;
            int row = ci >> 3, ch = ci & 7;
            long long go = baseK + (long long)(kt*64 + row)*QKV + ch*8;
            uint32_t sa = smem0 + 2*(so + row*KSP + ch*8);
            cpa16(sa, QKVh + go);
        }
        #pragma unroll
        for (int i = 0; i < 2; i++) {
            int ci = tid + i*256;
            int row = ci >> 3, ch = ci & 7;
            long long go = baseV + (long long)row*LL + kt*64 + ch*8;
            uint32_t sa = smem0 + 2*(so + KTH + row*VSP + ch*8);
            cpa16(sa, Vt + go);
        }
        asm volatile("cp.async.commit_group;");
    };

    float m_r[2] = {-1e30f, -1e30f};
    float l_r[2] = {0.f, 0.f};
    float o[8][4];
    #pragma unroll
    for (int n = 0; n < 8; n++)
        #pragma unroll
        for (int c = 0; c < 4; c++) o[n][c] = 0.f;

    load_tiles(0, 0);
    load_tiles(1, 1);

    int buf = 0;
    for (int kt = 0; kt < 32; kt++) {
        if (kt + 1 < 32) asm volatile("cp.async.wait_group 1;");
        else             asm volatile("cp.async.wait_group 0;");
        __syncthreads();
        if (kt + 2 < 32) {
            int nb = buf + 2; if (nb >= 3) nb -= 3;
            load_tiles(nb, kt + 2);
        }
        int so = buf * STG;

        float s[8][4];
        #pragma unroll
        for (int n = 0; n < 8; n++)
            #pragma unroll
            for (int c = 0; c < 4; c++) s[n][c] = 0.f;

        #pragma unroll
        for (int kf = 0; kf < 4; kf++) {
            #pragma unroll
            for (int np = 0; np < 4; np++) {
                uint32_t kd = smem0 + 2*(so + (np*16 + fRow)*KSP + kf*16 + fCol);
                uint32_t kh4[4];
                ldsm_x4(kh4, kd);
                #pragma unroll
                for (int q = 0; q < 2; q++)
                    mma16816(s[np*2+q], qa_h[kf], kh4 + 2*q);
            }
        }

        float mx0 = -1e30f, mx1 = -1e30f;
        #pragma unroll
        for (int n = 0; n < 8; n++) {
            mx0 = fmaxf(mx0, fmaxf(s[n][0], s[n][1]));
            mx1 = fmaxf(mx1, fmaxf(s[n][2], s[n][3]));
        }
        #pragma unroll
        for (int off = 1; off < 4; off <<= 1) {
            mx0 = fmaxf(mx0, __shfl_xor_sync(0xffffffffu, mx0, off));
            mx1 = fmaxf(mx1, __shfl_xor_sync(0xffffffffu, mx1, off));
        }
        float mn0 = fmaxf(m_r[0], mx0), mn1 = fmaxf(m_r[1], mx1);
        float sf0 = __expf(m_r[0] - mn0), sf1 = __expf(m_r[1] - mn1);
        m_r[0] = mn0; m_r[1] = mn1;
        float sum0 = 0.f, sum1 = 0.f;
        #pragma unroll
        for (int n = 0; n < 8; n++) {
            s[n][0] = __expf(s[n][0] - mn0); sum0 += s[n][0];
            s[n][1] = __expf(s[n][1] - mn0); sum0 += s[n][1];
            s[n][2] = __expf(s[n][2] - mn1); sum1 += s[n][2];
            s[n][3] = __expf(s[n][3] - mn1); sum1 += s[n][3];
        }
        #pragma unroll
        for (int off = 1; off < 4; off <<= 1) {
            sum0 += __shfl_xor_sync(0xffffffffu, sum0, off);
            sum1 += __shfl_xor_sync(0xffffffffu, sum1, off);
        }
        l_r[0] = l_r[0]*sf0 + sum0;
        l_r[1] = l_r[1]*sf1 + sum1;
        #pragma unroll
        for (int n = 0; n < 8; n++) {
            o[n][0] *= sf0; o[n][1] *= sf0;
            o[n][2] *= sf1; o[n][3] *= sf1;
        }

        #pragma unroll
        for (int kf2 = 0; kf2 < 4; kf2++) {
            uint32_t pa_h[4];
            #pragma unroll
            for (int q4 = 0; q4 < 2; q4++) {
                int t = 2*kf2 + q4;
                #pragma unroll
                for (int rr = 0; rr < 2; rr++) {
                    pa_h[q4*2+rr] = pack2(__float2half_rn(s[t][rr*2+0]),
                                          __float2half_rn(s[t][rr*2+1]));
                }
            }
            #pragma unroll
            for (int np2 = 0; np2 < 4; np2++) {
                uint32_t vd = smem0 + 2*(so + KTH + (np2*16 + fRow)*VSP + kf2*16 + fCol);
                uint32_t vh4[4];
                ldsm_x4(vh4, vd);
                #pragma unroll
                for (int q = 0; q < 2; q++)
                    mma16816(o[np2*2+q], pa_h, vh4 + 2*q);
            }
        }
        buf++; if (buf >= 3) buf = 0;
    }

    float il0 = 1.f / l_r[0], il1 = 1.f / l_r[1];
    long long r0 = baseO + (long long)(warp*16 + g)*DD;
    long long r8 = r0 + 8*DD;
    #pragma unroll
    for (int n = 0; n < 8; n++) {
        int c = n*8 + 2*tig;
        *(uint32_t*)(Oh + r0 + c) = pack2(__float2half_rn(o[n][0]*il0),
                                          __float2half_rn(o[n][1]*il0));
        *(uint32_t*)(Oh + r8 + c) = pack2(__float2half_rn(o[n][2]*il1),
                                          __float2half_rn(o[n][3]*il1));
    }
}

// ---------------- transpose + cast weights ----------------
__global__ void transpose_cast_kernel(const float* __restrict__ in,
                                      f16* __restrict__ oh,
                                      int rows, int cols, float alpha)
{
    __shared__ float t[32][33];
    long long bo = (long long)blockIdx.z * rows * cols;
    int c0 = blockIdx.x * 32, r0 = blockIdx.y * 32;
    int tx = threadIdx.x, ty = threadIdx.y;
    #pragma unroll
    for (int i = 0; i < 32; i += 8)
        t[ty+i][tx] = in[bo + (long long)(r0+ty+i)*cols + (c0+tx)];
    __syncthreads();
    #pragma unroll
    for (int i = 0; i < 32; i += 8) {
        float v = t[tx][ty+i] * alpha;
        long long o = bo + (long long)(c0+ty+i)*rows + (r0+tx);
        oh[o] = __float2half_rn(v);
    }
}

// ---------------- f16 transpose: V slice of packed qkv -> V^T ----------------
__global__ void transpose_half_kernel(const f16* __restrict__ inh,
                                      f16* __restrict__ oh)
{
    __shared__ unsigned short th[32][33];
    long long ibo = (long long)blockIdx.z * LL * QKV;
    long long obo = (long long)blockIdx.z * DD * LL;
    int c0 = blockIdx.x * 32, r0 = blockIdx.y * 32;
    int tx = threadIdx.x, ty = threadIdx.y;
    #pragma unroll
    for (int i = 0; i < 32; i += 8) {
        long long p = ibo + (long long)(r0+ty+i)*QKV + c0 + tx;
        th[ty+i][tx] = __half_as_ushort(inh[p]);
    }
    __syncthreads();
    #pragma unroll
    for (int i = 0; i < 32; i += 8) {
        long long o = obo + (long long)(c0+ty+i)*LL + r0 + tx;
        oh[o] = __ushort_as_half(th[tx][ty+i]);
    }
}

// ---------------- elementwise cast ----------------
__global__ void cast_kernel(const float* __restrict__ x, f16* __restrict__ oh)
{
    long long i = ((long long)blockIdx.x * 256 + threadIdx.x) * 4;
    float4 v = *(const float4*)(x + i);
    *(uint32_t*)(oh + i)     = pack2(__float2half_rn(v.x), __float2half_rn(v.y));
    *(uint32_t*)(oh + i + 2) = pack2(__float2half_rn(v.z), __float2half_rn(v.w));
}

// ---------------- FFT (radix-4 DIT, n=4096, 512 threads) ----------------
__device__ __forceinline__ int rev4(int i) {
    int r = __brev(i) >> 20;
    return ((r & 0x555) << 1) | ((r >> 1) & 0x555);
}
__device__ __forceinline__ float2 cmulf(float2 a, float2 b) {
    return make_float2(a.x*b.x - a.y*b.y, a.x*b.y + a.y*b.x);
}
__device__ __forceinline__ void tw_init(float2* tw, int tid) {
    for (int m = tid; m < 1024; m += 512) {
        float sv, cv;
        sincosf(-6.283185307179586f * (float)m / 4096.0f, &sv, &cv);
        tw[m] = make_float2(cv, sv);
    }
}

__device__ void do_fft4(float2* s, const float2* tw, int tid) {
    #pragma unroll 1
    for (int st = 0; st < 6; st++) {
        int Q  = 1 << (2*st);
        int sh = 10 - 2*st;
        #pragma unroll 1
        for (int idx = tid; idx < 1024; idx += 512) {
            int j    = idx & (Q - 1);
            int blk  = idx >> (2*st);
            int base = blk*(Q << 2) + j;
            float2 x0 = s[base];
            float2 x1 = s[base + Q];
            float2 x2 = s[base + 2*Q];
            float2 x3 = s[base + 3*Q];
            float2 w1 = tw[j << sh];
            float2 w2 = cmulf(w1, w1);
            float2 w3 = cmulf(w2, w1);
            float2 y1 = cmulf(w1, x1);
            float2 y2 = cmulf(w2, x2);
            float2 y3 = cmulf(w3, x3);
            float2 u0 = make_float2(x0.x + y2.x, x0.y + y2.y);
            float2 u1 = make_float2(x0.x - y2.x, x0.y - y2.y);
            float2 u2 = make_float2(y1.x + y3.x, y1.y + y3.y);
            float2 u3 = make_float2(y1.x - y3.x, y1.y - y3.y);
            s[base]       = make_float2(u0.x + u2.x, u0.y + u2.y);
            s[base + Q]   = make_float2(u1.x + u3.y, u1.y - u3.x);
            s[base + 2*Q] = make_float2(u0.x - u2.x, u0.y - u2.y);
            s[base + 3*Q] = make_float2(u1.x - u3.y, u1.y + u3.x);
        }
        __syncthreads();
    }
}

__global__ void __launch_bounds__(512) filters_kernel(
    const float* __restrict__ eig_vals, const float* __restrict__ eig_vecs,
    const float* __restrict__ w_filters, float2* __restrict__ Ffilt)
{
    __shared__ float2 s[NF4096];
    __shared__ float2 tw[1024];
    __shared__ float  wk[KK];
    int d = blockIdx.x, tid = threadIdx.x;
    if (tid < KK) wk[tid] = powf(eig_vals[tid], 0.25f) * w_filters[tid*DD + d];
    tw_init(tw, tid);
    for (int i = tid; i < NF4096; i += 512) s[i] = make_float2(0.f, 0.f);
    __syncthreads();
    for (int t = tid; t < LL; t += 512) {
        float f = 0.f;
        #pragma unroll
        for (int k = 0; k < KK; k++) f += eig_vecs[t*KK + k] * wk[k];
        s[rev4(t)] = make_float2(f, 0.f);
    }
    __syncthreads();
    do_fft4(s, tw, tid);
    for (int i = tid; i < NF4096; i += 512)
        Ffilt[(long long)d*NF4096 + i] = s[i];
}

// 2-for-1 packed conv with fused gather/scatter
__global__ void __launch_bounds__(512) conv3_kernel(
    const float* __restrict__ xi, const float2* __restrict__ Ffilt,
    float* __restrict__ stu)
{
    __shared__ float2 s[NF4096];
    __shared__ float2 tw[1024];
    int z = blockIdx.x, tid = threadIdx.x;
    int b = z >> 9, dp = z & 511;
    int d0 = 2*dp;
    const float* xib = xi + (long long)b*LL*DD + d0;
    float* stb = stu + (long long)b*LL*DD + d0;
    tw_init(tw, tid);
    for (int i = tid; i < NF4096; i += 512) s[i] = make_float2(0.f, 0.f);
    __syncthreads();
    for (int t = tid; t < LL; t += 512)
        s[rev4(t)] = *(const float2*)(xib + (long long)t*DD);
    __syncthreads();
    do_fft4(s, tw, tid);

    const float2* F0 = Ffilt + (long long)d0 * NF4096;
    const float2* F1 = F0 + NF4096;
    for (int i = tid; i < 2048; i += 512) {
        if (i == 0) {
            #pragma unroll
            for (int q = 0; q < 2; q++) {
                int idx = q * 2048;
                float2 Z = s[idx];
                float X1 = Z.x, X2 = Z.y;
                float2 f0 = F0[idx], f1 = F1[idx];
                float2 Y1 = make_float2(X1*f0.x, X1*f0.y);
                float2 Y2 = make_float2(X2*f1.x, X2*f1.y);
                s[idx] = make_float2(Y1.x - Y2.y, -(Y1.y + Y2.x));
            }
        } else {
            float2 Za = s[i], Zb = s[NF4096 - i];
            float2 X1 = make_float2(0.5f*(Za.x + Zb.x), 0.5f*(Za.y - Zb.y));
            float2 Dd = make_float2(Za.x - Zb.x, Za.y + Zb.y);
            float2 X2 = make_float2(0.5f*Dd.y, -0.5f*Dd.x);
            float2 f0 = F0[i], f1 = F1[i];
            float2 Y1 = make_float2(X1.x*f0.x - X1.y*f0.y, X1.x*f0.y + X1.y*f0.x);
            float2 Y2 = make_float2(X2.x*f1.x - X2.y*f1.y, X2.x*f1.y + X2.y*f1.x);
            s[i]          = make_float2(Y1.x - Y2.y, -(Y1.y + Y2.x));
            s[NF4096 - i] = make_float2(Y1.x + Y2.y, Y1.y - Y2.x);
        }
    }
    __syncthreads();
    float2 r[8];
    #pragma unroll
    for (int k = 0; k < 8; k++) r[k] = s[rev4(tid + k*512)];
    __syncthreads();
    #pragma unroll
    for (int k = 0; k < 8; k++) s[tid + k*512] = r[k];
    __syncthreads();
    do_fft4(s, tw, tid);
    const float inv = 1.0f / 4096.0f;
    for (int l = tid; l < LL; l += 512) {
        float2 w = make_float2(s[l].x * inv, -s[l].y * inv);
        *(float2*)(stb + (long long)l*DD) = w;
    }
}

// ---------------- LayerNorm: cast-fp16 output ----------------
__global__ void __launch_bounds__(256) ln_cast_kernel(
    const float* __restrict__ x, f16* __restrict__ yh,
    const float* __restrict__ sc, const float* __restrict__ bi)
{
    long long base = (long long)blockIdx.x * DD;
    int tid = threadIdx.x;
    float4 v = *(const float4*)(x + base + tid*4);
    float mean = block_sum256(v.x + v.y + v.z + v.w) * (1.0f/DD);
    float dx = v.x - mean, dy = v.y - mean, dz = v.z - mean, dw = v.w - mean;
    float var = block_sum256(dx*dx + dy*dy + dz*dz + dw*dw) * (1.0f/DD);
    float rstd = rsqrtf(var + 1e-6f);
    float4 s4 = *(const float4*)(sc + tid*4);
    float4 b4 = *(const float4*)(bi + tid*4);
    long long i = base + tid*4;
    *(uint32_t*)(yh + i)     = pack2(__float2half_rn(dx*rstd*s4.x + b4.x),
                                     __float2half_rn(dy*rstd*s4.y + b4.y));
    *(uint32_t*)(yh + i + 2) = pack2(__float2half_rn(dz*rstd*s4.z + b4.z),
                                     __float2half_rn(dw*rstd*s4.w + b4.w));
}

// ---------------- launch ----------------
static void* symv(const void* s) { void* p = nullptr; cudaGetSymbolAddress(&p, s); return p; }

extern "C" void kernel_launch(void* const* d_in, const int* in_sizes, int n_in,
                              void* d_out, int out_size)
{
    const float* inputs    = (const float*)d_in[0];
    const float* eig_vals  = (const float*)d_in[1];
    const float* eig_vecs  = (const float*)d_in[2];
    const float* w_filters = (const float*)d_in[3];
    const float* w_inputs  = (const float*)d_in[4];
    const float* ln1_s     = (const float*)d_in[5];
    const float* ln1_b     = (const float*)d_in[6];
    const float* wq        = (const float*)d_in[7];
    const float* wk        = (const float*)d_in[8];
    const float* wv        = (const float*)d_in[9];
    const float* wo        = (const float*)d_in[10];
    const float* ln2_s     = (const float*)d_in[11];
    const float* ln2_b     = (const float*)d_in[12];
    const float* mlp_w1    = (const float*)d_in[13];
    const float* mlp_b1    = (const float*)d_in[14];
    const float* mlp_w2    = (const float*)d_in[15];
    const float* mlp_b2    = (const float*)d_in[16];
    float* out = (float*)d_out;

    float*  xi    = (float*)symv(g_xi);
    float2* Ffilt = (float2*)symv(g_Ffilt);
    float*  stu   = (float*)symv(g_stu);
    float*  xres  = (float*)symv(g_xres);

    f16 *inh=(f16*)symv(g_inh);
    f16 *x1h=(f16*)symv(g_x1h);
    f16 *qkvh=(f16*)symv(g_qkvh);
    f16 *vTh=(f16*)symv(g_vTh);
    f16 *ath=(f16*)symv(g_ath);
    f16 *y1h=(f16*)symv(g_y1h);
    f16 *hh =(f16*)symv(g_hh);
    f16 *wiT=(f16*)symv(g_wiT);
    f16 *wqkvT=(f16*)symv(g_wqkvT);
    f16 *woT=(f16*)symv(g_woT);
    f16 *w1T=(f16*)symv(g_w1T);
    f16 *w2T=(f16*)symv(g_w2T);

    const int SMG1 = 61440;   // 3 x 20480
    const int SMFL = 55296;   // 3 x 18432
    cudaFuncSetAttribute(gemm_fp16,    cudaFuncAttributeMaxDynamicSharedMemorySize, SMG1);
    cudaFuncSetAttribute(flash_kernel, cudaFuncAttributeMaxDynamicSharedMemorySize, SMFL);

    dim3 t328(32, 8);

    // 1. filter spectrum per channel d
    filters_kernel<<<DD, 512>>>(eig_vals, eig_vecs, w_filters, Ffilt);

    // 2. cast inputs; transpose-cast all weights (wq pre-scaled 1/8)
    cast_kernel<<<(BL*DD)/1024, 256>>>(inputs, inh);
    transpose_cast_kernel<<<dim3(32, 32, 1), t328>>>(w_inputs, wiT, DD, DD, 1.0f);
    transpose_cast_kernel<<<dim3(32, 32, 1), t328>>>(wq, wqkvT,           DD, DD, 0.125f);
    transpose_cast_kernel<<<dim3(32, 32, 1), t328>>>(wk, wqkvT + DD*DD,   DD, DD, 1.0f);
    transpose_cast_kernel<<<dim3(32, 32, 1), t328>>>(wv, wqkvT + 2*DD*DD, DD, DD, 1.0f);
    transpose_cast_kernel<<<dim3(32, 32, 1), t328>>>(wo, woT, DD, DD, 1.0f);
    transpose_cast_kernel<<<dim3(MLPD/32, DD/32, 1), t328>>>(mlp_w1, w1T, DD, MLPD, 1.0f);
    transpose_cast_kernel<<<dim3(DD/32, MLPD/32, 1), t328>>>(mlp_w2, w2T, MLPD, DD, 1.0f);

    // 3. xi = inputs @ w_inputs (f32 out for FFT)
    gemm_fp16<<<dim3(8, 64, 1), 256, SMG1>>>(
        inh, wiT, xi, nullptr,
        BL, DD, DD, DD, DD, DD, 1.0f, nullptr, nullptr, 0);

    // 4. spectral causal conv
    conv3_kernel<<<BB*DD/2, 512>>>(xi, Ffilt, stu);

    // 5. LN1 -> cast x1
    ln_cast_kernel<<<BL, 256>>>(stu, x1h, ln1_s, ln1_b);

    // 6. fused QKV gemm (N=3072), cast out
    gemm_fp16<<<dim3(QKV/128, BL/128, 1), 256, SMG1>>>(
        x1h, wqkvT, nullptr, qkvh,
        BL, QKV, DD, DD, DD, QKV, 1.0f, nullptr, nullptr, 8);

    // 7. V^T transpose from packed qkv
    transpose_half_kernel<<<dim3(DD/32, LL/32, BB), t328>>>(qkvh + 2*DD, vTh);

    // 8. fused flash attention -> att (fp16)
    flash_kernel<<<dim3(LL/128, BB*HH), 256, SMFL>>>(qkvh, vTh, ath);

    // 9. x = att @ wo + stu (f32)
    gemm_fp16<<<dim3(8, 64, 1), 256, SMG1>>>(
        ath, woT, xres, nullptr,
        BL, DD, DD, DD, DD, DD, 1.0f, nullptr, stu, 4);

    // 10. LN2 -> cast y1
    ln_cast_kernel<<<BL, 256>>>(xres, y1h, ln2_s, ln2_b);

    // 11. h = gelu(y1 @ w1 + b1), cast out
    gemm_fp16<<<dim3(MLPD/128, 64, 1), 256, SMG1>>>(
        y1h, w1T, nullptr, hh,
        BL, MLPD, DD, DD, DD, MLPD, 1.0f, mlp_b1, nullptr, 11);

    // 12. out = h @ w2 + b2 + x (f32)
    gemm_fp16<<<dim3(8, 64, 1), 256, SMG1>>>(
        hh, w2T, out, nullptr,
        BL, DD, MLPD, MLPD, MLPD, DD, 1.0f, mlp_b2, xres, 5);
}